// round 2
// baseline (speedup 1.0000x reference)
#include <cuda_runtime.h>

#define BB 32
#define CC 512
#define LL 16
#define DD 256
#define HH 1024
#define PP 16
#define NHD 8
#define NLL 4

// ---------------- scratch (static device globals; allocation-free) ----------------
__device__ float g_x [BB*CC*DD];          // 16 MB  [B*C, D]
__device__ float g_t0[BB*CC*HH];          // 64 MB  qkv(768) / ff1(1024)
__device__ float g_t1[BB*CC*DD];          // 16 MB  attn concat
__device__ float g_t2[BB*CC*DD];          // 16 MB  proj out / ln tmp
__device__ float g_S [67108864];          // 268 MB [B, NH, C, C] scores
__device__ float g_ch[BB*CC*HH];          // 64 MB
__device__ float g_kp[BB*CC*HH];          // 64 MB
__device__ float g_vp[BB*CC*HH];          // 64 MB
__device__ float g_qh[PP*HH];
__device__ float g_S2[BB*NHD*PP*CC];      // 8 MB
__device__ float g_p1[BB*PP*HH];
__device__ float g_p2[BB*PP*HH];
__device__ int   g_maskmode;              // 0 = int32 mask, 1 = byte mask

// ---------------- mask dtype detection (deterministic) ----------------
__global__ void detect_mask_kernel(const int* __restrict__ m) {
    // int32-bool buffers contain only words 0 or 1. Byte-packed bools read as
    // int32 give words like 0x01010101. Any word outside {0,1} => byte mode.
    __shared__ int found;
    if (threadIdx.x == 0) found = 0;
    __syncthreads();
    int idx = blockIdx.x * blockDim.x + threadIdx.x;   // 4096 words scanned
    unsigned v = (unsigned)m[idx];
    if (v > 1u) found = 1;
    __syncthreads();
    if (threadIdx.x == 0 && blockIdx.x == 0) g_maskmode = 0;  // default
    __threadfence();
    if (found) g_maskmode = 1;
}

// ---------------- pool: literal embed gathers + masked mean ----------------
__global__ void pool_kernel(const int* __restrict__ vi, const int* __restrict__ si,
                            const void* __restrict__ maskraw,
                            const float* __restrict__ ve, const float* __restrict__ se,
                            const float* __restrict__ lpe, const float* __restrict__ cpe,
                            float* __restrict__ x) {
    int bc = blockIdx.x;            // 0..B*C-1
    int c  = bc % CC;
    int d  = threadIdx.x;           // 256 = D
    const int* viR = vi + bc * LL;
    const int* siR = si + bc * LL;
    __shared__ int mloc[LL];
    if (threadIdx.x < LL) {
        int mv;
        if (g_maskmode == 0) mv = ((const int*)maskraw)[bc * LL + threadIdx.x];
        else                 mv = ((const unsigned char*)maskraw)[bc * LL + threadIdx.x];
        mloc[threadIdx.x] = mv;
    }
    __syncthreads();
    float acc = 0.f; int cnt = 0;
    #pragma unroll
    for (int l = 0; l < LL; l++) {
        if (mloc[l]) {
            cnt++;
            acc += ve[viR[l]*DD + d] + se[siR[l]*DD + d] + lpe[l*DD + d];
        }
    }
    x[(size_t)bc*DD + d] = acc / (float)cnt + cpe[c*DD + d];
}

// ---------------- layernorm (+ optional residual), block per row ----------------
__global__ void ln_kernel(const float* __restrict__ xin, const float* __restrict__ res,
                          const float* __restrict__ w, const float* __restrict__ b,
                          float* __restrict__ out, int N, int resMod) {
    int row = blockIdx.x;
    int tid = threadIdx.x;          // 256
    const float* xr = xin + (size_t)row * N;
    const float* rr = nullptr;
    if (res) rr = res + (size_t)(resMod ? (row % resMod) : row) * N;
    int per = N >> 8;               // N/256 : 1 or 4
    float v[4];
    float s = 0.f;
    for (int i = 0; i < per; i++) {
        int cI = tid + (i << 8);
        float t = xr[cI];
        if (rr) t += rr[cI];
        v[i] = t; s += t;
    }
    __shared__ float red[256];
    red[tid] = s; __syncthreads();
    for (int o = 128; o; o >>= 1) { if (tid < o) red[tid] += red[tid+o]; __syncthreads(); }
    float mean = red[0] / (float)N;
    __syncthreads();
    float vs = 0.f;
    for (int i = 0; i < per; i++) { float d = v[i] - mean; vs += d*d; }
    red[tid] = vs; __syncthreads();
    for (int o = 128; o; o >>= 1) { if (tid < o) red[tid] += red[tid+o]; __syncthreads(); }
    float inv = rsqrtf(red[0] / (float)N + 1e-5f);
    for (int i = 0; i < per; i++) {
        int cI = tid + (i << 8);
        out[(size_t)row*N + cI] = (v[i] - mean) * inv * w[cI] + b[cI];
    }
}

// ---------------- softmax over last dim (512), warp per row ----------------
__global__ void softmax_kernel(float* __restrict__ S, int cols) {
    int row  = blockIdx.x * 8 + (threadIdx.x >> 5);
    int lane = threadIdx.x & 31;
    float* r = S + (size_t)row * cols;
    int per = cols >> 5;            // 16
    float vals[16];
    float mx = -1e30f;
    for (int t = 0; t < per; t++) { vals[t] = r[lane + (t<<5)]; mx = fmaxf(mx, vals[t]); }
    for (int o = 16; o; o >>= 1) mx = fmaxf(mx, __shfl_xor_sync(0xffffffffu, mx, o));
    float sum = 0.f;
    for (int t = 0; t < per; t++) { vals[t] = __expf(vals[t] - mx); sum += vals[t]; }
    for (int o = 16; o; o >>= 1) sum += __shfl_xor_sync(0xffffffffu, sum, o);
    float inv = 1.f / sum;
    for (int t = 0; t < per; t++) r[lane + (t<<5)] = vals[t] * inv;
}

// ---------------- generic strided-batched SGEMM: C = act(alpha*A@W^T + bias) --------
__device__ __forceinline__ float gelu_f(float v) {
    return 0.5f * v * (1.f + erff(v * 0.70710678118654752f));
}

template<int BM, int BN, int BK, int TM, int TN, int ACT, int TRW, int HASB>
__global__ void gemm_kernel(const float* __restrict__ A, const float* __restrict__ W,
                            const float* __restrict__ bias, float* __restrict__ Cp,
                            int M, int N, int K, int lda, int ldw, int ldc,
                            int nsub, long sAb, long sAs, long sWb, long sWs,
                            long sCb, long sCs, float alpha) {
    constexpr int NT = (BM/TM)*(BN/TN);
    __shared__ float As[BK][BM];
    __shared__ float Ws[BK][BN];
    int tid = threadIdx.x;
    int tx = tid % (BN/TN);
    int ty = tid / (BN/TN);
    int bm = blockIdx.y * BM;
    int bn = blockIdx.x * BN;
    int z  = blockIdx.z;
    int zb = z / nsub, zs = z % nsub;
    const float* Ab = A + (size_t)zb*sAb + (size_t)zs*sAs;
    const float* Wb = W + (size_t)zb*sWb + (size_t)zs*sWs;
    float*       Cb = Cp + (size_t)zb*sCb + (size_t)zs*sCs;

    float acc[TM][TN];
    #pragma unroll
    for (int i = 0; i < TM; i++)
        #pragma unroll
        for (int j = 0; j < TN; j++) acc[i][j] = 0.f;

    for (int k0 = 0; k0 < K; k0 += BK) {
        for (int idx = tid; idx < BM*BK/4; idx += NT) {
            int arow = idx / (BK/4);
            int kq   = (idx % (BK/4)) * 4;
            float4 a4 = make_float4(0.f,0.f,0.f,0.f);
            int gm = bm + arow;
            if (gm < M) a4 = *reinterpret_cast<const float4*>(Ab + (size_t)gm*lda + k0 + kq);
            As[kq+0][arow]=a4.x; As[kq+1][arow]=a4.y; As[kq+2][arow]=a4.z; As[kq+3][arow]=a4.w;
        }
        if (!TRW) {
            for (int idx = tid; idx < BN*BK/4; idx += NT) {
                int nrow = idx / (BK/4);
                int kq   = (idx % (BK/4)) * 4;
                float4 w4 = *reinterpret_cast<const float4*>(Wb + (size_t)(bn+nrow)*ldw + k0 + kq);
                Ws[kq+0][nrow]=w4.x; Ws[kq+1][nrow]=w4.y; Ws[kq+2][nrow]=w4.z; Ws[kq+3][nrow]=w4.w;
            }
        } else {
            for (int idx = tid; idx < BK*BN/4; idx += NT) {
                int krow = idx / (BN/4);
                int nq   = (idx % (BN/4)) * 4;
                float4 w4 = *reinterpret_cast<const float4*>(Wb + (size_t)(k0+krow)*ldw + bn + nq);
                Ws[krow][nq+0]=w4.x; Ws[krow][nq+1]=w4.y; Ws[krow][nq+2]=w4.z; Ws[krow][nq+3]=w4.w;
            }
        }
        __syncthreads();
        #pragma unroll
        for (int kk = 0; kk < BK; kk++) {
            float ra[TM], rb[TN];
            #pragma unroll
            for (int i = 0; i < TM; i++) ra[i] = As[kk][ty*TM+i];
            #pragma unroll
            for (int j = 0; j < TN; j++) rb[j] = Ws[kk][tx*TN+j];
            #pragma unroll
            for (int i = 0; i < TM; i++)
                #pragma unroll
                for (int j = 0; j < TN; j++) acc[i][j] += ra[i]*rb[j];
        }
        __syncthreads();
    }
    #pragma unroll
    for (int i = 0; i < TM; i++) {
        int m = bm + ty*TM + i;
        if (m >= M) continue;
        #pragma unroll
        for (int j = 0; j < TN; j++) {
            int n = bn + tx*TN + j;
            float v = acc[i][j] * alpha;
            if (HASB) v += bias[n];
            if (ACT)  v = gelu_f(v);
            Cb[(size_t)m*ldc + n] = v;
        }
    }
}

// instantiation aliases
#define GEMM_MAIN  gemm_kernel<128,128,8,8,8,0,0,1>
#define GEMM_GELU  gemm_kernel<128,128,8,8,8,1,0,1>
#define GEMM_NOB   gemm_kernel<128,128,8,8,8,0,0,0>
#define GEMM_AV    gemm_kernel<128, 32,8,8,4,0,1,0>

extern "C" void kernel_launch(void* const* d_in, const int* in_sizes, int n_in,
                              void* d_out, int out_size) {
    const int*   var_idx   = (const int*)  d_in[0];
    const int*   sign_idx  = (const int*)  d_in[1];
    const void*  lit_mask  = (const void*) d_in[2];
    const float* var_emb   = (const float*)d_in[3];
    const float* sign_emb  = (const float*)d_in[4];
    const float* litpos    = (const float*)d_in[5];
    const float* clausepos = (const float*)d_in[6];
    const float* enc_in_w  = (const float*)d_in[7];
    const float* enc_in_b  = (const float*)d_in[8];
    const float* enc_out_w = (const float*)d_in[9];
    const float* enc_out_b = (const float*)d_in[10];
    const float* enc_ff1_w = (const float*)d_in[11];
    const float* enc_ff1_b = (const float*)d_in[12];
    const float* enc_ff2_w = (const float*)d_in[13];
    const float* enc_ff2_b = (const float*)d_in[14];
    const float* n1w = (const float*)d_in[15];
    const float* n1b = (const float*)d_in[16];
    const float* n2w = (const float*)d_in[17];
    const float* n2b = (const float*)d_in[18];
    const float* th_ln_w = (const float*)d_in[19];
    const float* th_ln_b = (const float*)d_in[20];
    const float* th_w = (const float*)d_in[21];
    const float* th_b = (const float*)d_in[22];
    const float* pq   = (const float*)d_in[23];
    const float* pa_in_w  = (const float*)d_in[24];
    const float* pa_in_b  = (const float*)d_in[25];
    const float* pa_out_w = (const float*)d_in[26];
    const float* pa_out_b = (const float*)d_in[27];
    const float* pn_w = (const float*)d_in[28];
    const float* pn_b = (const float*)d_in[29];
    float* out = (float*)d_out;

    float *x,*t0,*t1,*t2,*S,*ch,*kp,*vp,*qh,*S2,*p1,*p2;
    cudaGetSymbolAddress((void**)&x,  g_x);
    cudaGetSymbolAddress((void**)&t0, g_t0);
    cudaGetSymbolAddress((void**)&t1, g_t1);
    cudaGetSymbolAddress((void**)&t2, g_t2);
    cudaGetSymbolAddress((void**)&S,  g_S);
    cudaGetSymbolAddress((void**)&ch, g_ch);
    cudaGetSymbolAddress((void**)&kp, g_kp);
    cudaGetSymbolAddress((void**)&vp, g_vp);
    cudaGetSymbolAddress((void**)&qh, g_qh);
    cudaGetSymbolAddress((void**)&S2, g_S2);
    cudaGetSymbolAddress((void**)&p1, g_p1);
    cudaGetSymbolAddress((void**)&p2, g_p2);

    const int M = BB*CC;               // 16384
    const float escale = 0.17677669529663687f;   // 1/sqrt(32)
    const float pscale = 0.08838834764831845f;   // 1/sqrt(128)

    // 0) detect mask element width (int32 vs byte), then
    // 1) embed + masked mean pool -> x [M, 256]
    detect_mask_kernel<<<16, 256>>>((const int*)lit_mask);
    pool_kernel<<<M, 256>>>(var_idx, sign_idx, lit_mask, var_emb, sign_emb,
                            litpos, clausepos, x);

    // 2) encoder layers
    for (int i = 0; i < NLL; i++) {
        const float* wqkv = enc_in_w  + (size_t)i*768*DD;
        const float* bqkv = enc_in_b  + (size_t)i*768;
        const float* wo   = enc_out_w + (size_t)i*DD*DD;
        const float* bo   = enc_out_b + (size_t)i*DD;
        const float* w1   = enc_ff1_w + (size_t)i*HH*DD;
        const float* b1   = enc_ff1_b + (size_t)i*HH;
        const float* w2   = enc_ff2_w + (size_t)i*DD*HH;
        const float* b2   = enc_ff2_b + (size_t)i*DD;

        // qkv = x @ Wqkv^T + b  -> t0 [M, 768]
        GEMM_MAIN<<<dim3(6,128,1),256>>>(x, wqkv, bqkv, t0, M,768,DD,
                                         DD,DD,768, 1,0,0,0,0,0,0, 1.f);
        // scores: per (b,h): S = (q @ k^T) * scale   [512,512], K=32
        GEMM_NOB<<<dim3(4,4,BB*NHD),256>>>(t0, t0+DD, nullptr, S, CC,CC,32,
                                           768,768,CC, NHD,
                                           (long)CC*768, 32, (long)CC*768, 32,
                                           (long)NHD*CC*CC, (long)CC*CC, escale);
        softmax_kernel<<<(BB*NHD*CC)/8, 256>>>(S, CC);
        // AV: per (b,h): t1 slice = P @ V   [512,32], K=512 (V transposed access)
        GEMM_AV<<<dim3(1,4,BB*NHD),128>>>(S, t0+2*DD, nullptr, t1, CC,32,CC,
                                          CC,768,DD, NHD,
                                          (long)NHD*CC*CC, (long)CC*CC,
                                          (long)CC*768, 32,
                                          (long)CC*DD, 32, 1.f);
        // out proj -> t2
        GEMM_MAIN<<<dim3(2,128,1),256>>>(t1, wo, bo, t2, M,DD,DD,
                                         DD,DD,DD, 1,0,0,0,0,0,0, 1.f);
        // x = LN(x + attn)
        ln_kernel<<<M,256>>>(t2, x, n1w + i*DD, n1b + i*DD, x, DD, 0);
        // ff1 (gelu) -> t0 [M,1024]
        GEMM_GELU<<<dim3(8,128,1),256>>>(x, w1, b1, t0, M,HH,DD,
                                         DD,DD,HH, 1,0,0,0,0,0,0, 1.f);
        // ff2 -> t2
        GEMM_MAIN<<<dim3(2,128,1),256>>>(t0, w2, b2, t2, M,DD,HH,
                                         HH,HH,DD, 1,0,0,0,0,0,0, 1.f);
        // x = LN(x + ff)
        ln_kernel<<<M,256>>>(t2, x, n2w + i*DD, n2b + i*DD, x, DD, 0);
    }

    // 3) ch = LN(x) @ th_w^T + th_b   [M, 1024]
    ln_kernel<<<M,256>>>(x, nullptr, th_ln_w, th_ln_b, t2, DD, 0);
    GEMM_MAIN<<<dim3(8,128,1),256>>>(t2, th_w, th_b, ch, M,HH,DD,
                                     DD,DD,HH, 1,0,0,0,0,0,0, 1.f);

    // 4) prefix cross-attention
    // qh = pq @ wq^T + bq  [16, 1024]
    GEMM_MAIN<<<dim3(8,1,1),256>>>(pq, pa_in_w, pa_in_b, qh, PP,HH,HH,
                                   HH,HH,HH, 1,0,0,0,0,0,0, 1.f);
    // kp, vp = ch @ wk^T, ch @ wv^T
    GEMM_MAIN<<<dim3(8,128,1),256>>>(ch, pa_in_w + (size_t)HH*HH, pa_in_b + HH, kp,
                                     M,HH,HH, HH,HH,HH, 1,0,0,0,0,0,0, 1.f);
    GEMM_MAIN<<<dim3(8,128,1),256>>>(ch, pa_in_w + (size_t)2*HH*HH, pa_in_b + 2*HH, vp,
                                     M,HH,HH, HH,HH,HH, 1,0,0,0,0,0,0, 1.f);
    // scores2: per (b,h): [16,512], K=128
    GEMM_NOB<<<dim3(4,1,BB*NHD),256>>>(qh, kp, nullptr, S2, PP,CC,128,
                                       HH,HH,CC, NHD,
                                       0L, 128L, (long)CC*HH, 128L,
                                       (long)NHD*PP*CC, (long)PP*CC, pscale);
    softmax_kernel<<<(BB*NHD*PP)/8, 256>>>(S2, CC);
    // AV2: per (b,h): [16,128], K=512
    GEMM_AV<<<dim3(4,1,BB*NHD),128>>>(S2, vp, nullptr, p1, PP,128,CC,
                                      CC,HH,HH, NHD,
                                      (long)NHD*PP*CC, (long)PP*CC,
                                      (long)CC*HH, 128L,
                                      (long)PP*HH, 128L, 1.f);
    // out proj
    GEMM_MAIN<<<dim3(8,4,1),256>>>(p1, pa_out_w, pa_out_b, p2, BB*PP,HH,HH,
                                   HH,HH,HH, 1,0,0,0,0,0,0, 1.f);
    // 5) out = LN(p2 + pq_broadcast)
    ln_kernel<<<BB*PP,256>>>(p2, pq, pn_w, pn_b, out, HH, PP);
}

// round 4
// speedup vs baseline: 2.2864x; 2.2864x over previous
#include <cuda_runtime.h>
#include <cstdint>

#define BB 32
#define CC 512
#define LL 16
#define DD 256
#define HH 1024
#define PP 16
#define NHD 8
#define NLL 4

// ---------------- scratch (static device globals; allocation-free) ----------------
__device__ float g_x [BB*CC*DD];
__device__ float g_t0[BB*CC*HH];
__device__ float g_t1[BB*CC*DD];
__device__ float g_t2[BB*CC*DD];
__device__ float g_S [67108864];          // [B, NH, C, C]
__device__ float g_ch[BB*CC*HH];
__device__ float g_kp[BB*CC*HH];
__device__ float g_vp[BB*CC*HH];
__device__ float g_qh[PP*HH];
__device__ float g_S2[BB*NHD*PP*CC];
__device__ float g_p1[BB*PP*HH];
__device__ float g_p2[BB*PP*HH];
__device__ int   g_maskmode;

// ---------------- small helpers ----------------
__device__ __forceinline__ uint32_t f2tf32(float f) {
    uint32_t u; asm("cvt.rna.tf32.f32 %0, %1;" : "=r"(u) : "f"(f)); return u;
}
__device__ __forceinline__ float gelu_f(float v) {
    return 0.5f * v * (1.f + erff(v * 0.70710678118654752f));
}
__device__ __forceinline__ void mma_tf32(float* c, const uint32_t* a, const uint32_t* b) {
    asm volatile(
        "mma.sync.aligned.m16n8k8.row.col.f32.tf32.tf32.f32 "
        "{%0,%1,%2,%3}, {%4,%5,%6,%7}, {%8,%9}, {%0,%1,%2,%3};"
        : "+f"(c[0]), "+f"(c[1]), "+f"(c[2]), "+f"(c[3])
        : "r"(a[0]), "r"(a[1]), "r"(a[2]), "r"(a[3]), "r"(b[0]), "r"(b[1]));
}

// ============================ tf32 mma.sync GEMM ============================
// C[m,n] = act(alpha * sum_k A[m,k] * B(k,n) + bias[n])
// TRB=0: B given as W[N,K] row-major; TRB=1: B given as [K,N] row-major.
template<int BN, int TRB, int ACT, int HASB>
__global__ __launch_bounds__(256, 2) void mma_gemm(
    const float* __restrict__ A, const float* __restrict__ W,
    const float* __restrict__ bias, float* __restrict__ Cp,
    int M, int N, int K, int lda, int ldw, int ldc,
    int nsub, long sAb, long sAs, long sWb, long sWs, long sCb, long sCs,
    float alpha)
{
    constexpr int BM = 128, BK = 32;
    constexpr int LDSR = BK + 4;                 // 36: padded k-stride
    constexpr int WN = (BN == 128) ? 32 : 8;     // warp n-tile
    constexpr int MI = 4;                        // 64/16 m-frags per warp
    constexpr int NJ = WN / 8;                   // n-frags per warp

    __shared__ uint32_t As[BM * LDSR];
    __shared__ uint32_t Ws[BN * LDSR];

    int tid = threadIdx.x, wid = tid >> 5, lane = tid & 31;
    int warpM = wid >> 2;                        // 0..1
    int warpN = wid & 3;                         // 0..3
    int g = lane >> 2, tg = lane & 3;

    int bm = blockIdx.y * BM;
    int bn = blockIdx.x * BN;
    int z = blockIdx.z;
    int zb = z / nsub, zs = z % nsub;
    const float* Ab = A + (size_t)zb * sAb + (size_t)zs * sAs;
    const float* Wb = W + (size_t)zb * sWb + (size_t)zs * sWs;
    float*       Cb = Cp + (size_t)zb * sCb + (size_t)zs * sCs;

    float acc[MI][NJ][4];
    #pragma unroll
    for (int i = 0; i < MI; i++)
        #pragma unroll
        for (int j = 0; j < NJ; j++)
            #pragma unroll
            for (int q = 0; q < 4; q++) acc[i][j][q] = 0.f;

    for (int k0 = 0; k0 < K; k0 += BK) {
        // ---- load A tile [BM x BK] (tf32-converted, padded) ----
        #pragma unroll
        for (int idx = tid; idx < BM * (BK / 4); idx += 256) {
            int row = idx >> 3, q = idx & 7;
            int gm = bm + row;
            if (gm < M) {
                float4 v = *(const float4*)(Ab + (size_t)gm * lda + k0 + q * 4);
                uint32_t* p = &As[row * LDSR + q * 4];
                p[0] = f2tf32(v.x); p[1] = f2tf32(v.y); p[2] = f2tf32(v.z); p[3] = f2tf32(v.w);
            }
        }
        // ---- load B tile as Ws[n][k] ----
        if (!TRB) {
            #pragma unroll
            for (int idx = tid; idx < BN * (BK / 4); idx += 256) {
                int row = idx >> 3, q = idx & 7;
                float4 v = *(const float4*)(Wb + (size_t)(bn + row) * ldw + k0 + q * 4);
                uint32_t* p = &Ws[row * LDSR + q * 4];
                p[0] = f2tf32(v.x); p[1] = f2tf32(v.y); p[2] = f2tf32(v.z); p[3] = f2tf32(v.w);
            }
        } else {
            #pragma unroll
            for (int idx = tid; idx < (BK * BN) / 4; idx += 256) {
                int kk = idx / (BN / 4);
                int n4 = (idx % (BN / 4)) * 4;
                float4 v = *(const float4*)(Wb + (size_t)(k0 + kk) * ldw + bn + n4);
                Ws[(n4 + 0) * LDSR + kk] = f2tf32(v.x);
                Ws[(n4 + 1) * LDSR + kk] = f2tf32(v.y);
                Ws[(n4 + 2) * LDSR + kk] = f2tf32(v.z);
                Ws[(n4 + 3) * LDSR + kk] = f2tf32(v.w);
            }
        }
        __syncthreads();

        // ---- compute ----
        #pragma unroll
        for (int kk = 0; kk < BK; kk += 8) {
            uint32_t af[MI][4], bf[NJ][2];
            #pragma unroll
            for (int mi = 0; mi < MI; mi++) {
                int r0 = warpM * 64 + mi * 16 + g;
                af[mi][0] = As[r0 * LDSR + kk + tg];
                af[mi][1] = As[(r0 + 8) * LDSR + kk + tg];
                af[mi][2] = As[r0 * LDSR + kk + tg + 4];
                af[mi][3] = As[(r0 + 8) * LDSR + kk + tg + 4];
            }
            #pragma unroll
            for (int nj = 0; nj < NJ; nj++) {
                int c0 = warpN * WN + nj * 8 + g;
                bf[nj][0] = Ws[c0 * LDSR + kk + tg];
                bf[nj][1] = Ws[c0 * LDSR + kk + tg + 4];
            }
            #pragma unroll
            for (int mi = 0; mi < MI; mi++)
                #pragma unroll
                for (int nj = 0; nj < NJ; nj++)
                    mma_tf32(acc[mi][nj], af[mi], bf[nj]);
        }
        __syncthreads();
    }

    // ---- epilogue: alpha, bias, gelu ----
    #pragma unroll
    for (int mi = 0; mi < MI; mi++) {
        int r0 = bm + warpM * 64 + mi * 16 + g;
        #pragma unroll
        for (int nj = 0; nj < NJ; nj++) {
            int c = bn + warpN * WN + nj * 8 + 2 * tg;
            float b0 = 0.f, b1 = 0.f;
            if (HASB) { b0 = bias[c]; b1 = bias[c + 1]; }
            if (r0 < M) {
                float v0 = acc[mi][nj][0] * alpha + b0;
                float v1 = acc[mi][nj][1] * alpha + b1;
                if (ACT) { v0 = gelu_f(v0); v1 = gelu_f(v1); }
                Cb[(size_t)r0 * ldc + c]     = v0;
                Cb[(size_t)r0 * ldc + c + 1] = v1;
            }
            if (r0 + 8 < M) {
                float v2 = acc[mi][nj][2] * alpha + b0;
                float v3 = acc[mi][nj][3] * alpha + b1;
                if (ACT) { v2 = gelu_f(v2); v3 = gelu_f(v3); }
                Cb[(size_t)(r0 + 8) * ldc + c]     = v2;
                Cb[(size_t)(r0 + 8) * ldc + c + 1] = v3;
            }
        }
    }
}

// ---------------- mask dtype detection ----------------
__global__ void detect_mask_kernel(const int* __restrict__ m) {
    __shared__ int found;
    if (threadIdx.x == 0) found = 0;
    __syncthreads();
    int idx = blockIdx.x * blockDim.x + threadIdx.x;
    unsigned v = (unsigned)m[idx];
    if (v > 1u) found = 1;
    __syncthreads();
    if (threadIdx.x == 0 && blockIdx.x == 0) g_maskmode = 0;
    __threadfence();
    if (found) g_maskmode = 1;
}

// ---------------- pool ----------------
__global__ void pool_kernel(const int* __restrict__ vi, const int* __restrict__ si,
                            const void* __restrict__ maskraw,
                            const float* __restrict__ ve, const float* __restrict__ se,
                            const float* __restrict__ lpe, const float* __restrict__ cpe,
                            float* __restrict__ x) {
    int bc = blockIdx.x;
    int c  = bc % CC;
    int d  = threadIdx.x;
    const int* viR = vi + bc * LL;
    const int* siR = si + bc * LL;
    __shared__ int mloc[LL];
    if (threadIdx.x < LL) {
        int mv;
        if (g_maskmode == 0) mv = ((const int*)maskraw)[bc * LL + threadIdx.x];
        else                 mv = ((const unsigned char*)maskraw)[bc * LL + threadIdx.x];
        mloc[threadIdx.x] = mv;
    }
    __syncthreads();
    float acc = 0.f; int cnt = 0;
    #pragma unroll
    for (int l = 0; l < LL; l++) {
        if (mloc[l]) {
            cnt++;
            acc += ve[viR[l]*DD + d] + se[siR[l]*DD + d] + lpe[l*DD + d];
        }
    }
    x[(size_t)bc*DD + d] = acc / (float)cnt + cpe[c*DD + d];
}

// ---------------- layernorm ----------------
__global__ void ln_kernel(const float* __restrict__ xin, const float* __restrict__ res,
                          const float* __restrict__ w, const float* __restrict__ b,
                          float* __restrict__ out, int N, int resMod) {
    int row = blockIdx.x;
    int tid = threadIdx.x;
    const float* xr = xin + (size_t)row * N;
    const float* rr = nullptr;
    if (res) rr = res + (size_t)(resMod ? (row % resMod) : row) * N;
    int per = N >> 8;
    float v[4];
    float s = 0.f;
    for (int i = 0; i < per; i++) {
        int cI = tid + (i << 8);
        float t = xr[cI];
        if (rr) t += rr[cI];
        v[i] = t; s += t;
    }
    __shared__ float red[256];
    red[tid] = s; __syncthreads();
    for (int o = 128; o; o >>= 1) { if (tid < o) red[tid] += red[tid+o]; __syncthreads(); }
    float mean = red[0] / (float)N;
    __syncthreads();
    float vs = 0.f;
    for (int i = 0; i < per; i++) { float d = v[i] - mean; vs += d*d; }
    red[tid] = vs; __syncthreads();
    for (int o = 128; o; o >>= 1) { if (tid < o) red[tid] += red[tid+o]; __syncthreads(); }
    float inv = rsqrtf(red[0] / (float)N + 1e-5f);
    for (int i = 0; i < per; i++) {
        int cI = tid + (i << 8);
        out[(size_t)row*N + cI] = (v[i] - mean) * inv * w[cI] + b[cI];
    }
}

// ---------------- softmax ----------------
__global__ void softmax_kernel(float* __restrict__ S, int cols) {
    int row  = blockIdx.x * 8 + (threadIdx.x >> 5);
    int lane = threadIdx.x & 31;
    float* r = S + (size_t)row * cols;
    int per = cols >> 5;
    float vals[16];
    float mx = -1e30f;
    for (int t = 0; t < per; t++) { vals[t] = r[lane + (t<<5)]; mx = fmaxf(mx, vals[t]); }
    for (int o = 16; o; o >>= 1) mx = fmaxf(mx, __shfl_xor_sync(0xffffffffu, mx, o));
    float sum = 0.f;
    for (int t = 0; t < per; t++) { vals[t] = __expf(vals[t] - mx); sum += vals[t]; }
    for (int o = 16; o; o >>= 1) sum += __shfl_xor_sync(0xffffffffu, sum, o);
    float inv = 1.f / sum;
    for (int t = 0; t < per; t++) r[lane + (t<<5)] = vals[t] * inv;
}

// ============================ host orchestration ============================
#define TCG_B   mma_gemm<128,0,0,1>
#define TCG_G   mma_gemm<128,0,1,1>
#define TCG_N   mma_gemm<128,0,0,0>
#define TCG_AV  mma_gemm<32,1,0,0>

extern "C" void kernel_launch(void* const* d_in, const int* in_sizes, int n_in,
                              void* d_out, int out_size) {
    const int*   var_idx   = (const int*)  d_in[0];
    const int*   sign_idx  = (const int*)  d_in[1];
    const void*  lit_mask  = (const void*) d_in[2];
    const float* var_emb   = (const float*)d_in[3];
    const float* sign_emb  = (const float*)d_in[4];
    const float* litpos    = (const float*)d_in[5];
    const float* clausepos = (const float*)d_in[6];
    const float* enc_in_w  = (const float*)d_in[7];
    const float* enc_in_b  = (const float*)d_in[8];
    const float* enc_out_w = (const float*)d_in[9];
    const float* enc_out_b = (const float*)d_in[10];
    const float* enc_ff1_w = (const float*)d_in[11];
    const float* enc_ff1_b = (const float*)d_in[12];
    const float* enc_ff2_w = (const float*)d_in[13];
    const float* enc_ff2_b = (const float*)d_in[14];
    const float* n1w = (const float*)d_in[15];
    const float* n1b = (const float*)d_in[16];
    const float* n2w = (const float*)d_in[17];
    const float* n2b = (const float*)d_in[18];
    const float* th_ln_w = (const float*)d_in[19];
    const float* th_ln_b = (const float*)d_in[20];
    const float* th_w = (const float*)d_in[21];
    const float* th_b = (const float*)d_in[22];
    const float* pq   = (const float*)d_in[23];
    const float* pa_in_w  = (const float*)d_in[24];
    const float* pa_in_b  = (const float*)d_in[25];
    const float* pa_out_w = (const float*)d_in[26];
    const float* pa_out_b = (const float*)d_in[27];
    const float* pn_w = (const float*)d_in[28];
    const float* pn_b = (const float*)d_in[29];
    float* out = (float*)d_out;

    float *x,*t0,*t1,*t2,*S,*ch,*kp,*vp,*qh,*S2,*p1,*p2;
    cudaGetSymbolAddress((void**)&x,  g_x);
    cudaGetSymbolAddress((void**)&t0, g_t0);
    cudaGetSymbolAddress((void**)&t1, g_t1);
    cudaGetSymbolAddress((void**)&t2, g_t2);
    cudaGetSymbolAddress((void**)&S,  g_S);
    cudaGetSymbolAddress((void**)&ch, g_ch);
    cudaGetSymbolAddress((void**)&kp, g_kp);
    cudaGetSymbolAddress((void**)&vp, g_vp);
    cudaGetSymbolAddress((void**)&qh, g_qh);
    cudaGetSymbolAddress((void**)&S2, g_S2);
    cudaGetSymbolAddress((void**)&p1, g_p1);
    cudaGetSymbolAddress((void**)&p2, g_p2);

    const int M = BB*CC;
    const float escale = 0.17677669529663687f;   // 1/sqrt(32)
    const float pscale = 0.08838834764831845f;   // 1/sqrt(128)

    detect_mask_kernel<<<16, 256>>>((const int*)lit_mask);
    pool_kernel<<<M, 256>>>(var_idx, sign_idx, lit_mask, var_emb, sign_emb,
                            litpos, clausepos, x);

    for (int i = 0; i < NLL; i++) {
        const float* wqkv = enc_in_w  + (size_t)i*768*DD;
        const float* bqkv = enc_in_b  + (size_t)i*768;
        const float* wo   = enc_out_w + (size_t)i*DD*DD;
        const float* bo   = enc_out_b + (size_t)i*DD;
        const float* w1   = enc_ff1_w + (size_t)i*HH*DD;
        const float* b1   = enc_ff1_b + (size_t)i*HH;
        const float* w2   = enc_ff2_w + (size_t)i*DD*HH;
        const float* b2   = enc_ff2_b + (size_t)i*DD;

        // qkv = x @ Wqkv^T + b -> t0 [M,768]
        TCG_B<<<dim3(6,128,1),256>>>(x, wqkv, bqkv, t0, M,768,DD,
                                     DD,DD,768, 1,0,0,0,0,0,0, 1.f);
        // scores per (b,h): [512,512], K=32
        TCG_N<<<dim3(4,4,BB*NHD),256>>>(t0, t0+DD, nullptr, S, CC,CC,32,
                                        768,768,CC, NHD,
                                        (long)CC*768, 32, (long)CC*768, 32,
                                        (long)NHD*CC*CC, (long)CC*CC, escale);
        softmax_kernel<<<(BB*NHD*CC)/8, 256>>>(S, CC);
        // AV per (b,h): [512,32], K=512, B = V in [K,N] layout (TRB)
        TCG_AV<<<dim3(1,4,BB*NHD),256>>>(S, t0+2*DD, nullptr, t1, CC,32,CC,
                                         CC,768,DD, NHD,
                                         (long)NHD*CC*CC, (long)CC*CC,
                                         (long)CC*768, 32,
                                         (long)CC*DD, 32, 1.f);
        // out proj -> t2
        TCG_B<<<dim3(2,128,1),256>>>(t1, wo, bo, t2, M,DD,DD,
                                     DD,DD,DD, 1,0,0,0,0,0,0, 1.f);
        ln_kernel<<<M,256>>>(t2, x, n1w + i*DD, n1b + i*DD, x, DD, 0);
        // ff1 gelu -> t0 [M,1024]
        TCG_G<<<dim3(8,128,1),256>>>(x, w1, b1, t0, M,HH,DD,
                                     DD,DD,HH, 1,0,0,0,0,0,0, 1.f);
        // ff2 -> t2
        TCG_B<<<dim3(2,128,1),256>>>(t0, w2, b2, t2, M,DD,HH,
                                     HH,HH,DD, 1,0,0,0,0,0,0, 1.f);
        ln_kernel<<<M,256>>>(t2, x, n2w + i*DD, n2b + i*DD, x, DD, 0);
    }

    // ch = LN(x) @ th_w^T + th_b
    ln_kernel<<<M,256>>>(x, nullptr, th_ln_w, th_ln_b, t2, DD, 0);
    TCG_B<<<dim3(8,128,1),256>>>(t2, th_w, th_b, ch, M,HH,DD,
                                 DD,DD,HH, 1,0,0,0,0,0,0, 1.f);

    // prefix cross-attention
    TCG_B<<<dim3(8,1,1),256>>>(pq, pa_in_w, pa_in_b, qh, PP,HH,HH,
                               HH,HH,HH, 1,0,0,0,0,0,0, 1.f);
    TCG_B<<<dim3(8,128,1),256>>>(ch, pa_in_w + (size_t)HH*HH, pa_in_b + HH, kp,
                                 M,HH,HH, HH,HH,HH, 1,0,0,0,0,0,0, 1.f);
    TCG_B<<<dim3(8,128,1),256>>>(ch, pa_in_w + (size_t)2*HH*HH, pa_in_b + 2*HH, vp,
                                 M,HH,HH, HH,HH,HH, 1,0,0,0,0,0,0, 1.f);
    // scores2 per (b,h): [16,512], K=128
    TCG_N<<<dim3(4,1,BB*NHD),256>>>(qh, kp, nullptr, S2, PP,CC,128,
                                    HH,HH,CC, NHD,
                                    0L, 128L, (long)CC*HH, 128L,
                                    (long)NHD*PP*CC, (long)PP*CC, pscale);
    softmax_kernel<<<(BB*NHD*PP)/8, 256>>>(S2, CC);
    // AV2 per (b,h): [16,128], K=512, B = vp [K,N] (TRB)
    TCG_AV<<<dim3(4,1,BB*NHD),256>>>(S2, vp, nullptr, p1, PP,128,CC,
                                     CC,HH,HH, NHD,
                                     (long)NHD*PP*CC, (long)PP*CC,
                                     (long)CC*HH, 128L,
                                     (long)PP*HH, 128L, 1.f);
    // out proj
    TCG_B<<<dim3(8,4,1),256>>>(p1, pa_out_w, pa_out_b, p2, BB*PP,HH,HH,
                               HH,HH,HH, 1,0,0,0,0,0,0, 1.f);
    ln_kernel<<<BB*PP,256>>>(p2, pq, pn_w, pn_b, out, HH, PP);
}

// round 5
// speedup vs baseline: 3.1000x; 1.3558x over previous
#include <cuda_runtime.h>
#include <cstdint>

#define BB 32
#define CC 512
#define LL 16
#define DD 256
#define HH 1024
#define PP 16
#define NHD 8
#define NLL 4

// ---------------- scratch (static device globals; allocation-free) ----------------
__device__ float g_x [BB*CC*DD];
__device__ float g_t0[BB*CC*HH];
__device__ float g_t1[BB*CC*DD];
__device__ float g_t2[BB*CC*DD];
__device__ float g_ch[BB*CC*HH];
__device__ float g_kp[BB*CC*HH];
__device__ float g_vp[BB*CC*HH];
__device__ float g_qh[PP*HH];
__device__ float g_S2[BB*NHD*PP*CC];
__device__ float g_p1[BB*PP*HH];
__device__ float g_p2[BB*PP*HH];
__device__ int   g_maskmode;

// ---------------- small helpers ----------------
__device__ __forceinline__ uint32_t f2tf32(float f) {
    uint32_t u; asm("cvt.rna.tf32.f32 %0, %1;" : "=r"(u) : "f"(f)); return u;
}
__device__ __forceinline__ float gelu_f(float v) {
    return 0.5f * v * (1.f + erff(v * 0.70710678118654752f));
}
__device__ __forceinline__ void mma_tf32(float* c, const uint32_t* a, const uint32_t* b) {
    asm volatile(
        "mma.sync.aligned.m16n8k8.row.col.f32.tf32.tf32.f32 "
        "{%0,%1,%2,%3}, {%4,%5,%6,%7}, {%8,%9}, {%0,%1,%2,%3};"
        : "+f"(c[0]), "+f"(c[1]), "+f"(c[2]), "+f"(c[3])
        : "r"(a[0]), "r"(a[1]), "r"(a[2]), "r"(a[3]), "r"(b[0]), "r"(b[1]));
}

// ============================ tf32 mma.sync GEMM ============================
template<int BN, int TRB, int ACT, int HASB>
__global__ __launch_bounds__(256, 2) void mma_gemm(
    const float* __restrict__ A, const float* __restrict__ W,
    const float* __restrict__ bias, float* __restrict__ Cp,
    int M, int N, int K, int lda, int ldw, int ldc,
    int nsub, long sAb, long sAs, long sWb, long sWs, long sCb, long sCs,
    float alpha)
{
    constexpr int BM = 128, BK = 32;
    constexpr int LDSR = BK + 4;
    constexpr int WN = (BN == 128) ? 32 : 8;
    constexpr int MI = 4;
    constexpr int NJ = WN / 8;

    __shared__ uint32_t As[BM * LDSR];
    __shared__ uint32_t Ws[BN * LDSR];

    int tid = threadIdx.x, wid = tid >> 5, lane = tid & 31;
    int warpM = wid >> 2;
    int warpN = wid & 3;
    int g = lane >> 2, tg = lane & 3;

    int bm = blockIdx.y * BM;
    int bn = blockIdx.x * BN;
    int z = blockIdx.z;
    int zb = z / nsub, zs = z % nsub;
    const float* Ab = A + (size_t)zb * sAb + (size_t)zs * sAs;
    const float* Wb = W + (size_t)zb * sWb + (size_t)zs * sWs;
    float*       Cb = Cp + (size_t)zb * sCb + (size_t)zs * sCs;

    float acc[MI][NJ][4];
    #pragma unroll
    for (int i = 0; i < MI; i++)
        #pragma unroll
        for (int j = 0; j < NJ; j++)
            #pragma unroll
            for (int q = 0; q < 4; q++) acc[i][j][q] = 0.f;

    for (int k0 = 0; k0 < K; k0 += BK) {
        #pragma unroll
        for (int idx = tid; idx < BM * (BK / 4); idx += 256) {
            int row = idx >> 3, q = idx & 7;
            int gm = bm + row;
            if (gm < M) {
                float4 v = *(const float4*)(Ab + (size_t)gm * lda + k0 + q * 4);
                uint32_t* p = &As[row * LDSR + q * 4];
                p[0] = f2tf32(v.x); p[1] = f2tf32(v.y); p[2] = f2tf32(v.z); p[3] = f2tf32(v.w);
            }
        }
        if (!TRB) {
            #pragma unroll
            for (int idx = tid; idx < BN * (BK / 4); idx += 256) {
                int row = idx >> 3, q = idx & 7;
                float4 v = *(const float4*)(Wb + (size_t)(bn + row) * ldw + k0 + q * 4);
                uint32_t* p = &Ws[row * LDSR + q * 4];
                p[0] = f2tf32(v.x); p[1] = f2tf32(v.y); p[2] = f2tf32(v.z); p[3] = f2tf32(v.w);
            }
        } else {
            #pragma unroll
            for (int idx = tid; idx < (BK * BN) / 4; idx += 256) {
                int kk = idx / (BN / 4);
                int n4 = (idx % (BN / 4)) * 4;
                float4 v = *(const float4*)(Wb + (size_t)(k0 + kk) * ldw + bn + n4);
                Ws[(n4 + 0) * LDSR + kk] = f2tf32(v.x);
                Ws[(n4 + 1) * LDSR + kk] = f2tf32(v.y);
                Ws[(n4 + 2) * LDSR + kk] = f2tf32(v.z);
                Ws[(n4 + 3) * LDSR + kk] = f2tf32(v.w);
            }
        }
        __syncthreads();

        #pragma unroll
        for (int kk = 0; kk < BK; kk += 8) {
            uint32_t af[MI][4], bf[NJ][2];
            #pragma unroll
            for (int mi = 0; mi < MI; mi++) {
                int r0 = warpM * 64 + mi * 16 + g;
                af[mi][0] = As[r0 * LDSR + kk + tg];
                af[mi][1] = As[(r0 + 8) * LDSR + kk + tg];
                af[mi][2] = As[r0 * LDSR + kk + tg + 4];
                af[mi][3] = As[(r0 + 8) * LDSR + kk + tg + 4];
            }
            #pragma unroll
            for (int nj = 0; nj < NJ; nj++) {
                int c0 = warpN * WN + nj * 8 + g;
                bf[nj][0] = Ws[c0 * LDSR + kk + tg];
                bf[nj][1] = Ws[c0 * LDSR + kk + tg + 4];
            }
            #pragma unroll
            for (int mi = 0; mi < MI; mi++)
                #pragma unroll
                for (int nj = 0; nj < NJ; nj++)
                    mma_tf32(acc[mi][nj], af[mi], bf[nj]);
        }
        __syncthreads();
    }

    #pragma unroll
    for (int mi = 0; mi < MI; mi++) {
        int r0 = bm + warpM * 64 + mi * 16 + g;
        #pragma unroll
        for (int nj = 0; nj < NJ; nj++) {
            int c = bn + warpN * WN + nj * 8 + 2 * tg;
            float b0 = 0.f, b1 = 0.f;
            if (HASB) { b0 = bias[c]; b1 = bias[c + 1]; }
            if (r0 < M) {
                float v0 = acc[mi][nj][0] * alpha + b0;
                float v1 = acc[mi][nj][1] * alpha + b1;
                if (ACT) { v0 = gelu_f(v0); v1 = gelu_f(v1); }
                Cb[(size_t)r0 * ldc + c]     = v0;
                Cb[(size_t)r0 * ldc + c + 1] = v1;
            }
            if (r0 + 8 < M) {
                float v2 = acc[mi][nj][2] * alpha + b0;
                float v3 = acc[mi][nj][3] * alpha + b1;
                if (ACT) { v2 = gelu_f(v2); v3 = gelu_f(v3); }
                Cb[(size_t)(r0 + 8) * ldc + c]     = v2;
                Cb[(size_t)(r0 + 8) * ldc + c + 1] = v3;
            }
        }
    }
}

// ============================ fused flash attention (encoder) ============================
// qkv: [B*C, 768] rows = [q(256)|k(256)|v(256)], head h at +h*32 in each third.
// out: [B*C, 256], head h at cols h*32..h*32+31.
// grid: (4 q-tiles, B*NH). 256 threads = 8 warps; warp w owns rows w*16..w*16+15.
__global__ __launch_bounds__(256) void fused_attn(
    const float* __restrict__ qkv, float* __restrict__ o, float escale)
{
    extern __shared__ uint32_t fa_sm[];
    uint32_t* Qs = fa_sm;                 // [128][36]
    uint32_t* Ks = Qs + 128 * 36;         // [128][36]
    uint32_t* Vs = Ks + 128 * 36;         // [32][132]  (transposed: [d][key])

    int tid = threadIdx.x, lane = tid & 31, w = tid >> 5;
    int g = lane >> 2, tg = lane & 3;
    int qt = blockIdx.x;
    int z  = blockIdx.y;
    int b  = z >> 3, h = z & 7;
    const float* base = qkv + (size_t)b * CC * 768;

    // load Q tile (tf32)
    #pragma unroll
    for (int idx = tid; idx < 128 * 8; idx += 256) {
        int r = idx >> 3, q4 = idx & 7;
        float4 v = *(const float4*)(base + (size_t)(qt * 128 + r) * 768 + h * 32 + q4 * 4);
        uint32_t* p = &Qs[r * 36 + q4 * 4];
        p[0] = f2tf32(v.x); p[1] = f2tf32(v.y); p[2] = f2tf32(v.z); p[3] = f2tf32(v.w);
    }

    float oacc[4][4];
    #pragma unroll
    for (int i = 0; i < 4; i++)
        #pragma unroll
        for (int q = 0; q < 4; q++) oacc[i][q] = 0.f;
    float rm0 = -1e30f, rm1 = -1e30f, rs0 = 0.f, rs1 = 0.f;

    for (int kt = 0; kt < 4; kt++) {
        __syncthreads();   // covers Q-load (kt=0) and prior-tile reads (kt>0)
        // load K tile + V tile (V transposed)
        #pragma unroll
        for (int idx = tid; idx < 128 * 8; idx += 256) {
            int r = idx >> 3, q4 = idx & 7;
            const float* kr = base + (size_t)(kt * 128 + r) * 768 + 256 + h * 32 + q4 * 4;
            float4 kv = *(const float4*)kr;
            uint32_t* p = &Ks[r * 36 + q4 * 4];
            p[0] = f2tf32(kv.x); p[1] = f2tf32(kv.y); p[2] = f2tf32(kv.z); p[3] = f2tf32(kv.w);
            float4 vv = *(const float4*)(kr + 256);
            int d = q4 * 4;
            Vs[(d + 0) * 132 + r] = f2tf32(vv.x);
            Vs[(d + 1) * 132 + r] = f2tf32(vv.y);
            Vs[(d + 2) * 132 + r] = f2tf32(vv.z);
            Vs[(d + 3) * 132 + r] = f2tf32(vv.w);
        }
        __syncthreads();

        // ---- S = Q @ K^T for this warp's 16 rows x 128 keys ----
        float sacc[16][4];
        #pragma unroll
        for (int nj = 0; nj < 16; nj++)
            #pragma unroll
            for (int q = 0; q < 4; q++) sacc[nj][q] = 0.f;

        #pragma unroll
        for (int kk = 0; kk < 32; kk += 8) {
            uint32_t af[4];
            int r0 = w * 16 + g;
            af[0] = Qs[r0 * 36 + kk + tg];
            af[1] = Qs[(r0 + 8) * 36 + kk + tg];
            af[2] = Qs[r0 * 36 + kk + tg + 4];
            af[3] = Qs[(r0 + 8) * 36 + kk + tg + 4];
            #pragma unroll
            for (int nj = 0; nj < 16; nj++) {
                uint32_t bf[2] = { Ks[(nj * 8 + g) * 36 + kk + tg],
                                   Ks[(nj * 8 + g) * 36 + kk + tg + 4] };
                mma_tf32(sacc[nj], af, bf);
            }
        }

        // ---- online softmax (rows g and g+8) ----
        float tm0 = -1e30f, tm1 = -1e30f;
        #pragma unroll
        for (int nj = 0; nj < 16; nj++) {
            tm0 = fmaxf(tm0, fmaxf(sacc[nj][0], sacc[nj][1]));
            tm1 = fmaxf(tm1, fmaxf(sacc[nj][2], sacc[nj][3]));
        }
        tm0 *= escale; tm1 *= escale;
        tm0 = fmaxf(tm0, __shfl_xor_sync(0xffffffffu, tm0, 1));
        tm0 = fmaxf(tm0, __shfl_xor_sync(0xffffffffu, tm0, 2));
        tm1 = fmaxf(tm1, __shfl_xor_sync(0xffffffffu, tm1, 1));
        tm1 = fmaxf(tm1, __shfl_xor_sync(0xffffffffu, tm1, 2));
        float nm0 = fmaxf(rm0, tm0), nm1 = fmaxf(rm1, tm1);
        float cr0 = __expf(rm0 - nm0), cr1 = __expf(rm1 - nm1);
        rm0 = nm0; rm1 = nm1;
        float ps0 = 0.f, ps1 = 0.f;
        #pragma unroll
        for (int nj = 0; nj < 16; nj++) {
            float p0 = __expf(sacc[nj][0] * escale - nm0);
            float p1 = __expf(sacc[nj][1] * escale - nm0);
            float p2 = __expf(sacc[nj][2] * escale - nm1);
            float p3 = __expf(sacc[nj][3] * escale - nm1);
            sacc[nj][0] = p0; sacc[nj][1] = p1; sacc[nj][2] = p2; sacc[nj][3] = p3;
            ps0 += p0 + p1; ps1 += p2 + p3;
        }
        ps0 += __shfl_xor_sync(0xffffffffu, ps0, 1);
        ps0 += __shfl_xor_sync(0xffffffffu, ps0, 2);
        ps1 += __shfl_xor_sync(0xffffffffu, ps1, 1);
        ps1 += __shfl_xor_sync(0xffffffffu, ps1, 2);
        rs0 = rs0 * cr0 + ps0;
        rs1 = rs1 * cr1 + ps1;
        #pragma unroll
        for (int vj = 0; vj < 4; vj++) {
            oacc[vj][0] *= cr0; oacc[vj][1] *= cr0;
            oacc[vj][2] *= cr1; oacc[vj][3] *= cr1;
        }

        // ---- O += P @ V : relayout P C-frag -> A-frag via shuffles ----
        int srcA = (lane & ~3) | (tg >> 1);
        int srcB = srcA + 2;
        bool odd = (tg & 1);
        #pragma unroll
        for (int nj = 0; nj < 16; nj++) {
            float x0 = __shfl_sync(0xffffffffu, sacc[nj][0], srcA);
            float x1 = __shfl_sync(0xffffffffu, sacc[nj][1], srcA);
            float y0 = __shfl_sync(0xffffffffu, sacc[nj][0], srcB);
            float y1 = __shfl_sync(0xffffffffu, sacc[nj][1], srcB);
            float z0 = __shfl_sync(0xffffffffu, sacc[nj][2], srcA);
            float z1 = __shfl_sync(0xffffffffu, sacc[nj][3], srcA);
            float w0 = __shfl_sync(0xffffffffu, sacc[nj][2], srcB);
            float w1 = __shfl_sync(0xffffffffu, sacc[nj][3], srcB);
            uint32_t a[4];
            a[0] = f2tf32(odd ? x1 : x0);   // (g,      tg)
            a[1] = f2tf32(odd ? z1 : z0);   // (g+8,    tg)
            a[2] = f2tf32(odd ? y1 : y0);   // (g,    tg+4)
            a[3] = f2tf32(odd ? w1 : w0);   // (g+8,  tg+4)
            #pragma unroll
            for (int vj = 0; vj < 4; vj++) {
                uint32_t bf[2] = { Vs[(vj * 8 + g) * 132 + nj * 8 + tg],
                                   Vs[(vj * 8 + g) * 132 + nj * 8 + tg + 4] };
                mma_tf32(oacc[vj], a, bf);
            }
        }
    }

    // ---- write O ----
    float inv0 = 1.f / rs0, inv1 = 1.f / rs1;
    int row0 = b * CC + qt * 128 + w * 16 + g;
    #pragma unroll
    for (int vj = 0; vj < 4; vj++) {
        int c = h * 32 + vj * 8 + 2 * tg;
        o[(size_t)row0 * 256 + c]           = oacc[vj][0] * inv0;
        o[(size_t)row0 * 256 + c + 1]       = oacc[vj][1] * inv0;
        o[(size_t)(row0 + 8) * 256 + c]     = oacc[vj][2] * inv1;
        o[(size_t)(row0 + 8) * 256 + c + 1] = oacc[vj][3] * inv1;
    }
}

// ---------------- mask dtype detection ----------------
__global__ void detect_mask_kernel(const int* __restrict__ m) {
    __shared__ int found;
    if (threadIdx.x == 0) found = 0;
    __syncthreads();
    int idx = blockIdx.x * blockDim.x + threadIdx.x;
    unsigned v = (unsigned)m[idx];
    if (v > 1u) found = 1;
    __syncthreads();
    if (threadIdx.x == 0 && blockIdx.x == 0) g_maskmode = 0;
    __threadfence();
    if (found) g_maskmode = 1;
}

// ---------------- pool ----------------
__global__ void pool_kernel(const int* __restrict__ vi, const int* __restrict__ si,
                            const void* __restrict__ maskraw,
                            const float* __restrict__ ve, const float* __restrict__ se,
                            const float* __restrict__ lpe, const float* __restrict__ cpe,
                            float* __restrict__ x) {
    int bc = blockIdx.x;
    int c  = bc % CC;
    int d  = threadIdx.x;
    const int* viR = vi + bc * LL;
    const int* siR = si + bc * LL;
    __shared__ int mloc[LL];
    if (threadIdx.x < LL) {
        int mv;
        if (g_maskmode == 0) mv = ((const int*)maskraw)[bc * LL + threadIdx.x];
        else                 mv = ((const unsigned char*)maskraw)[bc * LL + threadIdx.x];
        mloc[threadIdx.x] = mv;
    }
    __syncthreads();
    float acc = 0.f; int cnt = 0;
    #pragma unroll
    for (int l = 0; l < LL; l++) {
        if (mloc[l]) {
            cnt++;
            acc += ve[viR[l]*DD + d] + se[siR[l]*DD + d] + lpe[l*DD + d];
        }
    }
    x[(size_t)bc*DD + d] = acc / (float)cnt + cpe[c*DD + d];
}

// ---------------- layernorm ----------------
__global__ void ln_kernel(const float* __restrict__ xin, const float* __restrict__ res,
                          const float* __restrict__ w, const float* __restrict__ b,
                          float* __restrict__ out, int N, int resMod) {
    int row = blockIdx.x;
    int tid = threadIdx.x;
    const float* xr = xin + (size_t)row * N;
    const float* rr = nullptr;
    if (res) rr = res + (size_t)(resMod ? (row % resMod) : row) * N;
    int per = N >> 8;
    float v[4];
    float s = 0.f;
    for (int i = 0; i < per; i++) {
        int cI = tid + (i << 8);
        float t = xr[cI];
        if (rr) t += rr[cI];
        v[i] = t; s += t;
    }
    __shared__ float red[256];
    red[tid] = s; __syncthreads();
    for (int o = 128; o; o >>= 1) { if (tid < o) red[tid] += red[tid+o]; __syncthreads(); }
    float mean = red[0] / (float)N;
    __syncthreads();
    float vs = 0.f;
    for (int i = 0; i < per; i++) { float d = v[i] - mean; vs += d*d; }
    red[tid] = vs; __syncthreads();
    for (int o = 128; o; o >>= 1) { if (tid < o) red[tid] += red[tid+o]; __syncthreads(); }
    float inv = rsqrtf(red[0] / (float)N + 1e-5f);
    for (int i = 0; i < per; i++) {
        int cI = tid + (i << 8);
        out[(size_t)row*N + cI] = (v[i] - mean) * inv * w[cI] + b[cI];
    }
}

// ---------------- softmax (prefix path) ----------------
__global__ void softmax_kernel(float* __restrict__ S, int cols) {
    int row  = blockIdx.x * 8 + (threadIdx.x >> 5);
    int lane = threadIdx.x & 31;
    float* r = S + (size_t)row * cols;
    int per = cols >> 5;
    float vals[16];
    float mx = -1e30f;
    for (int t = 0; t < per; t++) { vals[t] = r[lane + (t<<5)]; mx = fmaxf(mx, vals[t]); }
    for (int o = 16; o; o >>= 1) mx = fmaxf(mx, __shfl_xor_sync(0xffffffffu, mx, o));
    float sum = 0.f;
    for (int t = 0; t < per; t++) { vals[t] = __expf(vals[t] - mx); sum += vals[t]; }
    for (int o = 16; o; o >>= 1) sum += __shfl_xor_sync(0xffffffffu, sum, o);
    float inv = 1.f / sum;
    for (int t = 0; t < per; t++) r[lane + (t<<5)] = vals[t] * inv;
}

// ============================ host orchestration ============================
#define TCG_B   mma_gemm<128,0,0,1>
#define TCG_G   mma_gemm<128,0,1,1>
#define TCG_N   mma_gemm<128,0,0,0>
#define TCG_AV  mma_gemm<32,1,0,0>

static const int FA_SMEM = (128*36 + 128*36 + 32*132) * 4;   // 53760 B

extern "C" void kernel_launch(void* const* d_in, const int* in_sizes, int n_in,
                              void* d_out, int out_size) {
    const int*   var_idx   = (const int*)  d_in[0];
    const int*   sign_idx  = (const int*)  d_in[1];
    const void*  lit_mask  = (const void*) d_in[2];
    const float* var_emb   = (const float*)d_in[3];
    const float* sign_emb  = (const float*)d_in[4];
    const float* litpos    = (const float*)d_in[5];
    const float* clausepos = (const float*)d_in[6];
    const float* enc_in_w  = (const float*)d_in[7];
    const float* enc_in_b  = (const float*)d_in[8];
    const float* enc_out_w = (const float*)d_in[9];
    const float* enc_out_b = (const float*)d_in[10];
    const float* enc_ff1_w = (const float*)d_in[11];
    const float* enc_ff1_b = (const float*)d_in[12];
    const float* enc_ff2_w = (const float*)d_in[13];
    const float* enc_ff2_b = (const float*)d_in[14];
    const float* n1w = (const float*)d_in[15];
    const float* n1b = (const float*)d_in[16];
    const float* n2w = (const float*)d_in[17];
    const float* n2b = (const float*)d_in[18];
    const float* th_ln_w = (const float*)d_in[19];
    const float* th_ln_b = (const float*)d_in[20];
    const float* th_w = (const float*)d_in[21];
    const float* th_b = (const float*)d_in[22];
    const float* pq   = (const float*)d_in[23];
    const float* pa_in_w  = (const float*)d_in[24];
    const float* pa_in_b  = (const float*)d_in[25];
    const float* pa_out_w = (const float*)d_in[26];
    const float* pa_out_b = (const float*)d_in[27];
    const float* pn_w = (const float*)d_in[28];
    const float* pn_b = (const float*)d_in[29];
    float* out = (float*)d_out;

    float *x,*t0,*t1,*t2,*ch,*kp,*vp,*qh,*S2,*p1,*p2;
    cudaGetSymbolAddress((void**)&x,  g_x);
    cudaGetSymbolAddress((void**)&t0, g_t0);
    cudaGetSymbolAddress((void**)&t1, g_t1);
    cudaGetSymbolAddress((void**)&t2, g_t2);
    cudaGetSymbolAddress((void**)&ch, g_ch);
    cudaGetSymbolAddress((void**)&kp, g_kp);
    cudaGetSymbolAddress((void**)&vp, g_vp);
    cudaGetSymbolAddress((void**)&qh, g_qh);
    cudaGetSymbolAddress((void**)&S2, g_S2);
    cudaGetSymbolAddress((void**)&p1, g_p1);
    cudaGetSymbolAddress((void**)&p2, g_p2);

    cudaFuncSetAttribute(fused_attn, cudaFuncAttributeMaxDynamicSharedMemorySize, FA_SMEM);

    const int M = BB*CC;
    const float escale = 0.17677669529663687f;   // 1/sqrt(32)
    const float pscale = 0.08838834764831845f;   // 1/sqrt(128)

    detect_mask_kernel<<<16, 256>>>((const int*)lit_mask);
    pool_kernel<<<M, 256>>>(var_idx, sign_idx, lit_mask, var_emb, sign_emb,
                            litpos, clausepos, x);

    for (int i = 0; i < NLL; i++) {
        const float* wqkv = enc_in_w  + (size_t)i*768*DD;
        const float* bqkv = enc_in_b  + (size_t)i*768;
        const float* wo   = enc_out_w + (size_t)i*DD*DD;
        const float* bo   = enc_out_b + (size_t)i*DD;
        const float* w1   = enc_ff1_w + (size_t)i*HH*DD;
        const float* b1   = enc_ff1_b + (size_t)i*HH;
        const float* w2   = enc_ff2_w + (size_t)i*DD*HH;
        const float* b2   = enc_ff2_b + (size_t)i*DD;

        // qkv = x @ Wqkv^T + b -> t0 [M,768]
        TCG_B<<<dim3(6,128,1),256>>>(x, wqkv, bqkv, t0, M,768,DD,
                                     DD,DD,768, 1,0,0,0,0,0,0, 1.f);
        // fused attention -> t1 [M,256]
        fused_attn<<<dim3(4, BB*NHD), 256, FA_SMEM>>>(t0, t1, escale);
        // out proj -> t2
        TCG_B<<<dim3(2,128,1),256>>>(t1, wo, bo, t2, M,DD,DD,
                                     DD,DD,DD, 1,0,0,0,0,0,0, 1.f);
        ln_kernel<<<M,256>>>(t2, x, n1w + i*DD, n1b + i*DD, x, DD, 0);
        // ff1 gelu -> t0 [M,1024]
        TCG_G<<<dim3(8,128,1),256>>>(x, w1, b1, t0, M,HH,DD,
                                     DD,DD,HH, 1,0,0,0,0,0,0, 1.f);
        // ff2 -> t2
        TCG_B<<<dim3(2,128,1),256>>>(t0, w2, b2, t2, M,DD,HH,
                                     HH,HH,DD, 1,0,0,0,0,0,0, 1.f);
        ln_kernel<<<M,256>>>(t2, x, n2w + i*DD, n2b + i*DD, x, DD, 0);
    }

    // ch = LN(x) @ th_w^T + th_b
    ln_kernel<<<M,256>>>(x, nullptr, th_ln_w, th_ln_b, t2, DD, 0);
    TCG_B<<<dim3(8,128,1),256>>>(t2, th_w, th_b, ch, M,HH,DD,
                                 DD,DD,HH, 1,0,0,0,0,0,0, 1.f);

    // prefix cross-attention
    TCG_B<<<dim3(8,1,1),256>>>(pq, pa_in_w, pa_in_b, qh, PP,HH,HH,
                               HH,HH,HH, 1,0,0,0,0,0,0, 1.f);
    TCG_B<<<dim3(8,128,1),256>>>(ch, pa_in_w + (size_t)HH*HH, pa_in_b + HH, kp,
                                 M,HH,HH, HH,HH,HH, 1,0,0,0,0,0,0, 1.f);
    TCG_B<<<dim3(8,128,1),256>>>(ch, pa_in_w + (size_t)2*HH*HH, pa_in_b + 2*HH, vp,
                                 M,HH,HH, HH,HH,HH, 1,0,0,0,0,0,0, 1.f);
    // scores2 per (b,h): [16,512], K=128
    TCG_N<<<dim3(4,1,BB*NHD),256>>>(qh, kp, nullptr, S2, PP,CC,128,
                                    HH,HH,CC, NHD,
                                    0L, 128L, (long)CC*HH, 128L,
                                    (long)NHD*PP*CC, (long)PP*CC, pscale);
    softmax_kernel<<<(BB*NHD*PP)/8, 256>>>(S2, CC);
    // AV2 per (b,h): [16,128], K=512
    TCG_AV<<<dim3(4,1,BB*NHD),256>>>(S2, vp, nullptr, p1, PP,128,CC,
                                     CC,HH,HH, NHD,
                                     (long)NHD*PP*CC, (long)PP*CC,
                                     (long)CC*HH, 128L,
                                     (long)PP*HH, 128L, 1.f);
    // out proj
    TCG_B<<<dim3(8,4,1),256>>>(p1, pa_out_w, pa_out_b, p2, BB*PP,HH,HH,
                               HH,HH,HH, 1,0,0,0,0,0,0, 1.f);
    ln_kernel<<<BB*PP,256>>>(p2, pq, pn_w, pn_b, out, HH, PP);
}

// round 6
// speedup vs baseline: 3.6115x; 1.1650x over previous
#include <cuda_runtime.h>
#include <cstdint>

#define BB 32
#define CC 512
#define LL 16
#define DD 256
#define HH 1024
#define PP 16
#define NHD 8
#define NLL 4

// ---------------- scratch (static device globals; allocation-free) ----------------
__device__ float g_x [BB*CC*DD];
__device__ float g_t0[BB*CC*HH];
__device__ float g_t1[BB*CC*DD];
__device__ float g_t2[BB*CC*DD];
__device__ float g_ch[BB*CC*HH];
__device__ float g_kp[BB*CC*HH];
__device__ float g_vp[BB*CC*HH];
__device__ float g_qh[PP*HH];
__device__ float g_S2[BB*NHD*PP*CC];
__device__ float g_p1[BB*PP*HH];
__device__ float g_p2[BB*PP*HH];
__device__ int   g_maskmode;

// ---------------- small helpers ----------------
__device__ __forceinline__ uint32_t f2tf32(float f) {
    uint32_t u; asm("cvt.rna.tf32.f32 %0, %1;" : "=r"(u) : "f"(f)); return u;
}
__device__ __forceinline__ uint32_t smem_u32(const void* p) {
    uint32_t a;
    asm("{ .reg .u64 t; cvta.to.shared.u64 t, %1; cvt.u32.u64 %0, t; }" : "=r"(a) : "l"(p));
    return a;
}
__device__ __forceinline__ float gelu_f(float v) {
    return 0.5f * v * (1.f + erff(v * 0.70710678118654752f));
}
__device__ __forceinline__ void mma_tf32(float* c, const uint32_t* a, const uint32_t* b) {
    asm volatile(
        "mma.sync.aligned.m16n8k8.row.col.f32.tf32.tf32.f32 "
        "{%0,%1,%2,%3}, {%4,%5,%6,%7}, {%8,%9}, {%0,%1,%2,%3};"
        : "+f"(c[0]), "+f"(c[1]), "+f"(c[2]), "+f"(c[3])
        : "r"(a[0]), "r"(a[1]), "r"(a[2]), "r"(a[3]), "r"(b[0]), "r"(b[1]));
}
#define CPA16(dst, src, pred) \
    asm volatile("cp.async.cg.shared.global [%0], [%1], 16, %2;" \
                 :: "r"(dst), "l"(src), "r"((pred) ? 16 : 0))
#define CP_COMMIT() asm volatile("cp.async.commit_group;")
#define CP_WAIT1()  asm volatile("cp.async.wait_group 1;")
#define CP_WAIT0()  asm volatile("cp.async.wait_group 0;")

// ============================ v2: cp.async-pipelined tf32 GEMM (BN=128, W[N,K]) ===========
// C[m,n] = act(alpha * A@W^T + bias). Requires N % 128 == 0, K % 32 == 0, lda/ldw % 4 == 0.
template<int ACT, int HASB>
__global__ __launch_bounds__(256) void mma_gemm2(
    const float* __restrict__ A, const float* __restrict__ W,
    const float* __restrict__ bias, float* __restrict__ Cp,
    int M, int N, int K, int lda, int ldw, int ldc,
    int nsub, long sAb, long sAs, long sWb, long sWs, long sCb, long sCs,
    float alpha)
{
    constexpr int BM = 128, BN = 128, BK = 32, LDSR = 36;
    extern __shared__ uint32_t sm2[];
    uint32_t* AsBuf = sm2;                       // 2 x [BM*LDSR]
    uint32_t* WsBuf = sm2 + 2 * BM * LDSR;       // 2 x [BN*LDSR]

    int tid = threadIdx.x, wid = tid >> 5, lane = tid & 31;
    int warpM = wid >> 2, warpN = wid & 3;
    int g = lane >> 2, tg = lane & 3;
    int bm = blockIdx.y * BM, bn = blockIdx.x * BN;
    int z = blockIdx.z, zb = z / nsub, zs = z % nsub;
    const float* Ab = A + (size_t)zb * sAb + (size_t)zs * sAs;
    const float* Wb = W + (size_t)zb * sWb + (size_t)zs * sWs;
    float*       Cb = Cp + (size_t)zb * sCb + (size_t)zs * sCs;

    uint32_t asAddr = smem_u32(AsBuf);
    uint32_t wsAddr = smem_u32(WsBuf);

    auto load_stage = [&](int st, int k0) {
        uint32_t ab = asAddr + (uint32_t)st * BM * LDSR * 4;
        uint32_t wb = wsAddr + (uint32_t)st * BN * LDSR * 4;
        #pragma unroll
        for (int idx = tid; idx < BM * 8; idx += 256) {
            int row = idx >> 3, q = idx & 7;
            int gm = bm + row;
            bool ok = gm < M;
            int gmc = ok ? gm : 0;
            CPA16(ab + (uint32_t)(row * LDSR + q * 4) * 4,
                  Ab + (size_t)gmc * lda + k0 + q * 4, ok);
        }
        #pragma unroll
        for (int idx = tid; idx < BN * 8; idx += 256) {
            int row = idx >> 3, q = idx & 7;
            CPA16(wb + (uint32_t)(row * LDSR + q * 4) * 4,
                  Wb + (size_t)(bn + row) * ldw + k0 + q * 4, true);
        }
        CP_COMMIT();
    };

    float acc[4][4][4];
    #pragma unroll
    for (int i = 0; i < 4; i++)
        #pragma unroll
        for (int j = 0; j < 4; j++)
            #pragma unroll
            for (int q = 0; q < 4; q++) acc[i][j][q] = 0.f;

    int nk = K / BK;
    load_stage(0, 0);

    for (int i = 0; i < nk; i++) {
        int cur = i & 1;
        if (i + 1 < nk) { load_stage((i + 1) & 1, (i + 1) * BK); CP_WAIT1(); }
        else            { CP_WAIT0(); }
        __syncthreads();

        const uint32_t* As = AsBuf + cur * BM * LDSR;
        const uint32_t* Ws = WsBuf + cur * BN * LDSR;
        #pragma unroll
        for (int kk = 0; kk < BK; kk += 8) {
            uint32_t af[4][4], bf[4][2];
            #pragma unroll
            for (int mi = 0; mi < 4; mi++) {
                int r0 = warpM * 64 + mi * 16 + g;
                // +0x1000 = round-half-away to tf32 (HW truncates low 13 bits)
                af[mi][0] = As[r0 * LDSR + kk + tg] + 0x1000;
                af[mi][1] = As[(r0 + 8) * LDSR + kk + tg] + 0x1000;
                af[mi][2] = As[r0 * LDSR + kk + tg + 4] + 0x1000;
                af[mi][3] = As[(r0 + 8) * LDSR + kk + tg + 4] + 0x1000;
            }
            #pragma unroll
            for (int nj = 0; nj < 4; nj++) {
                int c0 = warpN * 32 + nj * 8 + g;
                bf[nj][0] = Ws[c0 * LDSR + kk + tg] + 0x1000;
                bf[nj][1] = Ws[c0 * LDSR + kk + tg + 4] + 0x1000;
            }
            #pragma unroll
            for (int mi = 0; mi < 4; mi++)
                #pragma unroll
                for (int nj = 0; nj < 4; nj++)
                    mma_tf32(acc[mi][nj], af[mi], bf[nj]);
        }
        __syncthreads();
    }

    #pragma unroll
    for (int mi = 0; mi < 4; mi++) {
        int r0 = bm + warpM * 64 + mi * 16 + g;
        #pragma unroll
        for (int nj = 0; nj < 4; nj++) {
            int c = bn + warpN * 32 + nj * 8 + 2 * tg;
            float b0 = 0.f, b1 = 0.f;
            if (HASB) { b0 = bias[c]; b1 = bias[c + 1]; }
            if (r0 < M) {
                float v0 = acc[mi][nj][0] * alpha + b0;
                float v1 = acc[mi][nj][1] * alpha + b1;
                if (ACT) { v0 = gelu_f(v0); v1 = gelu_f(v1); }
                Cb[(size_t)r0 * ldc + c]     = v0;
                Cb[(size_t)r0 * ldc + c + 1] = v1;
            }
            if (r0 + 8 < M) {
                float v2 = acc[mi][nj][2] * alpha + b0;
                float v3 = acc[mi][nj][3] * alpha + b1;
                if (ACT) { v2 = gelu_f(v2); v3 = gelu_f(v3); }
                Cb[(size_t)(r0 + 8) * ldc + c]     = v2;
                Cb[(size_t)(r0 + 8) * ldc + c + 1] = v3;
            }
        }
    }
}

// ============================ v1 GEMM (TRB path, AV2 only) ============================
template<int BN, int TRB, int ACT, int HASB>
__global__ __launch_bounds__(256, 2) void mma_gemm(
    const float* __restrict__ A, const float* __restrict__ W,
    const float* __restrict__ bias, float* __restrict__ Cp,
    int M, int N, int K, int lda, int ldw, int ldc,
    int nsub, long sAb, long sAs, long sWb, long sWs, long sCb, long sCs,
    float alpha)
{
    constexpr int BM = 128, BK = 32;
    constexpr int LDSR = BK + 4;
    constexpr int WN = (BN == 128) ? 32 : 8;
    constexpr int MI = 4;
    constexpr int NJ = WN / 8;

    __shared__ uint32_t As[BM * LDSR];
    __shared__ uint32_t Ws[BN * LDSR];

    int tid = threadIdx.x, wid = tid >> 5, lane = tid & 31;
    int warpM = wid >> 2;
    int warpN = wid & 3;
    int g = lane >> 2, tg = lane & 3;

    int bm = blockIdx.y * BM;
    int bn = blockIdx.x * BN;
    int z = blockIdx.z;
    int zb = z / nsub, zs = z % nsub;
    const float* Ab = A + (size_t)zb * sAb + (size_t)zs * sAs;
    const float* Wb = W + (size_t)zb * sWb + (size_t)zs * sWs;
    float*       Cb = Cp + (size_t)zb * sCb + (size_t)zs * sCs;

    float acc[MI][NJ][4];
    #pragma unroll
    for (int i = 0; i < MI; i++)
        #pragma unroll
        for (int j = 0; j < NJ; j++)
            #pragma unroll
            for (int q = 0; q < 4; q++) acc[i][j][q] = 0.f;

    for (int k0 = 0; k0 < K; k0 += BK) {
        #pragma unroll
        for (int idx = tid; idx < BM * (BK / 4); idx += 256) {
            int row = idx >> 3, q = idx & 7;
            int gm = bm + row;
            if (gm < M) {
                float4 v = *(const float4*)(Ab + (size_t)gm * lda + k0 + q * 4);
                uint32_t* p = &As[row * LDSR + q * 4];
                p[0] = f2tf32(v.x); p[1] = f2tf32(v.y); p[2] = f2tf32(v.z); p[3] = f2tf32(v.w);
            }
        }
        if (!TRB) {
            #pragma unroll
            for (int idx = tid; idx < BN * (BK / 4); idx += 256) {
                int row = idx >> 3, q = idx & 7;
                float4 v = *(const float4*)(Wb + (size_t)(bn + row) * ldw + k0 + q * 4);
                uint32_t* p = &Ws[row * LDSR + q * 4];
                p[0] = f2tf32(v.x); p[1] = f2tf32(v.y); p[2] = f2tf32(v.z); p[3] = f2tf32(v.w);
            }
        } else {
            #pragma unroll
            for (int idx = tid; idx < (BK * BN) / 4; idx += 256) {
                int kk = idx / (BN / 4);
                int n4 = (idx % (BN / 4)) * 4;
                float4 v = *(const float4*)(Wb + (size_t)(k0 + kk) * ldw + bn + n4);
                Ws[(n4 + 0) * LDSR + kk] = f2tf32(v.x);
                Ws[(n4 + 1) * LDSR + kk] = f2tf32(v.y);
                Ws[(n4 + 2) * LDSR + kk] = f2tf32(v.z);
                Ws[(n4 + 3) * LDSR + kk] = f2tf32(v.w);
            }
        }
        __syncthreads();

        #pragma unroll
        for (int kk = 0; kk < BK; kk += 8) {
            uint32_t af[MI][4], bf[NJ][2];
            #pragma unroll
            for (int mi = 0; mi < MI; mi++) {
                int r0 = warpM * 64 + mi * 16 + g;
                af[mi][0] = As[r0 * LDSR + kk + tg];
                af[mi][1] = As[(r0 + 8) * LDSR + kk + tg];
                af[mi][2] = As[r0 * LDSR + kk + tg + 4];
                af[mi][3] = As[(r0 + 8) * LDSR + kk + tg + 4];
            }
            #pragma unroll
            for (int nj = 0; nj < NJ; nj++) {
                int c0 = warpN * WN + nj * 8 + g;
                bf[nj][0] = Ws[c0 * LDSR + kk + tg];
                bf[nj][1] = Ws[c0 * LDSR + kk + tg + 4];
            }
            #pragma unroll
            for (int mi = 0; mi < MI; mi++)
                #pragma unroll
                for (int nj = 0; nj < NJ; nj++)
                    mma_tf32(acc[mi][nj], af[mi], bf[nj]);
        }
        __syncthreads();
    }

    #pragma unroll
    for (int mi = 0; mi < MI; mi++) {
        int r0 = bm + warpM * 64 + mi * 16 + g;
        #pragma unroll
        for (int nj = 0; nj < NJ; nj++) {
            int c = bn + warpN * WN + nj * 8 + 2 * tg;
            float b0 = 0.f, b1 = 0.f;
            if (HASB) { b0 = bias[c]; b1 = bias[c + 1]; }
            if (r0 < M) {
                float v0 = acc[mi][nj][0] * alpha + b0;
                float v1 = acc[mi][nj][1] * alpha + b1;
                if (ACT) { v0 = gelu_f(v0); v1 = gelu_f(v1); }
                Cb[(size_t)r0 * ldc + c]     = v0;
                Cb[(size_t)r0 * ldc + c + 1] = v1;
            }
            if (r0 + 8 < M) {
                float v2 = acc[mi][nj][2] * alpha + b0;
                float v3 = acc[mi][nj][3] * alpha + b1;
                if (ACT) { v2 = gelu_f(v2); v3 = gelu_f(v3); }
                Cb[(size_t)(r0 + 8) * ldc + c]     = v2;
                Cb[(size_t)(r0 + 8) * ldc + c + 1] = v3;
            }
        }
    }
}

// ============================ fused flash attention (encoder) ============================
__global__ __launch_bounds__(256) void fused_attn(
    const float* __restrict__ qkv, float* __restrict__ o, float escale)
{
    extern __shared__ uint32_t fa_sm[];
    uint32_t* Qs = fa_sm;                 // [128][36]
    uint32_t* Ks = Qs + 128 * 36;         // [128][36]
    uint32_t* Vs = Ks + 128 * 36;         // [32][132]  (transposed: [d][key])

    int tid = threadIdx.x, lane = tid & 31, w = tid >> 5;
    int g = lane >> 2, tg = lane & 3;
    int qt = blockIdx.x;
    int z  = blockIdx.y;
    int b  = z >> 3, h = z & 7;
    const float* base = qkv + (size_t)b * CC * 768;

    #pragma unroll
    for (int idx = tid; idx < 128 * 8; idx += 256) {
        int r = idx >> 3, q4 = idx & 7;
        float4 v = *(const float4*)(base + (size_t)(qt * 128 + r) * 768 + h * 32 + q4 * 4);
        uint32_t* p = &Qs[r * 36 + q4 * 4];
        p[0] = f2tf32(v.x); p[1] = f2tf32(v.y); p[2] = f2tf32(v.z); p[3] = f2tf32(v.w);
    }

    float oacc[4][4];
    #pragma unroll
    for (int i = 0; i < 4; i++)
        #pragma unroll
        for (int q = 0; q < 4; q++) oacc[i][q] = 0.f;
    float rm0 = -1e30f, rm1 = -1e30f, rs0 = 0.f, rs1 = 0.f;

    for (int kt = 0; kt < 4; kt++) {
        __syncthreads();
        #pragma unroll
        for (int idx = tid; idx < 128 * 8; idx += 256) {
            int r = idx >> 3, q4 = idx & 7;
            const float* kr = base + (size_t)(kt * 128 + r) * 768 + 256 + h * 32 + q4 * 4;
            float4 kv = *(const float4*)kr;
            uint32_t* p = &Ks[r * 36 + q4 * 4];
            p[0] = f2tf32(kv.x); p[1] = f2tf32(kv.y); p[2] = f2tf32(kv.z); p[3] = f2tf32(kv.w);
            float4 vv = *(const float4*)(kr + 256);
            int d = q4 * 4;
            Vs[(d + 0) * 132 + r] = f2tf32(vv.x);
            Vs[(d + 1) * 132 + r] = f2tf32(vv.y);
            Vs[(d + 2) * 132 + r] = f2tf32(vv.z);
            Vs[(d + 3) * 132 + r] = f2tf32(vv.w);
        }
        __syncthreads();

        float sacc[16][4];
        #pragma unroll
        for (int nj = 0; nj < 16; nj++)
            #pragma unroll
            for (int q = 0; q < 4; q++) sacc[nj][q] = 0.f;

        #pragma unroll
        for (int kk = 0; kk < 32; kk += 8) {
            uint32_t af[4];
            int r0 = w * 16 + g;
            af[0] = Qs[r0 * 36 + kk + tg];
            af[1] = Qs[(r0 + 8) * 36 + kk + tg];
            af[2] = Qs[r0 * 36 + kk + tg + 4];
            af[3] = Qs[(r0 + 8) * 36 + kk + tg + 4];
            #pragma unroll
            for (int nj = 0; nj < 16; nj++) {
                uint32_t bf[2] = { Ks[(nj * 8 + g) * 36 + kk + tg],
                                   Ks[(nj * 8 + g) * 36 + kk + tg + 4] };
                mma_tf32(sacc[nj], af, bf);
            }
        }

        float tm0 = -1e30f, tm1 = -1e30f;
        #pragma unroll
        for (int nj = 0; nj < 16; nj++) {
            tm0 = fmaxf(tm0, fmaxf(sacc[nj][0], sacc[nj][1]));
            tm1 = fmaxf(tm1, fmaxf(sacc[nj][2], sacc[nj][3]));
        }
        tm0 *= escale; tm1 *= escale;
        tm0 = fmaxf(tm0, __shfl_xor_sync(0xffffffffu, tm0, 1));
        tm0 = fmaxf(tm0, __shfl_xor_sync(0xffffffffu, tm0, 2));
        tm1 = fmaxf(tm1, __shfl_xor_sync(0xffffffffu, tm1, 1));
        tm1 = fmaxf(tm1, __shfl_xor_sync(0xffffffffu, tm1, 2));
        float nm0 = fmaxf(rm0, tm0), nm1 = fmaxf(rm1, tm1);
        float cr0 = __expf(rm0 - nm0), cr1 = __expf(rm1 - nm1);
        rm0 = nm0; rm1 = nm1;
        float ps0 = 0.f, ps1 = 0.f;
        #pragma unroll
        for (int nj = 0; nj < 16; nj++) {
            float p0 = __expf(sacc[nj][0] * escale - nm0);
            float p1 = __expf(sacc[nj][1] * escale - nm0);
            float p2 = __expf(sacc[nj][2] * escale - nm1);
            float p3 = __expf(sacc[nj][3] * escale - nm1);
            sacc[nj][0] = p0; sacc[nj][1] = p1; sacc[nj][2] = p2; sacc[nj][3] = p3;
            ps0 += p0 + p1; ps1 += p2 + p3;
        }
        ps0 += __shfl_xor_sync(0xffffffffu, ps0, 1);
        ps0 += __shfl_xor_sync(0xffffffffu, ps0, 2);
        ps1 += __shfl_xor_sync(0xffffffffu, ps1, 1);
        ps1 += __shfl_xor_sync(0xffffffffu, ps1, 2);
        rs0 = rs0 * cr0 + ps0;
        rs1 = rs1 * cr1 + ps1;
        #pragma unroll
        for (int vj = 0; vj < 4; vj++) {
            oacc[vj][0] *= cr0; oacc[vj][1] *= cr0;
            oacc[vj][2] *= cr1; oacc[vj][3] *= cr1;
        }

        int srcA = (lane & ~3) | (tg >> 1);
        int srcB = srcA + 2;
        bool odd = (tg & 1);
        #pragma unroll
        for (int nj = 0; nj < 16; nj++) {
            float x0 = __shfl_sync(0xffffffffu, sacc[nj][0], srcA);
            float x1 = __shfl_sync(0xffffffffu, sacc[nj][1], srcA);
            float y0 = __shfl_sync(0xffffffffu, sacc[nj][0], srcB);
            float y1 = __shfl_sync(0xffffffffu, sacc[nj][1], srcB);
            float z0 = __shfl_sync(0xffffffffu, sacc[nj][2], srcA);
            float z1 = __shfl_sync(0xffffffffu, sacc[nj][3], srcA);
            float w0 = __shfl_sync(0xffffffffu, sacc[nj][2], srcB);
            float w1 = __shfl_sync(0xffffffffu, sacc[nj][3], srcB);
            uint32_t a[4];
            a[0] = f2tf32(odd ? x1 : x0);
            a[1] = f2tf32(odd ? z1 : z0);
            a[2] = f2tf32(odd ? y1 : y0);
            a[3] = f2tf32(odd ? w1 : w0);
            #pragma unroll
            for (int vj = 0; vj < 4; vj++) {
                uint32_t bf[2] = { Vs[(vj * 8 + g) * 132 + nj * 8 + tg],
                                   Vs[(vj * 8 + g) * 132 + nj * 8 + tg + 4] };
                mma_tf32(oacc[vj], a, bf);
            }
        }
    }

    float inv0 = 1.f / rs0, inv1 = 1.f / rs1;
    int row0 = b * CC + qt * 128 + w * 16 + g;
    #pragma unroll
    for (int vj = 0; vj < 4; vj++) {
        int c = h * 32 + vj * 8 + 2 * tg;
        o[(size_t)row0 * 256 + c]           = oacc[vj][0] * inv0;
        o[(size_t)row0 * 256 + c + 1]       = oacc[vj][1] * inv0;
        o[(size_t)(row0 + 8) * 256 + c]     = oacc[vj][2] * inv1;
        o[(size_t)(row0 + 8) * 256 + c + 1] = oacc[vj][3] * inv1;
    }
}

// ---------------- mask dtype detection ----------------
__global__ void detect_mask_kernel(const int* __restrict__ m) {
    __shared__ int found;
    if (threadIdx.x == 0) found = 0;
    __syncthreads();
    int idx = blockIdx.x * blockDim.x + threadIdx.x;
    unsigned v = (unsigned)m[idx];
    if (v > 1u) found = 1;
    __syncthreads();
    if (threadIdx.x == 0 && blockIdx.x == 0) g_maskmode = 0;
    __threadfence();
    if (found) g_maskmode = 1;
}

// ---------------- pool ----------------
__global__ void pool_kernel(const int* __restrict__ vi, const int* __restrict__ si,
                            const void* __restrict__ maskraw,
                            const float* __restrict__ ve, const float* __restrict__ se,
                            const float* __restrict__ lpe, const float* __restrict__ cpe,
                            float* __restrict__ x) {
    int bc = blockIdx.x;
    int c  = bc % CC;
    int d  = threadIdx.x;
    const int* viR = vi + bc * LL;
    const int* siR = si + bc * LL;
    __shared__ int mloc[LL];
    if (threadIdx.x < LL) {
        int mv;
        if (g_maskmode == 0) mv = ((const int*)maskraw)[bc * LL + threadIdx.x];
        else                 mv = ((const unsigned char*)maskraw)[bc * LL + threadIdx.x];
        mloc[threadIdx.x] = mv;
    }
    __syncthreads();
    float acc = 0.f; int cnt = 0;
    #pragma unroll
    for (int l = 0; l < LL; l++) {
        if (mloc[l]) {
            cnt++;
            acc += ve[viR[l]*DD + d] + se[siR[l]*DD + d] + lpe[l*DD + d];
        }
    }
    x[(size_t)bc*DD + d] = acc / (float)cnt + cpe[c*DD + d];
}

// ---------------- layernorm ----------------
__global__ void ln_kernel(const float* __restrict__ xin, const float* __restrict__ res,
                          const float* __restrict__ w, const float* __restrict__ b,
                          float* __restrict__ out, int N, int resMod) {
    int row = blockIdx.x;
    int tid = threadIdx.x;
    const float* xr = xin + (size_t)row * N;
    const float* rr = nullptr;
    if (res) rr = res + (size_t)(resMod ? (row % resMod) : row) * N;
    int per = N >> 8;
    float v[4];
    float s = 0.f;
    for (int i = 0; i < per; i++) {
        int cI = tid + (i << 8);
        float t = xr[cI];
        if (rr) t += rr[cI];
        v[i] = t; s += t;
    }
    __shared__ float red[256];
    red[tid] = s; __syncthreads();
    for (int o = 128; o; o >>= 1) { if (tid < o) red[tid] += red[tid+o]; __syncthreads(); }
    float mean = red[0] / (float)N;
    __syncthreads();
    float vs = 0.f;
    for (int i = 0; i < per; i++) { float d = v[i] - mean; vs += d*d; }
    red[tid] = vs; __syncthreads();
    for (int o = 128; o; o >>= 1) { if (tid < o) red[tid] += red[tid+o]; __syncthreads(); }
    float inv = rsqrtf(red[0] / (float)N + 1e-5f);
    for (int i = 0; i < per; i++) {
        int cI = tid + (i << 8);
        out[(size_t)row*N + cI] = (v[i] - mean) * inv * w[cI] + b[cI];
    }
}

// ---------------- softmax (prefix path) ----------------
__global__ void softmax_kernel(float* __restrict__ S, int cols) {
    int row  = blockIdx.x * 8 + (threadIdx.x >> 5);
    int lane = threadIdx.x & 31;
    float* r = S + (size_t)row * cols;
    int per = cols >> 5;
    float vals[16];
    float mx = -1e30f;
    for (int t = 0; t < per; t++) { vals[t] = r[lane + (t<<5)]; mx = fmaxf(mx, vals[t]); }
    for (int o = 16; o; o >>= 1) mx = fmaxf(mx, __shfl_xor_sync(0xffffffffu, mx, o));
    float sum = 0.f;
    for (int t = 0; t < per; t++) { vals[t] = __expf(vals[t] - mx); sum += vals[t]; }
    for (int o = 16; o; o >>= 1) sum += __shfl_xor_sync(0xffffffffu, sum, o);
    float inv = 1.f / sum;
    for (int t = 0; t < per; t++) r[lane + (t<<5)] = vals[t] * inv;
}

// ============================ host orchestration ============================
#define G2B   mma_gemm2<0,1>
#define G2G   mma_gemm2<1,1>
#define G2N   mma_gemm2<0,0>
#define TCG_AV  mma_gemm<32,1,0,0>

static const int FA_SMEM = (128*36 + 128*36 + 32*132) * 4;   // 53760 B
static const int G2_SMEM = (2*128*36 + 2*128*36) * 4;        // 73728 B

extern "C" void kernel_launch(void* const* d_in, const int* in_sizes, int n_in,
                              void* d_out, int out_size) {
    const int*   var_idx   = (const int*)  d_in[0];
    const int*   sign_idx  = (const int*)  d_in[1];
    const void*  lit_mask  = (const void*) d_in[2];
    const float* var_emb   = (const float*)d_in[3];
    const float* sign_emb  = (const float*)d_in[4];
    const float* litpos    = (const float*)d_in[5];
    const float* clausepos = (const float*)d_in[6];
    const float* enc_in_w  = (const float*)d_in[7];
    const float* enc_in_b  = (const float*)d_in[8];
    const float* enc_out_w = (const float*)d_in[9];
    const float* enc_out_b = (const float*)d_in[10];
    const float* enc_ff1_w = (const float*)d_in[11];
    const float* enc_ff1_b = (const float*)d_in[12];
    const float* enc_ff2_w = (const float*)d_in[13];
    const float* enc_ff2_b = (const float*)d_in[14];
    const float* n1w = (const float*)d_in[15];
    const float* n1b = (const float*)d_in[16];
    const float* n2w = (const float*)d_in[17];
    const float* n2b = (const float*)d_in[18];
    const float* th_ln_w = (const float*)d_in[19];
    const float* th_ln_b = (const float*)d_in[20];
    const float* th_w = (const float*)d_in[21];
    const float* th_b = (const float*)d_in[22];
    const float* pq   = (const float*)d_in[23];
    const float* pa_in_w  = (const float*)d_in[24];
    const float* pa_in_b  = (const float*)d_in[25];
    const float* pa_out_w = (const float*)d_in[26];
    const float* pa_out_b = (const float*)d_in[27];
    const float* pn_w = (const float*)d_in[28];
    const float* pn_b = (const float*)d_in[29];
    float* out = (float*)d_out;

    float *x,*t0,*t1,*t2,*ch,*kp,*vp,*qh,*S2,*p1,*p2;
    cudaGetSymbolAddress((void**)&x,  g_x);
    cudaGetSymbolAddress((void**)&t0, g_t0);
    cudaGetSymbolAddress((void**)&t1, g_t1);
    cudaGetSymbolAddress((void**)&t2, g_t2);
    cudaGetSymbolAddress((void**)&ch, g_ch);
    cudaGetSymbolAddress((void**)&kp, g_kp);
    cudaGetSymbolAddress((void**)&vp, g_vp);
    cudaGetSymbolAddress((void**)&qh, g_qh);
    cudaGetSymbolAddress((void**)&S2, g_S2);
    cudaGetSymbolAddress((void**)&p1, g_p1);
    cudaGetSymbolAddress((void**)&p2, g_p2);

    cudaFuncSetAttribute(fused_attn, cudaFuncAttributeMaxDynamicSharedMemorySize, FA_SMEM);
    cudaFuncSetAttribute(G2B, cudaFuncAttributeMaxDynamicSharedMemorySize, G2_SMEM);
    cudaFuncSetAttribute(G2G, cudaFuncAttributeMaxDynamicSharedMemorySize, G2_SMEM);
    cudaFuncSetAttribute(G2N, cudaFuncAttributeMaxDynamicSharedMemorySize, G2_SMEM);

    const int M = BB*CC;
    const float escale = 0.17677669529663687f;   // 1/sqrt(32)
    const float pscale = 0.08838834764831845f;   // 1/sqrt(128)

    detect_mask_kernel<<<16, 256>>>((const int*)lit_mask);
    pool_kernel<<<M, 256>>>(var_idx, sign_idx, lit_mask, var_emb, sign_emb,
                            litpos, clausepos, x);

    for (int i = 0; i < NLL; i++) {
        const float* wqkv = enc_in_w  + (size_t)i*768*DD;
        const float* bqkv = enc_in_b  + (size_t)i*768;
        const float* wo   = enc_out_w + (size_t)i*DD*DD;
        const float* bo   = enc_out_b + (size_t)i*DD;
        const float* w1   = enc_ff1_w + (size_t)i*HH*DD;
        const float* b1   = enc_ff1_b + (size_t)i*HH;
        const float* w2   = enc_ff2_w + (size_t)i*DD*HH;
        const float* b2   = enc_ff2_b + (size_t)i*DD;

        // qkv = x @ Wqkv^T + b -> t0 [M,768]
        G2B<<<dim3(6,128,1),256,G2_SMEM>>>(x, wqkv, bqkv, t0, M,768,DD,
                                           DD,DD,768, 1,0,0,0,0,0,0, 1.f);
        // fused attention -> t1 [M,256]
        fused_attn<<<dim3(4, BB*NHD), 256, FA_SMEM>>>(t0, t1, escale);
        // out proj -> t2
        G2B<<<dim3(2,128,1),256,G2_SMEM>>>(t1, wo, bo, t2, M,DD,DD,
                                           DD,DD,DD, 1,0,0,0,0,0,0, 1.f);
        ln_kernel<<<M,256>>>(t2, x, n1w + i*DD, n1b + i*DD, x, DD, 0);
        // ff1 gelu -> t0 [M,1024]
        G2G<<<dim3(8,128,1),256,G2_SMEM>>>(x, w1, b1, t0, M,HH,DD,
                                           DD,DD,HH, 1,0,0,0,0,0,0, 1.f);
        // ff2 -> t2
        G2B<<<dim3(2,128,1),256,G2_SMEM>>>(t0, w2, b2, t2, M,DD,HH,
                                           HH,HH,DD, 1,0,0,0,0,0,0, 1.f);
        ln_kernel<<<M,256>>>(t2, x, n2w + i*DD, n2b + i*DD, x, DD, 0);
    }

    // ch = LN(x) @ th_w^T + th_b
    ln_kernel<<<M,256>>>(x, nullptr, th_ln_w, th_ln_b, t2, DD, 0);
    G2B<<<dim3(8,128,1),256,G2_SMEM>>>(t2, th_w, th_b, ch, M,HH,DD,
                                       DD,DD,HH, 1,0,0,0,0,0,0, 1.f);

    // prefix cross-attention
    G2B<<<dim3(8,1,1),256,G2_SMEM>>>(pq, pa_in_w, pa_in_b, qh, PP,HH,HH,
                                     HH,HH,HH, 1,0,0,0,0,0,0, 1.f);
    G2B<<<dim3(8,128,1),256,G2_SMEM>>>(ch, pa_in_w + (size_t)HH*HH, pa_in_b + HH, kp,
                                       M,HH,HH, HH,HH,HH, 1,0,0,0,0,0,0, 1.f);
    G2B<<<dim3(8,128,1),256,G2_SMEM>>>(ch, pa_in_w + (size_t)2*HH*HH, pa_in_b + 2*HH, vp,
                                       M,HH,HH, HH,HH,HH, 1,0,0,0,0,0,0, 1.f);
    // scores2 per (b,h): [16,512], K=128
    G2N<<<dim3(4,1,BB*NHD),256,G2_SMEM>>>(qh, kp, nullptr, S2, PP,CC,128,
                                          HH,HH,CC, NHD,
                                          0L, 128L, (long)CC*HH, 128L,
                                          (long)NHD*PP*CC, (long)PP*CC, pscale);
    softmax_kernel<<<(BB*NHD*PP)/8, 256>>>(S2, CC);
    // AV2 per (b,h): [16,128], K=512
    TCG_AV<<<dim3(4,1,BB*NHD),256>>>(S2, vp, nullptr, p1, PP,128,CC,
                                     CC,HH,HH, NHD,
                                     (long)NHD*PP*CC, (long)PP*CC,
                                     (long)CC*HH, 128L,
                                     (long)PP*HH, 128L, 1.f);
    // out proj
    G2B<<<dim3(8,4,1),256,G2_SMEM>>>(p1, pa_out_w, pa_out_b, p2, BB*PP,HH,HH,
                                     HH,HH,HH, 1,0,0,0,0,0,0, 1.f);
    ln_kernel<<<BB*PP,256>>>(p2, pq, pn_w, pn_b, out, HH, PP);
}

// round 7
// speedup vs baseline: 3.6495x; 1.0105x over previous
#include <cuda_runtime.h>
#include <cstdint>

#define BB 32
#define CC 512
#define LL 16
#define DD 256
#define HH 1024
#define PP 16
#define NHD 8
#define NLL 4

// ---------------- scratch (static device globals; allocation-free) ----------------
__device__ float g_x [BB*CC*DD];
__device__ float g_t0[BB*CC*HH];
__device__ float g_t1[BB*CC*DD];
__device__ float g_t2[BB*CC*DD];
__device__ float g_ch[BB*CC*HH];
__device__ float g_kp[BB*CC*HH];
__device__ float g_vp[BB*CC*HH];
__device__ float g_qh[PP*HH];
__device__ float g_S2[BB*NHD*PP*CC];
__device__ float g_p1[BB*PP*HH];
__device__ float g_p2[BB*PP*HH];
__device__ int   g_maskmode;

// ---------------- small helpers ----------------
__device__ __forceinline__ uint32_t f2tf32(float f) {
    uint32_t u; asm("cvt.rna.tf32.f32 %0, %1;" : "=r"(u) : "f"(f)); return u;
}
__device__ __forceinline__ uint32_t smem_u32(const void* p) {
    uint32_t a;
    asm("{ .reg .u64 t; cvta.to.shared.u64 t, %1; cvt.u32.u64 %0, t; }" : "=r"(a) : "l"(p));
    return a;
}
__device__ __forceinline__ float gelu_f(float v) {
    return 0.5f * v * (1.f + erff(v * 0.70710678118654752f));
}
__device__ __forceinline__ void mma_tf32(float* c, const uint32_t* a, const uint32_t* b) {
    asm volatile(
        "mma.sync.aligned.m16n8k8.row.col.f32.tf32.tf32.f32 "
        "{%0,%1,%2,%3}, {%4,%5,%6,%7}, {%8,%9}, {%0,%1,%2,%3};"
        : "+f"(c[0]), "+f"(c[1]), "+f"(c[2]), "+f"(c[3])
        : "r"(a[0]), "r"(a[1]), "r"(a[2]), "r"(a[3]), "r"(b[0]), "r"(b[1]));
}
#define LDM_X4(r0, r1, r2, r3, addr) \
    asm volatile("ldmatrix.sync.aligned.m8n8.x4.shared.b16 {%0,%1,%2,%3}, [%4];" \
        : "=r"(r0), "=r"(r1), "=r"(r2), "=r"(r3) : "r"(addr))
#define CPA16(dst, src, pred) \
    asm volatile("cp.async.cg.shared.global [%0], [%1], 16, %2;" \
                 :: "r"(dst), "l"(src), "r"((pred) ? 16 : 0))
#define CP_COMMIT() asm volatile("cp.async.commit_group;")
#define CP_WAIT1()  asm volatile("cp.async.wait_group 1;")
#define CP_WAIT0()  asm volatile("cp.async.wait_group 0;")

// ============================ v2: cp.async + ldmatrix tf32 GEMM (BN=128, W[N,K]) =========
template<int ACT, int HASB>
__global__ __launch_bounds__(256) void mma_gemm2(
    const float* __restrict__ A, const float* __restrict__ W,
    const float* __restrict__ bias, float* __restrict__ Cp,
    int M, int N, int K, int lda, int ldw, int ldc,
    int nsub, long sAb, long sAs, long sWb, long sWs, long sCb, long sCs,
    float alpha)
{
    constexpr int BM = 128, BN = 128, BK = 32, LDSR = 36;
    constexpr uint32_t STB = BM * LDSR * 4;      // 18432 bytes per stage buffer
    extern __shared__ uint32_t sm2[];
    uint32_t* AsBuf = sm2;                       // 2 x [BM*LDSR]
    uint32_t* WsBuf = sm2 + 2 * BM * LDSR;       // 2 x [BN*LDSR]

    int tid = threadIdx.x, wid = tid >> 5, lane = tid & 31;
    int warpM = wid >> 2, warpN = wid & 3;
    int g = lane >> 2, tg = lane & 3;
    int bm = blockIdx.y * BM, bn = blockIdx.x * BN;
    int z = blockIdx.z, zb = z / nsub, zs = z % nsub;
    const float* Ab = A + (size_t)zb * sAb + (size_t)zs * sAs;
    const float* Wb = W + (size_t)zb * sWb + (size_t)zs * sWs;
    float*       Cb = Cp + (size_t)zb * sCb + (size_t)zs * sCs;

    uint32_t asAddr = smem_u32(AsBuf);
    uint32_t wsAddr = smem_u32(WsBuf);

    // ldmatrix per-lane address components
    int arow = (lane & 7) + ((lane & 8) ? 8 : 0);      // A: row within 16-row frag
    int acol = (lane & 16) ? 4 : 0;
    int brow = (lane & 7) + ((lane & 16) ? 8 : 0);     // B pair: row within 16 n-rows
    int bcol = (lane & 8) ? 4 : 0;
    uint32_t aLane = (uint32_t)((warpM * 64 + arow) * LDSR + acol) * 4;
    uint32_t bLane = (uint32_t)((warpN * 32 + brow) * LDSR + bcol) * 4;

    auto load_stage = [&](int st, int k0) {
        uint32_t ab = asAddr + (uint32_t)st * STB;
        uint32_t wb = wsAddr + (uint32_t)st * STB;
        #pragma unroll
        for (int idx = tid; idx < BM * 8; idx += 256) {
            int row = idx >> 3, q = idx & 7;
            int gm = bm + row;
            bool ok = gm < M;
            int gmc = ok ? gm : 0;
            CPA16(ab + (uint32_t)(row * LDSR + q * 4) * 4,
                  Ab + (size_t)gmc * lda + k0 + q * 4, ok);
        }
        #pragma unroll
        for (int idx = tid; idx < BN * 8; idx += 256) {
            int row = idx >> 3, q = idx & 7;
            CPA16(wb + (uint32_t)(row * LDSR + q * 4) * 4,
                  Wb + (size_t)(bn + row) * ldw + k0 + q * 4, true);
        }
        CP_COMMIT();
    };

    float acc[4][4][4];
    #pragma unroll
    for (int i = 0; i < 4; i++)
        #pragma unroll
        for (int j = 0; j < 4; j++)
            #pragma unroll
            for (int q = 0; q < 4; q++) acc[i][j][q] = 0.f;

    int nk = K / BK;
    load_stage(0, 0);

    for (int i = 0; i < nk; i++) {
        int cur = i & 1;
        if (i + 1 < nk) { load_stage((i + 1) & 1, (i + 1) * BK); CP_WAIT1(); }
        else            { CP_WAIT0(); }
        __syncthreads();

        uint32_t aB = asAddr + (uint32_t)cur * STB + aLane;
        uint32_t wB = wsAddr + (uint32_t)cur * STB + bLane;
        #pragma unroll
        for (int kk = 0; kk < BK; kk += 8) {
            uint32_t af[4][4], bf[4][2];
            #pragma unroll
            for (int mi = 0; mi < 4; mi++)
                LDM_X4(af[mi][0], af[mi][1], af[mi][2], af[mi][3],
                       aB + (uint32_t)(mi * 16 * LDSR + kk) * 4);
            LDM_X4(bf[0][0], bf[0][1], bf[1][0], bf[1][1], wB + (uint32_t)kk * 4);
            LDM_X4(bf[2][0], bf[2][1], bf[3][0], bf[3][1],
                   wB + (uint32_t)(16 * LDSR + kk) * 4);
            // +0x1000: round-half-away to tf32 (HW truncates low 13 mantissa bits)
            #pragma unroll
            for (int mi = 0; mi < 4; mi++)
                #pragma unroll
                for (int q = 0; q < 4; q++) af[mi][q] += 0x1000;
            #pragma unroll
            for (int nj = 0; nj < 4; nj++) { bf[nj][0] += 0x1000; bf[nj][1] += 0x1000; }
            #pragma unroll
            for (int mi = 0; mi < 4; mi++)
                #pragma unroll
                for (int nj = 0; nj < 4; nj++)
                    mma_tf32(acc[mi][nj], af[mi], bf[nj]);
        }
        __syncthreads();
    }

    #pragma unroll
    for (int mi = 0; mi < 4; mi++) {
        int r0 = bm + warpM * 64 + mi * 16 + g;
        #pragma unroll
        for (int nj = 0; nj < 4; nj++) {
            int c = bn + warpN * 32 + nj * 8 + 2 * tg;
            float b0 = 0.f, b1 = 0.f;
            if (HASB) { b0 = bias[c]; b1 = bias[c + 1]; }
            if (r0 < M) {
                float v0 = acc[mi][nj][0] * alpha + b0;
                float v1 = acc[mi][nj][1] * alpha + b1;
                if (ACT) { v0 = gelu_f(v0); v1 = gelu_f(v1); }
                Cb[(size_t)r0 * ldc + c]     = v0;
                Cb[(size_t)r0 * ldc + c + 1] = v1;
            }
            if (r0 + 8 < M) {
                float v2 = acc[mi][nj][2] * alpha + b0;
                float v3 = acc[mi][nj][3] * alpha + b1;
                if (ACT) { v2 = gelu_f(v2); v3 = gelu_f(v3); }
                Cb[(size_t)(r0 + 8) * ldc + c]     = v2;
                Cb[(size_t)(r0 + 8) * ldc + c + 1] = v3;
            }
        }
    }
}

// ============================ v1 GEMM (TRB path, AV2 only) ============================
template<int BN, int TRB, int ACT, int HASB>
__global__ __launch_bounds__(256, 2) void mma_gemm(
    const float* __restrict__ A, const float* __restrict__ W,
    const float* __restrict__ bias, float* __restrict__ Cp,
    int M, int N, int K, int lda, int ldw, int ldc,
    int nsub, long sAb, long sAs, long sWb, long sWs, long sCb, long sCs,
    float alpha)
{
    constexpr int BM = 128, BK = 32;
    constexpr int LDSR = BK + 4;
    constexpr int WN = (BN == 128) ? 32 : 8;
    constexpr int MI = 4;
    constexpr int NJ = WN / 8;

    __shared__ uint32_t As[BM * LDSR];
    __shared__ uint32_t Ws[BN * LDSR];

    int tid = threadIdx.x, wid = tid >> 5, lane = tid & 31;
    int warpM = wid >> 2;
    int warpN = wid & 3;
    int g = lane >> 2, tg = lane & 3;

    int bm = blockIdx.y * BM;
    int bn = blockIdx.x * BN;
    int z = blockIdx.z;
    int zb = z / nsub, zs = z % nsub;
    const float* Ab = A + (size_t)zb * sAb + (size_t)zs * sAs;
    const float* Wb = W + (size_t)zb * sWb + (size_t)zs * sWs;
    float*       Cb = Cp + (size_t)zb * sCb + (size_t)zs * sCs;

    float acc[MI][NJ][4];
    #pragma unroll
    for (int i = 0; i < MI; i++)
        #pragma unroll
        for (int j = 0; j < NJ; j++)
            #pragma unroll
            for (int q = 0; q < 4; q++) acc[i][j][q] = 0.f;

    for (int k0 = 0; k0 < K; k0 += BK) {
        #pragma unroll
        for (int idx = tid; idx < BM * (BK / 4); idx += 256) {
            int row = idx >> 3, q = idx & 7;
            int gm = bm + row;
            if (gm < M) {
                float4 v = *(const float4*)(Ab + (size_t)gm * lda + k0 + q * 4);
                uint32_t* p = &As[row * LDSR + q * 4];
                p[0] = f2tf32(v.x); p[1] = f2tf32(v.y); p[2] = f2tf32(v.z); p[3] = f2tf32(v.w);
            }
        }
        if (!TRB) {
            #pragma unroll
            for (int idx = tid; idx < BN * (BK / 4); idx += 256) {
                int row = idx >> 3, q = idx & 7;
                float4 v = *(const float4*)(Wb + (size_t)(bn + row) * ldw + k0 + q * 4);
                uint32_t* p = &Ws[row * LDSR + q * 4];
                p[0] = f2tf32(v.x); p[1] = f2tf32(v.y); p[2] = f2tf32(v.z); p[3] = f2tf32(v.w);
            }
        } else {
            #pragma unroll
            for (int idx = tid; idx < (BK * BN) / 4; idx += 256) {
                int kk = idx / (BN / 4);
                int n4 = (idx % (BN / 4)) * 4;
                float4 v = *(const float4*)(Wb + (size_t)(k0 + kk) * ldw + bn + n4);
                Ws[(n4 + 0) * LDSR + kk] = f2tf32(v.x);
                Ws[(n4 + 1) * LDSR + kk] = f2tf32(v.y);
                Ws[(n4 + 2) * LDSR + kk] = f2tf32(v.z);
                Ws[(n4 + 3) * LDSR + kk] = f2tf32(v.w);
            }
        }
        __syncthreads();

        #pragma unroll
        for (int kk = 0; kk < BK; kk += 8) {
            uint32_t af[MI][4], bf[NJ][2];
            #pragma unroll
            for (int mi = 0; mi < MI; mi++) {
                int r0 = warpM * 64 + mi * 16 + g;
                af[mi][0] = As[r0 * LDSR + kk + tg];
                af[mi][1] = As[(r0 + 8) * LDSR + kk + tg];
                af[mi][2] = As[r0 * LDSR + kk + tg + 4];
                af[mi][3] = As[(r0 + 8) * LDSR + kk + tg + 4];
            }
            #pragma unroll
            for (int nj = 0; nj < NJ; nj++) {
                int c0 = warpN * WN + nj * 8 + g;
                bf[nj][0] = Ws[c0 * LDSR + kk + tg];
                bf[nj][1] = Ws[c0 * LDSR + kk + tg + 4];
            }
            #pragma unroll
            for (int mi = 0; mi < MI; mi++)
                #pragma unroll
                for (int nj = 0; nj < NJ; nj++)
                    mma_tf32(acc[mi][nj], af[mi], bf[nj]);
        }
        __syncthreads();
    }

    #pragma unroll
    for (int mi = 0; mi < MI; mi++) {
        int r0 = bm + warpM * 64 + mi * 16 + g;
        #pragma unroll
        for (int nj = 0; nj < NJ; nj++) {
            int c = bn + warpN * WN + nj * 8 + 2 * tg;
            float b0 = 0.f, b1 = 0.f;
            if (HASB) { b0 = bias[c]; b1 = bias[c + 1]; }
            if (r0 < M) {
                float v0 = acc[mi][nj][0] * alpha + b0;
                float v1 = acc[mi][nj][1] * alpha + b1;
                if (ACT) { v0 = gelu_f(v0); v1 = gelu_f(v1); }
                Cb[(size_t)r0 * ldc + c]     = v0;
                Cb[(size_t)r0 * ldc + c + 1] = v1;
            }
            if (r0 + 8 < M) {
                float v2 = acc[mi][nj][2] * alpha + b0;
                float v3 = acc[mi][nj][3] * alpha + b1;
                if (ACT) { v2 = gelu_f(v2); v3 = gelu_f(v3); }
                Cb[(size_t)(r0 + 8) * ldc + c]     = v2;
                Cb[(size_t)(r0 + 8) * ldc + c + 1] = v3;
            }
        }
    }
}

// ============================ fused flash attention (encoder) ============================
__global__ __launch_bounds__(256) void fused_attn(
    const float* __restrict__ qkv, float* __restrict__ o, float escale)
{
    extern __shared__ uint32_t fa_sm[];
    uint32_t* Qs = fa_sm;                 // [128][36]
    uint32_t* Ks = Qs + 128 * 36;         // [128][36]
    uint32_t* Vs = Ks + 128 * 36;         // [32][132]  (transposed: [d][key])

    int tid = threadIdx.x, lane = tid & 31, w = tid >> 5;
    int g = lane >> 2, tg = lane & 3;
    int qt = blockIdx.x;
    int z  = blockIdx.y;
    int b  = z >> 3, h = z & 7;
    const float* base = qkv + (size_t)b * CC * 768;

    // ldmatrix lane address components
    int arow = (lane & 7) + ((lane & 8) ? 8 : 0);
    int acol = (lane & 16) ? 4 : 0;
    int brow = (lane & 7) + ((lane & 16) ? 8 : 0);
    int bcol = (lane & 8) ? 4 : 0;
    uint32_t qBase = smem_u32(Qs) + (uint32_t)((w * 16 + arow) * 36 + acol) * 4;
    uint32_t kBase = smem_u32(Ks) + (uint32_t)(brow * 36 + bcol) * 4;
    uint32_t vBase = smem_u32(Vs) + (uint32_t)(brow * 132 + bcol) * 4;

    #pragma unroll
    for (int idx = tid; idx < 128 * 8; idx += 256) {
        int r = idx >> 3, q4 = idx & 7;
        float4 v = *(const float4*)(base + (size_t)(qt * 128 + r) * 768 + h * 32 + q4 * 4);
        uint32_t* p = &Qs[r * 36 + q4 * 4];
        p[0] = f2tf32(v.x); p[1] = f2tf32(v.y); p[2] = f2tf32(v.z); p[3] = f2tf32(v.w);
    }

    float oacc[4][4];
    #pragma unroll
    for (int i = 0; i < 4; i++)
        #pragma unroll
        for (int q = 0; q < 4; q++) oacc[i][q] = 0.f;
    float rm0 = -1e30f, rm1 = -1e30f, rs0 = 0.f, rs1 = 0.f;

    for (int kt = 0; kt < 4; kt++) {
        __syncthreads();
        #pragma unroll
        for (int idx = tid; idx < 128 * 8; idx += 256) {
            int r = idx >> 3, q4 = idx & 7;
            const float* kr = base + (size_t)(kt * 128 + r) * 768 + 256 + h * 32 + q4 * 4;
            float4 kv = *(const float4*)kr;
            uint32_t* p = &Ks[r * 36 + q4 * 4];
            p[0] = f2tf32(kv.x); p[1] = f2tf32(kv.y); p[2] = f2tf32(kv.z); p[3] = f2tf32(kv.w);
            float4 vv = *(const float4*)(kr + 256);
            int d = q4 * 4;
            Vs[(d + 0) * 132 + r] = f2tf32(vv.x);
            Vs[(d + 1) * 132 + r] = f2tf32(vv.y);
            Vs[(d + 2) * 132 + r] = f2tf32(vv.z);
            Vs[(d + 3) * 132 + r] = f2tf32(vv.w);
        }
        __syncthreads();

        // ---- S = Q @ K^T : 16 rows x 128 keys per warp ----
        float sacc[16][4];
        #pragma unroll
        for (int nj = 0; nj < 16; nj++)
            #pragma unroll
            for (int q = 0; q < 4; q++) sacc[nj][q] = 0.f;

        #pragma unroll
        for (int kk = 0; kk < 32; kk += 8) {
            uint32_t af[4];
            LDM_X4(af[0], af[1], af[2], af[3], qBase + (uint32_t)kk * 4);
            #pragma unroll
            for (int p8 = 0; p8 < 8; p8++) {
                uint32_t bf[4];
                LDM_X4(bf[0], bf[1], bf[2], bf[3],
                       kBase + (uint32_t)(p8 * 16 * 36 + kk) * 4);
                mma_tf32(sacc[2 * p8],     af, bf);
                mma_tf32(sacc[2 * p8 + 1], af, bf + 2);
            }
        }

        // ---- online softmax (rows g and g+8) ----
        float tm0 = -1e30f, tm1 = -1e30f;
        #pragma unroll
        for (int nj = 0; nj < 16; nj++) {
            tm0 = fmaxf(tm0, fmaxf(sacc[nj][0], sacc[nj][1]));
            tm1 = fmaxf(tm1, fmaxf(sacc[nj][2], sacc[nj][3]));
        }
        tm0 *= escale; tm1 *= escale;
        tm0 = fmaxf(tm0, __shfl_xor_sync(0xffffffffu, tm0, 1));
        tm0 = fmaxf(tm0, __shfl_xor_sync(0xffffffffu, tm0, 2));
        tm1 = fmaxf(tm1, __shfl_xor_sync(0xffffffffu, tm1, 1));
        tm1 = fmaxf(tm1, __shfl_xor_sync(0xffffffffu, tm1, 2));
        float nm0 = fmaxf(rm0, tm0), nm1 = fmaxf(rm1, tm1);
        float cr0 = __expf(rm0 - nm0), cr1 = __expf(rm1 - nm1);
        rm0 = nm0; rm1 = nm1;
        float ps0 = 0.f, ps1 = 0.f;
        #pragma unroll
        for (int nj = 0; nj < 16; nj++) {
            float p0 = __expf(sacc[nj][0] * escale - nm0);
            float p1 = __expf(sacc[nj][1] * escale - nm0);
            float p2 = __expf(sacc[nj][2] * escale - nm1);
            float p3 = __expf(sacc[nj][3] * escale - nm1);
            sacc[nj][0] = p0; sacc[nj][1] = p1; sacc[nj][2] = p2; sacc[nj][3] = p3;
            ps0 += p0 + p1; ps1 += p2 + p3;
        }
        ps0 += __shfl_xor_sync(0xffffffffu, ps0, 1);
        ps0 += __shfl_xor_sync(0xffffffffu, ps0, 2);
        ps1 += __shfl_xor_sync(0xffffffffu, ps1, 1);
        ps1 += __shfl_xor_sync(0xffffffffu, ps1, 2);
        rs0 = rs0 * cr0 + ps0;
        rs1 = rs1 * cr1 + ps1;
        #pragma unroll
        for (int vj = 0; vj < 4; vj++) {
            oacc[vj][0] *= cr0; oacc[vj][1] *= cr0;
            oacc[vj][2] *= cr1; oacc[vj][3] *= cr1;
        }

        // ---- O += P @ V : P relayout via shuffles, V frags via ldmatrix ----
        int srcA = (lane & ~3) | (tg >> 1);
        int srcB = srcA + 2;
        bool odd = (tg & 1);
        #pragma unroll
        for (int nj = 0; nj < 16; nj++) {
            float x0 = __shfl_sync(0xffffffffu, sacc[nj][0], srcA);
            float x1 = __shfl_sync(0xffffffffu, sacc[nj][1], srcA);
            float y0 = __shfl_sync(0xffffffffu, sacc[nj][0], srcB);
            float y1 = __shfl_sync(0xffffffffu, sacc[nj][1], srcB);
            float z0 = __shfl_sync(0xffffffffu, sacc[nj][2], srcA);
            float z1 = __shfl_sync(0xffffffffu, sacc[nj][3], srcA);
            float w0 = __shfl_sync(0xffffffffu, sacc[nj][2], srcB);
            float w1 = __shfl_sync(0xffffffffu, sacc[nj][3], srcB);
            uint32_t a[4];
            a[0] = f2tf32(odd ? x1 : x0);
            a[1] = f2tf32(odd ? z1 : z0);
            a[2] = f2tf32(odd ? y1 : y0);
            a[3] = f2tf32(odd ? w1 : w0);
            #pragma unroll
            for (int vp = 0; vp < 2; vp++) {
                uint32_t bf[4];
                LDM_X4(bf[0], bf[1], bf[2], bf[3],
                       vBase + (uint32_t)(vp * 16 * 132 + nj * 8) * 4);
                mma_tf32(oacc[2 * vp],     a, bf);
                mma_tf32(oacc[2 * vp + 1], a, bf + 2);
            }
        }
    }

    float inv0 = 1.f / rs0, inv1 = 1.f / rs1;
    int row0 = b * CC + qt * 128 + w * 16 + g;
    #pragma unroll
    for (int vj = 0; vj < 4; vj++) {
        int c = h * 32 + vj * 8 + 2 * tg;
        o[(size_t)row0 * 256 + c]           = oacc[vj][0] * inv0;
        o[(size_t)row0 * 256 + c + 1]       = oacc[vj][1] * inv0;
        o[(size_t)(row0 + 8) * 256 + c]     = oacc[vj][2] * inv1;
        o[(size_t)(row0 + 8) * 256 + c + 1] = oacc[vj][3] * inv1;
    }
}

// ---------------- mask dtype detection ----------------
__global__ void detect_mask_kernel(const int* __restrict__ m) {
    __shared__ int found;
    if (threadIdx.x == 0) found = 0;
    __syncthreads();
    int idx = blockIdx.x * blockDim.x + threadIdx.x;
    unsigned v = (unsigned)m[idx];
    if (v > 1u) found = 1;
    __syncthreads();
    if (threadIdx.x == 0 && blockIdx.x == 0) g_maskmode = 0;
    __threadfence();
    if (found) g_maskmode = 1;
}

// ---------------- pool ----------------
__global__ void pool_kernel(const int* __restrict__ vi, const int* __restrict__ si,
                            const void* __restrict__ maskraw,
                            const float* __restrict__ ve, const float* __restrict__ se,
                            const float* __restrict__ lpe, const float* __restrict__ cpe,
                            float* __restrict__ x) {
    int bc = blockIdx.x;
    int c  = bc % CC;
    int d  = threadIdx.x;
    const int* viR = vi + bc * LL;
    const int* siR = si + bc * LL;
    __shared__ int mloc[LL];
    if (threadIdx.x < LL) {
        int mv;
        if (g_maskmode == 0) mv = ((const int*)maskraw)[bc * LL + threadIdx.x];
        else                 mv = ((const unsigned char*)maskraw)[bc * LL + threadIdx.x];
        mloc[threadIdx.x] = mv;
    }
    __syncthreads();
    float acc = 0.f; int cnt = 0;
    #pragma unroll
    for (int l = 0; l < LL; l++) {
        if (mloc[l]) {
            cnt++;
            acc += ve[viR[l]*DD + d] + se[siR[l]*DD + d] + lpe[l*DD + d];
        }
    }
    x[(size_t)bc*DD + d] = acc / (float)cnt + cpe[c*DD + d];
}

// ---------------- layernorm ----------------
__global__ void ln_kernel(const float* __restrict__ xin, const float* __restrict__ res,
                          const float* __restrict__ w, const float* __restrict__ b,
                          float* __restrict__ out, int N, int resMod) {
    int row = blockIdx.x;
    int tid = threadIdx.x;
    const float* xr = xin + (size_t)row * N;
    const float* rr = nullptr;
    if (res) rr = res + (size_t)(resMod ? (row % resMod) : row) * N;
    int per = N >> 8;
    float v[4];
    float s = 0.f;
    for (int i = 0; i < per; i++) {
        int cI = tid + (i << 8);
        float t = xr[cI];
        if (rr) t += rr[cI];
        v[i] = t; s += t;
    }
    __shared__ float red[256];
    red[tid] = s; __syncthreads();
    for (int o = 128; o; o >>= 1) { if (tid < o) red[tid] += red[tid+o]; __syncthreads(); }
    float mean = red[0] / (float)N;
    __syncthreads();
    float vs = 0.f;
    for (int i = 0; i < per; i++) { float d = v[i] - mean; vs += d*d; }
    red[tid] = vs; __syncthreads();
    for (int o = 128; o; o >>= 1) { if (tid < o) red[tid] += red[tid+o]; __syncthreads(); }
    float inv = rsqrtf(red[0] / (float)N + 1e-5f);
    for (int i = 0; i < per; i++) {
        int cI = tid + (i << 8);
        out[(size_t)row*N + cI] = (v[i] - mean) * inv * w[cI] + b[cI];
    }
}

// ---------------- softmax (prefix path) ----------------
__global__ void softmax_kernel(float* __restrict__ S, int cols) {
    int row  = blockIdx.x * 8 + (threadIdx.x >> 5);
    int lane = threadIdx.x & 31;
    float* r = S + (size_t)row * cols;
    int per = cols >> 5;
    float vals[16];
    float mx = -1e30f;
    for (int t = 0; t < per; t++) { vals[t] = r[lane + (t<<5)]; mx = fmaxf(mx, vals[t]); }
    for (int o = 16; o; o >>= 1) mx = fmaxf(mx, __shfl_xor_sync(0xffffffffu, mx, o));
    float sum = 0.f;
    for (int t = 0; t < per; t++) { vals[t] = __expf(vals[t] - mx); sum += vals[t]; }
    for (int o = 16; o; o >>= 1) sum += __shfl_xor_sync(0xffffffffu, sum, o);
    float inv = 1.f / sum;
    for (int t = 0; t < per; t++) r[lane + (t<<5)] = vals[t] * inv;
}

// ============================ host orchestration ============================
#define G2B   mma_gemm2<0,1>
#define G2G   mma_gemm2<1,1>
#define G2N   mma_gemm2<0,0>
#define TCG_AV  mma_gemm<32,1,0,0>

static const int FA_SMEM = (128*36 + 128*36 + 32*132) * 4;   // 53760 B
static const int G2_SMEM = (2*128*36 + 2*128*36) * 4;        // 73728 B

extern "C" void kernel_launch(void* const* d_in, const int* in_sizes, int n_in,
                              void* d_out, int out_size) {
    const int*   var_idx   = (const int*)  d_in[0];
    const int*   sign_idx  = (const int*)  d_in[1];
    const void*  lit_mask  = (const void*) d_in[2];
    const float* var_emb   = (const float*)d_in[3];
    const float* sign_emb  = (const float*)d_in[4];
    const float* litpos    = (const float*)d_in[5];
    const float* clausepos = (const float*)d_in[6];
    const float* enc_in_w  = (const float*)d_in[7];
    const float* enc_in_b  = (const float*)d_in[8];
    const float* enc_out_w = (const float*)d_in[9];
    const float* enc_out_b = (const float*)d_in[10];
    const float* enc_ff1_w = (const float*)d_in[11];
    const float* enc_ff1_b = (const float*)d_in[12];
    const float* enc_ff2_w = (const float*)d_in[13];
    const float* enc_ff2_b = (const float*)d_in[14];
    const float* n1w = (const float*)d_in[15];
    const float* n1b = (const float*)d_in[16];
    const float* n2w = (const float*)d_in[17];
    const float* n2b = (const float*)d_in[18];
    const float* th_ln_w = (const float*)d_in[19];
    const float* th_ln_b = (const float*)d_in[20];
    const float* th_w = (const float*)d_in[21];
    const float* th_b = (const float*)d_in[22];
    const float* pq   = (const float*)d_in[23];
    const float* pa_in_w  = (const float*)d_in[24];
    const float* pa_in_b  = (const float*)d_in[25];
    const float* pa_out_w = (const float*)d_in[26];
    const float* pa_out_b = (const float*)d_in[27];
    const float* pn_w = (const float*)d_in[28];
    const float* pn_b = (const float*)d_in[29];
    float* out = (float*)d_out;

    float *x,*t0,*t1,*t2,*ch,*kp,*vp,*qh,*S2,*p1,*p2;
    cudaGetSymbolAddress((void**)&x,  g_x);
    cudaGetSymbolAddress((void**)&t0, g_t0);
    cudaGetSymbolAddress((void**)&t1, g_t1);
    cudaGetSymbolAddress((void**)&t2, g_t2);
    cudaGetSymbolAddress((void**)&ch, g_ch);
    cudaGetSymbolAddress((void**)&kp, g_kp);
    cudaGetSymbolAddress((void**)&vp, g_vp);
    cudaGetSymbolAddress((void**)&qh, g_qh);
    cudaGetSymbolAddress((void**)&S2, g_S2);
    cudaGetSymbolAddress((void**)&p1, g_p1);
    cudaGetSymbolAddress((void**)&p2, g_p2);

    cudaFuncSetAttribute(fused_attn, cudaFuncAttributeMaxDynamicSharedMemorySize, FA_SMEM);
    cudaFuncSetAttribute(G2B, cudaFuncAttributeMaxDynamicSharedMemorySize, G2_SMEM);
    cudaFuncSetAttribute(G2G, cudaFuncAttributeMaxDynamicSharedMemorySize, G2_SMEM);
    cudaFuncSetAttribute(G2N, cudaFuncAttributeMaxDynamicSharedMemorySize, G2_SMEM);

    const int M = BB*CC;
    const float escale = 0.17677669529663687f;   // 1/sqrt(32)
    const float pscale = 0.08838834764831845f;   // 1/sqrt(128)

    detect_mask_kernel<<<16, 256>>>((const int*)lit_mask);
    pool_kernel<<<M, 256>>>(var_idx, sign_idx, lit_mask, var_emb, sign_emb,
                            litpos, clausepos, x);

    for (int i = 0; i < NLL; i++) {
        const float* wqkv = enc_in_w  + (size_t)i*768*DD;
        const float* bqkv = enc_in_b  + (size_t)i*768;
        const float* wo   = enc_out_w + (size_t)i*DD*DD;
        const float* bo   = enc_out_b + (size_t)i*DD;
        const float* w1   = enc_ff1_w + (size_t)i*HH*DD;
        const float* b1   = enc_ff1_b + (size_t)i*HH;
        const float* w2   = enc_ff2_w + (size_t)i*DD*HH;
        const float* b2   = enc_ff2_b + (size_t)i*DD;

        // qkv = x @ Wqkv^T + b -> t0 [M,768]
        G2B<<<dim3(6,128,1),256,G2_SMEM>>>(x, wqkv, bqkv, t0, M,768,DD,
                                           DD,DD,768, 1,0,0,0,0,0,0, 1.f);
        // fused attention -> t1 [M,256]
        fused_attn<<<dim3(4, BB*NHD), 256, FA_SMEM>>>(t0, t1, escale);
        // out proj -> t2
        G2B<<<dim3(2,128,1),256,G2_SMEM>>>(t1, wo, bo, t2, M,DD,DD,
                                           DD,DD,DD, 1,0,0,0,0,0,0, 1.f);
        ln_kernel<<<M,256>>>(t2, x, n1w + i*DD, n1b + i*DD, x, DD, 0);
        // ff1 gelu -> t0 [M,1024]
        G2G<<<dim3(8,128,1),256,G2_SMEM>>>(x, w1, b1, t0, M,HH,DD,
                                           DD,DD,HH, 1,0,0,0,0,0,0, 1.f);
        // ff2 -> t2
        G2B<<<dim3(2,128,1),256,G2_SMEM>>>(t0, w2, b2, t2, M,DD,HH,
                                           HH,HH,DD, 1,0,0,0,0,0,0, 1.f);
        ln_kernel<<<M,256>>>(t2, x, n2w + i*DD, n2b + i*DD, x, DD, 0);
    }

    // ch = LN(x) @ th_w^T + th_b
    ln_kernel<<<M,256>>>(x, nullptr, th_ln_w, th_ln_b, t2, DD, 0);
    G2B<<<dim3(8,128,1),256,G2_SMEM>>>(t2, th_w, th_b, ch, M,HH,DD,
                                       DD,DD,HH, 1,0,0,0,0,0,0, 1.f);

    // prefix cross-attention
    G2B<<<dim3(8,1,1),256,G2_SMEM>>>(pq, pa_in_w, pa_in_b, qh, PP,HH,HH,
                                     HH,HH,HH, 1,0,0,0,0,0,0, 1.f);
    G2B<<<dim3(8,128,1),256,G2_SMEM>>>(ch, pa_in_w + (size_t)HH*HH, pa_in_b + HH, kp,
                                       M,HH,HH, HH,HH,HH, 1,0,0,0,0,0,0, 1.f);
    G2B<<<dim3(8,128,1),256,G2_SMEM>>>(ch, pa_in_w + (size_t)2*HH*HH, pa_in_b + 2*HH, vp,
                                       M,HH,HH, HH,HH,HH, 1,0,0,0,0,0,0, 1.f);
    // scores2 per (b,h): [16,512], K=128
    G2N<<<dim3(4,1,BB*NHD),256,G2_SMEM>>>(qh, kp, nullptr, S2, PP,CC,128,
                                          HH,HH,CC, NHD,
                                          0L, 128L, (long)CC*HH, 128L,
                                          (long)NHD*PP*CC, (long)PP*CC, pscale);
    softmax_kernel<<<(BB*NHD*PP)/8, 256>>>(S2, CC);
    // AV2 per (b,h): [16,128], K=512
    TCG_AV<<<dim3(4,1,BB*NHD),256>>>(S2, vp, nullptr, p1, PP,128,CC,
                                     CC,HH,HH, NHD,
                                     (long)NHD*PP*CC, (long)PP*CC,
                                     (long)CC*HH, 128L,
                                     (long)PP*HH, 128L, 1.f);
    // out proj
    G2B<<<dim3(8,4,1),256,G2_SMEM>>>(p1, pa_out_w, pa_out_b, p2, BB*PP,HH,HH,
                                     HH,HH,HH, 1,0,0,0,0,0,0, 1.f);
    ln_kernel<<<BB*PP,256>>>(p2, pq, pn_w, pn_b, out, HH, PP);
}

// round 8
// speedup vs baseline: 3.7278x; 1.0215x over previous
#include <cuda_runtime.h>
#include <cstdint>

#define BB 32
#define CC 512
#define LL 16
#define DD 256
#define HH 1024
#define PP 16
#define NHD 8
#define NLL 4

// ---------------- scratch (static device globals; allocation-free) ----------------
__device__ float g_x [BB*CC*DD];
__device__ float g_t0[BB*CC*HH];
__device__ float g_t1[BB*CC*DD];
__device__ float g_t2[BB*CC*DD];
__device__ float g_ch[BB*CC*HH];
__device__ float g_kv[BB*CC*2*HH];        // merged K/V projections [M, 2048]
__device__ float g_qh[PP*HH];
__device__ float g_S2[BB*NHD*PP*CC];
__device__ float g_p1[BB*PP*HH];
__device__ float g_p2[BB*PP*HH];
__device__ int   g_maskmode;
// pre-rounded (tf32-in-fp32) weights
__device__ float g_rw_in [NLL*768*DD];
__device__ float g_rw_out[NLL*DD*DD];
__device__ float g_rw_f1 [NLL*HH*DD];
__device__ float g_rw_f2 [NLL*DD*HH];
__device__ float g_rw_th [HH*DD];
__device__ float g_rw_pa [3*HH*HH];
__device__ float g_rw_po [HH*HH];
__device__ float g_rw_pq [PP*HH];

// ---------------- small helpers ----------------
__device__ __forceinline__ uint32_t f2tf32(float f) {
    uint32_t u; asm("cvt.rna.tf32.f32 %0, %1;" : "=r"(u) : "f"(f)); return u;
}
__device__ __forceinline__ float rndf(float f) { return __uint_as_float(f2tf32(f)); }
__device__ __forceinline__ uint32_t smem_u32(const void* p) {
    uint32_t a;
    asm("{ .reg .u64 t; cvta.to.shared.u64 t, %1; cvt.u32.u64 %0, t; }" : "=r"(a) : "l"(p));
    return a;
}
__device__ __forceinline__ float gelu_f(float v) {
    return 0.5f * v * (1.f + erff(v * 0.70710678118654752f));
}
__device__ __forceinline__ void mma_tf32(float* c, const uint32_t* a, const uint32_t* b) {
    asm volatile(
        "mma.sync.aligned.m16n8k8.row.col.f32.tf32.tf32.f32 "
        "{%0,%1,%2,%3}, {%4,%5,%6,%7}, {%8,%9}, {%0,%1,%2,%3};"
        : "+f"(c[0]), "+f"(c[1]), "+f"(c[2]), "+f"(c[3])
        : "r"(a[0]), "r"(a[1]), "r"(a[2]), "r"(a[3]), "r"(b[0]), "r"(b[1]));
}
#define LDM_X4(r0, r1, r2, r3, addr) \
    asm volatile("ldmatrix.sync.aligned.m8n8.x4.shared.b16 {%0,%1,%2,%3}, [%4];" \
        : "=r"(r0), "=r"(r1), "=r"(r2), "=r"(r3) : "r"(addr))
#define CPA16(dst, src, pred) \
    asm volatile("cp.async.cg.shared.global [%0], [%1], 16, %2;" \
                 :: "r"(dst), "l"(src), "r"((pred) ? 16 : 0))
#define CP_COMMIT() asm volatile("cp.async.commit_group;")
#define CP_WAIT1()  asm volatile("cp.async.wait_group 1;")
#define CP_WAIT0()  asm volatile("cp.async.wait_group 0;")

// ---------------- roundify: fp32 -> tf32-rounded fp32 ----------------
__global__ void roundify(const float* __restrict__ src, float* __restrict__ dst, int n4) {
    int i = blockIdx.x * 256 + threadIdx.x;
    if (i < n4) {
        float4 v = ((const float4*)src)[i];
        v.x = rndf(v.x); v.y = rndf(v.y); v.z = rndf(v.z); v.w = rndf(v.w);
        ((float4*)dst)[i] = v;
    }
}

// ============================ v2: cp.async + ldmatrix tf32 GEMM ============================
// Inputs MUST be tf32-pre-rounded. C = act(alpha*A@W^T + bias), optional tf32-rounded store.
template<int ACT, int HASB, int ROUT>
__global__ __launch_bounds__(256) void mma_gemm2(
    const float* __restrict__ A, const float* __restrict__ W,
    const float* __restrict__ bias, float* __restrict__ Cp,
    int M, int N, int K, int lda, int ldw, int ldc,
    int nsub, long sAb, long sAs, long sWb, long sWs, long sCb, long sCs,
    float alpha)
{
    constexpr int BM = 128, BN = 128, BK = 32, LDSR = 36;
    constexpr uint32_t STB = BM * LDSR * 4;
    extern __shared__ uint32_t sm2[];
    uint32_t* AsBuf = sm2;
    uint32_t* WsBuf = sm2 + 2 * BM * LDSR;

    int tid = threadIdx.x, wid = tid >> 5, lane = tid & 31;
    int warpM = wid >> 2, warpN = wid & 3;
    int g = lane >> 2, tg = lane & 3;
    int bm = blockIdx.y * BM, bn = blockIdx.x * BN;
    int z = blockIdx.z, zb = z / nsub, zs = z % nsub;
    const float* Ab = A + (size_t)zb * sAb + (size_t)zs * sAs;
    const float* Wb = W + (size_t)zb * sWb + (size_t)zs * sWs;
    float*       Cb = Cp + (size_t)zb * sCb + (size_t)zs * sCs;

    uint32_t asAddr = smem_u32(AsBuf);
    uint32_t wsAddr = smem_u32(WsBuf);

    int arow = (lane & 7) + ((lane & 8) ? 8 : 0);
    int acol = (lane & 16) ? 4 : 0;
    int brow = (lane & 7) + ((lane & 16) ? 8 : 0);
    int bcol = (lane & 8) ? 4 : 0;
    uint32_t aLane = (uint32_t)((warpM * 64 + arow) * LDSR + acol) * 4;
    uint32_t bLane = (uint32_t)((warpN * 32 + brow) * LDSR + bcol) * 4;

    auto load_stage = [&](int st, int k0) {
        uint32_t ab = asAddr + (uint32_t)st * STB;
        uint32_t wb = wsAddr + (uint32_t)st * STB;
        #pragma unroll
        for (int idx = tid; idx < BM * 8; idx += 256) {
            int row = idx >> 3, q = idx & 7;
            int gm = bm + row;
            bool ok = gm < M;
            int gmc = ok ? gm : 0;
            CPA16(ab + (uint32_t)(row * LDSR + q * 4) * 4,
                  Ab + (size_t)gmc * lda + k0 + q * 4, ok);
        }
        #pragma unroll
        for (int idx = tid; idx < BN * 8; idx += 256) {
            int row = idx >> 3, q = idx & 7;
            CPA16(wb + (uint32_t)(row * LDSR + q * 4) * 4,
                  Wb + (size_t)(bn + row) * ldw + k0 + q * 4, true);
        }
        CP_COMMIT();
    };

    float acc[4][4][4];
    #pragma unroll
    for (int i = 0; i < 4; i++)
        #pragma unroll
        for (int j = 0; j < 4; j++)
            #pragma unroll
            for (int q = 0; q < 4; q++) acc[i][j][q] = 0.f;

    int nk = K / BK;
    load_stage(0, 0);

    for (int i = 0; i < nk; i++) {
        int cur = i & 1;
        if (i + 1 < nk) { load_stage((i + 1) & 1, (i + 1) * BK); CP_WAIT1(); }
        else            { CP_WAIT0(); }
        __syncthreads();

        uint32_t aB = asAddr + (uint32_t)cur * STB + aLane;
        uint32_t wB = wsAddr + (uint32_t)cur * STB + bLane;
        #pragma unroll
        for (int kk = 0; kk < BK; kk += 8) {
            uint32_t af[4][4], bf[4][2];
            #pragma unroll
            for (int mi = 0; mi < 4; mi++)
                LDM_X4(af[mi][0], af[mi][1], af[mi][2], af[mi][3],
                       aB + (uint32_t)(mi * 16 * LDSR + kk) * 4);
            LDM_X4(bf[0][0], bf[0][1], bf[1][0], bf[1][1], wB + (uint32_t)kk * 4);
            LDM_X4(bf[2][0], bf[2][1], bf[3][0], bf[3][1],
                   wB + (uint32_t)(16 * LDSR + kk) * 4);
            #pragma unroll
            for (int mi = 0; mi < 4; mi++)
                #pragma unroll
                for (int nj = 0; nj < 4; nj++)
                    mma_tf32(acc[mi][nj], af[mi], bf[nj]);
        }
        __syncthreads();
    }

    #pragma unroll
    for (int mi = 0; mi < 4; mi++) {
        int r0 = bm + warpM * 64 + mi * 16 + g;
        #pragma unroll
        for (int nj = 0; nj < 4; nj++) {
            int c = bn + warpN * 32 + nj * 8 + 2 * tg;
            float b0 = 0.f, b1 = 0.f;
            if (HASB) { b0 = bias[c]; b1 = bias[c + 1]; }
            float v0 = acc[mi][nj][0] * alpha + b0;
            float v1 = acc[mi][nj][1] * alpha + b1;
            float v2 = acc[mi][nj][2] * alpha + b0;
            float v3 = acc[mi][nj][3] * alpha + b1;
            if (ACT) { v0 = gelu_f(v0); v1 = gelu_f(v1); v2 = gelu_f(v2); v3 = gelu_f(v3); }
            if (ROUT) { v0 = rndf(v0); v1 = rndf(v1); v2 = rndf(v2); v3 = rndf(v3); }
            if (r0 < M) {
                Cb[(size_t)r0 * ldc + c]     = v0;
                Cb[(size_t)r0 * ldc + c + 1] = v1;
            }
            if (r0 + 8 < M) {
                Cb[(size_t)(r0 + 8) * ldc + c]     = v2;
                Cb[(size_t)(r0 + 8) * ldc + c + 1] = v3;
            }
        }
    }
}

// ============================ v1 GEMM (TRB path, AV2 only; cvt in loader is idempotent) ====
template<int BN, int TRB, int ACT, int HASB, int ROUT>
__global__ __launch_bounds__(256, 2) void mma_gemm(
    const float* __restrict__ A, const float* __restrict__ W,
    const float* __restrict__ bias, float* __restrict__ Cp,
    int M, int N, int K, int lda, int ldw, int ldc,
    int nsub, long sAb, long sAs, long sWb, long sWs, long sCb, long sCs,
    float alpha)
{
    constexpr int BM = 128, BK = 32;
    constexpr int LDSR = BK + 4;
    constexpr int WN = (BN == 128) ? 32 : 8;
    constexpr int MI = 4;
    constexpr int NJ = WN / 8;

    __shared__ uint32_t As[BM * LDSR];
    __shared__ uint32_t Ws[BN * LDSR];

    int tid = threadIdx.x, wid = tid >> 5, lane = tid & 31;
    int warpM = wid >> 2;
    int warpN = wid & 3;
    int g = lane >> 2, tg = lane & 3;

    int bm = blockIdx.y * BM;
    int bn = blockIdx.x * BN;
    int z = blockIdx.z;
    int zb = z / nsub, zs = z % nsub;
    const float* Ab = A + (size_t)zb * sAb + (size_t)zs * sAs;
    const float* Wb = W + (size_t)zb * sWb + (size_t)zs * sWs;
    float*       Cb = Cp + (size_t)zb * sCb + (size_t)zs * sCs;

    float acc[MI][NJ][4];
    #pragma unroll
    for (int i = 0; i < MI; i++)
        #pragma unroll
        for (int j = 0; j < NJ; j++)
            #pragma unroll
            for (int q = 0; q < 4; q++) acc[i][j][q] = 0.f;

    for (int k0 = 0; k0 < K; k0 += BK) {
        #pragma unroll
        for (int idx = tid; idx < BM * (BK / 4); idx += 256) {
            int row = idx >> 3, q = idx & 7;
            int gm = bm + row;
            if (gm < M) {
                float4 v = *(const float4*)(Ab + (size_t)gm * lda + k0 + q * 4);
                uint32_t* p = &As[row * LDSR + q * 4];
                p[0] = f2tf32(v.x); p[1] = f2tf32(v.y); p[2] = f2tf32(v.z); p[3] = f2tf32(v.w);
            }
        }
        if (!TRB) {
            #pragma unroll
            for (int idx = tid; idx < BN * (BK / 4); idx += 256) {
                int row = idx >> 3, q = idx & 7;
                float4 v = *(const float4*)(Wb + (size_t)(bn + row) * ldw + k0 + q * 4);
                uint32_t* p = &Ws[row * LDSR + q * 4];
                p[0] = f2tf32(v.x); p[1] = f2tf32(v.y); p[2] = f2tf32(v.z); p[3] = f2tf32(v.w);
            }
        } else {
            #pragma unroll
            for (int idx = tid; idx < (BK * BN) / 4; idx += 256) {
                int kk = idx / (BN / 4);
                int n4 = (idx % (BN / 4)) * 4;
                float4 v = *(const float4*)(Wb + (size_t)(k0 + kk) * ldw + bn + n4);
                Ws[(n4 + 0) * LDSR + kk] = f2tf32(v.x);
                Ws[(n4 + 1) * LDSR + kk] = f2tf32(v.y);
                Ws[(n4 + 2) * LDSR + kk] = f2tf32(v.z);
                Ws[(n4 + 3) * LDSR + kk] = f2tf32(v.w);
            }
        }
        __syncthreads();

        #pragma unroll
        for (int kk = 0; kk < BK; kk += 8) {
            uint32_t af[MI][4], bf[NJ][2];
            #pragma unroll
            for (int mi = 0; mi < MI; mi++) {
                int r0 = warpM * 64 + mi * 16 + g;
                af[mi][0] = As[r0 * LDSR + kk + tg];
                af[mi][1] = As[(r0 + 8) * LDSR + kk + tg];
                af[mi][2] = As[r0 * LDSR + kk + tg + 4];
                af[mi][3] = As[(r0 + 8) * LDSR + kk + tg + 4];
            }
            #pragma unroll
            for (int nj = 0; nj < NJ; nj++) {
                int c0 = warpN * WN + nj * 8 + g;
                bf[nj][0] = Ws[c0 * LDSR + kk + tg];
                bf[nj][1] = Ws[c0 * LDSR + kk + tg + 4];
            }
            #pragma unroll
            for (int mi = 0; mi < MI; mi++)
                #pragma unroll
                for (int nj = 0; nj < NJ; nj++)
                    mma_tf32(acc[mi][nj], af[mi], bf[nj]);
        }
        __syncthreads();
    }

    #pragma unroll
    for (int mi = 0; mi < MI; mi++) {
        int r0 = bm + warpM * 64 + mi * 16 + g;
        #pragma unroll
        for (int nj = 0; nj < NJ; nj++) {
            int c = bn + warpN * WN + nj * 8 + 2 * tg;
            float b0 = 0.f, b1 = 0.f;
            if (HASB) { b0 = bias[c]; b1 = bias[c + 1]; }
            float v0 = acc[mi][nj][0] * alpha + b0;
            float v1 = acc[mi][nj][1] * alpha + b1;
            float v2 = acc[mi][nj][2] * alpha + b0;
            float v3 = acc[mi][nj][3] * alpha + b1;
            if (ACT) { v0 = gelu_f(v0); v1 = gelu_f(v1); v2 = gelu_f(v2); v3 = gelu_f(v3); }
            if (ROUT) { v0 = rndf(v0); v1 = rndf(v1); v2 = rndf(v2); v3 = rndf(v3); }
            if (r0 < M) {
                Cb[(size_t)r0 * ldc + c]     = v0;
                Cb[(size_t)r0 * ldc + c + 1] = v1;
            }
            if (r0 + 8 < M) {
                Cb[(size_t)(r0 + 8) * ldc + c]     = v2;
                Cb[(size_t)(r0 + 8) * ldc + c + 1] = v3;
            }
        }
    }
}

// ============================ fused flash attention (encoder) ============================
// qkv is tf32-pre-rounded; loaders are raw bit copies.
__global__ __launch_bounds__(256) void fused_attn(
    const float* __restrict__ qkv, float* __restrict__ o, float escale)
{
    extern __shared__ uint32_t fa_sm[];
    uint32_t* Qs = fa_sm;                 // [128][36]
    uint32_t* Ks = Qs + 128 * 36;         // [128][36]
    uint32_t* Vs = Ks + 128 * 36;         // [32][132]

    int tid = threadIdx.x, lane = tid & 31, w = tid >> 5;
    int g = lane >> 2, tg = lane & 3;
    int qt = blockIdx.x;
    int z  = blockIdx.y;
    int b  = z >> 3, h = z & 7;
    const uint32_t* base = (const uint32_t*)(qkv + (size_t)b * CC * 768);

    int arow = (lane & 7) + ((lane & 8) ? 8 : 0);
    int acol = (lane & 16) ? 4 : 0;
    int brow = (lane & 7) + ((lane & 16) ? 8 : 0);
    int bcol = (lane & 8) ? 4 : 0;
    uint32_t qBase = smem_u32(Qs) + (uint32_t)((w * 16 + arow) * 36 + acol) * 4;
    uint32_t kBase = smem_u32(Ks) + (uint32_t)(brow * 36 + bcol) * 4;
    uint32_t vBase = smem_u32(Vs) + (uint32_t)(brow * 132 + bcol) * 4;

    #pragma unroll
    for (int idx = tid; idx < 128 * 8; idx += 256) {
        int r = idx >> 3, q4 = idx & 7;
        uint4 v = *(const uint4*)(base + (size_t)(qt * 128 + r) * 768 + h * 32 + q4 * 4);
        *(uint4*)&Qs[r * 36 + q4 * 4] = v;
    }

    float oacc[4][4];
    #pragma unroll
    for (int i = 0; i < 4; i++)
        #pragma unroll
        for (int q = 0; q < 4; q++) oacc[i][q] = 0.f;
    float rm0 = -1e30f, rm1 = -1e30f, rs0 = 0.f, rs1 = 0.f;

    for (int kt = 0; kt < 4; kt++) {
        __syncthreads();
        #pragma unroll
        for (int idx = tid; idx < 128 * 8; idx += 256) {
            int r = idx >> 3, q4 = idx & 7;
            const uint32_t* kr = base + (size_t)(kt * 128 + r) * 768 + 256 + h * 32 + q4 * 4;
            uint4 kv = *(const uint4*)kr;
            *(uint4*)&Ks[r * 36 + q4 * 4] = kv;
            uint4 vv = *(const uint4*)(kr + 256);
            int d = q4 * 4;
            Vs[(d + 0) * 132 + r] = vv.x;
            Vs[(d + 1) * 132 + r] = vv.y;
            Vs[(d + 2) * 132 + r] = vv.z;
            Vs[(d + 3) * 132 + r] = vv.w;
        }
        __syncthreads();

        float sacc[16][4];
        #pragma unroll
        for (int nj = 0; nj < 16; nj++)
            #pragma unroll
            for (int q = 0; q < 4; q++) sacc[nj][q] = 0.f;

        #pragma unroll
        for (int kk = 0; kk < 32; kk += 8) {
            uint32_t af[4];
            LDM_X4(af[0], af[1], af[2], af[3], qBase + (uint32_t)kk * 4);
            #pragma unroll
            for (int p8 = 0; p8 < 8; p8++) {
                uint32_t bf[4];
                LDM_X4(bf[0], bf[1], bf[2], bf[3],
                       kBase + (uint32_t)(p8 * 16 * 36 + kk) * 4);
                mma_tf32(sacc[2 * p8],     af, bf);
                mma_tf32(sacc[2 * p8 + 1], af, bf + 2);
            }
        }

        float tm0 = -1e30f, tm1 = -1e30f;
        #pragma unroll
        for (int nj = 0; nj < 16; nj++) {
            tm0 = fmaxf(tm0, fmaxf(sacc[nj][0], sacc[nj][1]));
            tm1 = fmaxf(tm1, fmaxf(sacc[nj][2], sacc[nj][3]));
        }
        tm0 *= escale; tm1 *= escale;
        tm0 = fmaxf(tm0, __shfl_xor_sync(0xffffffffu, tm0, 1));
        tm0 = fmaxf(tm0, __shfl_xor_sync(0xffffffffu, tm0, 2));
        tm1 = fmaxf(tm1, __shfl_xor_sync(0xffffffffu, tm1, 1));
        tm1 = fmaxf(tm1, __shfl_xor_sync(0xffffffffu, tm1, 2));
        float nm0 = fmaxf(rm0, tm0), nm1 = fmaxf(rm1, tm1);
        float cr0 = __expf(rm0 - nm0), cr1 = __expf(rm1 - nm1);
        rm0 = nm0; rm1 = nm1;
        float ps0 = 0.f, ps1 = 0.f;
        #pragma unroll
        for (int nj = 0; nj < 16; nj++) {
            float p0 = __expf(sacc[nj][0] * escale - nm0);
            float p1 = __expf(sacc[nj][1] * escale - nm0);
            float p2 = __expf(sacc[nj][2] * escale - nm1);
            float p3 = __expf(sacc[nj][3] * escale - nm1);
            sacc[nj][0] = p0; sacc[nj][1] = p1; sacc[nj][2] = p2; sacc[nj][3] = p3;
            ps0 += p0 + p1; ps1 += p2 + p3;
        }
        ps0 += __shfl_xor_sync(0xffffffffu, ps0, 1);
        ps0 += __shfl_xor_sync(0xffffffffu, ps0, 2);
        ps1 += __shfl_xor_sync(0xffffffffu, ps1, 1);
        ps1 += __shfl_xor_sync(0xffffffffu, ps1, 2);
        rs0 = rs0 * cr0 + ps0;
        rs1 = rs1 * cr1 + ps1;
        #pragma unroll
        for (int vj = 0; vj < 4; vj++) {
            oacc[vj][0] *= cr0; oacc[vj][1] *= cr0;
            oacc[vj][2] *= cr1; oacc[vj][3] *= cr1;
        }

        int srcA = (lane & ~3) | (tg >> 1);
        int srcB = srcA + 2;
        bool odd = (tg & 1);
        #pragma unroll
        for (int nj = 0; nj < 16; nj++) {
            float x0 = __shfl_sync(0xffffffffu, sacc[nj][0], srcA);
            float x1 = __shfl_sync(0xffffffffu, sacc[nj][1], srcA);
            float y0 = __shfl_sync(0xffffffffu, sacc[nj][0], srcB);
            float y1 = __shfl_sync(0xffffffffu, sacc[nj][1], srcB);
            float z0 = __shfl_sync(0xffffffffu, sacc[nj][2], srcA);
            float z1 = __shfl_sync(0xffffffffu, sacc[nj][3], srcA);
            float w0 = __shfl_sync(0xffffffffu, sacc[nj][2], srcB);
            float w1 = __shfl_sync(0xffffffffu, sacc[nj][3], srcB);
            uint32_t a[4];
            a[0] = f2tf32(odd ? x1 : x0);
            a[1] = f2tf32(odd ? z1 : z0);
            a[2] = f2tf32(odd ? y1 : y0);
            a[3] = f2tf32(odd ? w1 : w0);
            #pragma unroll
            for (int vp = 0; vp < 2; vp++) {
                uint32_t bf[4];
                LDM_X4(bf[0], bf[1], bf[2], bf[3],
                       vBase + (uint32_t)(vp * 16 * 132 + nj * 8) * 4);
                mma_tf32(oacc[2 * vp],     a, bf);
                mma_tf32(oacc[2 * vp + 1], a, bf + 2);
            }
        }
    }

    float inv0 = 1.f / rs0, inv1 = 1.f / rs1;
    int row0 = b * CC + qt * 128 + w * 16 + g;
    #pragma unroll
    for (int vj = 0; vj < 4; vj++) {
        int c = h * 32 + vj * 8 + 2 * tg;
        o[(size_t)row0 * 256 + c]           = rndf(oacc[vj][0] * inv0);
        o[(size_t)row0 * 256 + c + 1]       = rndf(oacc[vj][1] * inv0);
        o[(size_t)(row0 + 8) * 256 + c]     = rndf(oacc[vj][2] * inv1);
        o[(size_t)(row0 + 8) * 256 + c + 1] = rndf(oacc[vj][3] * inv1);
    }
}

// ---------------- mask dtype detection ----------------
__global__ void detect_mask_kernel(const int* __restrict__ m) {
    __shared__ int found;
    if (threadIdx.x == 0) found = 0;
    __syncthreads();
    int idx = blockIdx.x * blockDim.x + threadIdx.x;
    unsigned v = (unsigned)m[idx];
    if (v > 1u) found = 1;
    __syncthreads();
    if (threadIdx.x == 0 && blockIdx.x == 0) g_maskmode = 0;
    __threadfence();
    if (found) g_maskmode = 1;
}

// ---------------- pool (tf32-rounded output) ----------------
__global__ void pool_kernel(const int* __restrict__ vi, const int* __restrict__ si,
                            const void* __restrict__ maskraw,
                            const float* __restrict__ ve, const float* __restrict__ se,
                            const float* __restrict__ lpe, const float* __restrict__ cpe,
                            float* __restrict__ x) {
    int bc = blockIdx.x;
    int c  = bc % CC;
    int d  = threadIdx.x;
    const int* viR = vi + bc * LL;
    const int* siR = si + bc * LL;
    __shared__ int mloc[LL];
    if (threadIdx.x < LL) {
        int mv;
        if (g_maskmode == 0) mv = ((const int*)maskraw)[bc * LL + threadIdx.x];
        else                 mv = ((const unsigned char*)maskraw)[bc * LL + threadIdx.x];
        mloc[threadIdx.x] = mv;
    }
    __syncthreads();
    float acc = 0.f; int cnt = 0;
    #pragma unroll
    for (int l = 0; l < LL; l++) {
        if (mloc[l]) {
            cnt++;
            acc += ve[viR[l]*DD + d] + se[siR[l]*DD + d] + lpe[l*DD + d];
        }
    }
    x[(size_t)bc*DD + d] = rndf(acc / (float)cnt + cpe[c*DD + d]);
}

// ---------------- layernorm (optional tf32-rounded output) ----------------
__global__ void ln_kernel(const float* __restrict__ xin, const float* __restrict__ res,
                          const float* __restrict__ w, const float* __restrict__ b,
                          float* __restrict__ out, int N, int resMod, int rnd) {
    int row = blockIdx.x;
    int tid = threadIdx.x;
    const float* xr = xin + (size_t)row * N;
    const float* rr = nullptr;
    if (res) rr = res + (size_t)(resMod ? (row % resMod) : row) * N;
    int per = N >> 8;
    float v[4];
    float s = 0.f;
    for (int i = 0; i < per; i++) {
        int cI = tid + (i << 8);
        float t = xr[cI];
        if (rr) t += rr[cI];
        v[i] = t; s += t;
    }
    __shared__ float red[256];
    red[tid] = s; __syncthreads();
    for (int o = 128; o; o >>= 1) { if (tid < o) red[tid] += red[tid+o]; __syncthreads(); }
    float mean = red[0] / (float)N;
    __syncthreads();
    float vs = 0.f;
    for (int i = 0; i < per; i++) { float d = v[i] - mean; vs += d*d; }
    red[tid] = vs; __syncthreads();
    for (int o = 128; o; o >>= 1) { if (tid < o) red[tid] += red[tid+o]; __syncthreads(); }
    float inv = rsqrtf(red[0] / (float)N + 1e-5f);
    for (int i = 0; i < per; i++) {
        int cI = tid + (i << 8);
        float ov = (v[i] - mean) * inv * w[cI] + b[cI];
        out[(size_t)row*N + cI] = rnd ? rndf(ov) : ov;
    }
}

// ---------------- softmax (prefix path) ----------------
__global__ void softmax_kernel(float* __restrict__ S, int cols) {
    int row  = blockIdx.x * 8 + (threadIdx.x >> 5);
    int lane = threadIdx.x & 31;
    float* r = S + (size_t)row * cols;
    int per = cols >> 5;
    float vals[16];
    float mx = -1e30f;
    for (int t = 0; t < per; t++) { vals[t] = r[lane + (t<<5)]; mx = fmaxf(mx, vals[t]); }
    for (int o = 16; o; o >>= 1) mx = fmaxf(mx, __shfl_xor_sync(0xffffffffu, mx, o));
    float sum = 0.f;
    for (int t = 0; t < per; t++) { vals[t] = __expf(vals[t] - mx); sum += vals[t]; }
    for (int o = 16; o; o >>= 1) sum += __shfl_xor_sync(0xffffffffu, sum, o);
    float inv = 1.f / sum;
    for (int t = 0; t < per; t++) r[lane + (t<<5)] = vals[t] * inv;
}

// ============================ host orchestration ============================
#define G2B    mma_gemm2<0,1,0>
#define G2BR   mma_gemm2<0,1,1>
#define G2GR   mma_gemm2<1,1,1>
#define G2N    mma_gemm2<0,0,0>
#define TCG_AV mma_gemm<32,1,0,0,1>

static const int FA_SMEM = (128*36 + 128*36 + 32*132) * 4;   // 53760 B
static const int G2_SMEM = (2*128*36 + 2*128*36) * 4;        // 73728 B

static void rfy(const float* src, float* dst, int n) {
    roundify<<<(n/4 + 255)/256, 256>>>(src, dst, n/4);
}

extern "C" void kernel_launch(void* const* d_in, const int* in_sizes, int n_in,
                              void* d_out, int out_size) {
    const int*   var_idx   = (const int*)  d_in[0];
    const int*   sign_idx  = (const int*)  d_in[1];
    const void*  lit_mask  = (const void*) d_in[2];
    const float* var_emb   = (const float*)d_in[3];
    const float* sign_emb  = (const float*)d_in[4];
    const float* litpos    = (const float*)d_in[5];
    const float* clausepos = (const float*)d_in[6];
    const float* enc_in_w  = (const float*)d_in[7];
    const float* enc_in_b  = (const float*)d_in[8];
    const float* enc_out_w = (const float*)d_in[9];
    const float* enc_out_b = (const float*)d_in[10];
    const float* enc_ff1_w = (const float*)d_in[11];
    const float* enc_ff1_b = (const float*)d_in[12];
    const float* enc_ff2_w = (const float*)d_in[13];
    const float* enc_ff2_b = (const float*)d_in[14];
    const float* n1w = (const float*)d_in[15];
    const float* n1b = (const float*)d_in[16];
    const float* n2w = (const float*)d_in[17];
    const float* n2b = (const float*)d_in[18];
    const float* th_ln_w = (const float*)d_in[19];
    const float* th_ln_b = (const float*)d_in[20];
    const float* th_w = (const float*)d_in[21];
    const float* th_b = (const float*)d_in[22];
    const float* pq   = (const float*)d_in[23];
    const float* pa_in_w  = (const float*)d_in[24];
    const float* pa_in_b  = (const float*)d_in[25];
    const float* pa_out_w = (const float*)d_in[26];
    const float* pa_out_b = (const float*)d_in[27];
    const float* pn_w = (const float*)d_in[28];
    const float* pn_b = (const float*)d_in[29];
    float* out = (float*)d_out;

    float *x,*t0,*t1,*t2,*ch,*kv,*qh,*S2,*p1,*p2;
    float *rwin,*rwout,*rwf1,*rwf2,*rwth,*rwpa,*rwpo,*rwpq;
    cudaGetSymbolAddress((void**)&x,  g_x);
    cudaGetSymbolAddress((void**)&t0, g_t0);
    cudaGetSymbolAddress((void**)&t1, g_t1);
    cudaGetSymbolAddress((void**)&t2, g_t2);
    cudaGetSymbolAddress((void**)&ch, g_ch);
    cudaGetSymbolAddress((void**)&kv, g_kv);
    cudaGetSymbolAddress((void**)&qh, g_qh);
    cudaGetSymbolAddress((void**)&S2, g_S2);
    cudaGetSymbolAddress((void**)&p1, g_p1);
    cudaGetSymbolAddress((void**)&p2, g_p2);
    cudaGetSymbolAddress((void**)&rwin,  g_rw_in);
    cudaGetSymbolAddress((void**)&rwout, g_rw_out);
    cudaGetSymbolAddress((void**)&rwf1,  g_rw_f1);
    cudaGetSymbolAddress((void**)&rwf2,  g_rw_f2);
    cudaGetSymbolAddress((void**)&rwth,  g_rw_th);
    cudaGetSymbolAddress((void**)&rwpa,  g_rw_pa);
    cudaGetSymbolAddress((void**)&rwpo,  g_rw_po);
    cudaGetSymbolAddress((void**)&rwpq,  g_rw_pq);

    cudaFuncSetAttribute(fused_attn, cudaFuncAttributeMaxDynamicSharedMemorySize, FA_SMEM);
    cudaFuncSetAttribute(G2B,  cudaFuncAttributeMaxDynamicSharedMemorySize, G2_SMEM);
    cudaFuncSetAttribute(G2BR, cudaFuncAttributeMaxDynamicSharedMemorySize, G2_SMEM);
    cudaFuncSetAttribute(G2GR, cudaFuncAttributeMaxDynamicSharedMemorySize, G2_SMEM);
    cudaFuncSetAttribute(G2N,  cudaFuncAttributeMaxDynamicSharedMemorySize, G2_SMEM);

    const int M = BB*CC;
    const float escale = 0.17677669529663687f;   // 1/sqrt(32)
    const float pscale = 0.08838834764831845f;   // 1/sqrt(128)

    // ---- weight pre-rounding (tf32-in-fp32) ----
    rfy(enc_in_w,  rwin,  NLL*768*DD);
    rfy(enc_out_w, rwout, NLL*DD*DD);
    rfy(enc_ff1_w, rwf1,  NLL*HH*DD);
    rfy(enc_ff2_w, rwf2,  NLL*DD*HH);
    rfy(th_w,      rwth,  HH*DD);
    rfy(pa_in_w,   rwpa,  3*HH*HH);
    rfy(pa_out_w,  rwpo,  HH*HH);
    rfy(pq,        rwpq,  PP*HH);

    detect_mask_kernel<<<16, 256>>>((const int*)lit_mask);
    pool_kernel<<<M, 256>>>(var_idx, sign_idx, lit_mask, var_emb, sign_emb,
                            litpos, clausepos, x);

    for (int i = 0; i < NLL; i++) {
        const float* wqkv = rwin  + (size_t)i*768*DD;
        const float* bqkv = enc_in_b  + (size_t)i*768;
        const float* wo   = rwout + (size_t)i*DD*DD;
        const float* bo   = enc_out_b + (size_t)i*DD;
        const float* w1   = rwf1  + (size_t)i*HH*DD;
        const float* b1   = enc_ff1_b + (size_t)i*HH;
        const float* w2   = rwf2  + (size_t)i*DD*HH;
        const float* b2   = enc_ff2_b + (size_t)i*DD;

        // qkv = x @ Wqkv^T + b -> t0 [M,768], rounded
        G2BR<<<dim3(6,128,1),256,G2_SMEM>>>(x, wqkv, bqkv, t0, M,768,DD,
                                            DD,DD,768, 1,0,0,0,0,0,0, 1.f);
        // fused attention -> t1 [M,256], rounded
        fused_attn<<<dim3(4, BB*NHD), 256, FA_SMEM>>>(t0, t1, escale);
        // out proj -> t2 (no round; feeds LN)
        G2B<<<dim3(2,128,1),256,G2_SMEM>>>(t1, wo, bo, t2, M,DD,DD,
                                           DD,DD,DD, 1,0,0,0,0,0,0, 1.f);
        ln_kernel<<<M,256>>>(t2, x, n1w + i*DD, n1b + i*DD, x, DD, 0, 1);
        // ff1 gelu -> t0 [M,1024], rounded
        G2GR<<<dim3(8,128,1),256,G2_SMEM>>>(x, w1, b1, t0, M,HH,DD,
                                            DD,DD,HH, 1,0,0,0,0,0,0, 1.f);
        // ff2 -> t2 (no round)
        G2B<<<dim3(2,128,1),256,G2_SMEM>>>(t0, w2, b2, t2, M,DD,HH,
                                           HH,HH,DD, 1,0,0,0,0,0,0, 1.f);
        ln_kernel<<<M,256>>>(t2, x, n2w + i*DD, n2b + i*DD, x, DD, 0, 1);
    }

    // ch = LN(x) @ th_w^T + th_b, rounded (feeds K/V projections)
    ln_kernel<<<M,256>>>(x, nullptr, th_ln_w, th_ln_b, t2, DD, 0, 1);
    G2BR<<<dim3(8,128,1),256,G2_SMEM>>>(t2, rwth, th_b, ch, M,HH,DD,
                                        DD,DD,HH, 1,0,0,0,0,0,0, 1.f);

    // prefix cross-attention
    // qh = pq @ wq^T + bq, rounded
    G2BR<<<dim3(8,1,1),256,G2_SMEM>>>(rwpq, rwpa, pa_in_b, qh, PP,HH,HH,
                                      HH,HH,HH, 1,0,0,0,0,0,0, 1.f);
    // merged K/V: kv[M,2048] = ch @ [wk;wv]^T + [bk;bv], rounded
    G2BR<<<dim3(16,128,1),256,G2_SMEM>>>(ch, rwpa + (size_t)HH*HH, pa_in_b + HH, kv,
                                         M,2*HH,HH, HH,HH,2*HH, 1,0,0,0,0,0,0, 1.f);
    // scores2 per (b,h): [16,512], K=128 (kp slice of kv, row stride 2048)
    G2N<<<dim3(4,1,BB*NHD),256,G2_SMEM>>>(qh, kv, nullptr, S2, PP,CC,128,
                                          HH,2*HH,CC, NHD,
                                          0L, 128L, (long)CC*2*HH, 128L,
                                          (long)NHD*PP*CC, (long)PP*CC, pscale);
    softmax_kernel<<<(BB*NHD*PP)/8, 256>>>(S2, CC);
    // AV2 per (b,h): [16,128], K=512 (vp slice = kv+1024, [K,N] TRB), rounded out
    TCG_AV<<<dim3(4,1,BB*NHD),256>>>(S2, kv + HH, nullptr, p1, PP,128,CC,
                                     CC,2*HH,HH, NHD,
                                     (long)NHD*PP*CC, (long)PP*CC,
                                     (long)CC*2*HH, 128L,
                                     (long)PP*HH, 128L, 1.f);
    // out proj (no round; feeds final LN)
    G2B<<<dim3(8,4,1),256,G2_SMEM>>>(p1, rwpo, pa_out_b, p2, BB*PP,HH,HH,
                                     HH,HH,HH, 1,0,0,0,0,0,0, 1.f);
    ln_kernel<<<BB*PP,256>>>(p2, pq, pn_w, pn_b, out, HH, PP, 0);
}

// round 9
// speedup vs baseline: 5.7343x; 1.5382x over previous
#include <cuda_runtime.h>
#include <cuda_fp16.h>
#include <cstdint>

#define BB 32
#define CC 512
#define LL 16
#define DD 256
#define HH 1024
#define PP 16
#define NHD 8
#define NLL 4

// ---------------- scratch (static device globals; allocation-free) ----------------
__device__ __half g_x  [BB*CC*DD];
__device__ __half g_t0 [BB*CC*HH];
__device__ __half g_t1 [BB*CC*DD];
__device__ float  g_t2 [BB*CC*DD];
__device__ __half g_t2h[BB*CC*DD];
__device__ __half g_ch [BB*CC*HH];
__device__ __half g_kv [BB*CC*2*HH];
__device__ __half g_qh [PP*HH];
__device__ float  g_S2 [BB*NHD*PP*CC];
__device__ __half g_S2h[BB*NHD*PP*CC];
__device__ __half g_p1 [BB*PP*HH];
__device__ float  g_p2 [BB*PP*HH];
__device__ int    g_maskmode;
// half weights
__device__ __half g_hw_in [NLL*768*DD];
__device__ __half g_hw_out[NLL*DD*DD];
__device__ __half g_hw_f1 [NLL*HH*DD];
__device__ __half g_hw_f2 [NLL*DD*HH];
__device__ __half g_hw_th [HH*DD];
__device__ __half g_hw_pa [3*HH*HH];
__device__ __half g_hw_po [HH*HH];
__device__ __half g_hw_pq [PP*HH];

// ---------------- small helpers ----------------
__device__ __forceinline__ uint32_t smem_u32(const void* p) {
    uint32_t a;
    asm("{ .reg .u64 t; cvta.to.shared.u64 t, %1; cvt.u32.u64 %0, t; }" : "=r"(a) : "l"(p));
    return a;
}
__device__ __forceinline__ float gelu_f(float v) {
    return 0.5f * v * (1.f + erff(v * 0.70710678118654752f));
}
__device__ __forceinline__ uint32_t packh2(float lo, float hi) {
    __half2 h = __floats2half2_rn(lo, hi);
    return *(uint32_t*)&h;
}
__device__ __forceinline__ void hmma16(float* c, const uint32_t* a, const uint32_t* b) {
    asm volatile(
        "mma.sync.aligned.m16n8k16.row.col.f32.f16.f16.f32 "
        "{%0,%1,%2,%3}, {%4,%5,%6,%7}, {%8,%9}, {%0,%1,%2,%3};"
        : "+f"(c[0]), "+f"(c[1]), "+f"(c[2]), "+f"(c[3])
        : "r"(a[0]), "r"(a[1]), "r"(a[2]), "r"(a[3]), "r"(b[0]), "r"(b[1]));
}
#define LDM_X4(r0, r1, r2, r3, addr) \
    asm volatile("ldmatrix.sync.aligned.m8n8.x4.shared.b16 {%0,%1,%2,%3}, [%4];" \
        : "=r"(r0), "=r"(r1), "=r"(r2), "=r"(r3) : "r"(addr))
#define LDM_X2(r0, r1, addr) \
    asm volatile("ldmatrix.sync.aligned.m8n8.x2.shared.b16 {%0,%1}, [%2];" \
        : "=r"(r0), "=r"(r1) : "r"(addr))
#define CPA16(dst, src, pred) \
    asm volatile("cp.async.cg.shared.global [%0], [%1], 16, %2;" \
                 :: "r"(dst), "l"(src), "r"((pred) ? 16 : 0))
#define CP_COMMIT() asm volatile("cp.async.commit_group;")
#define CP_WAIT1()  asm volatile("cp.async.wait_group 1;")
#define CP_WAIT0()  asm volatile("cp.async.wait_group 0;")

// ---------------- fp32 -> fp16 weight conversion ----------------
__global__ void cvt_h(const float* __restrict__ src, __half* __restrict__ dst, int n4) {
    int i = blockIdx.x * 256 + threadIdx.x;
    if (i < n4) {
        float4 v = ((const float4*)src)[i];
        uint2 u;
        u.x = packh2(v.x, v.y);
        u.y = packh2(v.z, v.w);
        ((uint2*)dst)[i] = u;
    }
}

// ============================ fp16 cp.async + ldmatrix GEMM ============================
// C[m,n] = act(alpha * A@W^T + bias); A[M,K] half, W[N,K] half. N%128==0, K%64==0.
template<int ACT, int HASB, int OUTH>
__global__ __launch_bounds__(256) void hgemm(
    const __half* __restrict__ A, const __half* __restrict__ W,
    const float* __restrict__ bias, void* __restrict__ Cp,
    int M, int N, int K, int lda, int ldw, int ldc,
    int nsub, long sAb, long sAs, long sWb, long sWs, long sCb, long sCs,
    float alpha)
{
    constexpr int BM = 128, BN = 128, BK = 64, LDH = 72;   // halves
    constexpr uint32_t STB = BM * LDH * 2;                  // 18432 B per stage buffer
    extern __shared__ __half smh[];
    uint32_t base = smem_u32(smh);
    uint32_t asA = base;               // 2 stages A
    uint32_t wsA = base + 2 * STB;     // 2 stages W

    int tid = threadIdx.x, wid = tid >> 5, lane = tid & 31;
    int warpM = wid >> 2, warpN = wid & 3;
    int g = lane >> 2, tg = lane & 3;
    int bm = blockIdx.y * BM, bn = blockIdx.x * BN;
    int z = blockIdx.z, zb = z / nsub, zs = z % nsub;
    const __half* Ab = A + (size_t)zb * sAb + (size_t)zs * sAs;
    const __half* Wb = W + (size_t)zb * sWb + (size_t)zs * sWs;

    int arow = (lane & 7) + ((lane & 8) ? 8 : 0);
    int acol = (lane & 16) ? 8 : 0;
    int brow = (lane & 7) + ((lane & 16) ? 8 : 0);
    int bcol = (lane & 8) ? 8 : 0;
    uint32_t aLane = (uint32_t)((warpM * 64 + arow) * LDH + acol) * 2;
    uint32_t bLane = (uint32_t)((warpN * 32 + brow) * LDH + bcol) * 2;

    auto load_stage = [&](int st, int k0) {
        uint32_t ab = asA + (uint32_t)st * STB;
        uint32_t wb = wsA + (uint32_t)st * STB;
        #pragma unroll
        for (int idx = tid; idx < BM * 8; idx += 256) {
            int row = idx >> 3, q = idx & 7;
            int gm = bm + row;
            bool ok = gm < M;
            int gmc = ok ? gm : 0;
            CPA16(ab + (uint32_t)(row * LDH + q * 8) * 2,
                  Ab + (size_t)gmc * lda + k0 + q * 8, ok);
        }
        #pragma unroll
        for (int idx = tid; idx < BN * 8; idx += 256) {
            int row = idx >> 3, q = idx & 7;
            CPA16(wb + (uint32_t)(row * LDH + q * 8) * 2,
                  Wb + (size_t)(bn + row) * ldw + k0 + q * 8, true);
        }
        CP_COMMIT();
    };

    float acc[4][4][4];
    #pragma unroll
    for (int i = 0; i < 4; i++)
        #pragma unroll
        for (int j = 0; j < 4; j++)
            #pragma unroll
            for (int q = 0; q < 4; q++) acc[i][j][q] = 0.f;

    int nk = K / BK;
    load_stage(0, 0);

    for (int i = 0; i < nk; i++) {
        int cur = i & 1;
        if (i + 1 < nk) { load_stage((i + 1) & 1, (i + 1) * BK); CP_WAIT1(); }
        else            { CP_WAIT0(); }
        __syncthreads();

        uint32_t aB = asA + (uint32_t)cur * STB + aLane;
        uint32_t wB = wsA + (uint32_t)cur * STB + bLane;
        #pragma unroll
        for (int kk = 0; kk < BK; kk += 16) {
            uint32_t af[4][4], bf[4][2];
            #pragma unroll
            for (int mi = 0; mi < 4; mi++)
                LDM_X4(af[mi][0], af[mi][1], af[mi][2], af[mi][3],
                       aB + (uint32_t)(mi * 16 * LDH + kk) * 2);
            LDM_X4(bf[0][0], bf[0][1], bf[1][0], bf[1][1], wB + (uint32_t)kk * 2);
            LDM_X4(bf[2][0], bf[2][1], bf[3][0], bf[3][1],
                   wB + (uint32_t)(16 * LDH + kk) * 2);
            #pragma unroll
            for (int mi = 0; mi < 4; mi++)
                #pragma unroll
                for (int nj = 0; nj < 4; nj++)
                    hmma16(acc[mi][nj], af[mi], bf[nj]);
        }
        __syncthreads();
    }

    long cOff = (size_t)zb * sCb + (size_t)zs * sCs;
    #pragma unroll
    for (int mi = 0; mi < 4; mi++) {
        int r0 = bm + warpM * 64 + mi * 16 + g;
        #pragma unroll
        for (int nj = 0; nj < 4; nj++) {
            int c = bn + warpN * 32 + nj * 8 + 2 * tg;
            float b0 = 0.f, b1 = 0.f;
            if (HASB) { b0 = bias[c]; b1 = bias[c + 1]; }
            float v0 = acc[mi][nj][0] * alpha + b0;
            float v1 = acc[mi][nj][1] * alpha + b1;
            float v2 = acc[mi][nj][2] * alpha + b0;
            float v3 = acc[mi][nj][3] * alpha + b1;
            if (ACT) { v0 = gelu_f(v0); v1 = gelu_f(v1); v2 = gelu_f(v2); v3 = gelu_f(v3); }
            if (OUTH) {
                __half* Cb = (__half*)Cp + cOff;
                if (r0 < M)     *(uint32_t*)&Cb[(size_t)r0 * ldc + c]       = packh2(v0, v1);
                if (r0 + 8 < M) *(uint32_t*)&Cb[(size_t)(r0 + 8) * ldc + c] = packh2(v2, v3);
            } else {
                float* Cb = (float*)Cp + cOff;
                if (r0 < M)     { Cb[(size_t)r0 * ldc + c] = v0; Cb[(size_t)r0 * ldc + c + 1] = v1; }
                if (r0 + 8 < M) { Cb[(size_t)(r0 + 8) * ldc + c] = v2; Cb[(size_t)(r0 + 8) * ldc + c + 1] = v3; }
            }
        }
    }
}

// ============================ AV2 half kernel (prefix P@V) ============================
// p1[b*PP + p][h*128 + n] = sum_k S2h[z][p][k] * kv[b*CC + k][HH + h*128 + n]
__global__ __launch_bounds__(256) void av2h(
    const __half* __restrict__ S2h, const __half* __restrict__ kvv,
    __half* __restrict__ p1)
{
    constexpr int BK = 64, LDH = 72;
    __shared__ __half As[128 * LDH];
    __shared__ __half Ws[32 * LDH];

    int tid = threadIdx.x, wid = tid >> 5, lane = tid & 31;
    int warpM = wid >> 2, warpN = wid & 3;
    int g = lane >> 2, tg = lane & 3;
    int z = blockIdx.z, b = z >> 3, h = z & 7;
    int bn = blockIdx.x * 32;
    const __half* Ab = S2h + (size_t)z * PP * CC;
    const __half* Vb = kvv + (size_t)b * CC * 2048 + HH + h * 128;
    __half* Cb = p1 + (size_t)b * PP * HH + h * 128;

    int arow = (lane & 7) + ((lane & 8) ? 8 : 0);
    int acol = (lane & 16) ? 8 : 0;
    uint32_t aLane = smem_u32(As) + (uint32_t)((warpM * 64 + arow) * LDH + acol) * 2;
    int brow = warpN * 8 + (lane & 7);
    int bcol = (lane & 8) ? 8 : 0;
    uint32_t bLane = smem_u32(Ws) + (uint32_t)(brow * LDH + bcol) * 2;

    float acc[4][4];
    #pragma unroll
    for (int i = 0; i < 4; i++)
        #pragma unroll
        for (int q = 0; q < 4; q++) acc[i][q] = 0.f;

    for (int k0 = 0; k0 < CC; k0 += BK) {
        __syncthreads();
        #pragma unroll
        for (int idx = tid; idx < 128 * 8; idx += 256) {
            int row = idx >> 3, q = idx & 7;
            int gm = (row < PP) ? row : 0;
            *(uint4*)&As[row * LDH + q * 8] =
                *(const uint4*)(Ab + (size_t)gm * CC + k0 + q * 8);
        }
        #pragma unroll
        for (int idx = tid; idx < 64 * 4; idx += 256) {
            int kk = idx >> 2, q = idx & 3;
            union { uint4 u; __half h[8]; } vv;
            vv.u = *(const uint4*)(Vb + (size_t)(k0 + kk) * 2048 + bn + q * 8);
            #pragma unroll
            for (int j = 0; j < 8; j++) Ws[(q * 8 + j) * LDH + kk] = vv.h[j];
        }
        __syncthreads();

        #pragma unroll
        for (int kk = 0; kk < BK; kk += 16) {
            uint32_t af[4][4], bf[2];
            #pragma unroll
            for (int mi = 0; mi < 4; mi++)
                LDM_X4(af[mi][0], af[mi][1], af[mi][2], af[mi][3],
                       aLane + (uint32_t)(mi * 16 * LDH + kk) * 2);
            LDM_X2(bf[0], bf[1], bLane + (uint32_t)kk * 2);
            #pragma unroll
            for (int mi = 0; mi < 4; mi++)
                hmma16(acc[mi], af[mi], bf);
        }
    }

    #pragma unroll
    for (int mi = 0; mi < 4; mi++) {
        int r0 = warpM * 64 + mi * 16 + g;
        int c = bn + warpN * 8 + 2 * tg;
        if (r0 < PP)     *(uint32_t*)&Cb[(size_t)r0 * HH + c]       = packh2(acc[mi][0], acc[mi][1]);
        if (r0 + 8 < PP) *(uint32_t*)&Cb[(size_t)(r0 + 8) * HH + c] = packh2(acc[mi][2], acc[mi][3]);
    }
}

// ============================ fused flash attention (fp16) ============================
// qkv: [B*C, 768] half. out: [B*C, 256] half.
__global__ __launch_bounds__(256) void fused_attn_h(
    const __half* __restrict__ qkv, __half* __restrict__ o, float escale)
{
    __shared__ __half Qs[128 * 40];
    __shared__ __half Ks[128 * 40];
    __shared__ __half Vs[32 * 136];

    int tid = threadIdx.x, lane = tid & 31, w = tid >> 5;
    int g = lane >> 2, tg = lane & 3;
    int qt = blockIdx.x;
    int z  = blockIdx.y;
    int b  = z >> 3, h = z & 7;
    const __half* base = qkv + (size_t)b * CC * 768;

    int arow = (lane & 7) + ((lane & 8) ? 8 : 0);
    int acol = (lane & 16) ? 8 : 0;
    int brow = (lane & 7) + ((lane & 16) ? 8 : 0);
    int bcol = (lane & 8) ? 8 : 0;
    uint32_t qBase = smem_u32(Qs) + (uint32_t)((w * 16 + arow) * 40 + acol) * 2;
    uint32_t kBase = smem_u32(Ks) + (uint32_t)(brow * 40 + bcol) * 2;
    uint32_t vBase = smem_u32(Vs) + (uint32_t)(brow * 136 + bcol) * 2;

    // load Q tile (raw half copies)
    #pragma unroll
    for (int idx = tid; idx < 128 * 4; idx += 256) {
        int r = idx >> 2, q4 = idx & 3;
        *(uint4*)&Qs[r * 40 + q4 * 8] =
            *(const uint4*)(base + (size_t)(qt * 128 + r) * 768 + h * 32 + q4 * 8);
    }

    float oacc[4][4];
    #pragma unroll
    for (int i = 0; i < 4; i++)
        #pragma unroll
        for (int q = 0; q < 4; q++) oacc[i][q] = 0.f;
    float rm0 = -1e30f, rm1 = -1e30f, rs0 = 0.f, rs1 = 0.f;

    for (int kt = 0; kt < 4; kt++) {
        __syncthreads();
        #pragma unroll
        for (int idx = tid; idx < 128 * 4; idx += 256) {
            int r = idx >> 2, q4 = idx & 3;
            const __half* kr = base + (size_t)(kt * 128 + r) * 768 + 256 + h * 32 + q4 * 8;
            *(uint4*)&Ks[r * 40 + q4 * 8] = *(const uint4*)kr;
            union { uint4 u; __half hh[8]; } vv;
            vv.u = *(const uint4*)(kr + 256);
            #pragma unroll
            for (int j = 0; j < 8; j++) Vs[(q4 * 8 + j) * 136 + r] = vv.hh[j];
        }
        __syncthreads();

        // ---- S = Q @ K^T : 16 rows x 128 keys per warp ----
        float sacc[16][4];
        #pragma unroll
        for (int nj = 0; nj < 16; nj++)
            #pragma unroll
            for (int q = 0; q < 4; q++) sacc[nj][q] = 0.f;

        #pragma unroll
        for (int kk = 0; kk < 32; kk += 16) {
            uint32_t af[4];
            LDM_X4(af[0], af[1], af[2], af[3], qBase + (uint32_t)kk * 2);
            #pragma unroll
            for (int p8 = 0; p8 < 8; p8++) {
                uint32_t bf[4];
                LDM_X4(bf[0], bf[1], bf[2], bf[3],
                       kBase + (uint32_t)(p8 * 16 * 40 + kk) * 2);
                hmma16(sacc[2 * p8],     af, bf);
                hmma16(sacc[2 * p8 + 1], af, bf + 2);
            }
        }

        // ---- online softmax (rows g and g+8) ----
        float tm0 = -1e30f, tm1 = -1e30f;
        #pragma unroll
        for (int nj = 0; nj < 16; nj++) {
            tm0 = fmaxf(tm0, fmaxf(sacc[nj][0], sacc[nj][1]));
            tm1 = fmaxf(tm1, fmaxf(sacc[nj][2], sacc[nj][3]));
        }
        tm0 *= escale; tm1 *= escale;
        tm0 = fmaxf(tm0, __shfl_xor_sync(0xffffffffu, tm0, 1));
        tm0 = fmaxf(tm0, __shfl_xor_sync(0xffffffffu, tm0, 2));
        tm1 = fmaxf(tm1, __shfl_xor_sync(0xffffffffu, tm1, 1));
        tm1 = fmaxf(tm1, __shfl_xor_sync(0xffffffffu, tm1, 2));
        float nm0 = fmaxf(rm0, tm0), nm1 = fmaxf(rm1, tm1);
        float cr0 = __expf(rm0 - nm0), cr1 = __expf(rm1 - nm1);
        rm0 = nm0; rm1 = nm1;
        float ps0 = 0.f, ps1 = 0.f;
        #pragma unroll
        for (int nj = 0; nj < 16; nj++) {
            float p0 = __expf(sacc[nj][0] * escale - nm0);
            float p1 = __expf(sacc[nj][1] * escale - nm0);
            float p2 = __expf(sacc[nj][2] * escale - nm1);
            float p3 = __expf(sacc[nj][3] * escale - nm1);
            sacc[nj][0] = p0; sacc[nj][1] = p1; sacc[nj][2] = p2; sacc[nj][3] = p3;
            ps0 += p0 + p1; ps1 += p2 + p3;
        }
        ps0 += __shfl_xor_sync(0xffffffffu, ps0, 1);
        ps0 += __shfl_xor_sync(0xffffffffu, ps0, 2);
        ps1 += __shfl_xor_sync(0xffffffffu, ps1, 1);
        ps1 += __shfl_xor_sync(0xffffffffu, ps1, 2);
        rs0 = rs0 * cr0 + ps0;
        rs1 = rs1 * cr1 + ps1;
        #pragma unroll
        for (int vj = 0; vj < 4; vj++) {
            oacc[vj][0] *= cr0; oacc[vj][1] *= cr0;
            oacc[vj][2] *= cr1; oacc[vj][3] *= cr1;
        }

        // ---- O += P @ V : C-frag converts directly to A-frag (no shuffles) ----
        #pragma unroll
        for (int j2 = 0; j2 < 8; j2++) {
            uint32_t a[4];
            a[0] = packh2(sacc[2 * j2][0],     sacc[2 * j2][1]);
            a[1] = packh2(sacc[2 * j2][2],     sacc[2 * j2][3]);
            a[2] = packh2(sacc[2 * j2 + 1][0], sacc[2 * j2 + 1][1]);
            a[3] = packh2(sacc[2 * j2 + 1][2], sacc[2 * j2 + 1][3]);
            uint32_t bf0[4], bf1[4];
            LDM_X4(bf0[0], bf0[1], bf0[2], bf0[3], vBase + (uint32_t)(j2 * 16) * 2);
            LDM_X4(bf1[0], bf1[1], bf1[2], bf1[3],
                   vBase + (uint32_t)(16 * 136 + j2 * 16) * 2);
            hmma16(oacc[0], a, bf0);
            hmma16(oacc[1], a, bf0 + 2);
            hmma16(oacc[2], a, bf1);
            hmma16(oacc[3], a, bf1 + 2);
        }
    }

    float inv0 = 1.f / rs0, inv1 = 1.f / rs1;
    int row0 = b * CC + qt * 128 + w * 16 + g;
    #pragma unroll
    for (int vj = 0; vj < 4; vj++) {
        int c = h * 32 + vj * 8 + 2 * tg;
        *(uint32_t*)&o[(size_t)row0 * 256 + c] =
            packh2(oacc[vj][0] * inv0, oacc[vj][1] * inv0);
        *(uint32_t*)&o[(size_t)(row0 + 8) * 256 + c] =
            packh2(oacc[vj][2] * inv1, oacc[vj][3] * inv1);
    }
}

// ---------------- mask dtype detection ----------------
__global__ void detect_mask_kernel(const int* __restrict__ m) {
    __shared__ int found;
    if (threadIdx.x == 0) found = 0;
    __syncthreads();
    int idx = blockIdx.x * blockDim.x + threadIdx.x;
    unsigned v = (unsigned)m[idx];
    if (v > 1u) found = 1;
    __syncthreads();
    if (threadIdx.x == 0 && blockIdx.x == 0) g_maskmode = 0;
    __threadfence();
    if (found) g_maskmode = 1;
}

// ---------------- pool (half output) ----------------
__global__ void pool_kernel(const int* __restrict__ vi, const int* __restrict__ si,
                            const void* __restrict__ maskraw,
                            const float* __restrict__ ve, const float* __restrict__ se,
                            const float* __restrict__ lpe, const float* __restrict__ cpe,
                            __half* __restrict__ x) {
    int bc = blockIdx.x;
    int c  = bc % CC;
    int d  = threadIdx.x;
    const int* viR = vi + bc * LL;
    const int* siR = si + bc * LL;
    __shared__ int mloc[LL];
    if (threadIdx.x < LL) {
        int mv;
        if (g_maskmode == 0) mv = ((const int*)maskraw)[bc * LL + threadIdx.x];
        else                 mv = ((const unsigned char*)maskraw)[bc * LL + threadIdx.x];
        mloc[threadIdx.x] = mv;
    }
    __syncthreads();
    float acc = 0.f; int cnt = 0;
    #pragma unroll
    for (int l = 0; l < LL; l++) {
        if (mloc[l]) {
            cnt++;
            acc += ve[viR[l]*DD + d] + se[siR[l]*DD + d] + lpe[l*DD + d];
        }
    }
    x[(size_t)bc*DD + d] = __float2half(acc / (float)cnt + cpe[c*DD + d]);
}

// ---------------- layernorm (typed I/O via flags) ----------------
// inH: input half? resM: 0 none, 1 fp32, 2 half. outH: output half?
__global__ void ln_kernel(const void* __restrict__ xin, int inH,
                          const void* __restrict__ res, int resM,
                          const float* __restrict__ w, const float* __restrict__ b,
                          void* __restrict__ out, int outH, int N, int resMod) {
    int row = blockIdx.x;
    int tid = threadIdx.x;
    int rrow = resMod ? (row % resMod) : row;
    int per = N >> 8;
    float v[4];
    float s = 0.f;
    for (int i = 0; i < per; i++) {
        int cI = tid + (i << 8);
        float t = inH ? __half2float(((const __half*)xin)[(size_t)row * N + cI])
                      : ((const float*)xin)[(size_t)row * N + cI];
        if (resM == 1)      t += ((const float*)res)[(size_t)rrow * N + cI];
        else if (resM == 2) t += __half2float(((const __half*)res)[(size_t)rrow * N + cI]);
        v[i] = t; s += t;
    }
    __shared__ float red[256];
    red[tid] = s; __syncthreads();
    for (int o = 128; o; o >>= 1) { if (tid < o) red[tid] += red[tid+o]; __syncthreads(); }
    float mean = red[0] / (float)N;
    __syncthreads();
    float vs = 0.f;
    for (int i = 0; i < per; i++) { float d = v[i] - mean; vs += d*d; }
    red[tid] = vs; __syncthreads();
    for (int o = 128; o; o >>= 1) { if (tid < o) red[tid] += red[tid+o]; __syncthreads(); }
    float inv = rsqrtf(red[0] / (float)N + 1e-5f);
    for (int i = 0; i < per; i++) {
        int cI = tid + (i << 8);
        float ov = (v[i] - mean) * inv * w[cI] + b[cI];
        if (outH) ((__half*)out)[(size_t)row*N + cI] = __float2half(ov);
        else      ((float*)out)[(size_t)row*N + cI] = ov;
    }
}

// ---------------- softmax (prefix path; fp32 in, half copy out) ----------------
__global__ void softmax_kernel(const float* __restrict__ S, __half* __restrict__ Sh, int cols) {
    int row  = blockIdx.x * 8 + (threadIdx.x >> 5);
    int lane = threadIdx.x & 31;
    const float* r = S + (size_t)row * cols;
    __half* rh = Sh + (size_t)row * cols;
    int per = cols >> 5;
    float vals[16];
    float mx = -1e30f;
    for (int t = 0; t < per; t++) { vals[t] = r[lane + (t<<5)]; mx = fmaxf(mx, vals[t]); }
    for (int o = 16; o; o >>= 1) mx = fmaxf(mx, __shfl_xor_sync(0xffffffffu, mx, o));
    float sum = 0.f;
    for (int t = 0; t < per; t++) { vals[t] = __expf(vals[t] - mx); sum += vals[t]; }
    for (int o = 16; o; o >>= 1) sum += __shfl_xor_sync(0xffffffffu, sum, o);
    float inv = 1.f / sum;
    for (int t = 0; t < per; t++) rh[lane + (t<<5)] = __float2half(vals[t] * inv);
}

// ============================ host orchestration ============================
#define HG_B   hgemm<0,1,1>
#define HG_BF  hgemm<0,1,0>
#define HG_G   hgemm<1,1,1>
#define HG_N   hgemm<0,0,0>

static const int HG_SMEM = 4 * 128 * 72 * 2;   // 73728 B

static void cvh(const float* src, __half* dst, int n) {
    cvt_h<<<(n/4 + 255)/256, 256>>>(src, dst, n/4);
}

extern "C" void kernel_launch(void* const* d_in, const int* in_sizes, int n_in,
                              void* d_out, int out_size) {
    const int*   var_idx   = (const int*)  d_in[0];
    const int*   sign_idx  = (const int*)  d_in[1];
    const void*  lit_mask  = (const void*) d_in[2];
    const float* var_emb   = (const float*)d_in[3];
    const float* sign_emb  = (const float*)d_in[4];
    const float* litpos    = (const float*)d_in[5];
    const float* clausepos = (const float*)d_in[6];
    const float* enc_in_w  = (const float*)d_in[7];
    const float* enc_in_b  = (const float*)d_in[8];
    const float* enc_out_w = (const float*)d_in[9];
    const float* enc_out_b = (const float*)d_in[10];
    const float* enc_ff1_w = (const float*)d_in[11];
    const float* enc_ff1_b = (const float*)d_in[12];
    const float* enc_ff2_w = (const float*)d_in[13];
    const float* enc_ff2_b = (const float*)d_in[14];
    const float* n1w = (const float*)d_in[15];
    const float* n1b = (const float*)d_in[16];
    const float* n2w = (const float*)d_in[17];
    const float* n2b = (const float*)d_in[18];
    const float* th_ln_w = (const float*)d_in[19];
    const float* th_ln_b = (const float*)d_in[20];
    const float* th_w = (const float*)d_in[21];
    const float* th_b = (const float*)d_in[22];
    const float* pq   = (const float*)d_in[23];
    const float* pa_in_w  = (const float*)d_in[24];
    const float* pa_in_b  = (const float*)d_in[25];
    const float* pa_out_w = (const float*)d_in[26];
    const float* pa_out_b = (const float*)d_in[27];
    const float* pn_w = (const float*)d_in[28];
    const float* pn_b = (const float*)d_in[29];
    float* out = (float*)d_out;

    __half *x,*t0,*t1,*t2h,*ch,*kv,*qh,*S2h,*p1;
    float *t2,*S2,*p2;
    __half *hwin,*hwout,*hwf1,*hwf2,*hwth,*hwpa,*hwpo,*hwpq;
    cudaGetSymbolAddress((void**)&x,   g_x);
    cudaGetSymbolAddress((void**)&t0,  g_t0);
    cudaGetSymbolAddress((void**)&t1,  g_t1);
    cudaGetSymbolAddress((void**)&t2,  g_t2);
    cudaGetSymbolAddress((void**)&t2h, g_t2h);
    cudaGetSymbolAddress((void**)&ch,  g_ch);
    cudaGetSymbolAddress((void**)&kv,  g_kv);
    cudaGetSymbolAddress((void**)&qh,  g_qh);
    cudaGetSymbolAddress((void**)&S2,  g_S2);
    cudaGetSymbolAddress((void**)&S2h, g_S2h);
    cudaGetSymbolAddress((void**)&p1,  g_p1);
    cudaGetSymbolAddress((void**)&p2,  g_p2);
    cudaGetSymbolAddress((void**)&hwin,  g_hw_in);
    cudaGetSymbolAddress((void**)&hwout, g_hw_out);
    cudaGetSymbolAddress((void**)&hwf1,  g_hw_f1);
    cudaGetSymbolAddress((void**)&hwf2,  g_hw_f2);
    cudaGetSymbolAddress((void**)&hwth,  g_hw_th);
    cudaGetSymbolAddress((void**)&hwpa,  g_hw_pa);
    cudaGetSymbolAddress((void**)&hwpo,  g_hw_po);
    cudaGetSymbolAddress((void**)&hwpq,  g_hw_pq);

    cudaFuncSetAttribute(HG_B,  cudaFuncAttributeMaxDynamicSharedMemorySize, HG_SMEM);
    cudaFuncSetAttribute(HG_BF, cudaFuncAttributeMaxDynamicSharedMemorySize, HG_SMEM);
    cudaFuncSetAttribute(HG_G,  cudaFuncAttributeMaxDynamicSharedMemorySize, HG_SMEM);
    cudaFuncSetAttribute(HG_N,  cudaFuncAttributeMaxDynamicSharedMemorySize, HG_SMEM);

    const int M = BB*CC;
    const float escale = 0.17677669529663687f;   // 1/sqrt(32)
    const float pscale = 0.08838834764831845f;   // 1/sqrt(128)

    // ---- weight conversion to fp16 ----
    cvh(enc_in_w,  hwin,  NLL*768*DD);
    cvh(enc_out_w, hwout, NLL*DD*DD);
    cvh(enc_ff1_w, hwf1,  NLL*HH*DD);
    cvh(enc_ff2_w, hwf2,  NLL*DD*HH);
    cvh(th_w,      hwth,  HH*DD);
    cvh(pa_in_w,   hwpa,  3*HH*HH);
    cvh(pa_out_w,  hwpo,  HH*HH);
    cvh(pq,        hwpq,  PP*HH);

    detect_mask_kernel<<<16, 256>>>((const int*)lit_mask);
    pool_kernel<<<M, 256>>>(var_idx, sign_idx, lit_mask, var_emb, sign_emb,
                            litpos, clausepos, x);

    for (int i = 0; i < NLL; i++) {
        const __half* wqkv = hwin  + (size_t)i*768*DD;
        const float*  bqkv = enc_in_b  + (size_t)i*768;
        const __half* wo   = hwout + (size_t)i*DD*DD;
        const float*  bo   = enc_out_b + (size_t)i*DD;
        const __half* w1   = hwf1  + (size_t)i*HH*DD;
        const float*  b1   = enc_ff1_b + (size_t)i*HH;
        const __half* w2   = hwf2  + (size_t)i*DD*HH;
        const float*  b2   = enc_ff2_b + (size_t)i*DD;

        // qkv -> t0 half [M,768]
        HG_B<<<dim3(6,128,1),256,HG_SMEM>>>(x, wqkv, bqkv, t0, M,768,DD,
                                            DD,DD,768, 1,0,0,0,0,0,0, 1.f);
        // fused attention -> t1 half [M,256]
        fused_attn_h<<<dim3(4, BB*NHD), 256>>>(t0, t1, escale);
        // out proj -> t2 float (feeds LN)
        HG_BF<<<dim3(2,128,1),256,HG_SMEM>>>(t1, wo, bo, t2, M,DD,DD,
                                             DD,DD,DD, 1,0,0,0,0,0,0, 1.f);
        ln_kernel<<<M,256>>>(t2, 0, x, 2, n1w + i*DD, n1b + i*DD, x, 1, DD, 0);
        // ff1 gelu -> t0 half [M,1024]
        HG_G<<<dim3(8,128,1),256,HG_SMEM>>>(x, w1, b1, t0, M,HH,DD,
                                            DD,DD,HH, 1,0,0,0,0,0,0, 1.f);
        // ff2 -> t2 float
        HG_BF<<<dim3(2,128,1),256,HG_SMEM>>>(t0, w2, b2, t2, M,DD,HH,
                                             HH,HH,DD, 1,0,0,0,0,0,0, 1.f);
        ln_kernel<<<M,256>>>(t2, 0, x, 2, n2w + i*DD, n2b + i*DD, x, 1, DD, 0);
    }

    // ch = LN(x) @ th_w^T + th_b  (half)
    ln_kernel<<<M,256>>>(x, 1, nullptr, 0, th_ln_w, th_ln_b, t2h, 1, DD, 0);
    HG_B<<<dim3(8,128,1),256,HG_SMEM>>>(t2h, hwth, th_b, ch, M,HH,DD,
                                        DD,DD,HH, 1,0,0,0,0,0,0, 1.f);

    // prefix cross-attention
    HG_B<<<dim3(8,1,1),256,HG_SMEM>>>(hwpq, hwpa, pa_in_b, qh, PP,HH,HH,
                                      HH,HH,HH, 1,0,0,0,0,0,0, 1.f);
    // merged K/V: kv[M,2048]
    HG_B<<<dim3(16,128,1),256,HG_SMEM>>>(ch, hwpa + (size_t)HH*HH, pa_in_b + HH, kv,
                                         M,2*HH,HH, HH,HH,2*HH, 1,0,0,0,0,0,0, 1.f);
    // scores2 per (b,h): [16,512], K=128 -> S2 float
    HG_N<<<dim3(4,1,BB*NHD),256,HG_SMEM>>>(qh, kv, nullptr, S2, PP,CC,128,
                                           HH,2*HH,CC, NHD,
                                           0L, 128L, (long)CC*2*HH, 128L,
                                           (long)NHD*PP*CC, (long)PP*CC, pscale);
    softmax_kernel<<<(BB*NHD*PP)/8, 256>>>(S2, S2h, CC);
    // AV2 -> p1 half
    av2h<<<dim3(4,1,BB*NHD),256>>>(S2h, kv, p1);
    // out proj -> p2 float
    HG_BF<<<dim3(8,4,1),256,HG_SMEM>>>(p1, hwpo, pa_out_b, p2, BB*PP,HH,HH,
                                       HH,HH,HH, 1,0,0,0,0,0,0, 1.f);
    // final LN: p2 + pq (fp32 residual, broadcast over batch) -> out fp32
    ln_kernel<<<BB*PP,256>>>(p2, 0, pq, 1, pn_w, pn_b, out, 0, HH, PP);
}

// round 10
// speedup vs baseline: 5.8248x; 1.0158x over previous
#include <cuda_runtime.h>
#include <cuda_fp16.h>
#include <cstdint>

#define BB 32
#define CC 512
#define LL 16
#define DD 256
#define HH 1024
#define PP 16
#define NHD 8
#define NLL 4

// ---------------- scratch (static device globals; allocation-free) ----------------
__device__ __half g_x  [BB*CC*DD];
__device__ __half g_t0 [BB*CC*HH];
__device__ __half g_t1 [BB*CC*DD];
__device__ __half g_t2h[BB*CC*DD];
__device__ __half g_ch [BB*CC*HH];
__device__ __half g_kv [BB*CC*2*HH];
__device__ __half g_qh [PP*HH];
__device__ float  g_S2 [BB*NHD*PP*CC];
__device__ __half g_S2h[BB*NHD*PP*CC];
__device__ __half g_p1 [BB*PP*HH];
__device__ float  g_p2 [BB*PP*HH];
__device__ int    g_maskmode;
// half weights
__device__ __half g_hw_in [NLL*768*DD];
__device__ __half g_hw_out[NLL*DD*DD];
__device__ __half g_hw_f1 [NLL*HH*DD];
__device__ __half g_hw_f2 [NLL*DD*HH];
__device__ __half g_hw_th [HH*DD];
__device__ __half g_hw_pa [3*HH*HH];
__device__ __half g_hw_po [HH*HH];
__device__ __half g_hw_pq [PP*HH];

// ---------------- small helpers ----------------
__device__ __forceinline__ uint32_t smem_u32(const void* p) {
    uint32_t a;
    asm("{ .reg .u64 t; cvta.to.shared.u64 t, %1; cvt.u32.u64 %0, t; }" : "=r"(a) : "l"(p));
    return a;
}
__device__ __forceinline__ float gelu_f(float v) {
    return 0.5f * v * (1.f + erff(v * 0.70710678118654752f));
}
__device__ __forceinline__ uint32_t packh2(float lo, float hi) {
    __half2 h = __floats2half2_rn(lo, hi);
    return *(uint32_t*)&h;
}
__device__ __forceinline__ void hmma16(float* c, const uint32_t* a, const uint32_t* b) {
    asm volatile(
        "mma.sync.aligned.m16n8k16.row.col.f32.f16.f16.f32 "
        "{%0,%1,%2,%3}, {%4,%5,%6,%7}, {%8,%9}, {%0,%1,%2,%3};"
        : "+f"(c[0]), "+f"(c[1]), "+f"(c[2]), "+f"(c[3])
        : "r"(a[0]), "r"(a[1]), "r"(a[2]), "r"(a[3]), "r"(b[0]), "r"(b[1]));
}
#define LDM_X4(r0, r1, r2, r3, addr) \
    asm volatile("ldmatrix.sync.aligned.m8n8.x4.shared.b16 {%0,%1,%2,%3}, [%4];" \
        : "=r"(r0), "=r"(r1), "=r"(r2), "=r"(r3) : "r"(addr))
#define LDM_X2(r0, r1, addr) \
    asm volatile("ldmatrix.sync.aligned.m8n8.x2.shared.b16 {%0,%1}, [%2];" \
        : "=r"(r0), "=r"(r1) : "r"(addr))
#define CPA16(dst, src, pred) \
    asm volatile("cp.async.cg.shared.global [%0], [%1], 16, %2;" \
                 :: "r"(dst), "l"(src), "r"((pred) ? 16 : 0))
#define CP_COMMIT() asm volatile("cp.async.commit_group;")
#define CP_WAIT1()  asm volatile("cp.async.wait_group 1;")
#define CP_WAIT0()  asm volatile("cp.async.wait_group 0;")

// ---------------- fp32 -> fp16 weight conversion ----------------
__global__ void cvt_h(const float* __restrict__ src, __half* __restrict__ dst, int n4) {
    int i = blockIdx.x * 256 + threadIdx.x;
    if (i < n4) {
        float4 v = ((const float4*)src)[i];
        uint2 u;
        u.x = packh2(v.x, v.y);
        u.y = packh2(v.z, v.w);
        ((uint2*)dst)[i] = u;
    }
}

// ============================ fp16 3-stage cp.async + ldmatrix GEMM ============================
// C[m,n] = act(alpha * A@W^T + bias); A[M,K] half, W[N,K] half. N%128==0, K%64==0.
template<int ACT, int HASB, int OUTH>
__global__ __launch_bounds__(256, 2) void hgemm(
    const __half* __restrict__ A, const __half* __restrict__ W,
    const float* __restrict__ bias, void* __restrict__ Cp,
    int M, int N, int K, int lda, int ldw, int ldc,
    int nsub, long sAb, long sAs, long sWb, long sWs, long sCb, long sCs,
    float alpha)
{
    constexpr int BM = 128, BN = 128, BK = 64, LDH = 72, NST = 3;
    constexpr uint32_t STB = BM * LDH * 2;                  // 18432 B
    extern __shared__ __half smh[];
    uint32_t base = smem_u32(smh);
    uint32_t asA = base;                   // NST stages A
    uint32_t wsA = base + NST * STB;       // NST stages W

    int tid = threadIdx.x, wid = tid >> 5, lane = tid & 31;
    int warpM = wid >> 2, warpN = wid & 3;
    int g = lane >> 2, tg = lane & 3;
    int bm = blockIdx.y * BM, bn = blockIdx.x * BN;
    int z = blockIdx.z, zb = z / nsub, zs = z % nsub;
    const __half* Ab = A + (size_t)zb * sAb + (size_t)zs * sAs;
    const __half* Wb = W + (size_t)zb * sWb + (size_t)zs * sWs;

    int arow = (lane & 7) + ((lane & 8) ? 8 : 0);
    int acol = (lane & 16) ? 8 : 0;
    int brow = (lane & 7) + ((lane & 16) ? 8 : 0);
    int bcol = (lane & 8) ? 8 : 0;
    uint32_t aLane = (uint32_t)((warpM * 64 + arow) * LDH + acol) * 2;
    uint32_t bLane = (uint32_t)((warpN * 32 + brow) * LDH + bcol) * 2;

    auto load_stage = [&](int st, int k0) {
        uint32_t ab = asA + (uint32_t)st * STB;
        uint32_t wb = wsA + (uint32_t)st * STB;
        #pragma unroll
        for (int idx = tid; idx < BM * 8; idx += 256) {
            int row = idx >> 3, q = idx & 7;
            int gm = bm + row;
            bool ok = gm < M;
            int gmc = ok ? gm : 0;
            CPA16(ab + (uint32_t)(row * LDH + q * 8) * 2,
                  Ab + (size_t)gmc * lda + k0 + q * 8, ok);
        }
        #pragma unroll
        for (int idx = tid; idx < BN * 8; idx += 256) {
            int row = idx >> 3, q = idx & 7;
            CPA16(wb + (uint32_t)(row * LDH + q * 8) * 2,
                  Wb + (size_t)(bn + row) * ldw + k0 + q * 8, true);
        }
        CP_COMMIT();
    };

    float acc[4][4][4];
    #pragma unroll
    for (int i = 0; i < 4; i++)
        #pragma unroll
        for (int j = 0; j < 4; j++)
            #pragma unroll
            for (int q = 0; q < 4; q++) acc[i][j][q] = 0.f;

    int nk = K / BK;
    load_stage(0, 0);
    if (nk > 1) load_stage(1, BK);

    for (int i = 0; i < nk; i++) {
        if (i + 1 < nk) CP_WAIT1(); else CP_WAIT0();
        __syncthreads();
        // issue next-next stage load (buffer (i+2)%3 == (i-1)%3; all warps are past
        // the sync above, hence finished compute(i-1) -> safe to overwrite)
        if (i + 2 < nk) load_stage((i + 2) % NST, (i + 2) * BK);

        int cur = i % NST;
        uint32_t aB = asA + (uint32_t)cur * STB + aLane;
        uint32_t wB = wsA + (uint32_t)cur * STB + bLane;
        #pragma unroll
        for (int kk = 0; kk < BK; kk += 16) {
            uint32_t af[4][4], bf[4][2];
            #pragma unroll
            for (int mi = 0; mi < 4; mi++)
                LDM_X4(af[mi][0], af[mi][1], af[mi][2], af[mi][3],
                       aB + (uint32_t)(mi * 16 * LDH + kk) * 2);
            LDM_X4(bf[0][0], bf[0][1], bf[1][0], bf[1][1], wB + (uint32_t)kk * 2);
            LDM_X4(bf[2][0], bf[2][1], bf[3][0], bf[3][1],
                   wB + (uint32_t)(16 * LDH + kk) * 2);
            #pragma unroll
            for (int mi = 0; mi < 4; mi++)
                #pragma unroll
                for (int nj = 0; nj < 4; nj++)
                    hmma16(acc[mi][nj], af[mi], bf[nj]);
        }
    }

    long cOff = (size_t)zb * sCb + (size_t)zs * sCs;
    #pragma unroll
    for (int mi = 0; mi < 4; mi++) {
        int r0 = bm + warpM * 64 + mi * 16 + g;
        #pragma unroll
        for (int nj = 0; nj < 4; nj++) {
            int c = bn + warpN * 32 + nj * 8 + 2 * tg;
            float b0 = 0.f, b1 = 0.f;
            if (HASB) { b0 = bias[c]; b1 = bias[c + 1]; }
            float v0 = acc[mi][nj][0] * alpha + b0;
            float v1 = acc[mi][nj][1] * alpha + b1;
            float v2 = acc[mi][nj][2] * alpha + b0;
            float v3 = acc[mi][nj][3] * alpha + b1;
            if (ACT) { v0 = gelu_f(v0); v1 = gelu_f(v1); v2 = gelu_f(v2); v3 = gelu_f(v3); }
            if (OUTH) {
                __half* Cb = (__half*)Cp + cOff;
                if (r0 < M)     *(uint32_t*)&Cb[(size_t)r0 * ldc + c]       = packh2(v0, v1);
                if (r0 + 8 < M) *(uint32_t*)&Cb[(size_t)(r0 + 8) * ldc + c] = packh2(v2, v3);
            } else {
                float* Cb = (float*)Cp + cOff;
                if (r0 < M)     { Cb[(size_t)r0 * ldc + c] = v0; Cb[(size_t)r0 * ldc + c + 1] = v1; }
                if (r0 + 8 < M) { Cb[(size_t)(r0 + 8) * ldc + c] = v2; Cb[(size_t)(r0 + 8) * ldc + c + 1] = v3; }
            }
        }
    }
}

// ============================ AV2 half kernel (prefix P@V) ============================
__global__ __launch_bounds__(256) void av2h(
    const __half* __restrict__ S2h, const __half* __restrict__ kvv,
    __half* __restrict__ p1)
{
    constexpr int BK = 64, LDH = 72;
    __shared__ __half As[128 * LDH];
    __shared__ __half Ws[32 * LDH];

    int tid = threadIdx.x, wid = tid >> 5, lane = tid & 31;
    int warpM = wid >> 2, warpN = wid & 3;
    int g = lane >> 2, tg = lane & 3;
    int z = blockIdx.z, b = z >> 3, h = z & 7;
    int bn = blockIdx.x * 32;
    const __half* Ab = S2h + (size_t)z * PP * CC;
    const __half* Vb = kvv + (size_t)b * CC * 2048 + HH + h * 128;
    __half* Cb = p1 + (size_t)b * PP * HH + h * 128;

    int arow = (lane & 7) + ((lane & 8) ? 8 : 0);
    int acol = (lane & 16) ? 8 : 0;
    uint32_t aLane = smem_u32(As) + (uint32_t)((warpM * 64 + arow) * LDH + acol) * 2;
    int brow = warpN * 8 + (lane & 7);
    int bcol = (lane & 8) ? 8 : 0;
    uint32_t bLane = smem_u32(Ws) + (uint32_t)(brow * LDH + bcol) * 2;

    float acc[4][4];
    #pragma unroll
    for (int i = 0; i < 4; i++)
        #pragma unroll
        for (int q = 0; q < 4; q++) acc[i][q] = 0.f;

    for (int k0 = 0; k0 < CC; k0 += BK) {
        __syncthreads();
        #pragma unroll
        for (int idx = tid; idx < 128 * 8; idx += 256) {
            int row = idx >> 3, q = idx & 7;
            int gm = (row < PP) ? row : 0;
            *(uint4*)&As[row * LDH + q * 8] =
                *(const uint4*)(Ab + (size_t)gm * CC + k0 + q * 8);
        }
        #pragma unroll
        for (int idx = tid; idx < 64 * 4; idx += 256) {
            int kk = idx >> 2, q = idx & 3;
            union { uint4 u; __half h[8]; } vv;
            vv.u = *(const uint4*)(Vb + (size_t)(k0 + kk) * 2048 + bn + q * 8);
            #pragma unroll
            for (int j = 0; j < 8; j++) Ws[(q * 8 + j) * LDH + kk] = vv.h[j];
        }
        __syncthreads();

        #pragma unroll
        for (int kk = 0; kk < BK; kk += 16) {
            uint32_t af[4][4], bf[2];
            #pragma unroll
            for (int mi = 0; mi < 4; mi++)
                LDM_X4(af[mi][0], af[mi][1], af[mi][2], af[mi][3],
                       aLane + (uint32_t)(mi * 16 * LDH + kk) * 2);
            LDM_X2(bf[0], bf[1], bLane + (uint32_t)kk * 2);
            #pragma unroll
            for (int mi = 0; mi < 4; mi++)
                hmma16(acc[mi], af[mi], bf);
        }
    }

    #pragma unroll
    for (int mi = 0; mi < 4; mi++) {
        int r0 = warpM * 64 + mi * 16 + g;
        int c = bn + warpN * 8 + 2 * tg;
        if (r0 < PP)     *(uint32_t*)&Cb[(size_t)r0 * HH + c]       = packh2(acc[mi][0], acc[mi][1]);
        if (r0 + 8 < PP) *(uint32_t*)&Cb[(size_t)(r0 + 8) * HH + c] = packh2(acc[mi][2], acc[mi][3]);
    }
}

// ============================ fused flash attention (fp16) ============================
__global__ __launch_bounds__(256) void fused_attn_h(
    const __half* __restrict__ qkv, __half* __restrict__ o, float escale)
{
    __shared__ __half Qs[128 * 40];
    __shared__ __half Ks[128 * 40];
    __shared__ __half Vs[32 * 136];

    int tid = threadIdx.x, lane = tid & 31, w = tid >> 5;
    int g = lane >> 2, tg = lane & 3;
    int qt = blockIdx.x;
    int z  = blockIdx.y;
    int b  = z >> 3, h = z & 7;
    const __half* base = qkv + (size_t)b * CC * 768;

    int arow = (lane & 7) + ((lane & 8) ? 8 : 0);
    int acol = (lane & 16) ? 8 : 0;
    int brow = (lane & 7) + ((lane & 16) ? 8 : 0);
    int bcol = (lane & 8) ? 8 : 0;
    uint32_t qBase = smem_u32(Qs) + (uint32_t)((w * 16 + arow) * 40 + acol) * 2;
    uint32_t kBase = smem_u32(Ks) + (uint32_t)(brow * 40 + bcol) * 2;
    uint32_t vBase = smem_u32(Vs) + (uint32_t)(brow * 136 + bcol) * 2;

    #pragma unroll
    for (int idx = tid; idx < 128 * 4; idx += 256) {
        int r = idx >> 2, q4 = idx & 3;
        *(uint4*)&Qs[r * 40 + q4 * 8] =
            *(const uint4*)(base + (size_t)(qt * 128 + r) * 768 + h * 32 + q4 * 8);
    }

    float oacc[4][4];
    #pragma unroll
    for (int i = 0; i < 4; i++)
        #pragma unroll
        for (int q = 0; q < 4; q++) oacc[i][q] = 0.f;
    float rm0 = -1e30f, rm1 = -1e30f, rs0 = 0.f, rs1 = 0.f;

    for (int kt = 0; kt < 4; kt++) {
        __syncthreads();
        #pragma unroll
        for (int idx = tid; idx < 128 * 4; idx += 256) {
            int r = idx >> 2, q4 = idx & 3;
            const __half* kr = base + (size_t)(kt * 128 + r) * 768 + 256 + h * 32 + q4 * 8;
            *(uint4*)&Ks[r * 40 + q4 * 8] = *(const uint4*)kr;
            union { uint4 u; __half hh[8]; } vv;
            vv.u = *(const uint4*)(kr + 256);
            #pragma unroll
            for (int j = 0; j < 8; j++) Vs[(q4 * 8 + j) * 136 + r] = vv.hh[j];
        }
        __syncthreads();

        float sacc[16][4];
        #pragma unroll
        for (int nj = 0; nj < 16; nj++)
            #pragma unroll
            for (int q = 0; q < 4; q++) sacc[nj][q] = 0.f;

        #pragma unroll
        for (int kk = 0; kk < 32; kk += 16) {
            uint32_t af[4];
            LDM_X4(af[0], af[1], af[2], af[3], qBase + (uint32_t)kk * 2);
            #pragma unroll
            for (int p8 = 0; p8 < 8; p8++) {
                uint32_t bf[4];
                LDM_X4(bf[0], bf[1], bf[2], bf[3],
                       kBase + (uint32_t)(p8 * 16 * 40 + kk) * 2);
                hmma16(sacc[2 * p8],     af, bf);
                hmma16(sacc[2 * p8 + 1], af, bf + 2);
            }
        }

        float tm0 = -1e30f, tm1 = -1e30f;
        #pragma unroll
        for (int nj = 0; nj < 16; nj++) {
            tm0 = fmaxf(tm0, fmaxf(sacc[nj][0], sacc[nj][1]));
            tm1 = fmaxf(tm1, fmaxf(sacc[nj][2], sacc[nj][3]));
        }
        tm0 *= escale; tm1 *= escale;
        tm0 = fmaxf(tm0, __shfl_xor_sync(0xffffffffu, tm0, 1));
        tm0 = fmaxf(tm0, __shfl_xor_sync(0xffffffffu, tm0, 2));
        tm1 = fmaxf(tm1, __shfl_xor_sync(0xffffffffu, tm1, 1));
        tm1 = fmaxf(tm1, __shfl_xor_sync(0xffffffffu, tm1, 2));
        float nm0 = fmaxf(rm0, tm0), nm1 = fmaxf(rm1, tm1);
        float cr0 = __expf(rm0 - nm0), cr1 = __expf(rm1 - nm1);
        rm0 = nm0; rm1 = nm1;
        float ps0 = 0.f, ps1 = 0.f;
        #pragma unroll
        for (int nj = 0; nj < 16; nj++) {
            float p0 = __expf(sacc[nj][0] * escale - nm0);
            float p1 = __expf(sacc[nj][1] * escale - nm0);
            float p2 = __expf(sacc[nj][2] * escale - nm1);
            float p3 = __expf(sacc[nj][3] * escale - nm1);
            sacc[nj][0] = p0; sacc[nj][1] = p1; sacc[nj][2] = p2; sacc[nj][3] = p3;
            ps0 += p0 + p1; ps1 += p2 + p3;
        }
        ps0 += __shfl_xor_sync(0xffffffffu, ps0, 1);
        ps0 += __shfl_xor_sync(0xffffffffu, ps0, 2);
        ps1 += __shfl_xor_sync(0xffffffffu, ps1, 1);
        ps1 += __shfl_xor_sync(0xffffffffu, ps1, 2);
        rs0 = rs0 * cr0 + ps0;
        rs1 = rs1 * cr1 + ps1;
        #pragma unroll
        for (int vj = 0; vj < 4; vj++) {
            oacc[vj][0] *= cr0; oacc[vj][1] *= cr0;
            oacc[vj][2] *= cr1; oacc[vj][3] *= cr1;
        }

        #pragma unroll
        for (int j2 = 0; j2 < 8; j2++) {
            uint32_t a[4];
            a[0] = packh2(sacc[2 * j2][0],     sacc[2 * j2][1]);
            a[1] = packh2(sacc[2 * j2][2],     sacc[2 * j2][3]);
            a[2] = packh2(sacc[2 * j2 + 1][0], sacc[2 * j2 + 1][1]);
            a[3] = packh2(sacc[2 * j2 + 1][2], sacc[2 * j2 + 1][3]);
            uint32_t bf0[4], bf1[4];
            LDM_X4(bf0[0], bf0[1], bf0[2], bf0[3], vBase + (uint32_t)(j2 * 16) * 2);
            LDM_X4(bf1[0], bf1[1], bf1[2], bf1[3],
                   vBase + (uint32_t)(16 * 136 + j2 * 16) * 2);
            hmma16(oacc[0], a, bf0);
            hmma16(oacc[1], a, bf0 + 2);
            hmma16(oacc[2], a, bf1);
            hmma16(oacc[3], a, bf1 + 2);
        }
    }

    float inv0 = 1.f / rs0, inv1 = 1.f / rs1;
    int row0 = b * CC + qt * 128 + w * 16 + g;
    #pragma unroll
    for (int vj = 0; vj < 4; vj++) {
        int c = h * 32 + vj * 8 + 2 * tg;
        *(uint32_t*)&o[(size_t)row0 * 256 + c] =
            packh2(oacc[vj][0] * inv0, oacc[vj][1] * inv0);
        *(uint32_t*)&o[(size_t)(row0 + 8) * 256 + c] =
            packh2(oacc[vj][2] * inv1, oacc[vj][3] * inv1);
    }
}

// ---------------- mask dtype detection ----------------
__global__ void detect_mask_kernel(const int* __restrict__ m) {
    __shared__ int found;
    if (threadIdx.x == 0) found = 0;
    __syncthreads();
    int idx = blockIdx.x * blockDim.x + threadIdx.x;
    unsigned v = (unsigned)m[idx];
    if (v > 1u) found = 1;
    __syncthreads();
    if (threadIdx.x == 0 && blockIdx.x == 0) g_maskmode = 0;
    __threadfence();
    if (found) g_maskmode = 1;
}

// ---------------- pool (half output) ----------------
__global__ void pool_kernel(const int* __restrict__ vi, const int* __restrict__ si,
                            const void* __restrict__ maskraw,
                            const float* __restrict__ ve, const float* __restrict__ se,
                            const float* __restrict__ lpe, const float* __restrict__ cpe,
                            __half* __restrict__ x) {
    int bc = blockIdx.x;
    int c  = bc % CC;
    int d  = threadIdx.x;
    const int* viR = vi + bc * LL;
    const int* siR = si + bc * LL;
    __shared__ int mloc[LL];
    if (threadIdx.x < LL) {
        int mv;
        if (g_maskmode == 0) mv = ((const int*)maskraw)[bc * LL + threadIdx.x];
        else                 mv = ((const unsigned char*)maskraw)[bc * LL + threadIdx.x];
        mloc[threadIdx.x] = mv;
    }
    __syncthreads();
    float acc = 0.f; int cnt = 0;
    #pragma unroll
    for (int l = 0; l < LL; l++) {
        if (mloc[l]) {
            cnt++;
            acc += ve[viR[l]*DD + d] + se[siR[l]*DD + d] + lpe[l*DD + d];
        }
    }
    x[(size_t)bc*DD + d] = __float2half(acc / (float)cnt + cpe[c*DD + d]);
}

// ---------------- layernorm (typed I/O via flags) ----------------
__global__ void ln_kernel(const void* __restrict__ xin, int inH,
                          const void* __restrict__ res, int resM,
                          const float* __restrict__ w, const float* __restrict__ b,
                          void* __restrict__ out, int outH, int N, int resMod) {
    int row = blockIdx.x;
    int tid = threadIdx.x;
    int rrow = resMod ? (row % resMod) : row;
    int per = N >> 8;
    float v[4];
    float s = 0.f;
    for (int i = 0; i < per; i++) {
        int cI = tid + (i << 8);
        float t = inH ? __half2float(((const __half*)xin)[(size_t)row * N + cI])
                      : ((const float*)xin)[(size_t)row * N + cI];
        if (resM == 1)      t += ((const float*)res)[(size_t)rrow * N + cI];
        else if (resM == 2) t += __half2float(((const __half*)res)[(size_t)rrow * N + cI]);
        v[i] = t; s += t;
    }
    __shared__ float red[256];
    red[tid] = s; __syncthreads();
    for (int o = 128; o; o >>= 1) { if (tid < o) red[tid] += red[tid+o]; __syncthreads(); }
    float mean = red[0] / (float)N;
    __syncthreads();
    float vs = 0.f;
    for (int i = 0; i < per; i++) { float d = v[i] - mean; vs += d*d; }
    red[tid] = vs; __syncthreads();
    for (int o = 128; o; o >>= 1) { if (tid < o) red[tid] += red[tid+o]; __syncthreads(); }
    float inv = rsqrtf(red[0] / (float)N + 1e-5f);
    for (int i = 0; i < per; i++) {
        int cI = tid + (i << 8);
        float ov = (v[i] - mean) * inv * w[cI] + b[cI];
        if (outH) ((__half*)out)[(size_t)row*N + cI] = __float2half(ov);
        else      ((float*)out)[(size_t)row*N + cI] = ov;
    }
}

// ---------------- softmax (prefix path; fp32 in, half copy out) ----------------
__global__ void softmax_kernel(const float* __restrict__ S, __half* __restrict__ Sh, int cols) {
    int row  = blockIdx.x * 8 + (threadIdx.x >> 5);
    int lane = threadIdx.x & 31;
    const float* r = S + (size_t)row * cols;
    __half* rh = Sh + (size_t)row * cols;
    int per = cols >> 5;
    float vals[16];
    float mx = -1e30f;
    for (int t = 0; t < per; t++) { vals[t] = r[lane + (t<<5)]; mx = fmaxf(mx, vals[t]); }
    for (int o = 16; o; o >>= 1) mx = fmaxf(mx, __shfl_xor_sync(0xffffffffu, mx, o));
    float sum = 0.f;
    for (int t = 0; t < per; t++) { vals[t] = __expf(vals[t] - mx); sum += vals[t]; }
    for (int o = 16; o; o >>= 1) sum += __shfl_xor_sync(0xffffffffu, sum, o);
    float inv = 1.f / sum;
    for (int t = 0; t < per; t++) rh[lane + (t<<5)] = __float2half(vals[t] * inv);
}

// ============================ host orchestration ============================
#define HG_B   hgemm<0,1,1>
#define HG_BF  hgemm<0,1,0>
#define HG_G   hgemm<1,1,1>
#define HG_N   hgemm<0,0,0>

static const int HG_SMEM = 6 * 128 * 72 * 2;   // 110592 B (3 stages A + 3 stages W)

static void cvh(const float* src, __half* dst, int n) {
    cvt_h<<<(n/4 + 255)/256, 256>>>(src, dst, n/4);
}

extern "C" void kernel_launch(void* const* d_in, const int* in_sizes, int n_in,
                              void* d_out, int out_size) {
    const int*   var_idx   = (const int*)  d_in[0];
    const int*   sign_idx  = (const int*)  d_in[1];
    const void*  lit_mask  = (const void*) d_in[2];
    const float* var_emb   = (const float*)d_in[3];
    const float* sign_emb  = (const float*)d_in[4];
    const float* litpos    = (const float*)d_in[5];
    const float* clausepos = (const float*)d_in[6];
    const float* enc_in_w  = (const float*)d_in[7];
    const float* enc_in_b  = (const float*)d_in[8];
    const float* enc_out_w = (const float*)d_in[9];
    const float* enc_out_b = (const float*)d_in[10];
    const float* enc_ff1_w = (const float*)d_in[11];
    const float* enc_ff1_b = (const float*)d_in[12];
    const float* enc_ff2_w = (const float*)d_in[13];
    const float* enc_ff2_b = (const float*)d_in[14];
    const float* n1w = (const float*)d_in[15];
    const float* n1b = (const float*)d_in[16];
    const float* n2w = (const float*)d_in[17];
    const float* n2b = (const float*)d_in[18];
    const float* th_ln_w = (const float*)d_in[19];
    const float* th_ln_b = (const float*)d_in[20];
    const float* th_w = (const float*)d_in[21];
    const float* th_b = (const float*)d_in[22];
    const float* pq   = (const float*)d_in[23];
    const float* pa_in_w  = (const float*)d_in[24];
    const float* pa_in_b  = (const float*)d_in[25];
    const float* pa_out_w = (const float*)d_in[26];
    const float* pa_out_b = (const float*)d_in[27];
    const float* pn_w = (const float*)d_in[28];
    const float* pn_b = (const float*)d_in[29];
    float* out = (float*)d_out;

    __half *x,*t0,*t1,*t2h,*ch,*kv,*qh,*S2h,*p1;
    float *S2,*p2;
    __half *hwin,*hwout,*hwf1,*hwf2,*hwth,*hwpa,*hwpo,*hwpq;
    cudaGetSymbolAddress((void**)&x,   g_x);
    cudaGetSymbolAddress((void**)&t0,  g_t0);
    cudaGetSymbolAddress((void**)&t1,  g_t1);
    cudaGetSymbolAddress((void**)&t2h, g_t2h);
    cudaGetSymbolAddress((void**)&ch,  g_ch);
    cudaGetSymbolAddress((void**)&kv,  g_kv);
    cudaGetSymbolAddress((void**)&qh,  g_qh);
    cudaGetSymbolAddress((void**)&S2,  g_S2);
    cudaGetSymbolAddress((void**)&S2h, g_S2h);
    cudaGetSymbolAddress((void**)&p1,  g_p1);
    cudaGetSymbolAddress((void**)&p2,  g_p2);
    cudaGetSymbolAddress((void**)&hwin,  g_hw_in);
    cudaGetSymbolAddress((void**)&hwout, g_hw_out);
    cudaGetSymbolAddress((void**)&hwf1,  g_hw_f1);
    cudaGetSymbolAddress((void**)&hwf2,  g_hw_f2);
    cudaGetSymbolAddress((void**)&hwth,  g_hw_th);
    cudaGetSymbolAddress((void**)&hwpa,  g_hw_pa);
    cudaGetSymbolAddress((void**)&hwpo,  g_hw_po);
    cudaGetSymbolAddress((void**)&hwpq,  g_hw_pq);

    cudaFuncSetAttribute(HG_B,  cudaFuncAttributeMaxDynamicSharedMemorySize, HG_SMEM);
    cudaFuncSetAttribute(HG_BF, cudaFuncAttributeMaxDynamicSharedMemorySize, HG_SMEM);
    cudaFuncSetAttribute(HG_G,  cudaFuncAttributeMaxDynamicSharedMemorySize, HG_SMEM);
    cudaFuncSetAttribute(HG_N,  cudaFuncAttributeMaxDynamicSharedMemorySize, HG_SMEM);

    const int M = BB*CC;
    const float escale = 0.17677669529663687f;   // 1/sqrt(32)
    const float pscale = 0.08838834764831845f;   // 1/sqrt(128)

    // ---- weight conversion to fp16 ----
    cvh(enc_in_w,  hwin,  NLL*768*DD);
    cvh(enc_out_w, hwout, NLL*DD*DD);
    cvh(enc_ff1_w, hwf1,  NLL*HH*DD);
    cvh(enc_ff2_w, hwf2,  NLL*DD*HH);
    cvh(th_w,      hwth,  HH*DD);
    cvh(pa_in_w,   hwpa,  3*HH*HH);
    cvh(pa_out_w,  hwpo,  HH*HH);
    cvh(pq,        hwpq,  PP*HH);

    detect_mask_kernel<<<16, 256>>>((const int*)lit_mask);
    pool_kernel<<<M, 256>>>(var_idx, sign_idx, lit_mask, var_emb, sign_emb,
                            litpos, clausepos, x);

    for (int i = 0; i < NLL; i++) {
        const __half* wqkv = hwin  + (size_t)i*768*DD;
        const float*  bqkv = enc_in_b  + (size_t)i*768;
        const __half* wo   = hwout + (size_t)i*DD*DD;
        const float*  bo   = enc_out_b + (size_t)i*DD;
        const __half* w1   = hwf1  + (size_t)i*HH*DD;
        const float*  b1   = enc_ff1_b + (size_t)i*HH;
        const __half* w2   = hwf2  + (size_t)i*DD*HH;
        const float*  b2   = enc_ff2_b + (size_t)i*DD;

        // qkv -> t0 half [M,768]
        HG_B<<<dim3(6,128,1),256,HG_SMEM>>>(x, wqkv, bqkv, t0, M,768,DD,
                                            DD,DD,768, 1,0,0,0,0,0,0, 1.f);
        // fused attention -> t1 half [M,256]
        fused_attn_h<<<dim3(4, BB*NHD), 256>>>(t0, t1, escale);
        // out proj -> t2h half (feeds LN)
        HG_B<<<dim3(2,128,1),256,HG_SMEM>>>(t1, wo, bo, t2h, M,DD,DD,
                                            DD,DD,DD, 1,0,0,0,0,0,0, 1.f);
        ln_kernel<<<M,256>>>(t2h, 1, x, 2, n1w + i*DD, n1b + i*DD, x, 1, DD, 0);
        // ff1 gelu -> t0 half [M,1024]
        HG_G<<<dim3(8,128,1),256,HG_SMEM>>>(x, w1, b1, t0, M,HH,DD,
                                            DD,DD,HH, 1,0,0,0,0,0,0, 1.f);
        // ff2 -> t2h half
        HG_B<<<dim3(2,128,1),256,HG_SMEM>>>(t0, w2, b2, t2h, M,DD,HH,
                                            HH,HH,DD, 1,0,0,0,0,0,0, 1.f);
        ln_kernel<<<M,256>>>(t2h, 1, x, 2, n2w + i*DD, n2b + i*DD, x, 1, DD, 0);
    }

    // ch = LN(x) @ th_w^T + th_b  (half)
    ln_kernel<<<M,256>>>(x, 1, nullptr, 0, th_ln_w, th_ln_b, t2h, 1, DD, 0);
    HG_B<<<dim3(8,128,1),256,HG_SMEM>>>(t2h, hwth, th_b, ch, M,HH,DD,
                                        DD,DD,HH, 1,0,0,0,0,0,0, 1.f);

    // prefix cross-attention
    HG_B<<<dim3(8,1,1),256,HG_SMEM>>>(hwpq, hwpa, pa_in_b, qh, PP,HH,HH,
                                      HH,HH,HH, 1,0,0,0,0,0,0, 1.f);
    // merged K/V: kv[M,2048]
    HG_B<<<dim3(16,128,1),256,HG_SMEM>>>(ch, hwpa + (size_t)HH*HH, pa_in_b + HH, kv,
                                         M,2*HH,HH, HH,HH,2*HH, 1,0,0,0,0,0,0, 1.f);
    // scores2 per (b,h): [16,512], K=128 -> S2 float
    HG_N<<<dim3(4,1,BB*NHD),256,HG_SMEM>>>(qh, kv, nullptr, S2, PP,CC,128,
                                           HH,2*HH,CC, NHD,
                                           0L, 128L, (long)CC*2*HH, 128L,
                                           (long)NHD*PP*CC, (long)PP*CC, pscale);
    softmax_kernel<<<(BB*NHD*PP)/8, 256>>>(S2, S2h, CC);
    // AV2 -> p1 half
    av2h<<<dim3(4,1,BB*NHD),256>>>(S2h, kv, p1);
    // out proj -> p2 float
    HG_BF<<<dim3(8,4,1),256,HG_SMEM>>>(p1, hwpo, pa_out_b, p2, BB*PP,HH,HH,
                                       HH,HH,HH, 1,0,0,0,0,0,0, 1.f);
    // final LN: p2 + pq (fp32 residual, broadcast over batch) -> out fp32
    ln_kernel<<<BB*PP,256>>>(p2, 0, pq, 1, pn_w, pn_b, out, 0, HH, PP);
}

// round 11
// speedup vs baseline: 5.9028x; 1.0134x over previous
#include <cuda_runtime.h>
#include <cuda_fp16.h>
#include <cstdint>

#define BB 32
#define CC 512
#define LL 16
#define DD 256
#define HH 1024
#define PP 16
#define NHD 8
#define NLL 4

// ---------------- scratch (static device globals; allocation-free) ----------------
__device__ __half g_x  [BB*CC*DD];
__device__ __half g_t0 [BB*CC*HH];
__device__ __half g_t1 [BB*CC*DD];
__device__ __half g_t2h[BB*CC*DD];
__device__ __half g_ch [BB*CC*HH];
__device__ __half g_kv [BB*CC*2*HH];
__device__ __half g_qh [PP*HH];
__device__ float  g_S2 [BB*NHD*PP*CC];
__device__ __half g_S2h[BB*NHD*PP*CC];
__device__ __half g_p1 [BB*PP*HH];
__device__ float  g_p2 [BB*PP*HH];
__device__ int    g_maskmode;
// half weights
__device__ __half g_hw_in [NLL*768*DD];
__device__ __half g_hw_out[NLL*DD*DD];
__device__ __half g_hw_f1 [NLL*HH*DD];
__device__ __half g_hw_f2 [NLL*DD*HH];
__device__ __half g_hw_th [HH*DD];
__device__ __half g_hw_pa [3*HH*HH];
__device__ __half g_hw_po [HH*HH];
__device__ __half g_hw_pq [PP*HH];

// ---------------- small helpers ----------------
__device__ __forceinline__ uint32_t smem_u32(const void* p) {
    uint32_t a;
    asm("{ .reg .u64 t; cvta.to.shared.u64 t, %1; cvt.u32.u64 %0, t; }" : "=r"(a) : "l"(p));
    return a;
}
__device__ __forceinline__ float gelu_f(float v) {
    return 0.5f * v * (1.f + erff(v * 0.70710678118654752f));
}
__device__ __forceinline__ uint32_t packh2(float lo, float hi) {
    __half2 h = __floats2half2_rn(lo, hi);
    return *(uint32_t*)&h;
}
// NOTE: non-volatile on purpose — pure register asm, lets ptxas interleave with LDSM.
__device__ __forceinline__ void hmma16(float* c, const uint32_t* a, const uint32_t* b) {
    asm("mma.sync.aligned.m16n8k16.row.col.f32.f16.f16.f32 "
        "{%0,%1,%2,%3}, {%4,%5,%6,%7}, {%8,%9}, {%0,%1,%2,%3};"
        : "+f"(c[0]), "+f"(c[1]), "+f"(c[2]), "+f"(c[3])
        : "r"(a[0]), "r"(a[1]), "r"(a[2]), "r"(a[3]), "r"(b[0]), "r"(b[1]));
}
#define LDM_X4(r0, r1, r2, r3, addr) \
    asm volatile("ldmatrix.sync.aligned.m8n8.x4.shared.b16 {%0,%1,%2,%3}, [%4];" \
        : "=r"(r0), "=r"(r1), "=r"(r2), "=r"(r3) : "r"(addr))
#define LDM_X2(r0, r1, addr) \
    asm volatile("ldmatrix.sync.aligned.m8n8.x2.shared.b16 {%0,%1}, [%2];" \
        : "=r"(r0), "=r"(r1) : "r"(addr))
#define CPA16(dst, src, pred) \
    asm volatile("cp.async.cg.shared.global [%0], [%1], 16, %2;" \
                 :: "r"(dst), "l"(src), "r"((pred) ? 16 : 0))
#define CP_COMMIT() asm volatile("cp.async.commit_group;")
#define CP_WAIT1()  asm volatile("cp.async.wait_group 1;")
#define CP_WAIT0()  asm volatile("cp.async.wait_group 0;")

// ---------------- fp32 -> fp16 weight conversion ----------------
__global__ void cvt_h(const float* __restrict__ src, __half* __restrict__ dst, int n4) {
    int i = blockIdx.x * 256 + threadIdx.x;
    if (i < n4) {
        float4 v = ((const float4*)src)[i];
        uint2 u;
        u.x = packh2(v.x, v.y);
        u.y = packh2(v.z, v.w);
        ((uint2*)dst)[i] = u;
    }
}

// ============================ fp16 3-stage cp.async + ldmatrix GEMM ============================
// C[m,n] = act(alpha * A@W^T + bias); A[M,K] half, W[N,K] half. N%128==0, K%64==0.
// Inner loop software-pipelines fragment loads (double-buffered af/bf).
template<int ACT, int HASB, int OUTH>
__global__ __launch_bounds__(256, 2) void hgemm(
    const __half* __restrict__ A, const __half* __restrict__ W,
    const float* __restrict__ bias, void* __restrict__ Cp,
    int M, int N, int K, int lda, int ldw, int ldc,
    int nsub, long sAb, long sAs, long sWb, long sWs, long sCb, long sCs,
    float alpha)
{
    constexpr int BM = 128, BN = 128, BK = 64, LDH = 72, NST = 3;
    constexpr uint32_t STB = BM * LDH * 2;                  // 18432 B
    extern __shared__ __half smh[];
    uint32_t base = smem_u32(smh);
    uint32_t asA = base;                   // NST stages A
    uint32_t wsA = base + NST * STB;       // NST stages W

    int tid = threadIdx.x, wid = tid >> 5, lane = tid & 31;
    int warpM = wid >> 2, warpN = wid & 3;
    int g = lane >> 2, tg = lane & 3;
    int bm = blockIdx.y * BM, bn = blockIdx.x * BN;
    int z = blockIdx.z, zb = z / nsub, zs = z % nsub;
    const __half* Ab = A + (size_t)zb * sAb + (size_t)zs * sAs;
    const __half* Wb = W + (size_t)zb * sWb + (size_t)zs * sWs;

    int arow = (lane & 7) + ((lane & 8) ? 8 : 0);
    int acol = (lane & 16) ? 8 : 0;
    int brow = (lane & 7) + ((lane & 16) ? 8 : 0);
    int bcol = (lane & 8) ? 8 : 0;
    uint32_t aLane = (uint32_t)((warpM * 64 + arow) * LDH + acol) * 2;
    uint32_t bLane = (uint32_t)((warpN * 32 + brow) * LDH + bcol) * 2;

    auto load_stage = [&](int st, int k0) {
        uint32_t ab = asA + (uint32_t)st * STB;
        uint32_t wb = wsA + (uint32_t)st * STB;
        #pragma unroll
        for (int idx = tid; idx < BM * 8; idx += 256) {
            int row = idx >> 3, q = idx & 7;
            int gm = bm + row;
            bool ok = gm < M;
            int gmc = ok ? gm : 0;
            CPA16(ab + (uint32_t)(row * LDH + q * 8) * 2,
                  Ab + (size_t)gmc * lda + k0 + q * 8, ok);
        }
        #pragma unroll
        for (int idx = tid; idx < BN * 8; idx += 256) {
            int row = idx >> 3, q = idx & 7;
            CPA16(wb + (uint32_t)(row * LDH + q * 8) * 2,
                  Wb + (size_t)(bn + row) * ldw + k0 + q * 8, true);
        }
        CP_COMMIT();
    };

    float acc[4][4][4];
    #pragma unroll
    for (int i = 0; i < 4; i++)
        #pragma unroll
        for (int j = 0; j < 4; j++)
            #pragma unroll
            for (int q = 0; q < 4; q++) acc[i][j][q] = 0.f;

    int nk = K / BK;
    load_stage(0, 0);
    if (nk > 1) load_stage(1, BK);

    for (int i = 0; i < nk; i++) {
        if (i + 1 < nk) CP_WAIT1(); else CP_WAIT0();
        __syncthreads();
        if (i + 2 < nk) load_stage((i + 2) % NST, (i + 2) * BK);

        int cur = i % NST;
        uint32_t aB = asA + (uint32_t)cur * STB + aLane;
        uint32_t wB = wsA + (uint32_t)cur * STB + bLane;

        uint32_t af[2][4][4], bf[2][4][2];
        // prologue: fragments for k-step 0
        #pragma unroll
        for (int mi = 0; mi < 4; mi++)
            LDM_X4(af[0][mi][0], af[0][mi][1], af[0][mi][2], af[0][mi][3],
                   aB + (uint32_t)(mi * 16 * LDH) * 2);
        LDM_X4(bf[0][0][0], bf[0][0][1], bf[0][1][0], bf[0][1][1], wB);
        LDM_X4(bf[0][2][0], bf[0][2][1], bf[0][3][0], bf[0][3][1],
               wB + (uint32_t)(16 * LDH) * 2);

        #pragma unroll
        for (int ks = 0; ks < 4; ks++) {
            int cb = ks & 1, nb = cb ^ 1;
            if (ks < 3) {    // prefetch next k-step BEFORE this step's HMMAs
                int kk = (ks + 1) * 16;
                #pragma unroll
                for (int mi = 0; mi < 4; mi++)
                    LDM_X4(af[nb][mi][0], af[nb][mi][1], af[nb][mi][2], af[nb][mi][3],
                           aB + (uint32_t)(mi * 16 * LDH + kk) * 2);
                LDM_X4(bf[nb][0][0], bf[nb][0][1], bf[nb][1][0], bf[nb][1][1],
                       wB + (uint32_t)kk * 2);
                LDM_X4(bf[nb][2][0], bf[nb][2][1], bf[nb][3][0], bf[nb][3][1],
                       wB + (uint32_t)(16 * LDH + kk) * 2);
            }
            #pragma unroll
            for (int mi = 0; mi < 4; mi++)
                #pragma unroll
                for (int nj = 0; nj < 4; nj++)
                    hmma16(acc[mi][nj], af[cb][mi], bf[cb][nj]);
        }
    }

    long cOff = (size_t)zb * sCb + (size_t)zs * sCs;
    #pragma unroll
    for (int mi = 0; mi < 4; mi++) {
        int r0 = bm + warpM * 64 + mi * 16 + g;
        #pragma unroll
        for (int nj = 0; nj < 4; nj++) {
            int c = bn + warpN * 32 + nj * 8 + 2 * tg;
            float b0 = 0.f, b1 = 0.f;
            if (HASB) { b0 = bias[c]; b1 = bias[c + 1]; }
            float v0 = acc[mi][nj][0] * alpha + b0;
            float v1 = acc[mi][nj][1] * alpha + b1;
            float v2 = acc[mi][nj][2] * alpha + b0;
            float v3 = acc[mi][nj][3] * alpha + b1;
            if (ACT) { v0 = gelu_f(v0); v1 = gelu_f(v1); v2 = gelu_f(v2); v3 = gelu_f(v3); }
            if (OUTH) {
                __half* Cb = (__half*)Cp + cOff;
                if (r0 < M)     *(uint32_t*)&Cb[(size_t)r0 * ldc + c]       = packh2(v0, v1);
                if (r0 + 8 < M) *(uint32_t*)&Cb[(size_t)(r0 + 8) * ldc + c] = packh2(v2, v3);
            } else {
                float* Cb = (float*)Cp + cOff;
                if (r0 < M)     { Cb[(size_t)r0 * ldc + c] = v0; Cb[(size_t)r0 * ldc + c + 1] = v1; }
                if (r0 + 8 < M) { Cb[(size_t)(r0 + 8) * ldc + c] = v2; Cb[(size_t)(r0 + 8) * ldc + c + 1] = v3; }
            }
        }
    }
}

// ============================ AV2 half kernel (prefix P@V) ============================
__global__ __launch_bounds__(256) void av2h(
    const __half* __restrict__ S2h, const __half* __restrict__ kvv,
    __half* __restrict__ p1)
{
    constexpr int BK = 64, LDH = 72;
    __shared__ __half As[128 * LDH];
    __shared__ __half Ws[32 * LDH];

    int tid = threadIdx.x, wid = tid >> 5, lane = tid & 31;
    int warpM = wid >> 2, warpN = wid & 3;
    int g = lane >> 2, tg = lane & 3;
    int z = blockIdx.z, b = z >> 3, h = z & 7;
    int bn = blockIdx.x * 32;
    const __half* Ab = S2h + (size_t)z * PP * CC;
    const __half* Vb = kvv + (size_t)b * CC * 2048 + HH + h * 128;
    __half* Cb = p1 + (size_t)b * PP * HH + h * 128;

    int arow = (lane & 7) + ((lane & 8) ? 8 : 0);
    int acol = (lane & 16) ? 8 : 0;
    uint32_t aLane = smem_u32(As) + (uint32_t)((warpM * 64 + arow) * LDH + acol) * 2;
    int brow = warpN * 8 + (lane & 7);
    int bcol = (lane & 8) ? 8 : 0;
    uint32_t bLane = smem_u32(Ws) + (uint32_t)(brow * LDH + bcol) * 2;

    float acc[4][4];
    #pragma unroll
    for (int i = 0; i < 4; i++)
        #pragma unroll
        for (int q = 0; q < 4; q++) acc[i][q] = 0.f;

    for (int k0 = 0; k0 < CC; k0 += BK) {
        __syncthreads();
        #pragma unroll
        for (int idx = tid; idx < 128 * 8; idx += 256) {
            int row = idx >> 3, q = idx & 7;
            int gm = (row < PP) ? row : 0;
            *(uint4*)&As[row * LDH + q * 8] =
                *(const uint4*)(Ab + (size_t)gm * CC + k0 + q * 8);
        }
        #pragma unroll
        for (int idx = tid; idx < 64 * 4; idx += 256) {
            int kk = idx >> 2, q = idx & 3;
            union { uint4 u; __half h[8]; } vv;
            vv.u = *(const uint4*)(Vb + (size_t)(k0 + kk) * 2048 + bn + q * 8);
            #pragma unroll
            for (int j = 0; j < 8; j++) Ws[(q * 8 + j) * LDH + kk] = vv.h[j];
        }
        __syncthreads();

        #pragma unroll
        for (int kk = 0; kk < BK; kk += 16) {
            uint32_t af[4][4], bf[2];
            #pragma unroll
            for (int mi = 0; mi < 4; mi++)
                LDM_X4(af[mi][0], af[mi][1], af[mi][2], af[mi][3],
                       aLane + (uint32_t)(mi * 16 * LDH + kk) * 2);
            LDM_X2(bf[0], bf[1], bLane + (uint32_t)kk * 2);
            #pragma unroll
            for (int mi = 0; mi < 4; mi++)
                hmma16(acc[mi], af[mi], bf);
        }
    }

    #pragma unroll
    for (int mi = 0; mi < 4; mi++) {
        int r0 = warpM * 64 + mi * 16 + g;
        int c = bn + warpN * 8 + 2 * tg;
        if (r0 < PP)     *(uint32_t*)&Cb[(size_t)r0 * HH + c]       = packh2(acc[mi][0], acc[mi][1]);
        if (r0 + 8 < PP) *(uint32_t*)&Cb[(size_t)(r0 + 8) * HH + c] = packh2(acc[mi][2], acc[mi][3]);
    }
}

// ============================ fused flash attention (fp16, pipelined frags) ============================
__global__ __launch_bounds__(256) void fused_attn_h(
    const __half* __restrict__ qkv, __half* __restrict__ o, float escale)
{
    __shared__ __half Qs[128 * 40];
    __shared__ __half Ks[128 * 40];
    __shared__ __half Vs[32 * 136];

    int tid = threadIdx.x, lane = tid & 31, w = tid >> 5;
    int g = lane >> 2, tg = lane & 3;
    int qt = blockIdx.x;
    int z  = blockIdx.y;
    int b  = z >> 3, h = z & 7;
    const __half* base = qkv + (size_t)b * CC * 768;

    int arow = (lane & 7) + ((lane & 8) ? 8 : 0);
    int acol = (lane & 16) ? 8 : 0;
    int brow = (lane & 7) + ((lane & 16) ? 8 : 0);
    int bcol = (lane & 8) ? 8 : 0;
    uint32_t qBase = smem_u32(Qs) + (uint32_t)((w * 16 + arow) * 40 + acol) * 2;
    uint32_t kBase = smem_u32(Ks) + (uint32_t)(brow * 40 + bcol) * 2;
    uint32_t vBase = smem_u32(Vs) + (uint32_t)(brow * 136 + bcol) * 2;

    #pragma unroll
    for (int idx = tid; idx < 128 * 4; idx += 256) {
        int r = idx >> 2, q4 = idx & 3;
        *(uint4*)&Qs[r * 40 + q4 * 8] =
            *(const uint4*)(base + (size_t)(qt * 128 + r) * 768 + h * 32 + q4 * 8);
    }

    float oacc[4][4];
    #pragma unroll
    for (int i = 0; i < 4; i++)
        #pragma unroll
        for (int q = 0; q < 4; q++) oacc[i][q] = 0.f;
    float rm0 = -1e30f, rm1 = -1e30f, rs0 = 0.f, rs1 = 0.f;

    for (int kt = 0; kt < 4; kt++) {
        __syncthreads();
        #pragma unroll
        for (int idx = tid; idx < 128 * 4; idx += 256) {
            int r = idx >> 2, q4 = idx & 3;
            const __half* kr = base + (size_t)(kt * 128 + r) * 768 + 256 + h * 32 + q4 * 8;
            *(uint4*)&Ks[r * 40 + q4 * 8] = *(const uint4*)kr;
            union { uint4 u; __half hh[8]; } vv;
            vv.u = *(const uint4*)(kr + 256);
            #pragma unroll
            for (int j = 0; j < 8; j++) Vs[(q4 * 8 + j) * 136 + r] = vv.hh[j];
        }
        __syncthreads();

        // ---- S = Q @ K^T : pipelined over 16 (p8,kk) pairs ----
        float sacc[16][4];
        #pragma unroll
        for (int nj = 0; nj < 16; nj++)
            #pragma unroll
            for (int q = 0; q < 4; q++) sacc[nj][q] = 0.f;

        uint32_t af0[4], af1[4];
        LDM_X4(af0[0], af0[1], af0[2], af0[3], qBase);
        LDM_X4(af1[0], af1[1], af1[2], af1[3], qBase + 32u);
        uint32_t kbf[2][4];
        LDM_X4(kbf[0][0], kbf[0][1], kbf[0][2], kbf[0][3], kBase);
        #pragma unroll
        for (int t = 0; t < 16; t++) {
            int p8 = t >> 1;
            if (t < 15) {
                int tn = t + 1;
                int p8n = tn >> 1, kkn = (tn & 1) * 16;
                LDM_X4(kbf[tn & 1][0], kbf[tn & 1][1], kbf[tn & 1][2], kbf[tn & 1][3],
                       kBase + (uint32_t)(p8n * 16 * 40 + kkn) * 2);
            }
            const uint32_t* afc = (t & 1) ? af1 : af0;
            hmma16(sacc[2 * p8],     afc, kbf[t & 1]);
            hmma16(sacc[2 * p8 + 1], afc, kbf[t & 1] + 2);
        }

        // ---- online softmax (rows g and g+8) ----
        float tm0 = -1e30f, tm1 = -1e30f;
        #pragma unroll
        for (int nj = 0; nj < 16; nj++) {
            tm0 = fmaxf(tm0, fmaxf(sacc[nj][0], sacc[nj][1]));
            tm1 = fmaxf(tm1, fmaxf(sacc[nj][2], sacc[nj][3]));
        }
        tm0 *= escale; tm1 *= escale;
        tm0 = fmaxf(tm0, __shfl_xor_sync(0xffffffffu, tm0, 1));
        tm0 = fmaxf(tm0, __shfl_xor_sync(0xffffffffu, tm0, 2));
        tm1 = fmaxf(tm1, __shfl_xor_sync(0xffffffffu, tm1, 1));
        tm1 = fmaxf(tm1, __shfl_xor_sync(0xffffffffu, tm1, 2));
        float nm0 = fmaxf(rm0, tm0), nm1 = fmaxf(rm1, tm1);
        float cr0 = __expf(rm0 - nm0), cr1 = __expf(rm1 - nm1);
        rm0 = nm0; rm1 = nm1;
        float ps0 = 0.f, ps1 = 0.f;
        #pragma unroll
        for (int nj = 0; nj < 16; nj++) {
            float p0 = __expf(sacc[nj][0] * escale - nm0);
            float p1 = __expf(sacc[nj][1] * escale - nm0);
            float p2 = __expf(sacc[nj][2] * escale - nm1);
            float p3 = __expf(sacc[nj][3] * escale - nm1);
            sacc[nj][0] = p0; sacc[nj][1] = p1; sacc[nj][2] = p2; sacc[nj][3] = p3;
            ps0 += p0 + p1; ps1 += p2 + p3;
        }
        ps0 += __shfl_xor_sync(0xffffffffu, ps0, 1);
        ps0 += __shfl_xor_sync(0xffffffffu, ps0, 2);
        ps1 += __shfl_xor_sync(0xffffffffu, ps1, 1);
        ps1 += __shfl_xor_sync(0xffffffffu, ps1, 2);
        rs0 = rs0 * cr0 + ps0;
        rs1 = rs1 * cr1 + ps1;
        #pragma unroll
        for (int vj = 0; vj < 4; vj++) {
            oacc[vj][0] *= cr0; oacc[vj][1] *= cr0;
            oacc[vj][2] *= cr1; oacc[vj][3] *= cr1;
        }

        // ---- O += P @ V : pipelined over 16 (j2,vp) pairs ----
        uint32_t pvb[2][4];
        LDM_X4(pvb[0][0], pvb[0][1], pvb[0][2], pvb[0][3], vBase);
        uint32_t a[4];
        #pragma unroll
        for (int t = 0; t < 16; t++) {
            int j2 = t >> 1, vp = t & 1;
            if (vp == 0) {
                a[0] = packh2(sacc[2 * j2][0],     sacc[2 * j2][1]);
                a[1] = packh2(sacc[2 * j2][2],     sacc[2 * j2][3]);
                a[2] = packh2(sacc[2 * j2 + 1][0], sacc[2 * j2 + 1][1]);
                a[3] = packh2(sacc[2 * j2 + 1][2], sacc[2 * j2 + 1][3]);
            }
            if (t < 15) {
                int tn = t + 1;
                int j2n = tn >> 1, vpn = tn & 1;
                LDM_X4(pvb[tn & 1][0], pvb[tn & 1][1], pvb[tn & 1][2], pvb[tn & 1][3],
                       vBase + (uint32_t)(vpn * 16 * 136 + j2n * 16) * 2);
            }
            hmma16(oacc[2 * vp],     a, pvb[t & 1]);
            hmma16(oacc[2 * vp + 1], a, pvb[t & 1] + 2);
        }
    }

    float inv0 = 1.f / rs0, inv1 = 1.f / rs1;
    int row0 = b * CC + qt * 128 + w * 16 + g;
    #pragma unroll
    for (int vj = 0; vj < 4; vj++) {
        int c = h * 32 + vj * 8 + 2 * tg;
        *(uint32_t*)&o[(size_t)row0 * 256 + c] =
            packh2(oacc[vj][0] * inv0, oacc[vj][1] * inv0);
        *(uint32_t*)&o[(size_t)(row0 + 8) * 256 + c] =
            packh2(oacc[vj][2] * inv1, oacc[vj][3] * inv1);
    }
}

// ---------------- mask dtype detection ----------------
__global__ void detect_mask_kernel(const int* __restrict__ m) {
    __shared__ int found;
    if (threadIdx.x == 0) found = 0;
    __syncthreads();
    int idx = blockIdx.x * blockDim.x + threadIdx.x;
    unsigned v = (unsigned)m[idx];
    if (v > 1u) found = 1;
    __syncthreads();
    if (threadIdx.x == 0 && blockIdx.x == 0) g_maskmode = 0;
    __threadfence();
    if (found) g_maskmode = 1;
}

// ---------------- pool (half output) ----------------
__global__ void pool_kernel(const int* __restrict__ vi, const int* __restrict__ si,
                            const void* __restrict__ maskraw,
                            const float* __restrict__ ve, const float* __restrict__ se,
                            const float* __restrict__ lpe, const float* __restrict__ cpe,
                            __half* __restrict__ x) {
    int bc = blockIdx.x;
    int c  = bc % CC;
    int d  = threadIdx.x;
    const int* viR = vi + bc * LL;
    const int* siR = si + bc * LL;
    __shared__ int mloc[LL];
    if (threadIdx.x < LL) {
        int mv;
        if (g_maskmode == 0) mv = ((const int*)maskraw)[bc * LL + threadIdx.x];
        else                 mv = ((const unsigned char*)maskraw)[bc * LL + threadIdx.x];
        mloc[threadIdx.x] = mv;
    }
    __syncthreads();
    float acc = 0.f; int cnt = 0;
    #pragma unroll
    for (int l = 0; l < LL; l++) {
        if (mloc[l]) {
            cnt++;
            acc += ve[viR[l]*DD + d] + se[siR[l]*DD + d] + lpe[l*DD + d];
        }
    }
    x[(size_t)bc*DD + d] = __float2half(acc / (float)cnt + cpe[c*DD + d]);
}

// ---------------- layernorm (typed I/O via flags) ----------------
__global__ void ln_kernel(const void* __restrict__ xin, int inH,
                          const void* __restrict__ res, int resM,
                          const float* __restrict__ w, const float* __restrict__ b,
                          void* __restrict__ out, int outH, int N, int resMod) {
    int row = blockIdx.x;
    int tid = threadIdx.x;
    int rrow = resMod ? (row % resMod) : row;
    int per = N >> 8;
    float v[4];
    float s = 0.f;
    for (int i = 0; i < per; i++) {
        int cI = tid + (i << 8);
        float t = inH ? __half2float(((const __half*)xin)[(size_t)row * N + cI])
                      : ((const float*)xin)[(size_t)row * N + cI];
        if (resM == 1)      t += ((const float*)res)[(size_t)rrow * N + cI];
        else if (resM == 2) t += __half2float(((const __half*)res)[(size_t)rrow * N + cI]);
        v[i] = t; s += t;
    }
    __shared__ float red[256];
    red[tid] = s; __syncthreads();
    for (int o = 128; o; o >>= 1) { if (tid < o) red[tid] += red[tid+o]; __syncthreads(); }
    float mean = red[0] / (float)N;
    __syncthreads();
    float vs = 0.f;
    for (int i = 0; i < per; i++) { float d = v[i] - mean; vs += d*d; }
    red[tid] = vs; __syncthreads();
    for (int o = 128; o; o >>= 1) { if (tid < o) red[tid] += red[tid+o]; __syncthreads(); }
    float inv = rsqrtf(red[0] / (float)N + 1e-5f);
    for (int i = 0; i < per; i++) {
        int cI = tid + (i << 8);
        float ov = (v[i] - mean) * inv * w[cI] + b[cI];
        if (outH) ((__half*)out)[(size_t)row*N + cI] = __float2half(ov);
        else      ((float*)out)[(size_t)row*N + cI] = ov;
    }
}

// ---------------- softmax (prefix path; fp32 in, half copy out) ----------------
__global__ void softmax_kernel(const float* __restrict__ S, __half* __restrict__ Sh, int cols) {
    int row  = blockIdx.x * 8 + (threadIdx.x >> 5);
    int lane = threadIdx.x & 31;
    const float* r = S + (size_t)row * cols;
    __half* rh = Sh + (size_t)row * cols;
    int per = cols >> 5;
    float vals[16];
    float mx = -1e30f;
    for (int t = 0; t < per; t++) { vals[t] = r[lane + (t<<5)]; mx = fmaxf(mx, vals[t]); }
    for (int o = 16; o; o >>= 1) mx = fmaxf(mx, __shfl_xor_sync(0xffffffffu, mx, o));
    float sum = 0.f;
    for (int t = 0; t < per; t++) { vals[t] = __expf(vals[t] - mx); sum += vals[t]; }
    for (int o = 16; o; o >>= 1) sum += __shfl_xor_sync(0xffffffffu, sum, o);
    float inv = 1.f / sum;
    for (int t = 0; t < per; t++) rh[lane + (t<<5)] = __float2half(vals[t] * inv);
}

// ============================ host orchestration ============================
#define HG_B   hgemm<0,1,1>
#define HG_BF  hgemm<0,1,0>
#define HG_G   hgemm<1,1,1>
#define HG_N   hgemm<0,0,0>

static const int HG_SMEM = 6 * 128 * 72 * 2;   // 110592 B (3 stages A + 3 stages W)

static void cvh(const float* src, __half* dst, int n) {
    cvt_h<<<(n/4 + 255)/256, 256>>>(src, dst, n/4);
}

extern "C" void kernel_launch(void* const* d_in, const int* in_sizes, int n_in,
                              void* d_out, int out_size) {
    const int*   var_idx   = (const int*)  d_in[0];
    const int*   sign_idx  = (const int*)  d_in[1];
    const void*  lit_mask  = (const void*) d_in[2];
    const float* var_emb   = (const float*)d_in[3];
    const float* sign_emb  = (const float*)d_in[4];
    const float* litpos    = (const float*)d_in[5];
    const float* clausepos = (const float*)d_in[6];
    const float* enc_in_w  = (const float*)d_in[7];
    const float* enc_in_b  = (const float*)d_in[8];
    const float* enc_out_w = (const float*)d_in[9];
    const float* enc_out_b = (const float*)d_in[10];
    const float* enc_ff1_w = (const float*)d_in[11];
    const float* enc_ff1_b = (const float*)d_in[12];
    const float* enc_ff2_w = (const float*)d_in[13];
    const float* enc_ff2_b = (const float*)d_in[14];
    const float* n1w = (const float*)d_in[15];
    const float* n1b = (const float*)d_in[16];
    const float* n2w = (const float*)d_in[17];
    const float* n2b = (const float*)d_in[18];
    const float* th_ln_w = (const float*)d_in[19];
    const float* th_ln_b = (const float*)d_in[20];
    const float* th_w = (const float*)d_in[21];
    const float* th_b = (const float*)d_in[22];
    const float* pq   = (const float*)d_in[23];
    const float* pa_in_w  = (const float*)d_in[24];
    const float* pa_in_b  = (const float*)d_in[25];
    const float* pa_out_w = (const float*)d_in[26];
    const float* pa_out_b = (const float*)d_in[27];
    const float* pn_w = (const float*)d_in[28];
    const float* pn_b = (const float*)d_in[29];
    float* out = (float*)d_out;

    __half *x,*t0,*t1,*t2h,*ch,*kv,*qh,*S2h,*p1;
    float *S2,*p2;
    __half *hwin,*hwout,*hwf1,*hwf2,*hwth,*hwpa,*hwpo,*hwpq;
    cudaGetSymbolAddress((void**)&x,   g_x);
    cudaGetSymbolAddress((void**)&t0,  g_t0);
    cudaGetSymbolAddress((void**)&t1,  g_t1);
    cudaGetSymbolAddress((void**)&t2h, g_t2h);
    cudaGetSymbolAddress((void**)&ch,  g_ch);
    cudaGetSymbolAddress((void**)&kv,  g_kv);
    cudaGetSymbolAddress((void**)&qh,  g_qh);
    cudaGetSymbolAddress((void**)&S2,  g_S2);
    cudaGetSymbolAddress((void**)&S2h, g_S2h);
    cudaGetSymbolAddress((void**)&p1,  g_p1);
    cudaGetSymbolAddress((void**)&p2,  g_p2);
    cudaGetSymbolAddress((void**)&hwin,  g_hw_in);
    cudaGetSymbolAddress((void**)&hwout, g_hw_out);
    cudaGetSymbolAddress((void**)&hwf1,  g_hw_f1);
    cudaGetSymbolAddress((void**)&hwf2,  g_hw_f2);
    cudaGetSymbolAddress((void**)&hwth,  g_hw_th);
    cudaGetSymbolAddress((void**)&hwpa,  g_hw_pa);
    cudaGetSymbolAddress((void**)&hwpo,  g_hw_po);
    cudaGetSymbolAddress((void**)&hwpq,  g_hw_pq);

    cudaFuncSetAttribute(HG_B,  cudaFuncAttributeMaxDynamicSharedMemorySize, HG_SMEM);
    cudaFuncSetAttribute(HG_BF, cudaFuncAttributeMaxDynamicSharedMemorySize, HG_SMEM);
    cudaFuncSetAttribute(HG_G,  cudaFuncAttributeMaxDynamicSharedMemorySize, HG_SMEM);
    cudaFuncSetAttribute(HG_N,  cudaFuncAttributeMaxDynamicSharedMemorySize, HG_SMEM);

    const int M = BB*CC;
    const float escale = 0.17677669529663687f;   // 1/sqrt(32)
    const float pscale = 0.08838834764831845f;   // 1/sqrt(128)

    // ---- launch order: qkv(layer0) is the 6th launch (ncu -s 5 -c 1 target) ----
    cvh(enc_in_w,  hwin,  NLL*768*DD);                                   // 1
    detect_mask_kernel<<<16, 256>>>((const int*)lit_mask);               // 2
    pool_kernel<<<M, 256>>>(var_idx, sign_idx, lit_mask, var_emb,        // 3
                            sign_emb, litpos, clausepos, x);
    cvh(enc_out_w, hwout, NLL*DD*DD);                                    // 4
    cvh(enc_ff1_w, hwf1,  NLL*HH*DD);                                    // 5
    // layer-0 qkv (6th launch)
    HG_B<<<dim3(6,128,1),256,HG_SMEM>>>(x, hwin, enc_in_b, t0, M,768,DD,
                                        DD,DD,768, 1,0,0,0,0,0,0, 1.f);
    // remaining weight conversions
    cvh(enc_ff2_w, hwf2,  NLL*DD*HH);
    cvh(th_w,      hwth,  HH*DD);
    cvh(pa_in_w,   hwpa,  3*HH*HH);
    cvh(pa_out_w,  hwpo,  HH*HH);
    cvh(pq,        hwpq,  PP*HH);

    for (int i = 0; i < NLL; i++) {
        const __half* wqkv = hwin  + (size_t)i*768*DD;
        const float*  bqkv = enc_in_b  + (size_t)i*768;
        const __half* wo   = hwout + (size_t)i*DD*DD;
        const float*  bo   = enc_out_b + (size_t)i*DD;
        const __half* w1   = hwf1  + (size_t)i*HH*DD;
        const float*  b1   = enc_ff1_b + (size_t)i*HH;
        const __half* w2   = hwf2  + (size_t)i*DD*HH;
        const float*  b2   = enc_ff2_b + (size_t)i*DD;

        if (i > 0)
            HG_B<<<dim3(6,128,1),256,HG_SMEM>>>(x, wqkv, bqkv, t0, M,768,DD,
                                                DD,DD,768, 1,0,0,0,0,0,0, 1.f);
        // fused attention -> t1 half [M,256]
        fused_attn_h<<<dim3(4, BB*NHD), 256>>>(t0, t1, escale);
        // out proj -> t2h half
        HG_B<<<dim3(2,128,1),256,HG_SMEM>>>(t1, wo, bo, t2h, M,DD,DD,
                                            DD,DD,DD, 1,0,0,0,0,0,0, 1.f);
        ln_kernel<<<M,256>>>(t2h, 1, x, 2, n1w + i*DD, n1b + i*DD, x, 1, DD, 0);
        // ff1 gelu -> t0 half [M,1024]
        HG_G<<<dim3(8,128,1),256,HG_SMEM>>>(x, w1, b1, t0, M,HH,DD,
                                            DD,DD,HH, 1,0,0,0,0,0,0, 1.f);
        // ff2 -> t2h half
        HG_B<<<dim3(2,128,1),256,HG_SMEM>>>(t0, w2, b2, t2h, M,DD,HH,
                                            HH,HH,DD, 1,0,0,0,0,0,0, 1.f);
        ln_kernel<<<M,256>>>(t2h, 1, x, 2, n2w + i*DD, n2b + i*DD, x, 1, DD, 0);
    }

    // ch = LN(x) @ th_w^T + th_b  (half)
    ln_kernel<<<M,256>>>(x, 1, nullptr, 0, th_ln_w, th_ln_b, t2h, 1, DD, 0);
    HG_B<<<dim3(8,128,1),256,HG_SMEM>>>(t2h, hwth, th_b, ch, M,HH,DD,
                                        DD,DD,HH, 1,0,0,0,0,0,0, 1.f);

    // prefix cross-attention
    HG_B<<<dim3(8,1,1),256,HG_SMEM>>>(hwpq, hwpa, pa_in_b, qh, PP,HH,HH,
                                      HH,HH,HH, 1,0,0,0,0,0,0, 1.f);
    // merged K/V: kv[M,2048]
    HG_B<<<dim3(16,128,1),256,HG_SMEM>>>(ch, hwpa + (size_t)HH*HH, pa_in_b + HH, kv,
                                         M,2*HH,HH, HH,HH,2*HH, 1,0,0,0,0,0,0, 1.f);
    // scores2 per (b,h): [16,512], K=128 -> S2 float
    HG_N<<<dim3(4,1,BB*NHD),256,HG_SMEM>>>(qh, kv, nullptr, S2, PP,CC,128,
                                           HH,2*HH,CC, NHD,
                                           0L, 128L, (long)CC*2*HH, 128L,
                                           (long)NHD*PP*CC, (long)PP*CC, pscale);
    softmax_kernel<<<(BB*NHD*PP)/8, 256>>>(S2, S2h, CC);
    // AV2 -> p1 half
    av2h<<<dim3(4,1,BB*NHD),256>>>(S2h, kv, p1);
    // out proj -> p2 float
    HG_BF<<<dim3(8,4,1),256,HG_SMEM>>>(p1, hwpo, pa_out_b, p2, BB*PP,HH,HH,
                                       HH,HH,HH, 1,0,0,0,0,0,0, 1.f);
    // final LN: p2 + pq (fp32 residual, broadcast over batch) -> out fp32
    ln_kernel<<<BB*PP,256>>>(p2, 0, pq, 1, pn_w, pn_b, out, 0, HH, PP);
}

// round 12
// speedup vs baseline: 7.5583x; 1.2805x over previous
#include <cuda_runtime.h>
#include <cuda_fp16.h>
#include <cstdint>

#define BB 32
#define CC 512
#define LL 16
#define DD 256
#define HH 1024
#define PP 16
#define NHD 8
#define NLL 4

// ---------------- scratch (static device globals; allocation-free) ----------------
__device__ __half g_x  [BB*CC*DD];
__device__ __half g_t0 [BB*CC*HH];
__device__ __half g_t1 [BB*CC*DD];
__device__ __half g_t2h[BB*CC*DD];
__device__ __half g_ch [BB*CC*HH];
__device__ __half g_kv [BB*CC*2*HH];
__device__ __half g_qh [PP*HH];
__device__ float  g_S2 [BB*NHD*PP*CC];
__device__ __half g_S2h[BB*NHD*PP*CC];
__device__ __half g_p1 [BB*PP*HH];
__device__ float  g_p2 [BB*PP*HH];
__device__ int    g_maskmode;
// half weights
__device__ __half g_hw_in [NLL*768*DD];
__device__ __half g_hw_out[NLL*DD*DD];
__device__ __half g_hw_f1 [NLL*HH*DD];
__device__ __half g_hw_f2 [NLL*DD*HH];
__device__ __half g_hw_th [HH*DD];
__device__ __half g_hw_pa [3*HH*HH];
__device__ __half g_hw_po [HH*HH];
__device__ __half g_hw_pq [PP*HH];

// ---------------- small helpers ----------------
__device__ __forceinline__ uint32_t smem_u32(const void* p) {
    uint32_t a;
    asm("{ .reg .u64 t; cvta.to.shared.u64 t, %1; cvt.u32.u64 %0, t; }" : "=r"(a) : "l"(p));
    return a;
}
__device__ __forceinline__ float gelu_f(float v) {
    return 0.5f * v * (1.f + erff(v * 0.70710678118654752f));
}
__device__ __forceinline__ uint32_t packh2(float lo, float hi) {
    __half2 h = __floats2half2_rn(lo, hi);
    return *(uint32_t*)&h;
}
// non-volatile: pure register asm, lets ptxas interleave with LDSM
__device__ __forceinline__ void hmma16(float* c, const uint32_t* a, const uint32_t* b) {
    asm("mma.sync.aligned.m16n8k16.row.col.f32.f16.f16.f32 "
        "{%0,%1,%2,%3}, {%4,%5,%6,%7}, {%8,%9}, {%0,%1,%2,%3};"
        : "+f"(c[0]), "+f"(c[1]), "+f"(c[2]), "+f"(c[3])
        : "r"(a[0]), "r"(a[1]), "r"(a[2]), "r"(a[3]), "r"(b[0]), "r"(b[1]));
}
#define LDM_X4(r0, r1, r2, r3, addr) \
    asm volatile("ldmatrix.sync.aligned.m8n8.x4.shared.b16 {%0,%1,%2,%3}, [%4];" \
        : "=r"(r0), "=r"(r1), "=r"(r2), "=r"(r3) : "r"(addr))
#define LDM_X2(r0, r1, addr) \
    asm volatile("ldmatrix.sync.aligned.m8n8.x2.shared.b16 {%0,%1}, [%2];" \
        : "=r"(r0), "=r"(r1) : "r"(addr))
#define CPA16(dst, src, pred) \
    asm volatile("cp.async.cg.shared.global [%0], [%1], 16, %2;" \
                 :: "r"(dst), "l"(src), "r"((pred) ? 16 : 0))
#define CP_COMMIT() asm volatile("cp.async.commit_group;")
#define CP_WAIT1()  asm volatile("cp.async.wait_group 1;")
#define CP_WAIT0()  asm volatile("cp.async.wait_group 0;")

// ---------------- fp32 -> fp16 weight conversion ----------------
__global__ void cvt_h(const float* __restrict__ src, __half* __restrict__ dst, int n4) {
    int i = blockIdx.x * 256 + threadIdx.x;
    if (i < n4) {
        float4 v = ((const float4*)src)[i];
        uint2 u;
        u.x = packh2(v.x, v.y);
        u.y = packh2(v.z, v.w);
        ((uint2*)dst)[i] = u;
    }
}

// ============================ fp16 3-stage cp.async + ldmatrix GEMM ============================
template<int ACT, int HASB, int OUTH>
__global__ __launch_bounds__(256, 2) void hgemm(
    const __half* __restrict__ A, const __half* __restrict__ W,
    const float* __restrict__ bias, void* __restrict__ Cp,
    int M, int N, int K, int lda, int ldw, int ldc,
    int nsub, long sAb, long sAs, long sWb, long sWs, long sCb, long sCs,
    float alpha)
{
    constexpr int BM = 128, BN = 128, BK = 64, LDH = 72, NST = 3;
    constexpr uint32_t STB = BM * LDH * 2;
    extern __shared__ __half smh[];
    uint32_t base = smem_u32(smh);
    uint32_t asA = base;
    uint32_t wsA = base + NST * STB;

    int tid = threadIdx.x, wid = tid >> 5, lane = tid & 31;
    int warpM = wid >> 2, warpN = wid & 3;
    int g = lane >> 2, tg = lane & 3;
    int bm = blockIdx.y * BM, bn = blockIdx.x * BN;
    int z = blockIdx.z, zb = z / nsub, zs = z % nsub;
    const __half* Ab = A + (size_t)zb * sAb + (size_t)zs * sAs;
    const __half* Wb = W + (size_t)zb * sWb + (size_t)zs * sWs;

    int arow = (lane & 7) + ((lane & 8) ? 8 : 0);
    int acol = (lane & 16) ? 8 : 0;
    int brow = (lane & 7) + ((lane & 16) ? 8 : 0);
    int bcol = (lane & 8) ? 8 : 0;
    uint32_t aLane = (uint32_t)((warpM * 64 + arow) * LDH + acol) * 2;
    uint32_t bLane = (uint32_t)((warpN * 32 + brow) * LDH + bcol) * 2;

    auto load_stage = [&](int st, int k0) {
        uint32_t ab = asA + (uint32_t)st * STB;
        uint32_t wb = wsA + (uint32_t)st * STB;
        #pragma unroll
        for (int idx = tid; idx < BM * 8; idx += 256) {
            int row = idx >> 3, q = idx & 7;
            int gm = bm + row;
            bool ok = gm < M;
            int gmc = ok ? gm : 0;
            CPA16(ab + (uint32_t)(row * LDH + q * 8) * 2,
                  Ab + (size_t)gmc * lda + k0 + q * 8, ok);
        }
        #pragma unroll
        for (int idx = tid; idx < BN * 8; idx += 256) {
            int row = idx >> 3, q = idx & 7;
            CPA16(wb + (uint32_t)(row * LDH + q * 8) * 2,
                  Wb + (size_t)(bn + row) * ldw + k0 + q * 8, true);
        }
        CP_COMMIT();
    };

    float acc[4][4][4];
    #pragma unroll
    for (int i = 0; i < 4; i++)
        #pragma unroll
        for (int j = 0; j < 4; j++)
            #pragma unroll
            for (int q = 0; q < 4; q++) acc[i][j][q] = 0.f;

    int nk = K / BK;
    load_stage(0, 0);
    if (nk > 1) load_stage(1, BK);

    for (int i = 0; i < nk; i++) {
        if (i + 1 < nk) CP_WAIT1(); else CP_WAIT0();
        __syncthreads();
        if (i + 2 < nk) load_stage((i + 2) % NST, (i + 2) * BK);

        int cur = i % NST;
        uint32_t aB = asA + (uint32_t)cur * STB + aLane;
        uint32_t wB = wsA + (uint32_t)cur * STB + bLane;

        uint32_t af[2][4][4], bf[2][4][2];
        #pragma unroll
        for (int mi = 0; mi < 4; mi++)
            LDM_X4(af[0][mi][0], af[0][mi][1], af[0][mi][2], af[0][mi][3],
                   aB + (uint32_t)(mi * 16 * LDH) * 2);
        LDM_X4(bf[0][0][0], bf[0][0][1], bf[0][1][0], bf[0][1][1], wB);
        LDM_X4(bf[0][2][0], bf[0][2][1], bf[0][3][0], bf[0][3][1],
               wB + (uint32_t)(16 * LDH) * 2);

        #pragma unroll
        for (int ks = 0; ks < 4; ks++) {
            int cb = ks & 1, nb = cb ^ 1;
            if (ks < 3) {
                int kk = (ks + 1) * 16;
                #pragma unroll
                for (int mi = 0; mi < 4; mi++)
                    LDM_X4(af[nb][mi][0], af[nb][mi][1], af[nb][mi][2], af[nb][mi][3],
                           aB + (uint32_t)(mi * 16 * LDH + kk) * 2);
                LDM_X4(bf[nb][0][0], bf[nb][0][1], bf[nb][1][0], bf[nb][1][1],
                       wB + (uint32_t)kk * 2);
                LDM_X4(bf[nb][2][0], bf[nb][2][1], bf[nb][3][0], bf[nb][3][1],
                       wB + (uint32_t)(16 * LDH + kk) * 2);
            }
            #pragma unroll
            for (int mi = 0; mi < 4; mi++)
                #pragma unroll
                for (int nj = 0; nj < 4; nj++)
                    hmma16(acc[mi][nj], af[cb][mi], bf[cb][nj]);
        }
    }

    long cOff = (size_t)zb * sCb + (size_t)zs * sCs;
    #pragma unroll
    for (int mi = 0; mi < 4; mi++) {
        int r0 = bm + warpM * 64 + mi * 16 + g;
        #pragma unroll
        for (int nj = 0; nj < 4; nj++) {
            int c = bn + warpN * 32 + nj * 8 + 2 * tg;
            float b0 = 0.f, b1 = 0.f;
            if (HASB) { b0 = bias[c]; b1 = bias[c + 1]; }
            float v0 = acc[mi][nj][0] * alpha + b0;
            float v1 = acc[mi][nj][1] * alpha + b1;
            float v2 = acc[mi][nj][2] * alpha + b0;
            float v3 = acc[mi][nj][3] * alpha + b1;
            if (ACT) { v0 = gelu_f(v0); v1 = gelu_f(v1); v2 = gelu_f(v2); v3 = gelu_f(v3); }
            if (OUTH) {
                __half* Cb = (__half*)Cp + cOff;
                if (r0 < M)     *(uint32_t*)&Cb[(size_t)r0 * ldc + c]       = packh2(v0, v1);
                if (r0 + 8 < M) *(uint32_t*)&Cb[(size_t)(r0 + 8) * ldc + c] = packh2(v2, v3);
            } else {
                float* Cb = (float*)Cp + cOff;
                if (r0 < M)     { Cb[(size_t)r0 * ldc + c] = v0; Cb[(size_t)r0 * ldc + c + 1] = v1; }
                if (r0 + 8 < M) { Cb[(size_t)(r0 + 8) * ldc + c] = v2; Cb[(size_t)(r0 + 8) * ldc + c + 1] = v3; }
            }
        }
    }
}

// ============================ AV2 half kernel (prefix P@V) ============================
__global__ __launch_bounds__(256) void av2h(
    const __half* __restrict__ S2h, const __half* __restrict__ kvv,
    __half* __restrict__ p1)
{
    constexpr int BK = 64, LDH = 72;
    __shared__ __half As[128 * LDH];
    __shared__ __half Ws[32 * LDH];

    int tid = threadIdx.x, wid = tid >> 5, lane = tid & 31;
    int warpM = wid >> 2, warpN = wid & 3;
    int g = lane >> 2, tg = lane & 3;
    int z = blockIdx.z, b = z >> 3, h = z & 7;
    int bn = blockIdx.x * 32;
    const __half* Ab = S2h + (size_t)z * PP * CC;
    const __half* Vb = kvv + (size_t)b * CC * 2048 + HH + h * 128;
    __half* Cb = p1 + (size_t)b * PP * HH + h * 128;

    int arow = (lane & 7) + ((lane & 8) ? 8 : 0);
    int acol = (lane & 16) ? 8 : 0;
    uint32_t aLane = smem_u32(As) + (uint32_t)((warpM * 64 + arow) * LDH + acol) * 2;
    int brow = warpN * 8 + (lane & 7);
    int bcol = (lane & 8) ? 8 : 0;
    uint32_t bLane = smem_u32(Ws) + (uint32_t)(brow * LDH + bcol) * 2;

    float acc[4][4];
    #pragma unroll
    for (int i = 0; i < 4; i++)
        #pragma unroll
        for (int q = 0; q < 4; q++) acc[i][q] = 0.f;

    for (int k0 = 0; k0 < CC; k0 += BK) {
        __syncthreads();
        #pragma unroll
        for (int idx = tid; idx < 128 * 8; idx += 256) {
            int row = idx >> 3, q = idx & 7;
            int gm = (row < PP) ? row : 0;
            *(uint4*)&As[row * LDH + q * 8] =
                *(const uint4*)(Ab + (size_t)gm * CC + k0 + q * 8);
        }
        #pragma unroll
        for (int idx = tid; idx < 64 * 4; idx += 256) {
            int kk = idx >> 2, q = idx & 3;
            union { uint4 u; __half h[8]; } vv;
            vv.u = *(const uint4*)(Vb + (size_t)(k0 + kk) * 2048 + bn + q * 8);
            #pragma unroll
            for (int j = 0; j < 8; j++) Ws[(q * 8 + j) * LDH + kk] = vv.h[j];
        }
        __syncthreads();

        #pragma unroll
        for (int kk = 0; kk < BK; kk += 16) {
            uint32_t af[4][4], bf[2];
            #pragma unroll
            for (int mi = 0; mi < 4; mi++)
                LDM_X4(af[mi][0], af[mi][1], af[mi][2], af[mi][3],
                       aLane + (uint32_t)(mi * 16 * LDH + kk) * 2);
            LDM_X2(bf[0], bf[1], bLane + (uint32_t)kk * 2);
            #pragma unroll
            for (int mi = 0; mi < 4; mi++)
                hmma16(acc[mi], af[mi], bf);
        }
    }

    #pragma unroll
    for (int mi = 0; mi < 4; mi++) {
        int r0 = warpM * 64 + mi * 16 + g;
        int c = bn + warpN * 8 + 2 * tg;
        if (r0 < PP)     *(uint32_t*)&Cb[(size_t)r0 * HH + c]       = packh2(acc[mi][0], acc[mi][1]);
        if (r0 + 8 < PP) *(uint32_t*)&Cb[(size_t)(r0 + 8) * HH + c] = packh2(acc[mi][2], acc[mi][3]);
    }
}

// ============================ fused flash attention (fp16, h2exp2 softmax) ============================
__global__ __launch_bounds__(256) void fused_attn_h(
    const __half* __restrict__ qkv, __half* __restrict__ o, float escale)
{
    __shared__ __half Qs[128 * 40];
    __shared__ __half Ks[128 * 40];
    __shared__ __half Vs[32 * 136];

    int tid = threadIdx.x, lane = tid & 31, w = tid >> 5;
    int g = lane >> 2, tg = lane & 3;
    int qt = blockIdx.x;
    int z  = blockIdx.y;
    int b  = z >> 3, h = z & 7;
    const __half* base = qkv + (size_t)b * CC * 768;

    int arow = (lane & 7) + ((lane & 8) ? 8 : 0);
    int acol = (lane & 16) ? 8 : 0;
    int brow = (lane & 7) + ((lane & 16) ? 8 : 0);
    int bcol = (lane & 8) ? 8 : 0;
    uint32_t qBase = smem_u32(Qs) + (uint32_t)((w * 16 + arow) * 40 + acol) * 2;
    uint32_t kBase = smem_u32(Ks) + (uint32_t)(brow * 40 + bcol) * 2;
    uint32_t vBase = smem_u32(Vs) + (uint32_t)(brow * 136 + bcol) * 2;

    #pragma unroll
    for (int idx = tid; idx < 128 * 4; idx += 256) {
        int r = idx >> 2, q4 = idx & 3;
        *(uint4*)&Qs[r * 40 + q4 * 8] =
            *(const uint4*)(base + (size_t)(qt * 128 + r) * 768 + h * 32 + q4 * 8);
    }

    float oacc[4][4];
    #pragma unroll
    for (int i = 0; i < 4; i++)
        #pragma unroll
        for (int q = 0; q < 4; q++) oacc[i][q] = 0.f;
    float rm0 = -1e30f, rm1 = -1e30f, rs0 = 0.f, rs1 = 0.f;

    const float L2E = 1.4426950408889634f;

    for (int kt = 0; kt < 4; kt++) {
        __syncthreads();
        #pragma unroll
        for (int idx = tid; idx < 128 * 4; idx += 256) {
            int r = idx >> 2, q4 = idx & 3;
            const __half* kr = base + (size_t)(kt * 128 + r) * 768 + 256 + h * 32 + q4 * 8;
            *(uint4*)&Ks[r * 40 + q4 * 8] = *(const uint4*)kr;
            union { uint4 u; __half hh[8]; } vv;
            vv.u = *(const uint4*)(kr + 256);
            #pragma unroll
            for (int j = 0; j < 8; j++) Vs[(q4 * 8 + j) * 136 + r] = vv.hh[j];
        }
        __syncthreads();

        // ---- S = Q @ K^T ----
        float sacc[16][4];
        #pragma unroll
        for (int nj = 0; nj < 16; nj++)
            #pragma unroll
            for (int q = 0; q < 4; q++) sacc[nj][q] = 0.f;

        uint32_t af0[4], af1[4];
        LDM_X4(af0[0], af0[1], af0[2], af0[3], qBase);
        LDM_X4(af1[0], af1[1], af1[2], af1[3], qBase + 32u);
        uint32_t kbf[2][4];
        LDM_X4(kbf[0][0], kbf[0][1], kbf[0][2], kbf[0][3], kBase);
        #pragma unroll
        for (int t = 0; t < 16; t++) {
            int p8 = t >> 1;
            if (t < 15) {
                int tn = t + 1;
                int p8n = tn >> 1, kkn = (tn & 1) * 16;
                LDM_X4(kbf[tn & 1][0], kbf[tn & 1][1], kbf[tn & 1][2], kbf[tn & 1][3],
                       kBase + (uint32_t)(p8n * 16 * 40 + kkn) * 2);
            }
            const uint32_t* afc = (t & 1) ? af1 : af0;
            hmma16(sacc[2 * p8],     afc, kbf[t & 1]);
            hmma16(sacc[2 * p8 + 1], afc, kbf[t & 1] + 2);
        }

        // ---- online softmax (rows g and g+8), exp in fp16x2 ----
        float tm0 = -1e30f, tm1 = -1e30f;
        #pragma unroll
        for (int nj = 0; nj < 16; nj++) {
            tm0 = fmaxf(tm0, fmaxf(sacc[nj][0], sacc[nj][1]));
            tm1 = fmaxf(tm1, fmaxf(sacc[nj][2], sacc[nj][3]));
        }
        tm0 *= escale; tm1 *= escale;
        tm0 = fmaxf(tm0, __shfl_xor_sync(0xffffffffu, tm0, 1));
        tm0 = fmaxf(tm0, __shfl_xor_sync(0xffffffffu, tm0, 2));
        tm1 = fmaxf(tm1, __shfl_xor_sync(0xffffffffu, tm1, 1));
        tm1 = fmaxf(tm1, __shfl_xor_sync(0xffffffffu, tm1, 2));
        float nm0 = fmaxf(rm0, tm0), nm1 = fmaxf(rm1, tm1);
        float cr0 = __expf(rm0 - nm0), cr1 = __expf(rm1 - nm1);
        rm0 = nm0; rm1 = nm1;

        float se = escale * L2E;
        float c0 = -nm0 * L2E, c1 = -nm1 * L2E;
        float ps0 = 0.f, ps1 = 0.f;
        // sacc[nj][0] <- bits of half2(p0,p1); sacc[nj][1] <- bits of half2(p2,p3)
        #pragma unroll
        for (int nj = 0; nj < 16; nj++) {
            __half2 e01 = h2exp2(__floats2half2_rn(sacc[nj][0] * se + c0,
                                                   sacc[nj][1] * se + c0));
            __half2 e23 = h2exp2(__floats2half2_rn(sacc[nj][2] * se + c1,
                                                   sacc[nj][3] * se + c1));
            float2 f01 = __half22float2(e01);
            float2 f23 = __half22float2(e23);
            ps0 += f01.x + f01.y;
            ps1 += f23.x + f23.y;
            sacc[nj][0] = __uint_as_float(*(uint32_t*)&e01);
            sacc[nj][1] = __uint_as_float(*(uint32_t*)&e23);
        }
        ps0 += __shfl_xor_sync(0xffffffffu, ps0, 1);
        ps0 += __shfl_xor_sync(0xffffffffu, ps0, 2);
        ps1 += __shfl_xor_sync(0xffffffffu, ps1, 1);
        ps1 += __shfl_xor_sync(0xffffffffu, ps1, 2);
        rs0 = rs0 * cr0 + ps0;
        rs1 = rs1 * cr1 + ps1;
        #pragma unroll
        for (int vj = 0; vj < 4; vj++) {
            oacc[vj][0] *= cr0; oacc[vj][1] *= cr0;
            oacc[vj][2] *= cr1; oacc[vj][3] *= cr1;
        }

        // ---- O += P @ V (P already in half2 A-frag form) ----
        uint32_t pvb[2][4];
        LDM_X4(pvb[0][0], pvb[0][1], pvb[0][2], pvb[0][3], vBase);
        uint32_t a[4];
        #pragma unroll
        for (int t = 0; t < 16; t++) {
            int j2 = t >> 1, vp = t & 1;
            if (vp == 0) {
                a[0] = __float_as_uint(sacc[2 * j2][0]);
                a[1] = __float_as_uint(sacc[2 * j2][1]);
                a[2] = __float_as_uint(sacc[2 * j2 + 1][0]);
                a[3] = __float_as_uint(sacc[2 * j2 + 1][1]);
            }
            if (t < 15) {
                int tn = t + 1;
                int j2n = tn >> 1, vpn = tn & 1;
                LDM_X4(pvb[tn & 1][0], pvb[tn & 1][1], pvb[tn & 1][2], pvb[tn & 1][3],
                       vBase + (uint32_t)(vpn * 16 * 136 + j2n * 16) * 2);
            }
            hmma16(oacc[2 * vp],     a, pvb[t & 1]);
            hmma16(oacc[2 * vp + 1], a, pvb[t & 1] + 2);
        }
    }

    float inv0 = 1.f / rs0, inv1 = 1.f / rs1;
    int row0 = b * CC + qt * 128 + w * 16 + g;
    #pragma unroll
    for (int vj = 0; vj < 4; vj++) {
        int c = h * 32 + vj * 8 + 2 * tg;
        *(uint32_t*)&o[(size_t)row0 * 256 + c] =
            packh2(oacc[vj][0] * inv0, oacc[vj][1] * inv0);
        *(uint32_t*)&o[(size_t)(row0 + 8) * 256 + c] =
            packh2(oacc[vj][2] * inv1, oacc[vj][3] * inv1);
    }
}

// ---------------- mask dtype detection ----------------
__global__ void detect_mask_kernel(const int* __restrict__ m) {
    __shared__ int found;
    if (threadIdx.x == 0) found = 0;
    __syncthreads();
    int idx = blockIdx.x * blockDim.x + threadIdx.x;
    unsigned v = (unsigned)m[idx];
    if (v > 1u) found = 1;
    __syncthreads();
    if (threadIdx.x == 0 && blockIdx.x == 0) g_maskmode = 0;
    __threadfence();
    if (found) g_maskmode = 1;
}

// ---------------- pool (half output) ----------------
__global__ void pool_kernel(const int* __restrict__ vi, const int* __restrict__ si,
                            const void* __restrict__ maskraw,
                            const float* __restrict__ ve, const float* __restrict__ se,
                            const float* __restrict__ lpe, const float* __restrict__ cpe,
                            __half* __restrict__ x) {
    int bc = blockIdx.x;
    int c  = bc % CC;
    int d  = threadIdx.x;
    const int* viR = vi + bc * LL;
    const int* siR = si + bc * LL;
    __shared__ int mloc[LL];
    if (threadIdx.x < LL) {
        int mv;
        if (g_maskmode == 0) mv = ((const int*)maskraw)[bc * LL + threadIdx.x];
        else                 mv = ((const unsigned char*)maskraw)[bc * LL + threadIdx.x];
        mloc[threadIdx.x] = mv;
    }
    __syncthreads();
    float acc = 0.f; int cnt = 0;
    #pragma unroll
    for (int l = 0; l < LL; l++) {
        if (mloc[l]) {
            cnt++;
            acc += ve[viR[l]*DD + d] + se[siR[l]*DD + d] + lpe[l*DD + d];
        }
    }
    x[(size_t)bc*DD + d] = __float2half(acc / (float)cnt + cpe[c*DD + d]);
}

// ---------------- warp-per-row LN for N=256 half tensors ----------------
// out = LN(xin (+ res)) * w + b ; all data half, params fp32. grid*8 warps = rows.
template<int RES>
__global__ __launch_bounds__(256) void ln256(
    const __half* __restrict__ xin, const __half* __restrict__ res,
    const float* __restrict__ w, const float* __restrict__ b,
    __half* __restrict__ out)
{
    int row  = blockIdx.x * 8 + (threadIdx.x >> 5);
    int lane = threadIdx.x & 31;
    size_t off = (size_t)row * 256 + lane * 8;

    union { uint4 u; __half h[8]; } xv, rv;
    xv.u = *(const uint4*)(xin + off);
    if (RES) rv.u = *(const uint4*)(res + off);

    float v[8];
    float s = 0.f;
    #pragma unroll
    for (int j = 0; j < 8; j++) {
        float t = __half2float(xv.h[j]);
        if (RES) t += __half2float(rv.h[j]);
        v[j] = t; s += t;
    }
    #pragma unroll
    for (int o2 = 16; o2; o2 >>= 1) s += __shfl_xor_sync(0xffffffffu, s, o2);
    float mean = s * (1.f / 256.f);
    float vs = 0.f;
    #pragma unroll
    for (int j = 0; j < 8; j++) { float d = v[j] - mean; vs += d * d; }
    #pragma unroll
    for (int o2 = 16; o2; o2 >>= 1) vs += __shfl_xor_sync(0xffffffffu, vs, o2);
    float inv = rsqrtf(vs * (1.f / 256.f) + 1e-5f);

    float4 w0 = *(const float4*)(w + lane * 8);
    float4 w1 = *(const float4*)(w + lane * 8 + 4);
    float4 b0 = *(const float4*)(b + lane * 8);
    float4 b1 = *(const float4*)(b + lane * 8 + 4);
    float ww[8] = {w0.x, w0.y, w0.z, w0.w, w1.x, w1.y, w1.z, w1.w};
    float bb[8] = {b0.x, b0.y, b0.z, b0.w, b1.x, b1.y, b1.z, b1.w};

    union { uint4 u; __half h[8]; } ov;
    #pragma unroll
    for (int j = 0; j < 8; j++)
        ov.h[j] = __float2half((v[j] - mean) * inv * ww[j] + bb[j]);
    *(uint4*)(out + off) = ov.u;
}

// ---------------- generic layernorm (final N=1024 fp32 path) ----------------
__global__ void ln_kernel(const void* __restrict__ xin, int inH,
                          const void* __restrict__ res, int resM,
                          const float* __restrict__ w, const float* __restrict__ b,
                          void* __restrict__ out, int outH, int N, int resMod) {
    int row = blockIdx.x;
    int tid = threadIdx.x;
    int rrow = resMod ? (row % resMod) : row;
    int per = N >> 8;
    float v[4];
    float s = 0.f;
    for (int i = 0; i < per; i++) {
        int cI = tid + (i << 8);
        float t = inH ? __half2float(((const __half*)xin)[(size_t)row * N + cI])
                      : ((const float*)xin)[(size_t)row * N + cI];
        if (resM == 1)      t += ((const float*)res)[(size_t)rrow * N + cI];
        else if (resM == 2) t += __half2float(((const __half*)res)[(size_t)rrow * N + cI]);
        v[i] = t; s += t;
    }
    __shared__ float red[256];
    red[tid] = s; __syncthreads();
    for (int o = 128; o; o >>= 1) { if (tid < o) red[tid] += red[tid+o]; __syncthreads(); }
    float mean = red[0] / (float)N;
    __syncthreads();
    float vs = 0.f;
    for (int i = 0; i < per; i++) { float d = v[i] - mean; vs += d*d; }
    red[tid] = vs; __syncthreads();
    for (int o = 128; o; o >>= 1) { if (tid < o) red[tid] += red[tid+o]; __syncthreads(); }
    float inv = rsqrtf(red[0] / (float)N + 1e-5f);
    for (int i = 0; i < per; i++) {
        int cI = tid + (i << 8);
        float ov = (v[i] - mean) * inv * w[cI] + b[cI];
        if (outH) ((__half*)out)[(size_t)row*N + cI] = __float2half(ov);
        else      ((float*)out)[(size_t)row*N + cI] = ov;
    }
}

// ---------------- softmax (prefix path; fp32 in, half copy out) ----------------
__global__ void softmax_kernel(const float* __restrict__ S, __half* __restrict__ Sh, int cols) {
    int row  = blockIdx.x * 8 + (threadIdx.x >> 5);
    int lane = threadIdx.x & 31;
    const float* r = S + (size_t)row * cols;
    __half* rh = Sh + (size_t)row * cols;
    int per = cols >> 5;
    float vals[16];
    float mx = -1e30f;
    for (int t = 0; t < per; t++) { vals[t] = r[lane + (t<<5)]; mx = fmaxf(mx, vals[t]); }
    for (int o = 16; o; o >>= 1) mx = fmaxf(mx, __shfl_xor_sync(0xffffffffu, mx, o));
    float sum = 0.f;
    for (int t = 0; t < per; t++) { vals[t] = __expf(vals[t] - mx); sum += vals[t]; }
    for (int o = 16; o; o >>= 1) sum += __shfl_xor_sync(0xffffffffu, sum, o);
    float inv = 1.f / sum;
    for (int t = 0; t < per; t++) rh[lane + (t<<5)] = __float2half(vals[t] * inv);
}

// ============================ host orchestration ============================
#define HG_B   hgemm<0,1,1>
#define HG_BF  hgemm<0,1,0>
#define HG_G   hgemm<1,1,1>
#define HG_N   hgemm<0,0,0>

static const int HG_SMEM = 6 * 128 * 72 * 2;   // 110592 B

static void cvh(const float* src, __half* dst, int n) {
    cvt_h<<<(n/4 + 255)/256, 256>>>(src, dst, n/4);
}

extern "C" void kernel_launch(void* const* d_in, const int* in_sizes, int n_in,
                              void* d_out, int out_size) {
    const int*   var_idx   = (const int*)  d_in[0];
    const int*   sign_idx  = (const int*)  d_in[1];
    const void*  lit_mask  = (const void*) d_in[2];
    const float* var_emb   = (const float*)d_in[3];
    const float* sign_emb  = (const float*)d_in[4];
    const float* litpos    = (const float*)d_in[5];
    const float* clausepos = (const float*)d_in[6];
    const float* enc_in_w  = (const float*)d_in[7];
    const float* enc_in_b  = (const float*)d_in[8];
    const float* enc_out_w = (const float*)d_in[9];
    const float* enc_out_b = (const float*)d_in[10];
    const float* enc_ff1_w = (const float*)d_in[11];
    const float* enc_ff1_b = (const float*)d_in[12];
    const float* enc_ff2_w = (const float*)d_in[13];
    const float* enc_ff2_b = (const float*)d_in[14];
    const float* n1w = (const float*)d_in[15];
    const float* n1b = (const float*)d_in[16];
    const float* n2w = (const float*)d_in[17];
    const float* n2b = (const float*)d_in[18];
    const float* th_ln_w = (const float*)d_in[19];
    const float* th_ln_b = (const float*)d_in[20];
    const float* th_w = (const float*)d_in[21];
    const float* th_b = (const float*)d_in[22];
    const float* pq   = (const float*)d_in[23];
    const float* pa_in_w  = (const float*)d_in[24];
    const float* pa_in_b  = (const float*)d_in[25];
    const float* pa_out_w = (const float*)d_in[26];
    const float* pa_out_b = (const float*)d_in[27];
    const float* pn_w = (const float*)d_in[28];
    const float* pn_b = (const float*)d_in[29];
    float* out = (float*)d_out;

    __half *x,*t0,*t1,*t2h,*ch,*kv,*qh,*S2h,*p1;
    float *S2,*p2;
    __half *hwin,*hwout,*hwf1,*hwf2,*hwth,*hwpa,*hwpo,*hwpq;
    cudaGetSymbolAddress((void**)&x,   g_x);
    cudaGetSymbolAddress((void**)&t0,  g_t0);
    cudaGetSymbolAddress((void**)&t1,  g_t1);
    cudaGetSymbolAddress((void**)&t2h, g_t2h);
    cudaGetSymbolAddress((void**)&ch,  g_ch);
    cudaGetSymbolAddress((void**)&kv,  g_kv);
    cudaGetSymbolAddress((void**)&qh,  g_qh);
    cudaGetSymbolAddress((void**)&S2,  g_S2);
    cudaGetSymbolAddress((void**)&S2h, g_S2h);
    cudaGetSymbolAddress((void**)&p1,  g_p1);
    cudaGetSymbolAddress((void**)&p2,  g_p2);
    cudaGetSymbolAddress((void**)&hwin,  g_hw_in);
    cudaGetSymbolAddress((void**)&hwout, g_hw_out);
    cudaGetSymbolAddress((void**)&hwf1,  g_hw_f1);
    cudaGetSymbolAddress((void**)&hwf2,  g_hw_f2);
    cudaGetSymbolAddress((void**)&hwth,  g_hw_th);
    cudaGetSymbolAddress((void**)&hwpa,  g_hw_pa);
    cudaGetSymbolAddress((void**)&hwpo,  g_hw_po);
    cudaGetSymbolAddress((void**)&hwpq,  g_hw_pq);

    cudaFuncSetAttribute(HG_B,  cudaFuncAttributeMaxDynamicSharedMemorySize, HG_SMEM);
    cudaFuncSetAttribute(HG_BF, cudaFuncAttributeMaxDynamicSharedMemorySize, HG_SMEM);
    cudaFuncSetAttribute(HG_G,  cudaFuncAttributeMaxDynamicSharedMemorySize, HG_SMEM);
    cudaFuncSetAttribute(HG_N,  cudaFuncAttributeMaxDynamicSharedMemorySize, HG_SMEM);

    const int M = BB*CC;
    const float escale = 0.17677669529663687f;   // 1/sqrt(32)
    const float pscale = 0.08838834764831845f;   // 1/sqrt(128)

    cvh(enc_in_w,  hwin,  NLL*768*DD);
    detect_mask_kernel<<<16, 256>>>((const int*)lit_mask);
    pool_kernel<<<M, 256>>>(var_idx, sign_idx, lit_mask, var_emb,
                            sign_emb, litpos, clausepos, x);
    cvh(enc_out_w, hwout, NLL*DD*DD);
    cvh(enc_ff1_w, hwf1,  NLL*HH*DD);
    cvh(enc_ff2_w, hwf2,  NLL*DD*HH);
    cvh(th_w,      hwth,  HH*DD);
    cvh(pa_in_w,   hwpa,  3*HH*HH);
    cvh(pa_out_w,  hwpo,  HH*HH);
    cvh(pq,        hwpq,  PP*HH);

    for (int i = 0; i < NLL; i++) {
        const __half* wqkv = hwin  + (size_t)i*768*DD;
        const float*  bqkv = enc_in_b  + (size_t)i*768;
        const __half* wo   = hwout + (size_t)i*DD*DD;
        const float*  bo   = enc_out_b + (size_t)i*DD;
        const __half* w1   = hwf1  + (size_t)i*HH*DD;
        const float*  b1   = enc_ff1_b + (size_t)i*HH;
        const __half* w2   = hwf2  + (size_t)i*DD*HH;
        const float*  b2   = enc_ff2_b + (size_t)i*DD;

        HG_B<<<dim3(6,128,1),256,HG_SMEM>>>(x, wqkv, bqkv, t0, M,768,DD,
                                            DD,DD,768, 1,0,0,0,0,0,0, 1.f);
        fused_attn_h<<<dim3(4, BB*NHD), 256>>>(t0, t1, escale);
        HG_B<<<dim3(2,128,1),256,HG_SMEM>>>(t1, wo, bo, t2h, M,DD,DD,
                                            DD,DD,DD, 1,0,0,0,0,0,0, 1.f);
        ln256<1><<<M/8,256>>>(t2h, x, n1w + i*DD, n1b + i*DD, x);
        HG_G<<<dim3(8,128,1),256,HG_SMEM>>>(x, w1, b1, t0, M,HH,DD,
                                            DD,DD,HH, 1,0,0,0,0,0,0, 1.f);
        HG_B<<<dim3(2,128,1),256,HG_SMEM>>>(t0, w2, b2, t2h, M,DD,HH,
                                            HH,HH,DD, 1,0,0,0,0,0,0, 1.f);
        ln256<1><<<M/8,256>>>(t2h, x, n2w + i*DD, n2b + i*DD, x);
    }

    // ch = LN(x) @ th_w^T + th_b  (half)
    ln256<0><<<M/8,256>>>(x, nullptr, th_ln_w, th_ln_b, t2h);
    HG_B<<<dim3(8,128,1),256,HG_SMEM>>>(t2h, hwth, th_b, ch, M,HH,DD,
                                        DD,DD,HH, 1,0,0,0,0,0,0, 1.f);

    // prefix cross-attention
    HG_B<<<dim3(8,1,1),256,HG_SMEM>>>(hwpq, hwpa, pa_in_b, qh, PP,HH,HH,
                                      HH,HH,HH, 1,0,0,0,0,0,0, 1.f);
    HG_B<<<dim3(16,128,1),256,HG_SMEM>>>(ch, hwpa + (size_t)HH*HH, pa_in_b + HH, kv,
                                         M,2*HH,HH, HH,HH,2*HH, 1,0,0,0,0,0,0, 1.f);
    HG_N<<<dim3(4,1,BB*NHD),256,HG_SMEM>>>(qh, kv, nullptr, S2, PP,CC,128,
                                           HH,2*HH,CC, NHD,
                                           0L, 128L, (long)CC*2*HH, 128L,
                                           (long)NHD*PP*CC, (long)PP*CC, pscale);
    softmax_kernel<<<(BB*NHD*PP)/8, 256>>>(S2, S2h, CC);
    av2h<<<dim3(4,1,BB*NHD),256>>>(S2h, kv, p1);
    HG_BF<<<dim3(8,4,1),256,HG_SMEM>>>(p1, hwpo, pa_out_b, p2, BB*PP,HH,HH,
                                       HH,HH,HH, 1,0,0,0,0,0,0, 1.f);
    ln_kernel<<<BB*PP,256>>>(p2, 0, pq, 1, pn_w, pn_b, out, 0, HH, PP);
}

// round 13
// speedup vs baseline: 7.7647x; 1.0273x over previous
#include <cuda_runtime.h>
#include <cuda_fp16.h>
#include <cstdint>

#define BB 32
#define CC 512
#define LL 16
#define DD 256
#define HH 1024
#define PP 16
#define NHD 8
#define NLL 4

// ---------------- scratch (static device globals; allocation-free) ----------------
__device__ __half g_x  [BB*CC*DD];
__device__ __half g_t0 [BB*CC*HH];
__device__ __half g_t1 [BB*CC*DD];
__device__ __half g_t2h[BB*CC*DD];
__device__ __half g_ch [BB*CC*HH];
__device__ __half g_kv [BB*CC*2*HH];
__device__ __half g_qh [PP*HH];
__device__ float  g_S2 [BB*NHD*PP*CC];
__device__ __half g_S2h[BB*NHD*PP*CC];
__device__ __half g_p1 [BB*PP*HH];
__device__ float  g_p2 [BB*PP*HH];
__device__ int    g_maskmode;
// half weights
__device__ __half g_hw_in [NLL*768*DD];
__device__ __half g_hw_out[NLL*DD*DD];
__device__ __half g_hw_f1 [NLL*HH*DD];
__device__ __half g_hw_f2 [NLL*DD*HH];
__device__ __half g_hw_th [HH*DD];
__device__ __half g_hw_pa [3*HH*HH];
__device__ __half g_hw_po [HH*HH];
__device__ __half g_hw_pq [PP*HH];

// ---------------- small helpers ----------------
__device__ __forceinline__ uint32_t smem_u32(const void* p) {
    uint32_t a;
    asm("{ .reg .u64 t; cvta.to.shared.u64 t, %1; cvt.u32.u64 %0, t; }" : "=r"(a) : "l"(p));
    return a;
}
__device__ __forceinline__ float gelu_f(float v) {
    return 0.5f * v * (1.f + erff(v * 0.70710678118654752f));
}
__device__ __forceinline__ uint32_t packh2(float lo, float hi) {
    __half2 h = __floats2half2_rn(lo, hi);
    return *(uint32_t*)&h;
}
// non-volatile: pure register asm, lets ptxas interleave with LDSM
__device__ __forceinline__ void hmma16(float* c, const uint32_t* a, const uint32_t* b) {
    asm("mma.sync.aligned.m16n8k16.row.col.f32.f16.f16.f32 "
        "{%0,%1,%2,%3}, {%4,%5,%6,%7}, {%8,%9}, {%0,%1,%2,%3};"
        : "+f"(c[0]), "+f"(c[1]), "+f"(c[2]), "+f"(c[3])
        : "r"(a[0]), "r"(a[1]), "r"(a[2]), "r"(a[3]), "r"(b[0]), "r"(b[1]));
}
#define LDM_X4(r0, r1, r2, r3, addr) \
    asm volatile("ldmatrix.sync.aligned.m8n8.x4.shared.b16 {%0,%1,%2,%3}, [%4];" \
        : "=r"(r0), "=r"(r1), "=r"(r2), "=r"(r3) : "r"(addr))
#define LDM_X2(r0, r1, addr) \
    asm volatile("ldmatrix.sync.aligned.m8n8.x2.shared.b16 {%0,%1}, [%2];" \
        : "=r"(r0), "=r"(r1) : "r"(addr))
#define CPA16(dst, src, pred) \
    asm volatile("cp.async.cg.shared.global [%0], [%1], 16, %2;" \
                 :: "r"(dst), "l"(src), "r"((pred) ? 16 : 0))
#define CP_COMMIT() asm volatile("cp.async.commit_group;")
#define CP_WAIT1()  asm volatile("cp.async.wait_group 1;")
#define CP_WAIT0()  asm volatile("cp.async.wait_group 0;")

// ---------------- fp32 -> fp16 weight conversion ----------------
__global__ void cvt_h(const float* __restrict__ src, __half* __restrict__ dst, int n4) {
    int i = blockIdx.x * 256 + threadIdx.x;
    if (i < n4) {
        float4 v = ((const float4*)src)[i];
        uint2 u;
        u.x = packh2(v.x, v.y);
        u.y = packh2(v.z, v.w);
        ((uint2*)dst)[i] = u;
    }
}

// ============================ fp16 3-stage cp.async + ldmatrix GEMM ============================
template<int ACT, int HASB, int OUTH>
__global__ __launch_bounds__(256, 2) void hgemm(
    const __half* __restrict__ A, const __half* __restrict__ W,
    const float* __restrict__ bias, void* __restrict__ Cp,
    int M, int N, int K, int lda, int ldw, int ldc,
    int nsub, long sAb, long sAs, long sWb, long sWs, long sCb, long sCs,
    float alpha)
{
    constexpr int BM = 128, BN = 128, BK = 64, LDH = 72, NST = 3;
    constexpr uint32_t STB = BM * LDH * 2;
    extern __shared__ __half smh[];
    uint32_t base = smem_u32(smh);
    uint32_t asA = base;
    uint32_t wsA = base + NST * STB;

    int tid = threadIdx.x, wid = tid >> 5, lane = tid & 31;
    int warpM = wid >> 2, warpN = wid & 3;
    int g = lane >> 2, tg = lane & 3;
    int bm = blockIdx.y * BM, bn = blockIdx.x * BN;
    int z = blockIdx.z, zb = z / nsub, zs = z % nsub;
    const __half* Ab = A + (size_t)zb * sAb + (size_t)zs * sAs;
    const __half* Wb = W + (size_t)zb * sWb + (size_t)zs * sWs;

    int arow = (lane & 7) + ((lane & 8) ? 8 : 0);
    int acol = (lane & 16) ? 8 : 0;
    int brow = (lane & 7) + ((lane & 16) ? 8 : 0);
    int bcol = (lane & 8) ? 8 : 0;
    uint32_t aLane = (uint32_t)((warpM * 64 + arow) * LDH + acol) * 2;
    uint32_t bLane = (uint32_t)((warpN * 32 + brow) * LDH + bcol) * 2;

    auto load_stage = [&](int st, int k0) {
        uint32_t ab = asA + (uint32_t)st * STB;
        uint32_t wb = wsA + (uint32_t)st * STB;
        #pragma unroll
        for (int idx = tid; idx < BM * 8; idx += 256) {
            int row = idx >> 3, q = idx & 7;
            int gm = bm + row;
            bool ok = gm < M;
            int gmc = ok ? gm : 0;
            CPA16(ab + (uint32_t)(row * LDH + q * 8) * 2,
                  Ab + (size_t)gmc * lda + k0 + q * 8, ok);
        }
        #pragma unroll
        for (int idx = tid; idx < BN * 8; idx += 256) {
            int row = idx >> 3, q = idx & 7;
            CPA16(wb + (uint32_t)(row * LDH + q * 8) * 2,
                  Wb + (size_t)(bn + row) * ldw + k0 + q * 8, true);
        }
        CP_COMMIT();
    };

    float acc[4][4][4];
    #pragma unroll
    for (int i = 0; i < 4; i++)
        #pragma unroll
        for (int j = 0; j < 4; j++)
            #pragma unroll
            for (int q = 0; q < 4; q++) acc[i][j][q] = 0.f;

    int nk = K / BK;
    load_stage(0, 0);
    if (nk > 1) load_stage(1, BK);

    for (int i = 0; i < nk; i++) {
        if (i + 1 < nk) CP_WAIT1(); else CP_WAIT0();
        __syncthreads();
        if (i + 2 < nk) load_stage((i + 2) % NST, (i + 2) * BK);

        int cur = i % NST;
        uint32_t aB = asA + (uint32_t)cur * STB + aLane;
        uint32_t wB = wsA + (uint32_t)cur * STB + bLane;

        uint32_t af[2][4][4], bf[2][4][2];
        #pragma unroll
        for (int mi = 0; mi < 4; mi++)
            LDM_X4(af[0][mi][0], af[0][mi][1], af[0][mi][2], af[0][mi][3],
                   aB + (uint32_t)(mi * 16 * LDH) * 2);
        LDM_X4(bf[0][0][0], bf[0][0][1], bf[0][1][0], bf[0][1][1], wB);
        LDM_X4(bf[0][2][0], bf[0][2][1], bf[0][3][0], bf[0][3][1],
               wB + (uint32_t)(16 * LDH) * 2);

        #pragma unroll
        for (int ks = 0; ks < 4; ks++) {
            int cb = ks & 1, nb = cb ^ 1;
            if (ks < 3) {
                int kk = (ks + 1) * 16;
                #pragma unroll
                for (int mi = 0; mi < 4; mi++)
                    LDM_X4(af[nb][mi][0], af[nb][mi][1], af[nb][mi][2], af[nb][mi][3],
                           aB + (uint32_t)(mi * 16 * LDH + kk) * 2);
                LDM_X4(bf[nb][0][0], bf[nb][0][1], bf[nb][1][0], bf[nb][1][1],
                       wB + (uint32_t)kk * 2);
                LDM_X4(bf[nb][2][0], bf[nb][2][1], bf[nb][3][0], bf[nb][3][1],
                       wB + (uint32_t)(16 * LDH + kk) * 2);
            }
            #pragma unroll
            for (int mi = 0; mi < 4; mi++)
                #pragma unroll
                for (int nj = 0; nj < 4; nj++)
                    hmma16(acc[mi][nj], af[cb][mi], bf[cb][nj]);
        }
    }

    long cOff = (size_t)zb * sCb + (size_t)zs * sCs;
    #pragma unroll
    for (int mi = 0; mi < 4; mi++) {
        int r0 = bm + warpM * 64 + mi * 16 + g;
        #pragma unroll
        for (int nj = 0; nj < 4; nj++) {
            int c = bn + warpN * 32 + nj * 8 + 2 * tg;
            float b0 = 0.f, b1 = 0.f;
            if (HASB) { b0 = bias[c]; b1 = bias[c + 1]; }
            float v0 = acc[mi][nj][0] * alpha + b0;
            float v1 = acc[mi][nj][1] * alpha + b1;
            float v2 = acc[mi][nj][2] * alpha + b0;
            float v3 = acc[mi][nj][3] * alpha + b1;
            if (ACT) { v0 = gelu_f(v0); v1 = gelu_f(v1); v2 = gelu_f(v2); v3 = gelu_f(v3); }
            if (OUTH) {
                __half* Cb = (__half*)Cp + cOff;
                if (r0 < M)     *(uint32_t*)&Cb[(size_t)r0 * ldc + c]       = packh2(v0, v1);
                if (r0 + 8 < M) *(uint32_t*)&Cb[(size_t)(r0 + 8) * ldc + c] = packh2(v2, v3);
            } else {
                float* Cb = (float*)Cp + cOff;
                if (r0 < M)     { Cb[(size_t)r0 * ldc + c] = v0; Cb[(size_t)r0 * ldc + c + 1] = v1; }
                if (r0 + 8 < M) { Cb[(size_t)(r0 + 8) * ldc + c] = v2; Cb[(size_t)(r0 + 8) * ldc + c + 1] = v3; }
            }
        }
    }
}

// ============================ AV2 half kernel (prefix P@V) ============================
__global__ __launch_bounds__(256) void av2h(
    const __half* __restrict__ S2h, const __half* __restrict__ kvv,
    __half* __restrict__ p1)
{
    constexpr int BK = 64, LDH = 72;
    __shared__ __half As[128 * LDH];
    __shared__ __half Ws[32 * LDH];

    int tid = threadIdx.x, wid = tid >> 5, lane = tid & 31;
    int warpM = wid >> 2, warpN = wid & 3;
    int g = lane >> 2, tg = lane & 3;
    int z = blockIdx.z, b = z >> 3, h = z & 7;
    int bn = blockIdx.x * 32;
    const __half* Ab = S2h + (size_t)z * PP * CC;
    const __half* Vb = kvv + (size_t)b * CC * 2048 + HH + h * 128;
    __half* Cb = p1 + (size_t)b * PP * HH + h * 128;

    int arow = (lane & 7) + ((lane & 8) ? 8 : 0);
    int acol = (lane & 16) ? 8 : 0;
    uint32_t aLane = smem_u32(As) + (uint32_t)((warpM * 64 + arow) * LDH + acol) * 2;
    int brow = warpN * 8 + (lane & 7);
    int bcol = (lane & 8) ? 8 : 0;
    uint32_t bLane = smem_u32(Ws) + (uint32_t)(brow * LDH + bcol) * 2;

    float acc[4][4];
    #pragma unroll
    for (int i = 0; i < 4; i++)
        #pragma unroll
        for (int q = 0; q < 4; q++) acc[i][q] = 0.f;

    for (int k0 = 0; k0 < CC; k0 += BK) {
        __syncthreads();
        #pragma unroll
        for (int idx = tid; idx < 128 * 8; idx += 256) {
            int row = idx >> 3, q = idx & 7;
            int gm = (row < PP) ? row : 0;
            *(uint4*)&As[row * LDH + q * 8] =
                *(const uint4*)(Ab + (size_t)gm * CC + k0 + q * 8);
        }
        #pragma unroll
        for (int idx = tid; idx < 64 * 4; idx += 256) {
            int kk = idx >> 2, q = idx & 3;
            union { uint4 u; __half h[8]; } vv;
            vv.u = *(const uint4*)(Vb + (size_t)(k0 + kk) * 2048 + bn + q * 8);
            #pragma unroll
            for (int j = 0; j < 8; j++) Ws[(q * 8 + j) * LDH + kk] = vv.h[j];
        }
        __syncthreads();

        #pragma unroll
        for (int kk = 0; kk < BK; kk += 16) {
            uint32_t af[4][4], bf[2];
            #pragma unroll
            for (int mi = 0; mi < 4; mi++)
                LDM_X4(af[mi][0], af[mi][1], af[mi][2], af[mi][3],
                       aLane + (uint32_t)(mi * 16 * LDH + kk) * 2);
            LDM_X2(bf[0], bf[1], bLane + (uint32_t)kk * 2);
            #pragma unroll
            for (int mi = 0; mi < 4; mi++)
                hmma16(acc[mi], af[mi], bf);
        }
    }

    #pragma unroll
    for (int mi = 0; mi < 4; mi++) {
        int r0 = warpM * 64 + mi * 16 + g;
        int c = bn + warpN * 8 + 2 * tg;
        if (r0 < PP)     *(uint32_t*)&Cb[(size_t)r0 * HH + c]       = packh2(acc[mi][0], acc[mi][1]);
        if (r0 + 8 < PP) *(uint32_t*)&Cb[(size_t)(r0 + 8) * HH + c] = packh2(acc[mi][2], acc[mi][3]);
    }
}

// ============================ fused flash attention (no-max, fused S->exp->PV) ============
// Vs rows 0..31 = V (transposed [d][key]); row 32 = ones, rows 33..39 = 0 (denominator trick).
__global__ __launch_bounds__(256) void fused_attn_h(
    const __half* __restrict__ qkv, __half* __restrict__ o, float escale)
{
    __shared__ __half Qs[128 * 40];
    __shared__ __half Ks[128 * 40];
    __shared__ __half Vs[40 * 136];

    int tid = threadIdx.x, lane = tid & 31, w = tid >> 5;
    int g = lane >> 2, tg = lane & 3;
    int qt = blockIdx.x;
    int z  = blockIdx.y;
    int b  = z >> 3, h = z & 7;
    const __half* base = qkv + (size_t)b * CC * 768;

    int arow = (lane & 7) + ((lane & 8) ? 8 : 0);
    int acol = (lane & 16) ? 8 : 0;
    int brow = (lane & 7) + ((lane & 16) ? 8 : 0);
    int bcol = (lane & 8) ? 8 : 0;
    uint32_t qBase = smem_u32(Qs) + (uint32_t)((w * 16 + arow) * 40 + acol) * 2;
    uint32_t kBase = smem_u32(Ks) + (uint32_t)(brow * 40 + bcol) * 2;
    uint32_t vBase = smem_u32(Vs) + (uint32_t)(brow * 136 + bcol) * 2;
    // ones B-frag address: n-rows 32..39, k 0..15 (content k-independent)
    uint32_t onesAddr = smem_u32(Vs) +
        (uint32_t)((32 + (lane & 7)) * 136 + ((lane & 8) ? 8 : 0)) * 2;

    // load Q tile + init ones rows
    #pragma unroll
    for (int idx = tid; idx < 128 * 4; idx += 256) {
        int r = idx >> 2, q4 = idx & 3;
        *(uint4*)&Qs[r * 40 + q4 * 8] =
            *(const uint4*)(base + (size_t)(qt * 128 + r) * 768 + h * 32 + q4 * 8);
    }
    for (int idx = tid; idx < 8 * 136; idx += 256) {
        int r = 32 + idx / 136, c = idx % 136;
        Vs[r * 136 + c] = (r == 32) ? __float2half(1.f) : __float2half(0.f);
    }

    float oacc[4][4];
    #pragma unroll
    for (int i = 0; i < 4; i++)
        #pragma unroll
        for (int q = 0; q < 4; q++) oacc[i][q] = 0.f;
    float smsum[4] = {0.f, 0.f, 0.f, 0.f};

    const float se = escale * 1.4426950408889634f;   // scale * log2(e)

    uint32_t bones[2];
    bool onesLoaded = false;

    for (int kt = 0; kt < 4; kt++) {
        __syncthreads();
        #pragma unroll
        for (int idx = tid; idx < 128 * 4; idx += 256) {
            int r = idx >> 2, q4 = idx & 3;
            const __half* kr = base + (size_t)(kt * 128 + r) * 768 + 256 + h * 32 + q4 * 8;
            *(uint4*)&Ks[r * 40 + q4 * 8] = *(const uint4*)kr;
            union { uint4 u; __half hh[8]; } vv;
            vv.u = *(const uint4*)(kr + 256);
            #pragma unroll
            for (int j = 0; j < 8; j++) Vs[(q4 * 8 + j) * 136 + r] = vv.hh[j];
        }
        __syncthreads();
        if (!onesLoaded) { LDM_X2(bones[0], bones[1], onesAddr); onesLoaded = true; }

        uint32_t af0[4], af1[4];
        LDM_X4(af0[0], af0[1], af0[2], af0[3], qBase);
        LDM_X4(af1[0], af1[1], af1[2], af1[3], qBase + 32u);

        #pragma unroll
        for (int p8 = 0; p8 < 8; p8++) {
            // ---- S block: rows (g,g+8) x 16 keys ----
            uint32_t kb0[4], kb1[4];
            LDM_X4(kb0[0], kb0[1], kb0[2], kb0[3],
                   kBase + (uint32_t)(p8 * 16 * 40) * 2);
            LDM_X4(kb1[0], kb1[1], kb1[2], kb1[3],
                   kBase + (uint32_t)(p8 * 16 * 40 + 16) * 2);
            float sl[4] = {0.f, 0.f, 0.f, 0.f};
            float sh[4] = {0.f, 0.f, 0.f, 0.f};
            hmma16(sl, af0, kb0);
            hmma16(sh, af0, kb0 + 2);
            hmma16(sl, af1, kb1);
            hmma16(sh, af1, kb1 + 2);

            // ---- P = exp2(S * se), directly in A-frag layout ----
            uint32_t a[4];
            {
                __half2 e;
                e = h2exp2(__floats2half2_rn(sl[0] * se, sl[1] * se)); a[0] = *(uint32_t*)&e;
                e = h2exp2(__floats2half2_rn(sl[2] * se, sl[3] * se)); a[1] = *(uint32_t*)&e;
                e = h2exp2(__floats2half2_rn(sh[0] * se, sh[1] * se)); a[2] = *(uint32_t*)&e;
                e = h2exp2(__floats2half2_rn(sh[2] * se, sh[3] * se)); a[3] = *(uint32_t*)&e;
            }

            // ---- O += P @ V, denom += P @ ones ----
            uint32_t v0[4], v1[4];
            LDM_X4(v0[0], v0[1], v0[2], v0[3],
                   vBase + (uint32_t)(p8 * 16) * 2);
            LDM_X4(v1[0], v1[1], v1[2], v1[3],
                   vBase + (uint32_t)(16 * 136 + p8 * 16) * 2);
            hmma16(oacc[0], a, v0);
            hmma16(oacc[1], a, v0 + 2);
            hmma16(oacc[2], a, v1);
            hmma16(oacc[3], a, v1 + 2);
            hmma16(smsum, a, bones);
        }
    }

    // row sums live in col 32 (= n-block col 0) -> tg==0 threads; broadcast within quad
    float rs0 = __shfl_sync(0xffffffffu, smsum[0], lane & ~3);
    float rs1 = __shfl_sync(0xffffffffu, smsum[2], lane & ~3);
    float inv0 = 1.f / rs0, inv1 = 1.f / rs1;
    int row0 = b * CC + qt * 128 + w * 16 + g;
    #pragma unroll
    for (int vj = 0; vj < 4; vj++) {
        int c = h * 32 + vj * 8 + 2 * tg;
        *(uint32_t*)&o[(size_t)row0 * 256 + c] =
            packh2(oacc[vj][0] * inv0, oacc[vj][1] * inv0);
        *(uint32_t*)&o[(size_t)(row0 + 8) * 256 + c] =
            packh2(oacc[vj][2] * inv1, oacc[vj][3] * inv1);
    }
}

// ---------------- mask dtype detection ----------------
__global__ void detect_mask_kernel(const int* __restrict__ m) {
    __shared__ int found;
    if (threadIdx.x == 0) found = 0;
    __syncthreads();
    int idx = blockIdx.x * blockDim.x + threadIdx.x;
    unsigned v = (unsigned)m[idx];
    if (v > 1u) found = 1;
    __syncthreads();
    if (threadIdx.x == 0 && blockIdx.x == 0) g_maskmode = 0;
    __threadfence();
    if (found) g_maskmode = 1;
}

// ---------------- pool (half output) ----------------
__global__ void pool_kernel(const int* __restrict__ vi, const int* __restrict__ si,
                            const void* __restrict__ maskraw,
                            const float* __restrict__ ve, const float* __restrict__ se,
                            const float* __restrict__ lpe, const float* __restrict__ cpe,
                            __half* __restrict__ x) {
    int bc = blockIdx.x;
    int c  = bc % CC;
    int d  = threadIdx.x;
    const int* viR = vi + bc * LL;
    const int* siR = si + bc * LL;
    __shared__ int mloc[LL];
    if (threadIdx.x < LL) {
        int mv;
        if (g_maskmode == 0) mv = ((const int*)maskraw)[bc * LL + threadIdx.x];
        else                 mv = ((const unsigned char*)maskraw)[bc * LL + threadIdx.x];
        mloc[threadIdx.x] = mv;
    }
    __syncthreads();
    float acc = 0.f; int cnt = 0;
    #pragma unroll
    for (int l = 0; l < LL; l++) {
        if (mloc[l]) {
            cnt++;
            acc += ve[viR[l]*DD + d] + se[siR[l]*DD + d] + lpe[l*DD + d];
        }
    }
    x[(size_t)bc*DD + d] = __float2half(acc / (float)cnt + cpe[c*DD + d]);
}

// ---------------- warp-per-row LN for N=256 half tensors ----------------
template<int RES>
__global__ __launch_bounds__(256) void ln256(
    const __half* __restrict__ xin, const __half* __restrict__ res,
    const float* __restrict__ w, const float* __restrict__ b,
    __half* __restrict__ out)
{
    int row  = blockIdx.x * 8 + (threadIdx.x >> 5);
    int lane = threadIdx.x & 31;
    size_t off = (size_t)row * 256 + lane * 8;

    union { uint4 u; __half h[8]; } xv, rv;
    xv.u = *(const uint4*)(xin + off);
    if (RES) rv.u = *(const uint4*)(res + off);

    float v[8];
    float s = 0.f;
    #pragma unroll
    for (int j = 0; j < 8; j++) {
        float t = __half2float(xv.h[j]);
        if (RES) t += __half2float(rv.h[j]);
        v[j] = t; s += t;
    }
    #pragma unroll
    for (int o2 = 16; o2; o2 >>= 1) s += __shfl_xor_sync(0xffffffffu, s, o2);
    float mean = s * (1.f / 256.f);
    float vs = 0.f;
    #pragma unroll
    for (int j = 0; j < 8; j++) { float d = v[j] - mean; vs += d * d; }
    #pragma unroll
    for (int o2 = 16; o2; o2 >>= 1) vs += __shfl_xor_sync(0xffffffffu, vs, o2);
    float inv = rsqrtf(vs * (1.f / 256.f) + 1e-5f);

    float4 w0 = *(const float4*)(w + lane * 8);
    float4 w1 = *(const float4*)(w + lane * 8 + 4);
    float4 b0 = *(const float4*)(b + lane * 8);
    float4 b1 = *(const float4*)(b + lane * 8 + 4);
    float ww[8] = {w0.x, w0.y, w0.z, w0.w, w1.x, w1.y, w1.z, w1.w};
    float bb[8] = {b0.x, b0.y, b0.z, b0.w, b1.x, b1.y, b1.z, b1.w};

    union { uint4 u; __half h[8]; } ov;
    #pragma unroll
    for (int j = 0; j < 8; j++)
        ov.h[j] = __float2half((v[j] - mean) * inv * ww[j] + bb[j]);
    *(uint4*)(out + off) = ov.u;
}

// ---------------- generic layernorm (final N=1024 fp32 path) ----------------
__global__ void ln_kernel(const void* __restrict__ xin, int inH,
                          const void* __restrict__ res, int resM,
                          const float* __restrict__ w, const float* __restrict__ b,
                          void* __restrict__ out, int outH, int N, int resMod) {
    int row = blockIdx.x;
    int tid = threadIdx.x;
    int rrow = resMod ? (row % resMod) : row;
    int per = N >> 8;
    float v[4];
    float s = 0.f;
    for (int i = 0; i < per; i++) {
        int cI = tid + (i << 8);
        float t = inH ? __half2float(((const __half*)xin)[(size_t)row * N + cI])
                      : ((const float*)xin)[(size_t)row * N + cI];
        if (resM == 1)      t += ((const float*)res)[(size_t)rrow * N + cI];
        else if (resM == 2) t += __half2float(((const __half*)res)[(size_t)rrow * N + cI]);
        v[i] = t; s += t;
    }
    __shared__ float red[256];
    red[tid] = s; __syncthreads();
    for (int o = 128; o; o >>= 1) { if (tid < o) red[tid] += red[tid+o]; __syncthreads(); }
    float mean = red[0] / (float)N;
    __syncthreads();
    float vs = 0.f;
    for (int i = 0; i < per; i++) { float d = v[i] - mean; vs += d*d; }
    red[tid] = vs; __syncthreads();
    for (int o = 128; o; o >>= 1) { if (tid < o) red[tid] += red[tid+o]; __syncthreads(); }
    float inv = rsqrtf(red[0] / (float)N + 1e-5f);
    for (int i = 0; i < per; i++) {
        int cI = tid + (i << 8);
        float ov = (v[i] - mean) * inv * w[cI] + b[cI];
        if (outH) ((__half*)out)[(size_t)row*N + cI] = __float2half(ov);
        else      ((float*)out)[(size_t)row*N + cI] = ov;
    }
}

// ---------------- softmax (prefix path; fp32 in, half copy out) ----------------
__global__ void softmax_kernel(const float* __restrict__ S, __half* __restrict__ Sh, int cols) {
    int row  = blockIdx.x * 8 + (threadIdx.x >> 5);
    int lane = threadIdx.x & 31;
    const float* r = S + (size_t)row * cols;
    __half* rh = Sh + (size_t)row * cols;
    int per = cols >> 5;
    float vals[16];
    float mx = -1e30f;
    for (int t = 0; t < per; t++) { vals[t] = r[lane + (t<<5)]; mx = fmaxf(mx, vals[t]); }
    for (int o = 16; o; o >>= 1) mx = fmaxf(mx, __shfl_xor_sync(0xffffffffu, mx, o));
    float sum = 0.f;
    for (int t = 0; t < per; t++) { vals[t] = __expf(vals[t] - mx); sum += vals[t]; }
    for (int o = 16; o; o >>= 1) sum += __shfl_xor_sync(0xffffffffu, sum, o);
    float inv = 1.f / sum;
    for (int t = 0; t < per; t++) rh[lane + (t<<5)] = __float2half(vals[t] * inv);
}

// ============================ host orchestration ============================
#define HG_B   hgemm<0,1,1>
#define HG_BF  hgemm<0,1,0>
#define HG_G   hgemm<1,1,1>
#define HG_N   hgemm<0,0,0>

static const int HG_SMEM = 6 * 128 * 72 * 2;   // 110592 B

static void cvh(const float* src, __half* dst, int n) {
    cvt_h<<<(n/4 + 255)/256, 256>>>(src, dst, n/4);
}

extern "C" void kernel_launch(void* const* d_in, const int* in_sizes, int n_in,
                              void* d_out, int out_size) {
    const int*   var_idx   = (const int*)  d_in[0];
    const int*   sign_idx  = (const int*)  d_in[1];
    const void*  lit_mask  = (const void*) d_in[2];
    const float* var_emb   = (const float*)d_in[3];
    const float* sign_emb  = (const float*)d_in[4];
    const float* litpos    = (const float*)d_in[5];
    const float* clausepos = (const float*)d_in[6];
    const float* enc_in_w  = (const float*)d_in[7];
    const float* enc_in_b  = (const float*)d_in[8];
    const float* enc_out_w = (const float*)d_in[9];
    const float* enc_out_b = (const float*)d_in[10];
    const float* enc_ff1_w = (const float*)d_in[11];
    const float* enc_ff1_b = (const float*)d_in[12];
    const float* enc_ff2_w = (const float*)d_in[13];
    const float* enc_ff2_b = (const float*)d_in[14];
    const float* n1w = (const float*)d_in[15];
    const float* n1b = (const float*)d_in[16];
    const float* n2w = (const float*)d_in[17];
    const float* n2b = (const float*)d_in[18];
    const float* th_ln_w = (const float*)d_in[19];
    const float* th_ln_b = (const float*)d_in[20];
    const float* th_w = (const float*)d_in[21];
    const float* th_b = (const float*)d_in[22];
    const float* pq   = (const float*)d_in[23];
    const float* pa_in_w  = (const float*)d_in[24];
    const float* pa_in_b  = (const float*)d_in[25];
    const float* pa_out_w = (const float*)d_in[26];
    const float* pa_out_b = (const float*)d_in[27];
    const float* pn_w = (const float*)d_in[28];
    const float* pn_b = (const float*)d_in[29];
    float* out = (float*)d_out;

    __half *x,*t0,*t1,*t2h,*ch,*kv,*qh,*S2h,*p1;
    float *S2,*p2;
    __half *hwin,*hwout,*hwf1,*hwf2,*hwth,*hwpa,*hwpo,*hwpq;
    cudaGetSymbolAddress((void**)&x,   g_x);
    cudaGetSymbolAddress((void**)&t0,  g_t0);
    cudaGetSymbolAddress((void**)&t1,  g_t1);
    cudaGetSymbolAddress((void**)&t2h, g_t2h);
    cudaGetSymbolAddress((void**)&ch,  g_ch);
    cudaGetSymbolAddress((void**)&kv,  g_kv);
    cudaGetSymbolAddress((void**)&qh,  g_qh);
    cudaGetSymbolAddress((void**)&S2,  g_S2);
    cudaGetSymbolAddress((void**)&S2h, g_S2h);
    cudaGetSymbolAddress((void**)&p1,  g_p1);
    cudaGetSymbolAddress((void**)&p2,  g_p2);
    cudaGetSymbolAddress((void**)&hwin,  g_hw_in);
    cudaGetSymbolAddress((void**)&hwout, g_hw_out);
    cudaGetSymbolAddress((void**)&hwf1,  g_hw_f1);
    cudaGetSymbolAddress((void**)&hwf2,  g_hw_f2);
    cudaGetSymbolAddress((void**)&hwth,  g_hw_th);
    cudaGetSymbolAddress((void**)&hwpa,  g_hw_pa);
    cudaGetSymbolAddress((void**)&hwpo,  g_hw_po);
    cudaGetSymbolAddress((void**)&hwpq,  g_hw_pq);

    cudaFuncSetAttribute(HG_B,  cudaFuncAttributeMaxDynamicSharedMemorySize, HG_SMEM);
    cudaFuncSetAttribute(HG_BF, cudaFuncAttributeMaxDynamicSharedMemorySize, HG_SMEM);
    cudaFuncSetAttribute(HG_G,  cudaFuncAttributeMaxDynamicSharedMemorySize, HG_SMEM);
    cudaFuncSetAttribute(HG_N,  cudaFuncAttributeMaxDynamicSharedMemorySize, HG_SMEM);

    const int M = BB*CC;
    const float escale = 0.17677669529663687f;   // 1/sqrt(32)
    const float pscale = 0.08838834764831845f;   // 1/sqrt(128)

    cvh(enc_in_w,  hwin,  NLL*768*DD);
    detect_mask_kernel<<<16, 256>>>((const int*)lit_mask);
    pool_kernel<<<M, 256>>>(var_idx, sign_idx, lit_mask, var_emb,
                            sign_emb, litpos, clausepos, x);
    cvh(enc_out_w, hwout, NLL*DD*DD);
    cvh(enc_ff1_w, hwf1,  NLL*HH*DD);
    cvh(enc_ff2_w, hwf2,  NLL*DD*HH);
    cvh(th_w,      hwth,  HH*DD);
    cvh(pa_in_w,   hwpa,  3*HH*HH);
    cvh(pa_out_w,  hwpo,  HH*HH);
    cvh(pq,        hwpq,  PP*HH);

    for (int i = 0; i < NLL; i++) {
        const __half* wqkv = hwin  + (size_t)i*768*DD;
        const float*  bqkv = enc_in_b  + (size_t)i*768;
        const __half* wo   = hwout + (size_t)i*DD*DD;
        const float*  bo   = enc_out_b + (size_t)i*DD;
        const __half* w1   = hwf1  + (size_t)i*HH*DD;
        const float*  b1   = enc_ff1_b + (size_t)i*HH;
        const __half* w2   = hwf2  + (size_t)i*DD*HH;
        const float*  b2   = enc_ff2_b + (size_t)i*DD;

        HG_B<<<dim3(6,128,1),256,HG_SMEM>>>(x, wqkv, bqkv, t0, M,768,DD,
                                            DD,DD,768, 1,0,0,0,0,0,0, 1.f);
        fused_attn_h<<<dim3(4, BB*NHD), 256>>>(t0, t1, escale);
        HG_B<<<dim3(2,128,1),256,HG_SMEM>>>(t1, wo, bo, t2h, M,DD,DD,
                                            DD,DD,DD, 1,0,0,0,0,0,0, 1.f);
        ln256<1><<<M/8,256>>>(t2h, x, n1w + i*DD, n1b + i*DD, x);
        HG_G<<<dim3(8,128,1),256,HG_SMEM>>>(x, w1, b1, t0, M,HH,DD,
                                            DD,DD,HH, 1,0,0,0,0,0,0, 1.f);
        HG_B<<<dim3(2,128,1),256,HG_SMEM>>>(t0, w2, b2, t2h, M,DD,HH,
                                            HH,HH,DD, 1,0,0,0,0,0,0, 1.f);
        ln256<1><<<M/8,256>>>(t2h, x, n2w + i*DD, n2b + i*DD, x);
    }

    // ch = LN(x) @ th_w^T + th_b  (half)
    ln256<0><<<M/8,256>>>(x, nullptr, th_ln_w, th_ln_b, t2h);
    HG_B<<<dim3(8,128,1),256,HG_SMEM>>>(t2h, hwth, th_b, ch, M,HH,DD,
                                        DD,DD,HH, 1,0,0,0,0,0,0, 1.f);

    // prefix cross-attention
    HG_B<<<dim3(8,1,1),256,HG_SMEM>>>(hwpq, hwpa, pa_in_b, qh, PP,HH,HH,
                                      HH,HH,HH, 1,0,0,0,0,0,0, 1.f);
    HG_B<<<dim3(16,128,1),256,HG_SMEM>>>(ch, hwpa + (size_t)HH*HH, pa_in_b + HH, kv,
                                         M,2*HH,HH, HH,HH,2*HH, 1,0,0,0,0,0,0, 1.f);
    HG_N<<<dim3(4,1,BB*NHD),256,HG_SMEM>>>(qh, kv, nullptr, S2, PP,CC,128,
                                           HH,2*HH,CC, NHD,
                                           0L, 128L, (long)CC*2*HH, 128L,
                                           (long)NHD*PP*CC, (long)PP*CC, pscale);
    softmax_kernel<<<(BB*NHD*PP)/8, 256>>>(S2, S2h, CC);
    av2h<<<dim3(4,1,BB*NHD),256>>>(S2h, kv, p1);
    HG_BF<<<dim3(8,4,1),256,HG_SMEM>>>(p1, hwpo, pa_out_b, p2, BB*PP,HH,HH,
                                       HH,HH,HH, 1,0,0,0,0,0,0, 1.f);
    ln_kernel<<<BB*PP,256>>>(p2, 0, pq, 1, pn_w, pn_b, out, 0, HH, PP);
}

// round 14
// speedup vs baseline: 8.8613x; 1.1412x over previous
#include <cuda_runtime.h>
#include <cuda_fp16.h>
#include <cstdint>

#define BB 32
#define CC 512
#define LL 16
#define DD 256
#define HH 1024
#define PP 16
#define NHD 8
#define NLL 4

// ---------------- scratch (static device globals; allocation-free) ----------------
__device__ __half g_x  [BB*CC*DD];
__device__ __half g_t0 [BB*CC*HH];
__device__ __half g_t1 [BB*CC*DD];
__device__ __half g_t2h[BB*CC*DD];
__device__ __half g_ch [BB*CC*HH];
__device__ __half g_qh [PP*HH];
__device__ __half g_qw [128*HH];          // per-head qh @ wk  [h*16+p, e]
__device__ float  g_S2 [BB*CC*128];       // S2^T  [b][c][hp]
__device__ __half g_S2h[BB*128*CC];       // P     [b][hp][c]
__device__ __half g_pch[BB*128*HH];       // P @ ch [b][hp][e]
__device__ __half g_p1 [BB*PP*HH];
__device__ float  g_p2 [BB*PP*HH];
__device__ int    g_maskmode;
// half weights
__device__ __half g_hw_in [NLL*768*DD];
__device__ __half g_hw_out[NLL*DD*DD];
__device__ __half g_hw_f1 [NLL*HH*DD];
__device__ __half g_hw_f2 [NLL*DD*HH];
__device__ __half g_hw_th [HH*DD];
__device__ __half g_hw_pa [3*HH*HH];
__device__ __half g_hw_po [HH*HH];
__device__ __half g_hw_pq [PP*HH];

// ---------------- small helpers ----------------
__device__ __forceinline__ uint32_t smem_u32(const void* p) {
    uint32_t a;
    asm("{ .reg .u64 t; cvta.to.shared.u64 t, %1; cvt.u32.u64 %0, t; }" : "=r"(a) : "l"(p));
    return a;
}
__device__ __forceinline__ float gelu_f(float v) {
    return 0.5f * v * (1.f + erff(v * 0.70710678118654752f));
}
__device__ __forceinline__ uint32_t packh2(float lo, float hi) {
    __half2 h = __floats2half2_rn(lo, hi);
    return *(uint32_t*)&h;
}
__device__ __forceinline__ void hmma16(float* c, const uint32_t* a, const uint32_t* b) {
    asm("mma.sync.aligned.m16n8k16.row.col.f32.f16.f16.f32 "
        "{%0,%1,%2,%3}, {%4,%5,%6,%7}, {%8,%9}, {%0,%1,%2,%3};"
        : "+f"(c[0]), "+f"(c[1]), "+f"(c[2]), "+f"(c[3])
        : "r"(a[0]), "r"(a[1]), "r"(a[2]), "r"(a[3]), "r"(b[0]), "r"(b[1]));
}
#define LDM_X4(r0, r1, r2, r3, addr) \
    asm volatile("ldmatrix.sync.aligned.m8n8.x4.shared.b16 {%0,%1,%2,%3}, [%4];" \
        : "=r"(r0), "=r"(r1), "=r"(r2), "=r"(r3) : "r"(addr))
#define LDM_X2(r0, r1, addr) \
    asm volatile("ldmatrix.sync.aligned.m8n8.x2.shared.b16 {%0,%1}, [%2];" \
        : "=r"(r0), "=r"(r1) : "r"(addr))
#define CPA16(dst, src, pred) \
    asm volatile("cp.async.cg.shared.global [%0], [%1], 16, %2;" \
                 :: "r"(dst), "l"(src), "r"((pred) ? 16 : 0))
#define CP_COMMIT() asm volatile("cp.async.commit_group;")
#define CP_WAIT1()  asm volatile("cp.async.wait_group 1;")
#define CP_WAIT0()  asm volatile("cp.async.wait_group 0;")

// ---------------- fp32 -> fp16 weight conversion ----------------
__global__ void cvt_h(const float* __restrict__ src, __half* __restrict__ dst, int n4) {
    int i = blockIdx.x * 256 + threadIdx.x;
    if (i < n4) {
        float4 v = ((const float4*)src)[i];
        uint2 u;
        u.x = packh2(v.x, v.y);
        u.y = packh2(v.z, v.w);
        ((uint2*)dst)[i] = u;
    }
}

// ============================ fp16 3-stage cp.async + ldmatrix GEMM ============================
// C = act(alpha*A@W^T + bias[+zs*sBs]); A[M,K] half, W[N,K] half. N%128==0, K%64==0.
template<int ACT, int HASB, int OUTH>
__global__ __launch_bounds__(256, 2) void hgemm(
    const __half* __restrict__ A, const __half* __restrict__ W,
    const float* __restrict__ bias, void* __restrict__ Cp,
    int M, int N, int K, int lda, int ldw, int ldc,
    int nsub, long sAb, long sAs, long sWb, long sWs, long sCb, long sCs,
    long sBs, float alpha)
{
    constexpr int BM = 128, BN = 128, BK = 64, LDH = 72, NST = 3;
    constexpr uint32_t STB = BM * LDH * 2;
    extern __shared__ __half smh[];
    uint32_t base = smem_u32(smh);
    uint32_t asA = base;
    uint32_t wsA = base + NST * STB;

    int tid = threadIdx.x, wid = tid >> 5, lane = tid & 31;
    int warpM = wid >> 2, warpN = wid & 3;
    int g = lane >> 2, tg = lane & 3;
    int bm = blockIdx.y * BM, bn = blockIdx.x * BN;
    int z = blockIdx.z, zb = z / nsub, zs = z % nsub;
    const __half* Ab = A + (size_t)zb * sAb + (size_t)zs * sAs;
    const __half* Wb = W + (size_t)zb * sWb + (size_t)zs * sWs;
    const float* biasB = HASB ? (bias + (size_t)zs * sBs) : bias;

    int arow = (lane & 7) + ((lane & 8) ? 8 : 0);
    int acol = (lane & 16) ? 8 : 0;
    int brow = (lane & 7) + ((lane & 16) ? 8 : 0);
    int bcol = (lane & 8) ? 8 : 0;
    uint32_t aLane = (uint32_t)((warpM * 64 + arow) * LDH + acol) * 2;
    uint32_t bLane = (uint32_t)((warpN * 32 + brow) * LDH + bcol) * 2;

    auto load_stage = [&](int st, int k0) {
        uint32_t ab = asA + (uint32_t)st * STB;
        uint32_t wb = wsA + (uint32_t)st * STB;
        #pragma unroll
        for (int idx = tid; idx < BM * 8; idx += 256) {
            int row = idx >> 3, q = idx & 7;
            int gm = bm + row;
            bool ok = gm < M;
            int gmc = ok ? gm : 0;
            CPA16(ab + (uint32_t)(row * LDH + q * 8) * 2,
                  Ab + (size_t)gmc * lda + k0 + q * 8, ok);
        }
        #pragma unroll
        for (int idx = tid; idx < BN * 8; idx += 256) {
            int row = idx >> 3, q = idx & 7;
            CPA16(wb + (uint32_t)(row * LDH + q * 8) * 2,
                  Wb + (size_t)(bn + row) * ldw + k0 + q * 8, true);
        }
        CP_COMMIT();
    };

    float acc[4][4][4];
    #pragma unroll
    for (int i = 0; i < 4; i++)
        #pragma unroll
        for (int j = 0; j < 4; j++)
            #pragma unroll
            for (int q = 0; q < 4; q++) acc[i][j][q] = 0.f;

    int nk = K / BK;
    load_stage(0, 0);
    if (nk > 1) load_stage(1, BK);

    for (int i = 0; i < nk; i++) {
        if (i + 1 < nk) CP_WAIT1(); else CP_WAIT0();
        __syncthreads();
        if (i + 2 < nk) load_stage((i + 2) % NST, (i + 2) * BK);

        int cur = i % NST;
        uint32_t aB = asA + (uint32_t)cur * STB + aLane;
        uint32_t wB = wsA + (uint32_t)cur * STB + bLane;

        uint32_t af[2][4][4], bf[2][4][2];
        #pragma unroll
        for (int mi = 0; mi < 4; mi++)
            LDM_X4(af[0][mi][0], af[0][mi][1], af[0][mi][2], af[0][mi][3],
                   aB + (uint32_t)(mi * 16 * LDH) * 2);
        LDM_X4(bf[0][0][0], bf[0][0][1], bf[0][1][0], bf[0][1][1], wB);
        LDM_X4(bf[0][2][0], bf[0][2][1], bf[0][3][0], bf[0][3][1],
               wB + (uint32_t)(16 * LDH) * 2);

        #pragma unroll
        for (int ks = 0; ks < 4; ks++) {
            int cb = ks & 1, nb = cb ^ 1;
            if (ks < 3) {
                int kk = (ks + 1) * 16;
                #pragma unroll
                for (int mi = 0; mi < 4; mi++)
                    LDM_X4(af[nb][mi][0], af[nb][mi][1], af[nb][mi][2], af[nb][mi][3],
                           aB + (uint32_t)(mi * 16 * LDH + kk) * 2);
                LDM_X4(bf[nb][0][0], bf[nb][0][1], bf[nb][1][0], bf[nb][1][1],
                       wB + (uint32_t)kk * 2);
                LDM_X4(bf[nb][2][0], bf[nb][2][1], bf[nb][3][0], bf[nb][3][1],
                       wB + (uint32_t)(16 * LDH + kk) * 2);
            }
            #pragma unroll
            for (int mi = 0; mi < 4; mi++)
                #pragma unroll
                for (int nj = 0; nj < 4; nj++)
                    hmma16(acc[mi][nj], af[cb][mi], bf[cb][nj]);
        }
    }

    long cOff = (size_t)zb * sCb + (size_t)zs * sCs;
    #pragma unroll
    for (int mi = 0; mi < 4; mi++) {
        int r0 = bm + warpM * 64 + mi * 16 + g;
        #pragma unroll
        for (int nj = 0; nj < 4; nj++) {
            int c = bn + warpN * 32 + nj * 8 + 2 * tg;
            float b0 = 0.f, b1 = 0.f;
            if (HASB) { b0 = biasB[c]; b1 = biasB[c + 1]; }
            float v0 = acc[mi][nj][0] * alpha + b0;
            float v1 = acc[mi][nj][1] * alpha + b1;
            float v2 = acc[mi][nj][2] * alpha + b0;
            float v3 = acc[mi][nj][3] * alpha + b1;
            if (ACT) { v0 = gelu_f(v0); v1 = gelu_f(v1); v2 = gelu_f(v2); v3 = gelu_f(v3); }
            if (OUTH) {
                __half* Cb = (__half*)Cp + cOff;
                if (r0 < M)     *(uint32_t*)&Cb[(size_t)r0 * ldc + c]       = packh2(v0, v1);
                if (r0 + 8 < M) *(uint32_t*)&Cb[(size_t)(r0 + 8) * ldc + c] = packh2(v2, v3);
            } else {
                float* Cb = (float*)Cp + cOff;
                if (r0 < M)     { Cb[(size_t)r0 * ldc + c] = v0; Cb[(size_t)r0 * ldc + c + 1] = v1; }
                if (r0 + 8 < M) { Cb[(size_t)(r0 + 8) * ldc + c] = v2; Cb[(size_t)(r0 + 8) * ldc + c + 1] = v3; }
            }
        }
    }
}

// ============================ transposed-B fp16 GEMM (W given [K,N] row-major) ============
// C = A @ W, half output, no bias/act. Single-buffered SMEM.
__global__ __launch_bounds__(256, 2) void hgemm_trb(
    const __half* __restrict__ A, const __half* __restrict__ W, __half* __restrict__ Cp,
    int M, int N, int K, int lda, int ldw, int ldc,
    int nsub, long sAb, long sAs, long sWb, long sWs, long sCb, long sCs)
{
    constexpr int LDH = 72;
    __shared__ __half As[128 * LDH];
    __shared__ __half Ws[128 * LDH];

    int tid = threadIdx.x, wid = tid >> 5, lane = tid & 31;
    int warpM = wid >> 2, warpN = wid & 3;
    int g = lane >> 2, tg = lane & 3;
    int bm = blockIdx.y * 128, bn = blockIdx.x * 128;
    int z = blockIdx.z, zb = z / nsub, zs = z % nsub;
    const __half* Ab = A + (size_t)zb * sAb + (size_t)zs * sAs;
    const __half* Wb = W + (size_t)zb * sWb + (size_t)zs * sWs;
    __half* Cb = Cp + (size_t)zb * sCb + (size_t)zs * sCs;

    int arow = (lane & 7) + ((lane & 8) ? 8 : 0);
    int acol = (lane & 16) ? 8 : 0;
    int brow = (lane & 7) + ((lane & 16) ? 8 : 0);
    int bcol = (lane & 8) ? 8 : 0;
    uint32_t aLane = smem_u32(As) + (uint32_t)((warpM * 64 + arow) * LDH + acol) * 2;
    uint32_t bLane = smem_u32(Ws) + (uint32_t)((warpN * 32 + brow) * LDH + bcol) * 2;

    float acc[4][4][4];
    #pragma unroll
    for (int i = 0; i < 4; i++)
        #pragma unroll
        for (int j = 0; j < 4; j++)
            #pragma unroll
            for (int q = 0; q < 4; q++) acc[i][j][q] = 0.f;

    for (int k0 = 0; k0 < K; k0 += 64) {
        __syncthreads();
        #pragma unroll
        for (int idx = tid; idx < 128 * 8; idx += 256) {
            int row = idx >> 3, q = idx & 7;
            int gm = bm + row;
            int gmc = (gm < M) ? gm : 0;
            *(uint4*)&As[row * LDH + q * 8] =
                *(const uint4*)(Ab + (size_t)gmc * lda + k0 + q * 8);
        }
        #pragma unroll
        for (int idx = tid; idx < 64 * 16; idx += 256) {
            int kk = idx >> 4, q = idx & 15;
            union { uint4 u; __half h[8]; } vv;
            vv.u = *(const uint4*)(Wb + (size_t)(k0 + kk) * ldw + bn + q * 8);
            #pragma unroll
            for (int j = 0; j < 8; j++) Ws[(q * 8 + j) * LDH + kk] = vv.h[j];
        }
        __syncthreads();

        #pragma unroll
        for (int kk = 0; kk < 64; kk += 16) {
            uint32_t af[4][4], bf[4][2];
            #pragma unroll
            for (int mi = 0; mi < 4; mi++)
                LDM_X4(af[mi][0], af[mi][1], af[mi][2], af[mi][3],
                       aLane + (uint32_t)(mi * 16 * LDH + kk) * 2);
            LDM_X4(bf[0][0], bf[0][1], bf[1][0], bf[1][1], bLane + (uint32_t)kk * 2);
            LDM_X4(bf[2][0], bf[2][1], bf[3][0], bf[3][1],
                   bLane + (uint32_t)(16 * LDH + kk) * 2);
            #pragma unroll
            for (int mi = 0; mi < 4; mi++)
                #pragma unroll
                for (int nj = 0; nj < 4; nj++)
                    hmma16(acc[mi][nj], af[mi], bf[nj]);
        }
    }

    #pragma unroll
    for (int mi = 0; mi < 4; mi++) {
        int r0 = bm + warpM * 64 + mi * 16 + g;
        #pragma unroll
        for (int nj = 0; nj < 4; nj++) {
            int c = bn + warpN * 32 + nj * 8 + 2 * tg;
            if (r0 < M)
                *(uint32_t*)&Cb[(size_t)r0 * ldc + c] = packh2(acc[mi][nj][0], acc[mi][nj][1]);
            if (r0 + 8 < M)
                *(uint32_t*)&Cb[(size_t)(r0 + 8) * ldc + c] = packh2(acc[mi][nj][2], acc[mi][nj][3]);
        }
    }
}

// ============================ fused flash attention (no-max, fused S->exp->PV) ============
__global__ __launch_bounds__(256) void fused_attn_h(
    const __half* __restrict__ qkv, __half* __restrict__ o, float escale)
{
    __shared__ __half Qs[128 * 40];
    __shared__ __half Ks[128 * 40];
    __shared__ __half Vs[40 * 136];

    int tid = threadIdx.x, lane = tid & 31, w = tid >> 5;
    int g = lane >> 2, tg = lane & 3;
    int qt = blockIdx.x;
    int z  = blockIdx.y;
    int b  = z >> 3, h = z & 7;
    const __half* base = qkv + (size_t)b * CC * 768;

    int arow = (lane & 7) + ((lane & 8) ? 8 : 0);
    int acol = (lane & 16) ? 8 : 0;
    int brow = (lane & 7) + ((lane & 16) ? 8 : 0);
    int bcol = (lane & 8) ? 8 : 0;
    uint32_t qBase = smem_u32(Qs) + (uint32_t)((w * 16 + arow) * 40 + acol) * 2;
    uint32_t kBase = smem_u32(Ks) + (uint32_t)(brow * 40 + bcol) * 2;
    uint32_t vBase = smem_u32(Vs) + (uint32_t)(brow * 136 + bcol) * 2;
    uint32_t onesAddr = smem_u32(Vs) +
        (uint32_t)((32 + (lane & 7)) * 136 + ((lane & 8) ? 8 : 0)) * 2;

    #pragma unroll
    for (int idx = tid; idx < 128 * 4; idx += 256) {
        int r = idx >> 2, q4 = idx & 3;
        *(uint4*)&Qs[r * 40 + q4 * 8] =
            *(const uint4*)(base + (size_t)(qt * 128 + r) * 768 + h * 32 + q4 * 8);
    }
    for (int idx = tid; idx < 8 * 136; idx += 256) {
        int r = 32 + idx / 136, c = idx % 136;
        Vs[r * 136 + c] = (r == 32) ? __float2half(1.f) : __float2half(0.f);
    }

    float oacc[4][4];
    #pragma unroll
    for (int i = 0; i < 4; i++)
        #pragma unroll
        for (int q = 0; q < 4; q++) oacc[i][q] = 0.f;
    float smsum[4] = {0.f, 0.f, 0.f, 0.f};

    const float se = escale * 1.4426950408889634f;

    uint32_t bones[2];
    bool onesLoaded = false;

    for (int kt = 0; kt < 4; kt++) {
        __syncthreads();
        #pragma unroll
        for (int idx = tid; idx < 128 * 4; idx += 256) {
            int r = idx >> 2, q4 = idx & 3;
            const __half* kr = base + (size_t)(kt * 128 + r) * 768 + 256 + h * 32 + q4 * 8;
            *(uint4*)&Ks[r * 40 + q4 * 8] = *(const uint4*)kr;
            union { uint4 u; __half hh[8]; } vv;
            vv.u = *(const uint4*)(kr + 256);
            #pragma unroll
            for (int j = 0; j < 8; j++) Vs[(q4 * 8 + j) * 136 + r] = vv.hh[j];
        }
        __syncthreads();
        if (!onesLoaded) { LDM_X2(bones[0], bones[1], onesAddr); onesLoaded = true; }

        uint32_t af0[4], af1[4];
        LDM_X4(af0[0], af0[1], af0[2], af0[3], qBase);
        LDM_X4(af1[0], af1[1], af1[2], af1[3], qBase + 32u);

        #pragma unroll
        for (int p8 = 0; p8 < 8; p8++) {
            uint32_t kb0[4], kb1[4];
            LDM_X4(kb0[0], kb0[1], kb0[2], kb0[3],
                   kBase + (uint32_t)(p8 * 16 * 40) * 2);
            LDM_X4(kb1[0], kb1[1], kb1[2], kb1[3],
                   kBase + (uint32_t)(p8 * 16 * 40 + 16) * 2);
            float sl[4] = {0.f, 0.f, 0.f, 0.f};
            float sh[4] = {0.f, 0.f, 0.f, 0.f};
            hmma16(sl, af0, kb0);
            hmma16(sh, af0, kb0 + 2);
            hmma16(sl, af1, kb1);
            hmma16(sh, af1, kb1 + 2);

            uint32_t a[4];
            {
                __half2 e;
                e = h2exp2(__floats2half2_rn(sl[0] * se, sl[1] * se)); a[0] = *(uint32_t*)&e;
                e = h2exp2(__floats2half2_rn(sl[2] * se, sl[3] * se)); a[1] = *(uint32_t*)&e;
                e = h2exp2(__floats2half2_rn(sh[0] * se, sh[1] * se)); a[2] = *(uint32_t*)&e;
                e = h2exp2(__floats2half2_rn(sh[2] * se, sh[3] * se)); a[3] = *(uint32_t*)&e;
            }

            uint32_t v0[4], v1[4];
            LDM_X4(v0[0], v0[1], v0[2], v0[3],
                   vBase + (uint32_t)(p8 * 16) * 2);
            LDM_X4(v1[0], v1[1], v1[2], v1[3],
                   vBase + (uint32_t)(16 * 136 + p8 * 16) * 2);
            hmma16(oacc[0], a, v0);
            hmma16(oacc[1], a, v0 + 2);
            hmma16(oacc[2], a, v1);
            hmma16(oacc[3], a, v1 + 2);
            hmma16(smsum, a, bones);
        }
    }

    float rs0 = __shfl_sync(0xffffffffu, smsum[0], lane & ~3);
    float rs1 = __shfl_sync(0xffffffffu, smsum[2], lane & ~3);
    float inv0 = 1.f / rs0, inv1 = 1.f / rs1;
    int row0 = b * CC + qt * 128 + w * 16 + g;
    #pragma unroll
    for (int vj = 0; vj < 4; vj++) {
        int c = h * 32 + vj * 8 + 2 * tg;
        *(uint32_t*)&o[(size_t)row0 * 256 + c] =
            packh2(oacc[vj][0] * inv0, oacc[vj][1] * inv0);
        *(uint32_t*)&o[(size_t)(row0 + 8) * 256 + c] =
            packh2(oacc[vj][2] * inv1, oacc[vj][3] * inv1);
    }
}

// ---------------- mask dtype detection ----------------
__global__ void detect_mask_kernel(const int* __restrict__ m) {
    __shared__ int found;
    if (threadIdx.x == 0) found = 0;
    __syncthreads();
    int idx = blockIdx.x * blockDim.x + threadIdx.x;
    unsigned v = (unsigned)m[idx];
    if (v > 1u) found = 1;
    __syncthreads();
    if (threadIdx.x == 0 && blockIdx.x == 0) g_maskmode = 0;
    __threadfence();
    if (found) g_maskmode = 1;
}

// ---------------- pool (half output) ----------------
__global__ void pool_kernel(const int* __restrict__ vi, const int* __restrict__ si,
                            const void* __restrict__ maskraw,
                            const float* __restrict__ ve, const float* __restrict__ se,
                            const float* __restrict__ lpe, const float* __restrict__ cpe,
                            __half* __restrict__ x) {
    int bc = blockIdx.x;
    int c  = bc % CC;
    int d  = threadIdx.x;
    const int* viR = vi + bc * LL;
    const int* siR = si + bc * LL;
    __shared__ int mloc[LL];
    if (threadIdx.x < LL) {
        int mv;
        if (g_maskmode == 0) mv = ((const int*)maskraw)[bc * LL + threadIdx.x];
        else                 mv = ((const unsigned char*)maskraw)[bc * LL + threadIdx.x];
        mloc[threadIdx.x] = mv;
    }
    __syncthreads();
    float acc = 0.f; int cnt = 0;
    #pragma unroll
    for (int l = 0; l < LL; l++) {
        if (mloc[l]) {
            cnt++;
            acc += ve[viR[l]*DD + d] + se[siR[l]*DD + d] + lpe[l*DD + d];
        }
    }
    x[(size_t)bc*DD + d] = __float2half(acc / (float)cnt + cpe[c*DD + d]);
}

// ---------------- warp-per-row LN for N=256 half tensors ----------------
template<int RES>
__global__ __launch_bounds__(256) void ln256(
    const __half* __restrict__ xin, const __half* __restrict__ res,
    const float* __restrict__ w, const float* __restrict__ b,
    __half* __restrict__ out)
{
    int row  = blockIdx.x * 8 + (threadIdx.x >> 5);
    int lane = threadIdx.x & 31;
    size_t off = (size_t)row * 256 + lane * 8;

    union { uint4 u; __half h[8]; } xv, rv;
    xv.u = *(const uint4*)(xin + off);
    if (RES) rv.u = *(const uint4*)(res + off);

    float v[8];
    float s = 0.f;
    #pragma unroll
    for (int j = 0; j < 8; j++) {
        float t = __half2float(xv.h[j]);
        if (RES) t += __half2float(rv.h[j]);
        v[j] = t; s += t;
    }
    #pragma unroll
    for (int o2 = 16; o2; o2 >>= 1) s += __shfl_xor_sync(0xffffffffu, s, o2);
    float mean = s * (1.f / 256.f);
    float vs = 0.f;
    #pragma unroll
    for (int j = 0; j < 8; j++) { float d = v[j] - mean; vs += d * d; }
    #pragma unroll
    for (int o2 = 16; o2; o2 >>= 1) vs += __shfl_xor_sync(0xffffffffu, vs, o2);
    float inv = rsqrtf(vs * (1.f / 256.f) + 1e-5f);

    float4 w0 = *(const float4*)(w + lane * 8);
    float4 w1 = *(const float4*)(w + lane * 8 + 4);
    float4 b0 = *(const float4*)(b + lane * 8);
    float4 b1 = *(const float4*)(b + lane * 8 + 4);
    float ww[8] = {w0.x, w0.y, w0.z, w0.w, w1.x, w1.y, w1.z, w1.w};
    float bb[8] = {b0.x, b0.y, b0.z, b0.w, b1.x, b1.y, b1.z, b1.w};

    union { uint4 u; __half h[8]; } ov;
    #pragma unroll
    for (int j = 0; j < 8; j++)
        ov.h[j] = __float2half((v[j] - mean) * inv * ww[j] + bb[j]);
    *(uint4*)(out + off) = ov.u;
}

// ---------------- generic layernorm (final N=1024 fp32 path) ----------------
__global__ void ln_kernel(const void* __restrict__ xin, int inH,
                          const void* __restrict__ res, int resM,
                          const float* __restrict__ w, const float* __restrict__ b,
                          void* __restrict__ out, int outH, int N, int resMod) {
    int row = blockIdx.x;
    int tid = threadIdx.x;
    int rrow = resMod ? (row % resMod) : row;
    int per = N >> 8;
    float v[4];
    float s = 0.f;
    for (int i = 0; i < per; i++) {
        int cI = tid + (i << 8);
        float t = inH ? __half2float(((const __half*)xin)[(size_t)row * N + cI])
                      : ((const float*)xin)[(size_t)row * N + cI];
        if (resM == 1)      t += ((const float*)res)[(size_t)rrow * N + cI];
        else if (resM == 2) t += __half2float(((const __half*)res)[(size_t)rrow * N + cI]);
        v[i] = t; s += t;
    }
    __shared__ float red[256];
    red[tid] = s; __syncthreads();
    for (int o = 128; o; o >>= 1) { if (tid < o) red[tid] += red[tid+o]; __syncthreads(); }
    float mean = red[0] / (float)N;
    __syncthreads();
    float vs = 0.f;
    for (int i = 0; i < per; i++) { float d = v[i] - mean; vs += d*d; }
    red[tid] = vs; __syncthreads();
    for (int o = 128; o; o >>= 1) { if (tid < o) red[tid] += red[tid+o]; __syncthreads(); }
    float inv = rsqrtf(red[0] / (float)N + 1e-5f);
    for (int i = 0; i < per; i++) {
        int cI = tid + (i << 8);
        float ov = (v[i] - mean) * inv * w[cI] + b[cI];
        if (outH) ((__half*)out)[(size_t)row*N + cI] = __float2half(ov);
        else      ((float*)out)[(size_t)row*N + cI] = ov;
    }
}

// ---------------- strided softmax: S2T [b][c=512][hp=128] fp32 -> P [b][hp][c] half ------
__global__ void sm2T(const float* __restrict__ S2T, __half* __restrict__ Sh) {
    int wrow = blockIdx.x * 8 + (threadIdx.x >> 5);   // b*128 + hp
    int lane = threadIdx.x & 31;
    int b = wrow >> 7, hp = wrow & 127;
    const float* src = S2T + (size_t)b * CC * 128 + hp;
    float vals[16];
    float mx = -1e30f;
    #pragma unroll
    for (int t = 0; t < 16; t++) {
        vals[t] = src[(size_t)(lane + (t << 5)) * 128];
        mx = fmaxf(mx, vals[t]);
    }
    for (int o = 16; o; o >>= 1) mx = fmaxf(mx, __shfl_xor_sync(0xffffffffu, mx, o));
    float sum = 0.f;
    #pragma unroll
    for (int t = 0; t < 16; t++) { vals[t] = __expf(vals[t] - mx); sum += vals[t]; }
    for (int o = 16; o; o >>= 1) sum += __shfl_xor_sync(0xffffffffu, sum, o);
    float inv = 1.f / sum;
    __half* dst = Sh + (size_t)wrow * CC;
    #pragma unroll
    for (int t = 0; t < 16; t++) dst[lane + (t << 5)] = __float2half(vals[t] * inv);
}

// ============================ host orchestration ============================
#define HG_B   hgemm<0,1,1>
#define HG_BF  hgemm<0,1,0>
#define HG_G   hgemm<1,1,1>
#define HG_N   hgemm<0,0,0>

static const int HG_SMEM = 6 * 128 * 72 * 2;   // 110592 B

static void cvh(const float* src, __half* dst, int n) {
    cvt_h<<<(n/4 + 255)/256, 256>>>(src, dst, n/4);
}

extern "C" void kernel_launch(void* const* d_in, const int* in_sizes, int n_in,
                              void* d_out, int out_size) {
    const int*   var_idx   = (const int*)  d_in[0];
    const int*   sign_idx  = (const int*)  d_in[1];
    const void*  lit_mask  = (const void*) d_in[2];
    const float* var_emb   = (const float*)d_in[3];
    const float* sign_emb  = (const float*)d_in[4];
    const float* litpos    = (const float*)d_in[5];
    const float* clausepos = (const float*)d_in[6];
    const float* enc_in_w  = (const float*)d_in[7];
    const float* enc_in_b  = (const float*)d_in[8];
    const float* enc_out_w = (const float*)d_in[9];
    const float* enc_out_b = (const float*)d_in[10];
    const float* enc_ff1_w = (const float*)d_in[11];
    const float* enc_ff1_b = (const float*)d_in[12];
    const float* enc_ff2_w = (const float*)d_in[13];
    const float* enc_ff2_b = (const float*)d_in[14];
    const float* n1w = (const float*)d_in[15];
    const float* n1b = (const float*)d_in[16];
    const float* n2w = (const float*)d_in[17];
    const float* n2b = (const float*)d_in[18];
    const float* th_ln_w = (const float*)d_in[19];
    const float* th_ln_b = (const float*)d_in[20];
    const float* th_w = (const float*)d_in[21];
    const float* th_b = (const float*)d_in[22];
    const float* pq   = (const float*)d_in[23];
    const float* pa_in_w  = (const float*)d_in[24];
    const float* pa_in_b  = (const float*)d_in[25];
    const float* pa_out_w = (const float*)d_in[26];
    const float* pa_out_b = (const float*)d_in[27];
    const float* pn_w = (const float*)d_in[28];
    const float* pn_b = (const float*)d_in[29];
    float* out = (float*)d_out;

    __half *x,*t0,*t1,*t2h,*ch,*qh,*qw,*S2h,*pch,*p1;
    float *S2,*p2;
    __half *hwin,*hwout,*hwf1,*hwf2,*hwth,*hwpa,*hwpo,*hwpq;
    cudaGetSymbolAddress((void**)&x,   g_x);
    cudaGetSymbolAddress((void**)&t0,  g_t0);
    cudaGetSymbolAddress((void**)&t1,  g_t1);
    cudaGetSymbolAddress((void**)&t2h, g_t2h);
    cudaGetSymbolAddress((void**)&ch,  g_ch);
    cudaGetSymbolAddress((void**)&qh,  g_qh);
    cudaGetSymbolAddress((void**)&qw,  g_qw);
    cudaGetSymbolAddress((void**)&S2,  g_S2);
    cudaGetSymbolAddress((void**)&S2h, g_S2h);
    cudaGetSymbolAddress((void**)&pch, g_pch);
    cudaGetSymbolAddress((void**)&p1,  g_p1);
    cudaGetSymbolAddress((void**)&p2,  g_p2);
    cudaGetSymbolAddress((void**)&hwin,  g_hw_in);
    cudaGetSymbolAddress((void**)&hwout, g_hw_out);
    cudaGetSymbolAddress((void**)&hwf1,  g_hw_f1);
    cudaGetSymbolAddress((void**)&hwf2,  g_hw_f2);
    cudaGetSymbolAddress((void**)&hwth,  g_hw_th);
    cudaGetSymbolAddress((void**)&hwpa,  g_hw_pa);
    cudaGetSymbolAddress((void**)&hwpo,  g_hw_po);
    cudaGetSymbolAddress((void**)&hwpq,  g_hw_pq);

    cudaFuncSetAttribute(HG_B,  cudaFuncAttributeMaxDynamicSharedMemorySize, HG_SMEM);
    cudaFuncSetAttribute(HG_BF, cudaFuncAttributeMaxDynamicSharedMemorySize, HG_SMEM);
    cudaFuncSetAttribute(HG_G,  cudaFuncAttributeMaxDynamicSharedMemorySize, HG_SMEM);
    cudaFuncSetAttribute(HG_N,  cudaFuncAttributeMaxDynamicSharedMemorySize, HG_SMEM);

    const int M = BB*CC;
    const float escale = 0.17677669529663687f;   // 1/sqrt(32)
    const float pscale = 0.08838834764831845f;   // 1/sqrt(128)

    cvh(enc_in_w,  hwin,  NLL*768*DD);
    detect_mask_kernel<<<16, 256>>>((const int*)lit_mask);
    pool_kernel<<<M, 256>>>(var_idx, sign_idx, lit_mask, var_emb,
                            sign_emb, litpos, clausepos, x);
    cvh(enc_out_w, hwout, NLL*DD*DD);
    cvh(enc_ff1_w, hwf1,  NLL*HH*DD);
    cvh(enc_ff2_w, hwf2,  NLL*DD*HH);
    cvh(th_w,      hwth,  HH*DD);
    cvh(pa_in_w,   hwpa,  3*HH*HH);
    cvh(pa_out_w,  hwpo,  HH*HH);
    cvh(pq,        hwpq,  PP*HH);

    for (int i = 0; i < NLL; i++) {
        const __half* wqkv = hwin  + (size_t)i*768*DD;
        const float*  bqkv = enc_in_b  + (size_t)i*768;
        const __half* wo   = hwout + (size_t)i*DD*DD;
        const float*  bo   = enc_out_b + (size_t)i*DD;
        const __half* w1   = hwf1  + (size_t)i*HH*DD;
        const float*  b1   = enc_ff1_b + (size_t)i*HH;
        const __half* w2   = hwf2  + (size_t)i*DD*HH;
        const float*  b2   = enc_ff2_b + (size_t)i*DD;

        HG_B<<<dim3(6,128,1),256,HG_SMEM>>>(x, wqkv, bqkv, t0, M,768,DD,
                                            DD,DD,768, 1,0,0,0,0,0,0, 0, 1.f);
        fused_attn_h<<<dim3(4, BB*NHD), 256>>>(t0, t1, escale);
        HG_B<<<dim3(2,128,1),256,HG_SMEM>>>(t1, wo, bo, t2h, M,DD,DD,
                                            DD,DD,DD, 1,0,0,0,0,0,0, 0, 1.f);
        ln256<1><<<M/8,256>>>(t2h, x, n1w + i*DD, n1b + i*DD, x);
        HG_G<<<dim3(8,128,1),256,HG_SMEM>>>(x, w1, b1, t0, M,HH,DD,
                                            DD,DD,HH, 1,0,0,0,0,0,0, 0, 1.f);
        HG_B<<<dim3(2,128,1),256,HG_SMEM>>>(t0, w2, b2, t2h, M,DD,HH,
                                            HH,HH,DD, 1,0,0,0,0,0,0, 0, 1.f);
        ln256<1><<<M/8,256>>>(t2h, x, n2w + i*DD, n2b + i*DD, x);
    }

    // ch = LN(x) @ th_w^T + th_b  (half)
    ln256<0><<<M/8,256>>>(x, nullptr, th_ln_w, th_ln_b, t2h);
    HG_B<<<dim3(8,128,1),256,HG_SMEM>>>(t2h, hwth, th_b, ch, M,HH,DD,
                                        DD,DD,HH, 1,0,0,0,0,0,0, 0, 1.f);

    // ---- prefix cross-attention (restructured) ----
    // qh = pq @ wq^T + bq   [16, 1024]
    HG_B<<<dim3(8,1,1),256,HG_SMEM>>>(hwpq, hwpa, pa_in_b, qh, PP,HH,HH,
                                      HH,HH,HH, 1,0,0,0,0,0,0, 0, 1.f);
    // qw[h*16+p, e] = sum_k qh[p, h*128+k] * wk[h*128+k, e]   (bk is softmax-invariant)
    hgemm_trb<<<dim3(8,1,NHD),256>>>(qh, hwpa + (size_t)HH*HH, qw,
                                     16, HH, 128, HH, HH, HH,
                                     NHD, 0, 128, 0, (long)128*HH, 0, (long)16*HH);
    // S2T[b][c][hp] = pscale * ch_b @ qw^T   (fp32)
    HG_N<<<dim3(1,4,BB),256,HG_SMEM>>>(ch, qw, nullptr, S2, CC,128,HH,
                                       HH,HH,128, 1,
                                       (long)CC*HH, 0, 0, 0, (long)CC*128, 0, 0, pscale);
    // softmax over c -> P [b][hp][c] half
    sm2T<<<(BB*128)/8, 256>>>(S2, S2h);
    // PCH[b][hp][e] = P_b @ ch_b
    hgemm_trb<<<dim3(8,1,BB),256>>>(S2h, ch, pch,
                                    128, HH, CC, CC, HH, HH,
                                    1, (long)128*CC, 0, (long)CC*HH, 0, (long)128*HH, 0);
    // p1[b, p, h*128+n] = PCH_slice @ wv_h^T + bv_h   (sum P = 1 carries the bias)
    HG_B<<<dim3(1,1,BB*NHD),256,HG_SMEM>>>(pch, hwpa + (size_t)2*HH*HH, pa_in_b + 2*HH, p1,
                                           16,128,HH, HH,HH,HH, NHD,
                                           (long)128*HH, (long)16*HH, 0, (long)128*HH,
                                           (long)PP*HH, 128, 128, 1.f);
    // p2 = p1 @ wo^T + bo
    HG_BF<<<dim3(8,4,1),256,HG_SMEM>>>(p1, hwpo, pa_out_b, p2, BB*PP,HH,HH,
                                       HH,HH,HH, 1,0,0,0,0,0,0, 0, 1.f);
    // final LN: p2 + pq (fp32 residual, broadcast over batch) -> out fp32
    ln_kernel<<<BB*PP,256>>>(p2, 0, pq, 1, pn_w, pn_b, out, 0, HH, PP);
}

// round 15
// speedup vs baseline: 8.9573x; 1.0108x over previous
#include <cuda_runtime.h>
#include <cuda_fp16.h>
#include <cstdint>

#define BB 32
#define CC 512
#define LL 16
#define DD 256
#define HH 1024
#define PP 16
#define NHD 8
#define NLL 4

// ---------------- scratch (static device globals; allocation-free) ----------------
__device__ __half g_x  [BB*CC*DD];
__device__ __half g_t0 [BB*CC*HH];
__device__ __half g_t1 [BB*CC*DD];
__device__ __half g_t2h[BB*CC*DD];
__device__ __half g_ch [BB*CC*HH];
__device__ __half g_qh [PP*HH];
__device__ __half g_qw [128*HH];
__device__ float  g_S2 [BB*CC*128];
__device__ __half g_S2h[BB*128*CC];
__device__ __half g_pch[BB*128*HH];
__device__ __half g_p1 [BB*PP*HH];
__device__ float  g_p2 [BB*PP*HH];
__device__ int    g_maskmode;
// half weights
__device__ __half g_hw_in [NLL*768*DD];
__device__ __half g_hw_out[NLL*DD*DD];
__device__ __half g_hw_f1 [NLL*HH*DD];
__device__ __half g_hw_f2 [NLL*DD*HH];
__device__ __half g_hw_th [HH*DD];
__device__ __half g_hw_pa [3*HH*HH];
__device__ __half g_hw_po [HH*HH];
__device__ __half g_hw_pq [PP*HH];

// ---------------- small helpers ----------------
__device__ __forceinline__ uint32_t smem_u32(const void* p) {
    uint32_t a;
    asm("{ .reg .u64 t; cvta.to.shared.u64 t, %1; cvt.u32.u64 %0, t; }" : "=r"(a) : "l"(p));
    return a;
}
__device__ __forceinline__ float gelu_f(float v) {
    return 0.5f * v * (1.f + erff(v * 0.70710678118654752f));
}
__device__ __forceinline__ uint32_t packh2(float lo, float hi) {
    __half2 h = __floats2half2_rn(lo, hi);
    return *(uint32_t*)&h;
}
__device__ __forceinline__ void hmma16(float* c, const uint32_t* a, const uint32_t* b) {
    asm("mma.sync.aligned.m16n8k16.row.col.f32.f16.f16.f32 "
        "{%0,%1,%2,%3}, {%4,%5,%6,%7}, {%8,%9}, {%0,%1,%2,%3};"
        : "+f"(c[0]), "+f"(c[1]), "+f"(c[2]), "+f"(c[3])
        : "r"(a[0]), "r"(a[1]), "r"(a[2]), "r"(a[3]), "r"(b[0]), "r"(b[1]));
}
#define LDM_X4(r0, r1, r2, r3, addr) \
    asm volatile("ldmatrix.sync.aligned.m8n8.x4.shared.b16 {%0,%1,%2,%3}, [%4];" \
        : "=r"(r0), "=r"(r1), "=r"(r2), "=r"(r3) : "r"(addr))
#define LDM_X2(r0, r1, addr) \
    asm volatile("ldmatrix.sync.aligned.m8n8.x2.shared.b16 {%0,%1}, [%2];" \
        : "=r"(r0), "=r"(r1) : "r"(addr))
#define CPA16(dst, src, pred) \
    asm volatile("cp.async.cg.shared.global [%0], [%1], 16, %2;" \
                 :: "r"(dst), "l"(src), "r"((pred) ? 16 : 0))
#define CP_COMMIT() asm volatile("cp.async.commit_group;")
#define CP_WAIT1()  asm volatile("cp.async.wait_group 1;")
#define CP_WAIT0()  asm volatile("cp.async.wait_group 0;")

// ---------------- fp32 -> fp16 weight conversion ----------------
__global__ void cvt_h(const float* __restrict__ src, __half* __restrict__ dst, int n4) {
    int i = blockIdx.x * 256 + threadIdx.x;
    if (i < n4) {
        float4 v = ((const float4*)src)[i];
        uint2 u;
        u.x = packh2(v.x, v.y);
        u.y = packh2(v.z, v.w);
        ((uint2*)dst)[i] = u;
    }
}

// ============================ fp16 3-stage cp.async + ldmatrix GEMM ============================
template<int ACT, int HASB, int OUTH>
__global__ __launch_bounds__(256, 2) void hgemm(
    const __half* __restrict__ A, const __half* __restrict__ W,
    const float* __restrict__ bias, void* __restrict__ Cp,
    int M, int N, int K, int lda, int ldw, int ldc,
    int nsub, long sAb, long sAs, long sWb, long sWs, long sCb, long sCs,
    long sBs, float alpha)
{
    constexpr int BM = 128, BN = 128, BK = 64, LDH = 72, NST = 3;
    constexpr uint32_t STB = BM * LDH * 2;
    extern __shared__ __half smh[];
    uint32_t base = smem_u32(smh);
    uint32_t asA = base;
    uint32_t wsA = base + NST * STB;

    int tid = threadIdx.x, wid = tid >> 5, lane = tid & 31;
    int warpM = wid >> 2, warpN = wid & 3;
    int g = lane >> 2, tg = lane & 3;
    int bm = blockIdx.y * BM, bn = blockIdx.x * BN;
    int z = blockIdx.z, zb = z / nsub, zs = z % nsub;
    const __half* Ab = A + (size_t)zb * sAb + (size_t)zs * sAs;
    const __half* Wb = W + (size_t)zb * sWb + (size_t)zs * sWs;
    const float* biasB = HASB ? (bias + (size_t)zs * sBs) : bias;

    int arow = (lane & 7) + ((lane & 8) ? 8 : 0);
    int acol = (lane & 16) ? 8 : 0;
    int brow = (lane & 7) + ((lane & 16) ? 8 : 0);
    int bcol = (lane & 8) ? 8 : 0;
    uint32_t aLane = (uint32_t)((warpM * 64 + arow) * LDH + acol) * 2;
    uint32_t bLane = (uint32_t)((warpN * 32 + brow) * LDH + bcol) * 2;

    auto load_stage = [&](int st, int k0) {
        uint32_t ab = asA + (uint32_t)st * STB;
        uint32_t wb = wsA + (uint32_t)st * STB;
        #pragma unroll
        for (int idx = tid; idx < BM * 8; idx += 256) {
            int row = idx >> 3, q = idx & 7;
            int gm = bm + row;
            bool ok = gm < M;
            int gmc = ok ? gm : 0;
            CPA16(ab + (uint32_t)(row * LDH + q * 8) * 2,
                  Ab + (size_t)gmc * lda + k0 + q * 8, ok);
        }
        #pragma unroll
        for (int idx = tid; idx < BN * 8; idx += 256) {
            int row = idx >> 3, q = idx & 7;
            CPA16(wb + (uint32_t)(row * LDH + q * 8) * 2,
                  Wb + (size_t)(bn + row) * ldw + k0 + q * 8, true);
        }
        CP_COMMIT();
    };

    float acc[4][4][4];
    #pragma unroll
    for (int i = 0; i < 4; i++)
        #pragma unroll
        for (int j = 0; j < 4; j++)
            #pragma unroll
            for (int q = 0; q < 4; q++) acc[i][j][q] = 0.f;

    int nk = K / BK;
    load_stage(0, 0);
    if (nk > 1) load_stage(1, BK);

    for (int i = 0; i < nk; i++) {
        if (i + 1 < nk) CP_WAIT1(); else CP_WAIT0();
        __syncthreads();
        if (i + 2 < nk) load_stage((i + 2) % NST, (i + 2) * BK);

        int cur = i % NST;
        uint32_t aB = asA + (uint32_t)cur * STB + aLane;
        uint32_t wB = wsA + (uint32_t)cur * STB + bLane;

        uint32_t af[2][4][4], bf[2][4][2];
        #pragma unroll
        for (int mi = 0; mi < 4; mi++)
            LDM_X4(af[0][mi][0], af[0][mi][1], af[0][mi][2], af[0][mi][3],
                   aB + (uint32_t)(mi * 16 * LDH) * 2);
        LDM_X4(bf[0][0][0], bf[0][0][1], bf[0][1][0], bf[0][1][1], wB);
        LDM_X4(bf[0][2][0], bf[0][2][1], bf[0][3][0], bf[0][3][1],
               wB + (uint32_t)(16 * LDH) * 2);

        #pragma unroll
        for (int ks = 0; ks < 4; ks++) {
            int cb = ks & 1, nb = cb ^ 1;
            if (ks < 3) {
                int kk = (ks + 1) * 16;
                #pragma unroll
                for (int mi = 0; mi < 4; mi++)
                    LDM_X4(af[nb][mi][0], af[nb][mi][1], af[nb][mi][2], af[nb][mi][3],
                           aB + (uint32_t)(mi * 16 * LDH + kk) * 2);
                LDM_X4(bf[nb][0][0], bf[nb][0][1], bf[nb][1][0], bf[nb][1][1],
                       wB + (uint32_t)kk * 2);
                LDM_X4(bf[nb][2][0], bf[nb][2][1], bf[nb][3][0], bf[nb][3][1],
                       wB + (uint32_t)(16 * LDH + kk) * 2);
            }
            #pragma unroll
            for (int mi = 0; mi < 4; mi++)
                #pragma unroll
                for (int nj = 0; nj < 4; nj++)
                    hmma16(acc[mi][nj], af[cb][mi], bf[cb][nj]);
        }
    }

    long cOff = (size_t)zb * sCb + (size_t)zs * sCs;
    #pragma unroll
    for (int mi = 0; mi < 4; mi++) {
        int r0 = bm + warpM * 64 + mi * 16 + g;
        #pragma unroll
        for (int nj = 0; nj < 4; nj++) {
            int c = bn + warpN * 32 + nj * 8 + 2 * tg;
            float b0 = 0.f, b1 = 0.f;
            if (HASB) { b0 = biasB[c]; b1 = biasB[c + 1]; }
            float v0 = acc[mi][nj][0] * alpha + b0;
            float v1 = acc[mi][nj][1] * alpha + b1;
            float v2 = acc[mi][nj][2] * alpha + b0;
            float v3 = acc[mi][nj][3] * alpha + b1;
            if (ACT) { v0 = gelu_f(v0); v1 = gelu_f(v1); v2 = gelu_f(v2); v3 = gelu_f(v3); }
            if (OUTH) {
                __half* Cb = (__half*)Cp + cOff;
                if (r0 < M)     *(uint32_t*)&Cb[(size_t)r0 * ldc + c]       = packh2(v0, v1);
                if (r0 + 8 < M) *(uint32_t*)&Cb[(size_t)(r0 + 8) * ldc + c] = packh2(v2, v3);
            } else {
                float* Cb = (float*)Cp + cOff;
                if (r0 < M)     { Cb[(size_t)r0 * ldc + c] = v0; Cb[(size_t)r0 * ldc + c + 1] = v1; }
                if (r0 + 8 < M) { Cb[(size_t)(r0 + 8) * ldc + c] = v2; Cb[(size_t)(r0 + 8) * ldc + c + 1] = v3; }
            }
        }
    }
}

// ============================ transposed-B fp16 GEMM (W given [K,N] row-major) ============
__global__ __launch_bounds__(256, 2) void hgemm_trb(
    const __half* __restrict__ A, const __half* __restrict__ W, __half* __restrict__ Cp,
    int M, int N, int K, int lda, int ldw, int ldc,
    int nsub, long sAb, long sAs, long sWb, long sWs, long sCb, long sCs)
{
    constexpr int LDH = 72;
    __shared__ __half As[128 * LDH];
    __shared__ __half Ws[128 * LDH];

    int tid = threadIdx.x, wid = tid >> 5, lane = tid & 31;
    int warpM = wid >> 2, warpN = wid & 3;
    int g = lane >> 2, tg = lane & 3;
    int bm = blockIdx.y * 128, bn = blockIdx.x * 128;
    int z = blockIdx.z, zb = z / nsub, zs = z % nsub;
    const __half* Ab = A + (size_t)zb * sAb + (size_t)zs * sAs;
    const __half* Wb = W + (size_t)zb * sWb + (size_t)zs * sWs;
    __half* Cb = Cp + (size_t)zb * sCb + (size_t)zs * sCs;

    int arow = (lane & 7) + ((lane & 8) ? 8 : 0);
    int acol = (lane & 16) ? 8 : 0;
    int brow = (lane & 7) + ((lane & 16) ? 8 : 0);
    int bcol = (lane & 8) ? 8 : 0;
    uint32_t aLane = smem_u32(As) + (uint32_t)((warpM * 64 + arow) * LDH + acol) * 2;
    uint32_t bLane = smem_u32(Ws) + (uint32_t)((warpN * 32 + brow) * LDH + bcol) * 2;

    float acc[4][4][4];
    #pragma unroll
    for (int i = 0; i < 4; i++)
        #pragma unroll
        for (int j = 0; j < 4; j++)
            #pragma unroll
            for (int q = 0; q < 4; q++) acc[i][j][q] = 0.f;

    for (int k0 = 0; k0 < K; k0 += 64) {
        __syncthreads();
        #pragma unroll
        for (int idx = tid; idx < 128 * 8; idx += 256) {
            int row = idx >> 3, q = idx & 7;
            int gm = bm + row;
            int gmc = (gm < M) ? gm : 0;
            *(uint4*)&As[row * LDH + q * 8] =
                *(const uint4*)(Ab + (size_t)gmc * lda + k0 + q * 8);
        }
        #pragma unroll
        for (int idx = tid; idx < 64 * 16; idx += 256) {
            int kk = idx >> 4, q = idx & 15;
            union { uint4 u; __half h[8]; } vv;
            vv.u = *(const uint4*)(Wb + (size_t)(k0 + kk) * ldw + bn + q * 8);
            #pragma unroll
            for (int j = 0; j < 8; j++) Ws[(q * 8 + j) * LDH + kk] = vv.h[j];
        }
        __syncthreads();

        #pragma unroll
        for (int kk = 0; kk < 64; kk += 16) {
            uint32_t af[4][4], bf[4][2];
            #pragma unroll
            for (int mi = 0; mi < 4; mi++)
                LDM_X4(af[mi][0], af[mi][1], af[mi][2], af[mi][3],
                       aLane + (uint32_t)(mi * 16 * LDH + kk) * 2);
            LDM_X4(bf[0][0], bf[0][1], bf[1][0], bf[1][1], bLane + (uint32_t)kk * 2);
            LDM_X4(bf[2][0], bf[2][1], bf[3][0], bf[3][1],
                   bLane + (uint32_t)(16 * LDH + kk) * 2);
            #pragma unroll
            for (int mi = 0; mi < 4; mi++)
                #pragma unroll
                for (int nj = 0; nj < 4; nj++)
                    hmma16(acc[mi][nj], af[mi], bf[nj]);
        }
    }

    #pragma unroll
    for (int mi = 0; mi < 4; mi++) {
        int r0 = bm + warpM * 64 + mi * 16 + g;
        #pragma unroll
        for (int nj = 0; nj < 4; nj++) {
            int c = bn + warpN * 32 + nj * 8 + 2 * tg;
            if (r0 < M)
                *(uint32_t*)&Cb[(size_t)r0 * ldc + c] = packh2(acc[mi][nj][0], acc[mi][nj][1]);
            if (r0 + 8 < M)
                *(uint32_t*)&Cb[(size_t)(r0 + 8) * ldc + c] = packh2(acc[mi][nj][2], acc[mi][nj][3]);
        }
    }
}

// ============================ persistent fused attention (one CTA per (b,h)) ==============
// Dynamic SMEM: Qs[128*40] | Ks[512*40] | Vs[40*520] (rows 0..31 V^T, row 32 ones).
__global__ __launch_bounds__(256, 2) void fused_attn_h(
    const __half* __restrict__ qkv, __half* __restrict__ o, float escale)
{
    extern __shared__ __half fa_sm[];
    __half* Qs = fa_sm;                  // 128*40
    __half* Ks = Qs + 128 * 40;          // 512*40
    __half* Vs = Ks + 512 * 40;          // 40*520

    int tid = threadIdx.x, lane = tid & 31, w = tid >> 5;
    int g = lane >> 2, tg = lane & 3;
    int z  = blockIdx.x;
    int b  = z >> 3, h = z & 7;
    const __half* base = qkv + (size_t)b * CC * 768;

    int arow = (lane & 7) + ((lane & 8) ? 8 : 0);
    int acol = (lane & 16) ? 8 : 0;
    int brow = (lane & 7) + ((lane & 16) ? 8 : 0);
    int bcol = (lane & 8) ? 8 : 0;
    uint32_t qBase = smem_u32(Qs) + (uint32_t)((w * 16 + arow) * 40 + acol) * 2;
    uint32_t kBase = smem_u32(Ks) + (uint32_t)(brow * 40 + bcol) * 2;
    uint32_t vBase = smem_u32(Vs) + (uint32_t)(brow * 520 + bcol) * 2;
    uint32_t onesAddr = smem_u32(Vs) +
        (uint32_t)((32 + (lane & 7)) * 520 + ((lane & 8) ? 8 : 0)) * 2;

    // ---- load ALL K and V (transposed) once ----
    for (int idx = tid; idx < 512 * 4; idx += 256) {
        int r = idx >> 2, q4 = idx & 3;
        const __half* kr = base + (size_t)r * 768 + 256 + h * 32 + q4 * 8;
        *(uint4*)&Ks[r * 40 + q4 * 8] = *(const uint4*)kr;
        union { uint4 u; __half hh[8]; } vv;
        vv.u = *(const uint4*)(kr + 256);
        #pragma unroll
        for (int j = 0; j < 8; j++) Vs[(q4 * 8 + j) * 520 + r] = vv.hh[j];
    }
    for (int idx = tid; idx < 8 * 520; idx += 256) {
        int r = 32 + idx / 520, c = idx % 520;
        Vs[r * 520 + c] = (r == 32) ? __float2half(1.f) : __float2half(0.f);
    }
    __syncthreads();

    uint32_t bones[2];
    LDM_X2(bones[0], bones[1], onesAddr);

    const float se = escale * 1.4426950408889634f;

    for (int qt = 0; qt < 4; qt++) {
        if (qt) __syncthreads();   // prior qt's Qs reads done before overwrite
        #pragma unroll
        for (int idx = tid; idx < 128 * 4; idx += 256) {
            int r = idx >> 2, q4 = idx & 3;
            *(uint4*)&Qs[r * 40 + q4 * 8] =
                *(const uint4*)(base + (size_t)(qt * 128 + r) * 768 + h * 32 + q4 * 8);
        }
        __syncthreads();

        uint32_t af0[4], af1[4];
        LDM_X4(af0[0], af0[1], af0[2], af0[3], qBase);
        LDM_X4(af1[0], af1[1], af1[2], af1[3], qBase + 32u);

        float oacc[4][4];
        #pragma unroll
        for (int i = 0; i < 4; i++)
            #pragma unroll
            for (int q = 0; q < 4; q++) oacc[i][q] = 0.f;
        float smsum[4] = {0.f, 0.f, 0.f, 0.f};

        #pragma unroll 4
        for (int p8 = 0; p8 < 32; p8++) {
            uint32_t kb0[4], kb1[4];
            LDM_X4(kb0[0], kb0[1], kb0[2], kb0[3],
                   kBase + (uint32_t)(p8 * 16 * 40) * 2);
            LDM_X4(kb1[0], kb1[1], kb1[2], kb1[3],
                   kBase + (uint32_t)(p8 * 16 * 40 + 16) * 2);
            float sl[4] = {0.f, 0.f, 0.f, 0.f};
            float sh[4] = {0.f, 0.f, 0.f, 0.f};
            hmma16(sl, af0, kb0);
            hmma16(sh, af0, kb0 + 2);
            hmma16(sl, af1, kb1);
            hmma16(sh, af1, kb1 + 2);

            uint32_t a[4];
            {
                __half2 e;
                e = h2exp2(__floats2half2_rn(sl[0] * se, sl[1] * se)); a[0] = *(uint32_t*)&e;
                e = h2exp2(__floats2half2_rn(sl[2] * se, sl[3] * se)); a[1] = *(uint32_t*)&e;
                e = h2exp2(__floats2half2_rn(sh[0] * se, sh[1] * se)); a[2] = *(uint32_t*)&e;
                e = h2exp2(__floats2half2_rn(sh[2] * se, sh[3] * se)); a[3] = *(uint32_t*)&e;
            }

            uint32_t v0[4], v1[4];
            LDM_X4(v0[0], v0[1], v0[2], v0[3],
                   vBase + (uint32_t)(p8 * 16) * 2);
            LDM_X4(v1[0], v1[1], v1[2], v1[3],
                   vBase + (uint32_t)(16 * 520 + p8 * 16) * 2);
            hmma16(oacc[0], a, v0);
            hmma16(oacc[1], a, v0 + 2);
            hmma16(oacc[2], a, v1);
            hmma16(oacc[3], a, v1 + 2);
            hmma16(smsum, a, bones);
        }

        float rs0 = __shfl_sync(0xffffffffu, smsum[0], lane & ~3);
        float rs1 = __shfl_sync(0xffffffffu, smsum[2], lane & ~3);
        float inv0 = 1.f / rs0, inv1 = 1.f / rs1;
        int row0 = b * CC + qt * 128 + w * 16 + g;
        #pragma unroll
        for (int vj = 0; vj < 4; vj++) {
            int c = h * 32 + vj * 8 + 2 * tg;
            *(uint32_t*)&o[(size_t)row0 * 256 + c] =
                packh2(oacc[vj][0] * inv0, oacc[vj][1] * inv0);
            *(uint32_t*)&o[(size_t)(row0 + 8) * 256 + c] =
                packh2(oacc[vj][2] * inv1, oacc[vj][3] * inv1);
        }
    }
}

// ---------------- mask dtype detection ----------------
__global__ void detect_mask_kernel(const int* __restrict__ m) {
    __shared__ int found;
    if (threadIdx.x == 0) found = 0;
    __syncthreads();
    int idx = blockIdx.x * blockDim.x + threadIdx.x;
    unsigned v = (unsigned)m[idx];
    if (v > 1u) found = 1;
    __syncthreads();
    if (threadIdx.x == 0 && blockIdx.x == 0) g_maskmode = 0;
    __threadfence();
    if (found) g_maskmode = 1;
}

// ---------------- pool (half output) ----------------
__global__ void pool_kernel(const int* __restrict__ vi, const int* __restrict__ si,
                            const void* __restrict__ maskraw,
                            const float* __restrict__ ve, const float* __restrict__ se,
                            const float* __restrict__ lpe, const float* __restrict__ cpe,
                            __half* __restrict__ x) {
    int bc = blockIdx.x;
    int c  = bc % CC;
    int d  = threadIdx.x;
    const int* viR = vi + bc * LL;
    const int* siR = si + bc * LL;
    __shared__ int mloc[LL];
    if (threadIdx.x < LL) {
        int mv;
        if (g_maskmode == 0) mv = ((const int*)maskraw)[bc * LL + threadIdx.x];
        else                 mv = ((const unsigned char*)maskraw)[bc * LL + threadIdx.x];
        mloc[threadIdx.x] = mv;
    }
    __syncthreads();
    float acc = 0.f; int cnt = 0;
    #pragma unroll
    for (int l = 0; l < LL; l++) {
        if (mloc[l]) {
            cnt++;
            acc += ve[viR[l]*DD + d] + se[siR[l]*DD + d] + lpe[l*DD + d];
        }
    }
    x[(size_t)bc*DD + d] = __float2half(acc / (float)cnt + cpe[c*DD + d]);
}

// ---------------- warp-per-row LN for N=256 half tensors ----------------
template<int RES>
__global__ __launch_bounds__(256) void ln256(
    const __half* __restrict__ xin, const __half* __restrict__ res,
    const float* __restrict__ w, const float* __restrict__ b,
    __half* __restrict__ out)
{
    int row  = blockIdx.x * 8 + (threadIdx.x >> 5);
    int lane = threadIdx.x & 31;
    size_t off = (size_t)row * 256 + lane * 8;

    union { uint4 u; __half h[8]; } xv, rv;
    xv.u = *(const uint4*)(xin + off);
    if (RES) rv.u = *(const uint4*)(res + off);

    float v[8];
    float s = 0.f;
    #pragma unroll
    for (int j = 0; j < 8; j++) {
        float t = __half2float(xv.h[j]);
        if (RES) t += __half2float(rv.h[j]);
        v[j] = t; s += t;
    }
    #pragma unroll
    for (int o2 = 16; o2; o2 >>= 1) s += __shfl_xor_sync(0xffffffffu, s, o2);
    float mean = s * (1.f / 256.f);
    float vs = 0.f;
    #pragma unroll
    for (int j = 0; j < 8; j++) { float d = v[j] - mean; vs += d * d; }
    #pragma unroll
    for (int o2 = 16; o2; o2 >>= 1) vs += __shfl_xor_sync(0xffffffffu, vs, o2);
    float inv = rsqrtf(vs * (1.f / 256.f) + 1e-5f);

    float4 w0 = *(const float4*)(w + lane * 8);
    float4 w1 = *(const float4*)(w + lane * 8 + 4);
    float4 b0 = *(const float4*)(b + lane * 8);
    float4 b1 = *(const float4*)(b + lane * 8 + 4);
    float ww[8] = {w0.x, w0.y, w0.z, w0.w, w1.x, w1.y, w1.z, w1.w};
    float bb[8] = {b0.x, b0.y, b0.z, b0.w, b1.x, b1.y, b1.z, b1.w};

    union { uint4 u; __half h[8]; } ov;
    #pragma unroll
    for (int j = 0; j < 8; j++)
        ov.h[j] = __float2half((v[j] - mean) * inv * ww[j] + bb[j]);
    *(uint4*)(out + off) = ov.u;
}

// ---------------- generic layernorm (final N=1024 fp32 path) ----------------
__global__ void ln_kernel(const void* __restrict__ xin, int inH,
                          const void* __restrict__ res, int resM,
                          const float* __restrict__ w, const float* __restrict__ b,
                          void* __restrict__ out, int outH, int N, int resMod) {
    int row = blockIdx.x;
    int tid = threadIdx.x;
    int rrow = resMod ? (row % resMod) : row;
    int per = N >> 8;
    float v[4];
    float s = 0.f;
    for (int i = 0; i < per; i++) {
        int cI = tid + (i << 8);
        float t = inH ? __half2float(((const __half*)xin)[(size_t)row * N + cI])
                      : ((const float*)xin)[(size_t)row * N + cI];
        if (resM == 1)      t += ((const float*)res)[(size_t)rrow * N + cI];
        else if (resM == 2) t += __half2float(((const __half*)res)[(size_t)rrow * N + cI]);
        v[i] = t; s += t;
    }
    __shared__ float red[256];
    red[tid] = s; __syncthreads();
    for (int o = 128; o; o >>= 1) { if (tid < o) red[tid] += red[tid+o]; __syncthreads(); }
    float mean = red[0] / (float)N;
    __syncthreads();
    float vs = 0.f;
    for (int i = 0; i < per; i++) { float d = v[i] - mean; vs += d*d; }
    red[tid] = vs; __syncthreads();
    for (int o = 128; o; o >>= 1) { if (tid < o) red[tid] += red[tid+o]; __syncthreads(); }
    float inv = rsqrtf(red[0] / (float)N + 1e-5f);
    for (int i = 0; i < per; i++) {
        int cI = tid + (i << 8);
        float ov = (v[i] - mean) * inv * w[cI] + b[cI];
        if (outH) ((__half*)out)[(size_t)row*N + cI] = __float2half(ov);
        else      ((float*)out)[(size_t)row*N + cI] = ov;
    }
}

// ---------------- strided softmax: S2T [b][c=512][hp=128] fp32 -> P [b][hp][c] half ------
__global__ void sm2T(const float* __restrict__ S2T, __half* __restrict__ Sh) {
    int wrow = blockIdx.x * 8 + (threadIdx.x >> 5);
    int lane = threadIdx.x & 31;
    int b = wrow >> 7, hp = wrow & 127;
    const float* src = S2T + (size_t)b * CC * 128 + hp;
    float vals[16];
    float mx = -1e30f;
    #pragma unroll
    for (int t = 0; t < 16; t++) {
        vals[t] = src[(size_t)(lane + (t << 5)) * 128];
        mx = fmaxf(mx, vals[t]);
    }
    for (int o = 16; o; o >>= 1) mx = fmaxf(mx, __shfl_xor_sync(0xffffffffu, mx, o));
    float sum = 0.f;
    #pragma unroll
    for (int t = 0; t < 16; t++) { vals[t] = __expf(vals[t] - mx); sum += vals[t]; }
    for (int o = 16; o; o >>= 1) sum += __shfl_xor_sync(0xffffffffu, sum, o);
    float inv = 1.f / sum;
    __half* dst = Sh + (size_t)wrow * CC;
    #pragma unroll
    for (int t = 0; t < 16; t++) dst[lane + (t << 5)] = __float2half(vals[t] * inv);
}

// ============================ host orchestration ============================
#define HG_B   hgemm<0,1,1>
#define HG_BF  hgemm<0,1,0>
#define HG_G   hgemm<1,1,1>
#define HG_N   hgemm<0,0,0>

static const int HG_SMEM = 6 * 128 * 72 * 2;                 // 110592 B
static const int FA_SMEM = (128*40 + 512*40 + 40*520) * 2;   // 92800 B

static void cvh(const float* src, __half* dst, int n) {
    cvt_h<<<(n/4 + 255)/256, 256>>>(src, dst, n/4);
}

extern "C" void kernel_launch(void* const* d_in, const int* in_sizes, int n_in,
                              void* d_out, int out_size) {
    const int*   var_idx   = (const int*)  d_in[0];
    const int*   sign_idx  = (const int*)  d_in[1];
    const void*  lit_mask  = (const void*) d_in[2];
    const float* var_emb   = (const float*)d_in[3];
    const float* sign_emb  = (const float*)d_in[4];
    const float* litpos    = (const float*)d_in[5];
    const float* clausepos = (const float*)d_in[6];
    const float* enc_in_w  = (const float*)d_in[7];
    const float* enc_in_b  = (const float*)d_in[8];
    const float* enc_out_w = (const float*)d_in[9];
    const float* enc_out_b = (const float*)d_in[10];
    const float* enc_ff1_w = (const float*)d_in[11];
    const float* enc_ff1_b = (const float*)d_in[12];
    const float* enc_ff2_w = (const float*)d_in[13];
    const float* enc_ff2_b = (const float*)d_in[14];
    const float* n1w = (const float*)d_in[15];
    const float* n1b = (const float*)d_in[16];
    const float* n2w = (const float*)d_in[17];
    const float* n2b = (const float*)d_in[18];
    const float* th_ln_w = (const float*)d_in[19];
    const float* th_ln_b = (const float*)d_in[20];
    const float* th_w = (const float*)d_in[21];
    const float* th_b = (const float*)d_in[22];
    const float* pq   = (const float*)d_in[23];
    const float* pa_in_w  = (const float*)d_in[24];
    const float* pa_in_b  = (const float*)d_in[25];
    const float* pa_out_w = (const float*)d_in[26];
    const float* pa_out_b = (const float*)d_in[27];
    const float* pn_w = (const float*)d_in[28];
    const float* pn_b = (const float*)d_in[29];
    float* out = (float*)d_out;

    __half *x,*t0,*t1,*t2h,*ch,*qh,*qw,*S2h,*pch,*p1;
    float *S2,*p2;
    __half *hwin,*hwout,*hwf1,*hwf2,*hwth,*hwpa,*hwpo,*hwpq;
    cudaGetSymbolAddress((void**)&x,   g_x);
    cudaGetSymbolAddress((void**)&t0,  g_t0);
    cudaGetSymbolAddress((void**)&t1,  g_t1);
    cudaGetSymbolAddress((void**)&t2h, g_t2h);
    cudaGetSymbolAddress((void**)&ch,  g_ch);
    cudaGetSymbolAddress((void**)&qh,  g_qh);
    cudaGetSymbolAddress((void**)&qw,  g_qw);
    cudaGetSymbolAddress((void**)&S2,  g_S2);
    cudaGetSymbolAddress((void**)&S2h, g_S2h);
    cudaGetSymbolAddress((void**)&pch, g_pch);
    cudaGetSymbolAddress((void**)&p1,  g_p1);
    cudaGetSymbolAddress((void**)&p2,  g_p2);
    cudaGetSymbolAddress((void**)&hwin,  g_hw_in);
    cudaGetSymbolAddress((void**)&hwout, g_hw_out);
    cudaGetSymbolAddress((void**)&hwf1,  g_hw_f1);
    cudaGetSymbolAddress((void**)&hwf2,  g_hw_f2);
    cudaGetSymbolAddress((void**)&hwth,  g_hw_th);
    cudaGetSymbolAddress((void**)&hwpa,  g_hw_pa);
    cudaGetSymbolAddress((void**)&hwpo,  g_hw_po);
    cudaGetSymbolAddress((void**)&hwpq,  g_hw_pq);

    cudaFuncSetAttribute(HG_B,  cudaFuncAttributeMaxDynamicSharedMemorySize, HG_SMEM);
    cudaFuncSetAttribute(HG_BF, cudaFuncAttributeMaxDynamicSharedMemorySize, HG_SMEM);
    cudaFuncSetAttribute(HG_G,  cudaFuncAttributeMaxDynamicSharedMemorySize, HG_SMEM);
    cudaFuncSetAttribute(HG_N,  cudaFuncAttributeMaxDynamicSharedMemorySize, HG_SMEM);
    cudaFuncSetAttribute(fused_attn_h, cudaFuncAttributeMaxDynamicSharedMemorySize, FA_SMEM);

    const int M = BB*CC;
    const float escale = 0.17677669529663687f;   // 1/sqrt(32)
    const float pscale = 0.08838834764831845f;   // 1/sqrt(128)

    // launches 1-5, then layer-0 qkv as 6th (ncu -s 5 -c 1 target)
    cvh(enc_in_w,  hwin,  NLL*768*DD);                                   // 1
    detect_mask_kernel<<<16, 256>>>((const int*)lit_mask);               // 2
    pool_kernel<<<M, 256>>>(var_idx, sign_idx, lit_mask, var_emb,        // 3
                            sign_emb, litpos, clausepos, x);
    cvh(enc_out_w, hwout, NLL*DD*DD);                                    // 4
    cvh(enc_ff1_w, hwf1,  NLL*HH*DD);                                    // 5
    HG_B<<<dim3(6,128,1),256,HG_SMEM>>>(x, hwin, enc_in_b, t0, M,768,DD, // 6
                                        DD,DD,768, 1,0,0,0,0,0,0, 0, 1.f);
    cvh(enc_ff2_w, hwf2,  NLL*DD*HH);
    cvh(th_w,      hwth,  HH*DD);
    cvh(pa_in_w,   hwpa,  3*HH*HH);
    cvh(pa_out_w,  hwpo,  HH*HH);
    cvh(pq,        hwpq,  PP*HH);

    for (int i = 0; i < NLL; i++) {
        const __half* wqkv = hwin  + (size_t)i*768*DD;
        const float*  bqkv = enc_in_b  + (size_t)i*768;
        const __half* wo   = hwout + (size_t)i*DD*DD;
        const float*  bo   = enc_out_b + (size_t)i*DD;
        const __half* w1   = hwf1  + (size_t)i*HH*DD;
        const float*  b1   = enc_ff1_b + (size_t)i*HH;
        const __half* w2   = hwf2  + (size_t)i*DD*HH;
        const float*  b2   = enc_ff2_b + (size_t)i*DD;

        if (i > 0)
            HG_B<<<dim3(6,128,1),256,HG_SMEM>>>(x, wqkv, bqkv, t0, M,768,DD,
                                                DD,DD,768, 1,0,0,0,0,0,0, 0, 1.f);
        fused_attn_h<<<BB*NHD, 256, FA_SMEM>>>(t0, t1, escale);
        HG_B<<<dim3(2,128,1),256,HG_SMEM>>>(t1, wo, bo, t2h, M,DD,DD,
                                            DD,DD,DD, 1,0,0,0,0,0,0, 0, 1.f);
        ln256<1><<<M/8,256>>>(t2h, x, n1w + i*DD, n1b + i*DD, x);
        HG_G<<<dim3(8,128,1),256,HG_SMEM>>>(x, w1, b1, t0, M,HH,DD,
                                            DD,DD,HH, 1,0,0,0,0,0,0, 0, 1.f);
        HG_B<<<dim3(2,128,1),256,HG_SMEM>>>(t0, w2, b2, t2h, M,DD,HH,
                                            HH,HH,DD, 1,0,0,0,0,0,0, 0, 1.f);
        ln256<1><<<M/8,256>>>(t2h, x, n2w + i*DD, n2b + i*DD, x);
    }

    // ch = LN(x) @ th_w^T + th_b  (half)
    ln256<0><<<M/8,256>>>(x, nullptr, th_ln_w, th_ln_b, t2h);
    HG_B<<<dim3(8,128,1),256,HG_SMEM>>>(t2h, hwth, th_b, ch, M,HH,DD,
                                        DD,DD,HH, 1,0,0,0,0,0,0, 0, 1.f);

    // ---- prefix cross-attention (restructured) ----
    HG_B<<<dim3(8,1,1),256,HG_SMEM>>>(hwpq, hwpa, pa_in_b, qh, PP,HH,HH,
                                      HH,HH,HH, 1,0,0,0,0,0,0, 0, 1.f);
    hgemm_trb<<<dim3(8,1,NHD),256>>>(qh, hwpa + (size_t)HH*HH, qw,
                                     16, HH, 128, HH, HH, HH,
                                     NHD, 0, 128, 0, (long)128*HH, 0, (long)16*HH);
    HG_N<<<dim3(1,4,BB),256,HG_SMEM>>>(ch, qw, nullptr, S2, CC,128,HH,
                                       HH,HH,128, 1,
                                       (long)CC*HH, 0, 0, 0, (long)CC*128, 0, 0, pscale);
    sm2T<<<(BB*128)/8, 256>>>(S2, S2h);
    hgemm_trb<<<dim3(8,1,BB),256>>>(S2h, ch, pch,
                                    128, HH, CC, CC, HH, HH,
                                    1, (long)128*CC, 0, (long)CC*HH, 0, (long)128*HH, 0);
    HG_B<<<dim3(1,1,BB*NHD),256,HG_SMEM>>>(pch, hwpa + (size_t)2*HH*HH, pa_in_b + 2*HH, p1,
                                           16,128,HH, HH,HH,HH, NHD,
                                           (long)128*HH, (long)16*HH, 0, (long)128*HH,
                                           (long)PP*HH, 128, 128, 1.f);
    HG_BF<<<dim3(8,4,1),256,HG_SMEM>>>(p1, hwpo, pa_out_b, p2, BB*PP,HH,HH,
                                       HH,HH,HH, 1,0,0,0,0,0,0, 0, 1.f);
    ln_kernel<<<BB*PP,256>>>(p2, 0, pq, 1, pn_w, pn_b, out, 0, HH, PP);
}

// round 16
// speedup vs baseline: 9.1699x; 1.0237x over previous
#include <cuda_runtime.h>
#include <cuda_fp16.h>
#include <cstdint>

#define BB 32
#define CC 512
#define LL 16
#define DD 256
#define HH 1024
#define PP 16
#define NHD 8
#define NLL 4

// ---------------- scratch (static device globals; allocation-free) ----------------
__device__ __half g_x  [BB*CC*DD];
__device__ __half g_t0 [BB*CC*HH];
__device__ __half g_t1 [BB*CC*DD];
__device__ __half g_t2h[BB*CC*DD];
__device__ __half g_ch [BB*CC*HH];
__device__ __half g_qh [PP*HH];
__device__ __half g_qw [128*HH];
__device__ float  g_S2 [BB*128*CC];       // S2 [b][hp][c]  (row-major over c)
__device__ __half g_S2h[BB*128*CC];       // P  [b][hp][c]
__device__ __half g_pch[BB*128*HH];
__device__ __half g_p1 [BB*PP*HH];
__device__ float  g_p2 [BB*PP*HH];
__device__ int    g_maskmode;
// half weights
__device__ __half g_hw_in [NLL*768*DD];
__device__ __half g_hw_out[NLL*DD*DD];
__device__ __half g_hw_f1 [NLL*HH*DD];
__device__ __half g_hw_f2 [NLL*DD*HH];
__device__ __half g_hw_th [HH*DD];
__device__ __half g_hw_pa [3*HH*HH];
__device__ __half g_hw_po [HH*HH];
__device__ __half g_hw_pq [PP*HH];

// ---------------- small helpers ----------------
__device__ __forceinline__ uint32_t smem_u32(const void* p) {
    uint32_t a;
    asm("{ .reg .u64 t; cvta.to.shared.u64 t, %1; cvt.u32.u64 %0, t; }" : "=r"(a) : "l"(p));
    return a;
}
__device__ __forceinline__ float gelu_f(float v) {
    return 0.5f * v * (1.f + erff(v * 0.70710678118654752f));
}
__device__ __forceinline__ uint32_t packh2(float lo, float hi) {
    __half2 h = __floats2half2_rn(lo, hi);
    return *(uint32_t*)&h;
}
__device__ __forceinline__ void hmma16(float* c, const uint32_t* a, const uint32_t* b) {
    asm("mma.sync.aligned.m16n8k16.row.col.f32.f16.f16.f32 "
        "{%0,%1,%2,%3}, {%4,%5,%6,%7}, {%8,%9}, {%0,%1,%2,%3};"
        : "+f"(c[0]), "+f"(c[1]), "+f"(c[2]), "+f"(c[3])
        : "r"(a[0]), "r"(a[1]), "r"(a[2]), "r"(a[3]), "r"(b[0]), "r"(b[1]));
}
#define LDM_X4(r0, r1, r2, r3, addr) \
    asm volatile("ldmatrix.sync.aligned.m8n8.x4.shared.b16 {%0,%1,%2,%3}, [%4];" \
        : "=r"(r0), "=r"(r1), "=r"(r2), "=r"(r3) : "r"(addr))
#define LDM_X2(r0, r1, addr) \
    asm volatile("ldmatrix.sync.aligned.m8n8.x2.shared.b16 {%0,%1}, [%2];" \
        : "=r"(r0), "=r"(r1) : "r"(addr))
#define CPA16(dst, src, pred) \
    asm volatile("cp.async.cg.shared.global [%0], [%1], 16, %2;" \
                 :: "r"(dst), "l"(src), "r"((pred) ? 16 : 0))
#define CP_COMMIT() asm volatile("cp.async.commit_group;")
#define CP_WAIT1()  asm volatile("cp.async.wait_group 1;")
#define CP_WAIT0()  asm volatile("cp.async.wait_group 0;")

// ---------------- single-launch fp32->fp16 conversion of ALL weights ----------------
static const int CV_N0 = NLL*768*DD/4;     // in
static const int CV_N1 = CV_N0 + NLL*DD*DD/4;
static const int CV_N2 = CV_N1 + NLL*HH*DD/4;
static const int CV_N3 = CV_N2 + NLL*DD*HH/4;
static const int CV_N4 = CV_N3 + HH*DD/4;
static const int CV_N5 = CV_N4 + 3*HH*HH/4;
static const int CV_N6 = CV_N5 + HH*HH/4;
static const int CV_N7 = CV_N6 + PP*HH/4;

__global__ void cvt_all(
    const float* s0, const float* s1, const float* s2, const float* s3,
    const float* s4, const float* s5, const float* s6, const float* s7,
    __half* d0, __half* d1, __half* d2, __half* d3,
    __half* d4, __half* d5, __half* d6, __half* d7)
{
    for (int i = blockIdx.x * 256 + threadIdx.x; i < CV_N7; i += gridDim.x * 256) {
        const float* s; __half* d; int off;
        if      (i < CV_N0) { s = s0; d = d0; off = i; }
        else if (i < CV_N1) { s = s1; d = d1; off = i - CV_N0; }
        else if (i < CV_N2) { s = s2; d = d2; off = i - CV_N1; }
        else if (i < CV_N3) { s = s3; d = d3; off = i - CV_N2; }
        else if (i < CV_N4) { s = s4; d = d4; off = i - CV_N3; }
        else if (i < CV_N5) { s = s5; d = d5; off = i - CV_N4; }
        else if (i < CV_N6) { s = s6; d = d6; off = i - CV_N5; }
        else                { s = s7; d = d7; off = i - CV_N6; }
        float4 v = ((const float4*)s)[off];
        uint2 u;
        u.x = packh2(v.x, v.y);
        u.y = packh2(v.z, v.w);
        ((uint2*)d)[off] = u;
    }
}

// ============================ fp16 3-stage cp.async + ldmatrix GEMM ============================
template<int ACT, int HASB, int OUTH>
__global__ __launch_bounds__(256, 2) void hgemm(
    const __half* __restrict__ A, const __half* __restrict__ W,
    const float* __restrict__ bias, void* __restrict__ Cp,
    int M, int N, int K, int lda, int ldw, int ldc,
    int nsub, long sAb, long sAs, long sWb, long sWs, long sCb, long sCs,
    long sBs, float alpha)
{
    constexpr int BM = 128, BN = 128, BK = 64, LDH = 72, NST = 3;
    constexpr uint32_t STB = BM * LDH * 2;
    extern __shared__ __half smh[];
    uint32_t base = smem_u32(smh);
    uint32_t asA = base;
    uint32_t wsA = base + NST * STB;

    int tid = threadIdx.x, wid = tid >> 5, lane = tid & 31;
    int warpM = wid >> 2, warpN = wid & 3;
    int g = lane >> 2, tg = lane & 3;
    int bm = blockIdx.y * BM, bn = blockIdx.x * BN;
    int z = blockIdx.z, zb = z / nsub, zs = z % nsub;
    const __half* Ab = A + (size_t)zb * sAb + (size_t)zs * sAs;
    const __half* Wb = W + (size_t)zb * sWb + (size_t)zs * sWs;
    const float* biasB = HASB ? (bias + (size_t)zs * sBs) : bias;

    int arow = (lane & 7) + ((lane & 8) ? 8 : 0);
    int acol = (lane & 16) ? 8 : 0;
    int brow = (lane & 7) + ((lane & 16) ? 8 : 0);
    int bcol = (lane & 8) ? 8 : 0;
    uint32_t aLane = (uint32_t)((warpM * 64 + arow) * LDH + acol) * 2;
    uint32_t bLane = (uint32_t)((warpN * 32 + brow) * LDH + bcol) * 2;

    auto load_stage = [&](int st, int k0) {
        uint32_t ab = asA + (uint32_t)st * STB;
        uint32_t wb = wsA + (uint32_t)st * STB;
        #pragma unroll
        for (int idx = tid; idx < BM * 8; idx += 256) {
            int row = idx >> 3, q = idx & 7;
            int gm = bm + row;
            bool ok = gm < M;
            int gmc = ok ? gm : 0;
            CPA16(ab + (uint32_t)(row * LDH + q * 8) * 2,
                  Ab + (size_t)gmc * lda + k0 + q * 8, ok);
        }
        #pragma unroll
        for (int idx = tid; idx < BN * 8; idx += 256) {
            int row = idx >> 3, q = idx & 7;
            CPA16(wb + (uint32_t)(row * LDH + q * 8) * 2,
                  Wb + (size_t)(bn + row) * ldw + k0 + q * 8, true);
        }
        CP_COMMIT();
    };

    float acc[4][4][4];
    #pragma unroll
    for (int i = 0; i < 4; i++)
        #pragma unroll
        for (int j = 0; j < 4; j++)
            #pragma unroll
            for (int q = 0; q < 4; q++) acc[i][j][q] = 0.f;

    int nk = K / BK;
    load_stage(0, 0);
    if (nk > 1) load_stage(1, BK);

    for (int i = 0; i < nk; i++) {
        if (i + 1 < nk) CP_WAIT1(); else CP_WAIT0();
        __syncthreads();
        if (i + 2 < nk) load_stage((i + 2) % NST, (i + 2) * BK);

        int cur = i % NST;
        uint32_t aB = asA + (uint32_t)cur * STB + aLane;
        uint32_t wB = wsA + (uint32_t)cur * STB + bLane;

        uint32_t af[2][4][4], bf[2][4][2];
        #pragma unroll
        for (int mi = 0; mi < 4; mi++)
            LDM_X4(af[0][mi][0], af[0][mi][1], af[0][mi][2], af[0][mi][3],
                   aB + (uint32_t)(mi * 16 * LDH) * 2);
        LDM_X4(bf[0][0][0], bf[0][0][1], bf[0][1][0], bf[0][1][1], wB);
        LDM_X4(bf[0][2][0], bf[0][2][1], bf[0][3][0], bf[0][3][1],
               wB + (uint32_t)(16 * LDH) * 2);

        #pragma unroll
        for (int ks = 0; ks < 4; ks++) {
            int cb = ks & 1, nb = cb ^ 1;
            if (ks < 3) {
                int kk = (ks + 1) * 16;
                #pragma unroll
                for (int mi = 0; mi < 4; mi++)
                    LDM_X4(af[nb][mi][0], af[nb][mi][1], af[nb][mi][2], af[nb][mi][3],
                           aB + (uint32_t)(mi * 16 * LDH + kk) * 2);
                LDM_X4(bf[nb][0][0], bf[nb][0][1], bf[nb][1][0], bf[nb][1][1],
                       wB + (uint32_t)kk * 2);
                LDM_X4(bf[nb][2][0], bf[nb][2][1], bf[nb][3][0], bf[nb][3][1],
                       wB + (uint32_t)(16 * LDH + kk) * 2);
            }
            #pragma unroll
            for (int mi = 0; mi < 4; mi++)
                #pragma unroll
                for (int nj = 0; nj < 4; nj++)
                    hmma16(acc[mi][nj], af[cb][mi], bf[cb][nj]);
        }
    }

    long cOff = (size_t)zb * sCb + (size_t)zs * sCs;
    #pragma unroll
    for (int mi = 0; mi < 4; mi++) {
        int r0 = bm + warpM * 64 + mi * 16 + g;
        #pragma unroll
        for (int nj = 0; nj < 4; nj++) {
            int c = bn + warpN * 32 + nj * 8 + 2 * tg;
            float b0 = 0.f, b1 = 0.f;
            if (HASB) { b0 = biasB[c]; b1 = biasB[c + 1]; }
            float v0 = acc[mi][nj][0] * alpha + b0;
            float v1 = acc[mi][nj][1] * alpha + b1;
            float v2 = acc[mi][nj][2] * alpha + b0;
            float v3 = acc[mi][nj][3] * alpha + b1;
            if (ACT) { v0 = gelu_f(v0); v1 = gelu_f(v1); v2 = gelu_f(v2); v3 = gelu_f(v3); }
            if (OUTH) {
                __half* Cb = (__half*)Cp + cOff;
                if (r0 < M)     *(uint32_t*)&Cb[(size_t)r0 * ldc + c]       = packh2(v0, v1);
                if (r0 + 8 < M) *(uint32_t*)&Cb[(size_t)(r0 + 8) * ldc + c] = packh2(v2, v3);
            } else {
                float* Cb = (float*)Cp + cOff;
                if (r0 < M)     { Cb[(size_t)r0 * ldc + c] = v0; Cb[(size_t)r0 * ldc + c + 1] = v1; }
                if (r0 + 8 < M) { Cb[(size_t)(r0 + 8) * ldc + c] = v2; Cb[(size_t)(r0 + 8) * ldc + c + 1] = v3; }
            }
        }
    }
}

// ============================ transposed-B fp16 GEMM (W given [K,N] row-major) ============
__global__ __launch_bounds__(256, 2) void hgemm_trb(
    const __half* __restrict__ A, const __half* __restrict__ W, __half* __restrict__ Cp,
    int M, int N, int K, int lda, int ldw, int ldc,
    int nsub, long sAb, long sAs, long sWb, long sWs, long sCb, long sCs)
{
    constexpr int LDH = 72;
    __shared__ __half As[128 * LDH];
    __shared__ __half Ws[128 * LDH];

    int tid = threadIdx.x, wid = tid >> 5, lane = tid & 31;
    int warpM = wid >> 2, warpN = wid & 3;
    int g = lane >> 2, tg = lane & 3;
    int bm = blockIdx.y * 128, bn = blockIdx.x * 128;
    int z = blockIdx.z, zb = z / nsub, zs = z % nsub;
    const __half* Ab = A + (size_t)zb * sAb + (size_t)zs * sAs;
    const __half* Wb = W + (size_t)zb * sWb + (size_t)zs * sWs;
    __half* Cb = Cp + (size_t)zb * sCb + (size_t)zs * sCs;

    int arow = (lane & 7) + ((lane & 8) ? 8 : 0);
    int acol = (lane & 16) ? 8 : 0;
    int brow = (lane & 7) + ((lane & 16) ? 8 : 0);
    int bcol = (lane & 8) ? 8 : 0;
    uint32_t aLane = smem_u32(As) + (uint32_t)((warpM * 64 + arow) * LDH + acol) * 2;
    uint32_t bLane = smem_u32(Ws) + (uint32_t)((warpN * 32 + brow) * LDH + bcol) * 2;

    float acc[4][4][4];
    #pragma unroll
    for (int i = 0; i < 4; i++)
        #pragma unroll
        for (int j = 0; j < 4; j++)
            #pragma unroll
            for (int q = 0; q < 4; q++) acc[i][j][q] = 0.f;

    for (int k0 = 0; k0 < K; k0 += 64) {
        __syncthreads();
        #pragma unroll
        for (int idx = tid; idx < 128 * 8; idx += 256) {
            int row = idx >> 3, q = idx & 7;
            int gm = bm + row;
            int gmc = (gm < M) ? gm : 0;
            *(uint4*)&As[row * LDH + q * 8] =
                *(const uint4*)(Ab + (size_t)gmc * lda + k0 + q * 8);
        }
        #pragma unroll
        for (int idx = tid; idx < 64 * 16; idx += 256) {
            int kk = idx >> 4, q = idx & 15;
            union { uint4 u; __half h[8]; } vv;
            vv.u = *(const uint4*)(Wb + (size_t)(k0 + kk) * ldw + bn + q * 8);
            #pragma unroll
            for (int j = 0; j < 8; j++) Ws[(q * 8 + j) * LDH + kk] = vv.h[j];
        }
        __syncthreads();

        #pragma unroll
        for (int kk = 0; kk < 64; kk += 16) {
            uint32_t af[4][4], bf[4][2];
            #pragma unroll
            for (int mi = 0; mi < 4; mi++)
                LDM_X4(af[mi][0], af[mi][1], af[mi][2], af[mi][3],
                       aLane + (uint32_t)(mi * 16 * LDH + kk) * 2);
            LDM_X4(bf[0][0], bf[0][1], bf[1][0], bf[1][1], bLane + (uint32_t)kk * 2);
            LDM_X4(bf[2][0], bf[2][1], bf[3][0], bf[3][1],
                   bLane + (uint32_t)(16 * LDH + kk) * 2);
            #pragma unroll
            for (int mi = 0; mi < 4; mi++)
                #pragma unroll
                for (int nj = 0; nj < 4; nj++)
                    hmma16(acc[mi][nj], af[mi], bf[nj]);
        }
    }

    #pragma unroll
    for (int mi = 0; mi < 4; mi++) {
        int r0 = bm + warpM * 64 + mi * 16 + g;
        #pragma unroll
        for (int nj = 0; nj < 4; nj++) {
            int c = bn + warpN * 32 + nj * 8 + 2 * tg;
            if (r0 < M)
                *(uint32_t*)&Cb[(size_t)r0 * ldc + c] = packh2(acc[mi][nj][0], acc[mi][nj][1]);
            if (r0 + 8 < M)
                *(uint32_t*)&Cb[(size_t)(r0 + 8) * ldc + c] = packh2(acc[mi][nj][2], acc[mi][nj][3]);
        }
    }
}

// ============================ persistent fused attention (one CTA per (b,h)) ==============
__global__ __launch_bounds__(256, 2) void fused_attn_h(
    const __half* __restrict__ qkv, __half* __restrict__ o, float escale)
{
    extern __shared__ __half fa_sm[];
    __half* Qs = fa_sm;                  // 128*40
    __half* Ks = Qs + 128 * 40;          // 512*40
    __half* Vs = Ks + 512 * 40;          // 40*520

    int tid = threadIdx.x, lane = tid & 31, w = tid >> 5;
    int g = lane >> 2, tg = lane & 3;
    int z  = blockIdx.x;
    int b  = z >> 3, h = z & 7;
    const __half* base = qkv + (size_t)b * CC * 768;

    int arow = (lane & 7) + ((lane & 8) ? 8 : 0);
    int acol = (lane & 16) ? 8 : 0;
    int brow = (lane & 7) + ((lane & 16) ? 8 : 0);
    int bcol = (lane & 8) ? 8 : 0;
    uint32_t qBase = smem_u32(Qs) + (uint32_t)((w * 16 + arow) * 40 + acol) * 2;
    uint32_t kBase = smem_u32(Ks) + (uint32_t)(brow * 40 + bcol) * 2;
    uint32_t vBase = smem_u32(Vs) + (uint32_t)(brow * 520 + bcol) * 2;
    uint32_t onesAddr = smem_u32(Vs) +
        (uint32_t)((32 + (lane & 7)) * 520 + ((lane & 8) ? 8 : 0)) * 2;

    for (int idx = tid; idx < 512 * 4; idx += 256) {
        int r = idx >> 2, q4 = idx & 3;
        const __half* kr = base + (size_t)r * 768 + 256 + h * 32 + q4 * 8;
        *(uint4*)&Ks[r * 40 + q4 * 8] = *(const uint4*)kr;
        union { uint4 u; __half hh[8]; } vv;
        vv.u = *(const uint4*)(kr + 256);
        #pragma unroll
        for (int j = 0; j < 8; j++) Vs[(q4 * 8 + j) * 520 + r] = vv.hh[j];
    }
    for (int idx = tid; idx < 8 * 520; idx += 256) {
        int r = 32 + idx / 520, c = idx % 520;
        Vs[r * 520 + c] = (r == 32) ? __float2half(1.f) : __float2half(0.f);
    }
    __syncthreads();

    uint32_t bones[2];
    LDM_X2(bones[0], bones[1], onesAddr);

    const float se = escale * 1.4426950408889634f;

    for (int qt = 0; qt < 4; qt++) {
        if (qt) __syncthreads();
        #pragma unroll
        for (int idx = tid; idx < 128 * 4; idx += 256) {
            int r = idx >> 2, q4 = idx & 3;
            *(uint4*)&Qs[r * 40 + q4 * 8] =
                *(const uint4*)(base + (size_t)(qt * 128 + r) * 768 + h * 32 + q4 * 8);
        }
        __syncthreads();

        uint32_t af0[4], af1[4];
        LDM_X4(af0[0], af0[1], af0[2], af0[3], qBase);
        LDM_X4(af1[0], af1[1], af1[2], af1[3], qBase + 32u);

        float oacc[4][4];
        #pragma unroll
        for (int i = 0; i < 4; i++)
            #pragma unroll
            for (int q = 0; q < 4; q++) oacc[i][q] = 0.f;
        float smsum[4] = {0.f, 0.f, 0.f, 0.f};

        #pragma unroll 4
        for (int p8 = 0; p8 < 32; p8++) {
            uint32_t kb0[4], kb1[4];
            LDM_X4(kb0[0], kb0[1], kb0[2], kb0[3],
                   kBase + (uint32_t)(p8 * 16 * 40) * 2);
            LDM_X4(kb1[0], kb1[1], kb1[2], kb1[3],
                   kBase + (uint32_t)(p8 * 16 * 40 + 16) * 2);
            float sl[4] = {0.f, 0.f, 0.f, 0.f};
            float sh[4] = {0.f, 0.f, 0.f, 0.f};
            hmma16(sl, af0, kb0);
            hmma16(sh, af0, kb0 + 2);
            hmma16(sl, af1, kb1);
            hmma16(sh, af1, kb1 + 2);

            uint32_t a[4];
            {
                __half2 e;
                e = h2exp2(__floats2half2_rn(sl[0] * se, sl[1] * se)); a[0] = *(uint32_t*)&e;
                e = h2exp2(__floats2half2_rn(sl[2] * se, sl[3] * se)); a[1] = *(uint32_t*)&e;
                e = h2exp2(__floats2half2_rn(sh[0] * se, sh[1] * se)); a[2] = *(uint32_t*)&e;
                e = h2exp2(__floats2half2_rn(sh[2] * se, sh[3] * se)); a[3] = *(uint32_t*)&e;
            }

            uint32_t v0[4], v1[4];
            LDM_X4(v0[0], v0[1], v0[2], v0[3],
                   vBase + (uint32_t)(p8 * 16) * 2);
            LDM_X4(v1[0], v1[1], v1[2], v1[3],
                   vBase + (uint32_t)(16 * 520 + p8 * 16) * 2);
            hmma16(oacc[0], a, v0);
            hmma16(oacc[1], a, v0 + 2);
            hmma16(oacc[2], a, v1);
            hmma16(oacc[3], a, v1 + 2);
            hmma16(smsum, a, bones);
        }

        float rs0 = __shfl_sync(0xffffffffu, smsum[0], lane & ~3);
        float rs1 = __shfl_sync(0xffffffffu, smsum[2], lane & ~3);
        float inv0 = 1.f / rs0, inv1 = 1.f / rs1;
        int row0 = b * CC + qt * 128 + w * 16 + g;
        #pragma unroll
        for (int vj = 0; vj < 4; vj++) {
            int c = h * 32 + vj * 8 + 2 * tg;
            *(uint32_t*)&o[(size_t)row0 * 256 + c] =
                packh2(oacc[vj][0] * inv0, oacc[vj][1] * inv0);
            *(uint32_t*)&o[(size_t)(row0 + 8) * 256 + c] =
                packh2(oacc[vj][2] * inv1, oacc[vj][3] * inv1);
        }
    }
}

// ---------------- mask dtype detection ----------------
__global__ void detect_mask_kernel(const int* __restrict__ m) {
    __shared__ int found;
    if (threadIdx.x == 0) found = 0;
    __syncthreads();
    int idx = blockIdx.x * blockDim.x + threadIdx.x;
    unsigned v = (unsigned)m[idx];
    if (v > 1u) found = 1;
    __syncthreads();
    if (threadIdx.x == 0 && blockIdx.x == 0) g_maskmode = 0;
    __threadfence();
    if (found) g_maskmode = 1;
}

// ---------------- pool (half output) ----------------
__global__ void pool_kernel(const int* __restrict__ vi, const int* __restrict__ si,
                            const void* __restrict__ maskraw,
                            const float* __restrict__ ve, const float* __restrict__ se,
                            const float* __restrict__ lpe, const float* __restrict__ cpe,
                            __half* __restrict__ x) {
    int bc = blockIdx.x;
    int c  = bc % CC;
    int d  = threadIdx.x;
    const int* viR = vi + bc * LL;
    const int* siR = si + bc * LL;
    __shared__ int mloc[LL];
    if (threadIdx.x < LL) {
        int mv;
        if (g_maskmode == 0) mv = ((const int*)maskraw)[bc * LL + threadIdx.x];
        else                 mv = ((const unsigned char*)maskraw)[bc * LL + threadIdx.x];
        mloc[threadIdx.x] = mv;
    }
    __syncthreads();
    float acc = 0.f; int cnt = 0;
    #pragma unroll
    for (int l = 0; l < LL; l++) {
        if (mloc[l]) {
            cnt++;
            acc += ve[viR[l]*DD + d] + se[siR[l]*DD + d] + lpe[l*DD + d];
        }
    }
    x[(size_t)bc*DD + d] = __float2half(acc / (float)cnt + cpe[c*DD + d]);
}

// ---------------- warp-per-row LN for N=256 half tensors ----------------
template<int RES>
__global__ __launch_bounds__(256) void ln256(
    const __half* __restrict__ xin, const __half* __restrict__ res,
    const float* __restrict__ w, const float* __restrict__ b,
    __half* __restrict__ out)
{
    int row  = blockIdx.x * 8 + (threadIdx.x >> 5);
    int lane = threadIdx.x & 31;
    size_t off = (size_t)row * 256 + lane * 8;

    union { uint4 u; __half h[8]; } xv, rv;
    xv.u = *(const uint4*)(xin + off);
    if (RES) rv.u = *(const uint4*)(res + off);

    float v[8];
    float s = 0.f;
    #pragma unroll
    for (int j = 0; j < 8; j++) {
        float t = __half2float(xv.h[j]);
        if (RES) t += __half2float(rv.h[j]);
        v[j] = t; s += t;
    }
    #pragma unroll
    for (int o2 = 16; o2; o2 >>= 1) s += __shfl_xor_sync(0xffffffffu, s, o2);
    float mean = s * (1.f / 256.f);
    float vs = 0.f;
    #pragma unroll
    for (int j = 0; j < 8; j++) { float d = v[j] - mean; vs += d * d; }
    #pragma unroll
    for (int o2 = 16; o2; o2 >>= 1) vs += __shfl_xor_sync(0xffffffffu, vs, o2);
    float inv = rsqrtf(vs * (1.f / 256.f) + 1e-5f);

    float4 w0 = *(const float4*)(w + lane * 8);
    float4 w1 = *(const float4*)(w + lane * 8 + 4);
    float4 b0 = *(const float4*)(b + lane * 8);
    float4 b1 = *(const float4*)(b + lane * 8 + 4);
    float ww[8] = {w0.x, w0.y, w0.z, w0.w, w1.x, w1.y, w1.z, w1.w};
    float bb[8] = {b0.x, b0.y, b0.z, b0.w, b1.x, b1.y, b1.z, b1.w};

    union { uint4 u; __half h[8]; } ov;
    #pragma unroll
    for (int j = 0; j < 8; j++)
        ov.h[j] = __float2half((v[j] - mean) * inv * ww[j] + bb[j]);
    *(uint4*)(out + off) = ov.u;
}

// ---------------- generic layernorm (final N=1024 fp32 path) ----------------
__global__ void ln_kernel(const void* __restrict__ xin, int inH,
                          const void* __restrict__ res, int resM,
                          const float* __restrict__ w, const float* __restrict__ b,
                          void* __restrict__ out, int outH, int N, int resMod) {
    int row = blockIdx.x;
    int tid = threadIdx.x;
    int rrow = resMod ? (row % resMod) : row;
    int per = N >> 8;
    float v[4];
    float s = 0.f;
    for (int i = 0; i < per; i++) {
        int cI = tid + (i << 8);
        float t = inH ? __half2float(((const __half*)xin)[(size_t)row * N + cI])
                      : ((const float*)xin)[(size_t)row * N + cI];
        if (resM == 1)      t += ((const float*)res)[(size_t)rrow * N + cI];
        else if (resM == 2) t += __half2float(((const __half*)res)[(size_t)rrow * N + cI]);
        v[i] = t; s += t;
    }
    __shared__ float red[256];
    red[tid] = s; __syncthreads();
    for (int o = 128; o; o >>= 1) { if (tid < o) red[tid] += red[tid+o]; __syncthreads(); }
    float mean = red[0] / (float)N;
    __syncthreads();
    float vs = 0.f;
    for (int i = 0; i < per; i++) { float d = v[i] - mean; vs += d*d; }
    red[tid] = vs; __syncthreads();
    for (int o = 128; o; o >>= 1) { if (tid < o) red[tid] += red[tid+o]; __syncthreads(); }
    float inv = rsqrtf(red[0] / (float)N + 1e-5f);
    for (int i = 0; i < per; i++) {
        int cI = tid + (i << 8);
        float ov = (v[i] - mean) * inv * w[cI] + b[cI];
        if (outH) ((__half*)out)[(size_t)row*N + cI] = __float2half(ov);
        else      ((float*)out)[(size_t)row*N + cI] = ov;
    }
}

// ---------------- coalesced softmax: S2 [rows][512] fp32 -> half ----------------
__global__ void softmax_rows(const float* __restrict__ S, __half* __restrict__ Sh) {
    int row  = blockIdx.x * 8 + (threadIdx.x >> 5);
    int lane = threadIdx.x & 31;
    const float* r = S + (size_t)row * CC;
    __half* rh = Sh + (size_t)row * CC;
    float vals[16];
    float mx = -1e30f;
    #pragma unroll
    for (int t = 0; t < 16; t++) { vals[t] = r[lane + (t << 5)]; mx = fmaxf(mx, vals[t]); }
    for (int o = 16; o; o >>= 1) mx = fmaxf(mx, __shfl_xor_sync(0xffffffffu, mx, o));
    float sum = 0.f;
    #pragma unroll
    for (int t = 0; t < 16; t++) { vals[t] = __expf(vals[t] - mx); sum += vals[t]; }
    for (int o = 16; o; o >>= 1) sum += __shfl_xor_sync(0xffffffffu, sum, o);
    float inv = 1.f / sum;
    #pragma unroll
    for (int t = 0; t < 16; t++) rh[lane + (t << 5)] = __float2half(vals[t] * inv);
}

// ============================ host orchestration ============================
#define HG_B   hgemm<0,1,1>
#define HG_BF  hgemm<0,1,0>
#define HG_G   hgemm<1,1,1>
#define HG_N   hgemm<0,0,0>

static const int HG_SMEM = 6 * 128 * 72 * 2;                 // 110592 B
static const int FA_SMEM = (128*40 + 512*40 + 40*520) * 2;   // 92800 B

extern "C" void kernel_launch(void* const* d_in, const int* in_sizes, int n_in,
                              void* d_out, int out_size) {
    const int*   var_idx   = (const int*)  d_in[0];
    const int*   sign_idx  = (const int*)  d_in[1];
    const void*  lit_mask  = (const void*) d_in[2];
    const float* var_emb   = (const float*)d_in[3];
    const float* sign_emb  = (const float*)d_in[4];
    const float* litpos    = (const float*)d_in[5];
    const float* clausepos = (const float*)d_in[6];
    const float* enc_in_w  = (const float*)d_in[7];
    const float* enc_in_b  = (const float*)d_in[8];
    const float* enc_out_w = (const float*)d_in[9];
    const float* enc_out_b = (const float*)d_in[10];
    const float* enc_ff1_w = (const float*)d_in[11];
    const float* enc_ff1_b = (const float*)d_in[12];
    const float* enc_ff2_w = (const float*)d_in[13];
    const float* enc_ff2_b = (const float*)d_in[14];
    const float* n1w = (const float*)d_in[15];
    const float* n1b = (const float*)d_in[16];
    const float* n2w = (const float*)d_in[17];
    const float* n2b = (const float*)d_in[18];
    const float* th_ln_w = (const float*)d_in[19];
    const float* th_ln_b = (const float*)d_in[20];
    const float* th_w = (const float*)d_in[21];
    const float* th_b = (const float*)d_in[22];
    const float* pq   = (const float*)d_in[23];
    const float* pa_in_w  = (const float*)d_in[24];
    const float* pa_in_b  = (const float*)d_in[25];
    const float* pa_out_w = (const float*)d_in[26];
    const float* pa_out_b = (const float*)d_in[27];
    const float* pn_w = (const float*)d_in[28];
    const float* pn_b = (const float*)d_in[29];
    float* out = (float*)d_out;

    __half *x,*t0,*t1,*t2h,*ch,*qh,*qw,*S2h,*pch,*p1;
    float *S2,*p2;
    __half *hwin,*hwout,*hwf1,*hwf2,*hwth,*hwpa,*hwpo,*hwpq;
    cudaGetSymbolAddress((void**)&x,   g_x);
    cudaGetSymbolAddress((void**)&t0,  g_t0);
    cudaGetSymbolAddress((void**)&t1,  g_t1);
    cudaGetSymbolAddress((void**)&t2h, g_t2h);
    cudaGetSymbolAddress((void**)&ch,  g_ch);
    cudaGetSymbolAddress((void**)&qh,  g_qh);
    cudaGetSymbolAddress((void**)&qw,  g_qw);
    cudaGetSymbolAddress((void**)&S2,  g_S2);
    cudaGetSymbolAddress((void**)&S2h, g_S2h);
    cudaGetSymbolAddress((void**)&pch, g_pch);
    cudaGetSymbolAddress((void**)&p1,  g_p1);
    cudaGetSymbolAddress((void**)&p2,  g_p2);
    cudaGetSymbolAddress((void**)&hwin,  g_hw_in);
    cudaGetSymbolAddress((void**)&hwout, g_hw_out);
    cudaGetSymbolAddress((void**)&hwf1,  g_hw_f1);
    cudaGetSymbolAddress((void**)&hwf2,  g_hw_f2);
    cudaGetSymbolAddress((void**)&hwth,  g_hw_th);
    cudaGetSymbolAddress((void**)&hwpa,  g_hw_pa);
    cudaGetSymbolAddress((void**)&hwpo,  g_hw_po);
    cudaGetSymbolAddress((void**)&hwpq,  g_hw_pq);

    cudaFuncSetAttribute(HG_B,  cudaFuncAttributeMaxDynamicSharedMemorySize, HG_SMEM);
    cudaFuncSetAttribute(HG_BF, cudaFuncAttributeMaxDynamicSharedMemorySize, HG_SMEM);
    cudaFuncSetAttribute(HG_G,  cudaFuncAttributeMaxDynamicSharedMemorySize, HG_SMEM);
    cudaFuncSetAttribute(HG_N,  cudaFuncAttributeMaxDynamicSharedMemorySize, HG_SMEM);
    cudaFuncSetAttribute(fused_attn_h, cudaFuncAttributeMaxDynamicSharedMemorySize, FA_SMEM);

    const int M = BB*CC;
    const float escale = 0.17677669529663687f;   // 1/sqrt(32)
    const float pscale = 0.08838834764831845f;   // 1/sqrt(128)

    // single conversion launch for all weights
    cvt_all<<<2048, 256>>>(enc_in_w, enc_out_w, enc_ff1_w, enc_ff2_w,
                           th_w, pa_in_w, pa_out_w, pq,
                           hwin, hwout, hwf1, hwf2, hwth, hwpa, hwpo, hwpq);
    detect_mask_kernel<<<16, 256>>>((const int*)lit_mask);
    pool_kernel<<<M, 256>>>(var_idx, sign_idx, lit_mask, var_emb,
                            sign_emb, litpos, clausepos, x);
    // prefix query-side precompute (independent of encoder; weights only)
    HG_B<<<dim3(8,1,1),256,HG_SMEM>>>(hwpq, hwpa, pa_in_b, qh, PP,HH,HH,
                                      HH,HH,HH, 1,0,0,0,0,0,0, 0, 1.f);
    hgemm_trb<<<dim3(8,1,NHD),256>>>(qh, hwpa + (size_t)HH*HH, qw,
                                     16, HH, 128, HH, HH, HH,
                                     NHD, 0, 128, 0, (long)128*HH, 0, (long)16*HH);

    for (int i = 0; i < NLL; i++) {
        const __half* wqkv = hwin  + (size_t)i*768*DD;
        const float*  bqkv = enc_in_b  + (size_t)i*768;
        const __half* wo   = hwout + (size_t)i*DD*DD;
        const float*  bo   = enc_out_b + (size_t)i*DD;
        const __half* w1   = hwf1  + (size_t)i*HH*DD;
        const float*  b1   = enc_ff1_b + (size_t)i*HH;
        const __half* w2   = hwf2  + (size_t)i*DD*HH;
        const float*  b2   = enc_ff2_b + (size_t)i*DD;

        HG_B<<<dim3(6,128,1),256,HG_SMEM>>>(x, wqkv, bqkv, t0, M,768,DD,
                                            DD,DD,768, 1,0,0,0,0,0,0, 0, 1.f);
        fused_attn_h<<<BB*NHD, 256, FA_SMEM>>>(t0, t1, escale);
        HG_B<<<dim3(2,128,1),256,HG_SMEM>>>(t1, wo, bo, t2h, M,DD,DD,
                                            DD,DD,DD, 1,0,0,0,0,0,0, 0, 1.f);
        ln256<1><<<M/8,256>>>(t2h, x, n1w + i*DD, n1b + i*DD, x);
        HG_G<<<dim3(8,128,1),256,HG_SMEM>>>(x, w1, b1, t0, M,HH,DD,
                                            DD,DD,HH, 1,0,0,0,0,0,0, 0, 1.f);
        HG_B<<<dim3(2,128,1),256,HG_SMEM>>>(t0, w2, b2, t2h, M,DD,HH,
                                            HH,HH,DD, 1,0,0,0,0,0,0, 0, 1.f);
        ln256<1><<<M/8,256>>>(t2h, x, n2w + i*DD, n2b + i*DD, x);
    }

    // ch = LN(x) @ th_w^T + th_b  (half)
    ln256<0><<<M/8,256>>>(x, nullptr, th_ln_w, th_ln_b, t2h);
    HG_B<<<dim3(8,128,1),256,HG_SMEM>>>(t2h, hwth, th_b, ch, M,HH,DD,
                                        DD,DD,HH, 1,0,0,0,0,0,0, 0, 1.f);

    // ---- prefix cross-attention (restructured; S2 now row-major [b][hp][c]) ----
    // S2[b][hp][c] = pscale * qw @ ch_b^T
    HG_N<<<dim3(4,1,BB),256,HG_SMEM>>>(qw, ch, nullptr, S2, 128,CC,HH,
                                       HH,HH,CC, 1,
                                       0, 0, (long)CC*HH, 0, (long)128*CC, 0, 0, pscale);
    softmax_rows<<<(BB*128)/8, 256>>>(S2, S2h);
    // PCH[b][hp][e] = P_b @ ch_b
    hgemm_trb<<<dim3(8,1,BB),256>>>(S2h, ch, pch,
                                    128, HH, CC, CC, HH, HH,
                                    1, (long)128*CC, 0, (long)CC*HH, 0, (long)128*HH, 0);
    HG_B<<<dim3(1,1,BB*NHD),256,HG_SMEM>>>(pch, hwpa + (size_t)2*HH*HH, pa_in_b + 2*HH, p1,
                                           16,128,HH, HH,HH,HH, NHD,
                                           (long)128*HH, (long)16*HH, 0, (long)128*HH,
                                           (long)PP*HH, 128, 128, 1.f);
    HG_BF<<<dim3(8,4,1),256,HG_SMEM>>>(p1, hwpo, pa_out_b, p2, BB*PP,HH,HH,
                                       HH,HH,HH, 1,0,0,0,0,0,0, 0, 1.f);
    ln_kernel<<<BB*PP,256>>>(p2, 0, pq, 1, pn_w, pn_b, out, 0, HH, PP);
}